// round 7
// baseline (speedup 1.0000x reference)
#include <cuda_runtime.h>
#include <mma.h>
#include <math.h>
#include <stdint.h>

using namespace nvcuda;

// ---------------- static scratch (16B aligned) ----------------
__device__ __align__(16) float g_q    [40960u*224u];
__device__ __align__(16) float g_kv   [40960u*448u];
__device__ __align__(16) float g_attn [32*8*28*28];
__device__ __align__(16) float g_x1   [9175040];
__device__ __align__(16) float g_xn   [9175040];      // 286720 x 32
__device__ __align__(16) float g_xz   [36700160];     // 286720 x 128
__device__ __align__(16) float g_xc   [18350080];     // 286720 x 64
__device__ __align__(16) float g_xdbl [9748480];      // 286720 x 34
__device__ __align__(16) float g_dt   [18350080];
__device__ __align__(16) float g_Bm   [4587520];
__device__ __align__(16) float g_Cm   [4587520];
__device__ __align__(16) float g_y    [18350080];
__device__ __align__(16) float g_S    [2293760];      // 32*64*70*16
__device__ __align__(16) float g_sumdt[143360];       // 32*64*70
__device__ __align__(16) float g_H0   [2293760];
__device__ __align__(16) float g_xm2  [9175040];      // 286720 x 32
__device__ __align__(16) float g_x2   [9175040];
__device__ __align__(16) float g_x3   [9175040];
__device__ __align__(16) float g_xw   [11010048];     // 49152 x 224
__device__ __align__(16) float g_qkvw [33030144];     // 49152 x 672
__device__ __align__(16) float g_obuf [11010048];
__device__ __align__(16) float g_oproj[11010048];

__device__ __forceinline__ float siluf(float v){ return v / (1.f + __expf(-v)); }

struct GemmPtrs4 { const float* B[4]; const float* bias[4]; };

// ---------------- TF32 tensor-core GEMM (3xTF32 split for fp32 accuracy) ------
// C[M,N] = A[M,K] @ B[K,N] (+bias). M % 128 == 0, K % 16 == 0, lda % 4 == 0,
// A 16B-aligned. N arbitrary (predicated loads + staged predicated stores).
// Block: 256 threads = 8 warps as 4(m) x 2(n), each warp 32x32 output.
#define ALD 24   // A tile ld (16 + 8 pad)
#define BLD 72   // B tile / stage ld (64 + 8 pad)

__device__ __forceinline__ void tgemm_core(
    const float* __restrict__ A, const float* __restrict__ B,
    float* __restrict__ C, const float* __restrict__ bias,
    int N, int K, int lda, int ldb, int ldc, float* pool)
{
    const int bm = blockIdx.y * 128, bn = blockIdx.x * 64;
    const int tid = threadIdx.x;
    const int warp = tid >> 5;
    const int wm = warp >> 1, wn = warp & 1;

    float* Ah = pool;                 // [128][ALD]
    float* Al = pool + 128*ALD;      // [128][ALD]
    float* Bh = pool + 2*128*ALD;    // [16][BLD]
    float* Bl = pool + 2*128*ALD + 16*BLD;

    wmma::fragment<wmma::accumulator,16,16,8,float> c[2][2];
    #pragma unroll
    for (int i = 0; i < 2; i++)
        #pragma unroll
        for (int j = 0; j < 2; j++) wmma::fill_fragment(c[i][j], 0.f);

    for (int k0 = 0; k0 < K; k0 += 16) {
        // load A 128x16 as hi/lo tf32
        #pragma unroll
        for (int i = 0; i < 2; i++) {
            int idx = tid + i * 256;          // 512 float4
            int r = idx >> 2, c4 = (idx & 3) * 4;
            float4 v = *(const float4*)(A + (size_t)(bm + r) * lda + k0 + c4);
            float h0 = wmma::__float_to_tf32(v.x);
            float h1 = wmma::__float_to_tf32(v.y);
            float h2 = wmma::__float_to_tf32(v.z);
            float h3 = wmma::__float_to_tf32(v.w);
            Ah[r*ALD + c4+0] = h0; Al[r*ALD + c4+0] = wmma::__float_to_tf32(v.x - h0);
            Ah[r*ALD + c4+1] = h1; Al[r*ALD + c4+1] = wmma::__float_to_tf32(v.y - h1);
            Ah[r*ALD + c4+2] = h2; Al[r*ALD + c4+2] = wmma::__float_to_tf32(v.z - h2);
            Ah[r*ALD + c4+3] = h3; Al[r*ALD + c4+3] = wmma::__float_to_tf32(v.w - h3);
        }
        // load B 16x64 (N-predicated) as hi/lo tf32
        {
            int r = tid >> 4, c0 = (tid & 15) * 4;
            #pragma unroll
            for (int i = 0; i < 4; i++) {
                int n = bn + c0 + i;
                float v = (n < N) ? B[(size_t)(k0 + r) * ldb + n] : 0.f;
                float h = wmma::__float_to_tf32(v);
                Bh[r*BLD + c0 + i] = h;
                Bl[r*BLD + c0 + i] = wmma::__float_to_tf32(v - h);
            }
        }
        __syncthreads();
        #pragma unroll
        for (int ks = 0; ks < 2; ks++) {
            wmma::fragment<wmma::matrix_a,16,16,8,wmma::precision::tf32,wmma::row_major> ah[2], al[2];
            wmma::fragment<wmma::matrix_b,16,16,8,wmma::precision::tf32,wmma::row_major> bh[2], bl[2];
            #pragma unroll
            for (int i = 0; i < 2; i++) {
                wmma::load_matrix_sync(ah[i], Ah + (wm*32 + i*16)*ALD + ks*8, ALD);
                wmma::load_matrix_sync(al[i], Al + (wm*32 + i*16)*ALD + ks*8, ALD);
            }
            #pragma unroll
            for (int j = 0; j < 2; j++) {
                wmma::load_matrix_sync(bh[j], Bh + (ks*8)*BLD + wn*32 + j*16, BLD);
                wmma::load_matrix_sync(bl[j], Bl + (ks*8)*BLD + wn*32 + j*16, BLD);
            }
            #pragma unroll
            for (int i = 0; i < 2; i++)
                #pragma unroll
                for (int j = 0; j < 2; j++) {
                    wmma::mma_sync(c[i][j], ah[i], bh[j], c[i][j]);
                    wmma::mma_sync(c[i][j], ah[i], bl[j], c[i][j]);
                    wmma::mma_sync(c[i][j], al[i], bh[j], c[i][j]);
                }
        }
        __syncthreads();
    }
    // epilogue: stage to smem (reuse pool), then predicated writes
    float* St = pool;   // [128][BLD]
    #pragma unroll
    for (int i = 0; i < 2; i++)
        #pragma unroll
        for (int j = 0; j < 2; j++)
            wmma::store_matrix_sync(St + (wm*32 + i*16)*BLD + wn*32 + j*16,
                                    c[i][j], BLD, wmma::mem_row_major);
    __syncthreads();
    for (int idx = tid; idx < 128*64; idx += 256) {
        int r = idx >> 6, cc = idx & 63;
        int n = bn + cc;
        if (n < N) {
            float v = St[r*BLD + cc];
            if (bias) v += bias[n];
            C[(size_t)(bm + r) * ldc + n] = v;
        }
    }
}

__global__ __launch_bounds__(256) void tgemm(
    const float* __restrict__ A, const float* __restrict__ B,
    float* __restrict__ C, const float* __restrict__ bias,
    int N, int K, int lda, int ldb, int ldc)
{
    __shared__ __align__(32) float pool[128*BLD];   // 36.9 KB (loads fit inside)
    tgemm_core(A, B, C, bias, N, K, lda, ldb, ldc, pool);
}

__global__ __launch_bounds__(256) void tgemm_b4(
    const float* __restrict__ A, GemmPtrs4 p, float* __restrict__ C,
    int N, int K, int lda, int ldb, int ldc,
    long long strideA, long long strideC)
{
    __shared__ __align__(32) float pool[128*BLD];
    int z = blockIdx.z;
    tgemm_core(A + (size_t)z * strideA, p.B[z], C + (size_t)z * strideC,
               p.bias[z], N, K, lda, ldb, ldc, pool);
}

// ---------------- stage 1: channel attention ----------------
__global__ void k_gram(const float* __restrict__ q, const float* __restrict__ kv,
                       float* __restrict__ attn) {
    int b = blockIdx.x, h = blockIdx.y;
    __shared__ float kt[32][28], qt[32][28];
    __shared__ float G[840];
    int tid = threadIdx.x;   // 256
    float acc[4] = {0.f,0.f,0.f,0.f};
    for (int nt = 0; nt < 40; nt++) {
        for (int idx = tid; idx < 896; idx += 256) {
            int n = idx / 28, i = idx % 28;
            size_t row = (size_t)b*1280 + nt*32 + n;
            kt[n][i] = kv[row*448 + h*28 + i];
            qt[n][i] = q [row*224 + h*28 + i];
        }
        __syncthreads();
        #pragma unroll
        for (int s = 0; s < 4; s++) {
            int w = tid + 256*s;
            if (w < 784) {
                int i = w/28, j = w%28; float a = acc[s];
                #pragma unroll
                for (int n = 0; n < 32; n++) a += kt[n][i]*qt[n][j];
                acc[s] = a;
            } else if (w < 812) {
                int i = w - 784; float a = acc[s];
                #pragma unroll
                for (int n = 0; n < 32; n++) a += kt[n][i]*kt[n][i];
                acc[s] = a;
            } else if (w < 840) {
                int j = w - 812; float a = acc[s];
                #pragma unroll
                for (int n = 0; n < 32; n++) a += qt[n][j]*qt[n][j];
                acc[s] = a;
            }
        }
        __syncthreads();
    }
    #pragma unroll
    for (int s = 0; s < 4; s++) { int w = tid + 256*s; if (w < 840) G[w] = acc[s]; }
    __syncthreads();
    if (tid < 28) {
        int i = tid;
        float nk = fmaxf(sqrtf(G[784+i]), 1e-12f);
        float lg[28], m = -1e30f;
        #pragma unroll
        for (int j = 0; j < 28; j++) {
            float nq = fmaxf(sqrtf(G[812+j]), 1e-12f);
            lg[j] = G[i*28+j] / (nk*nq) * 0.18898223650461363f;
            m = fmaxf(m, lg[j]);
        }
        float sum = 0.f;
        #pragma unroll
        for (int j = 0; j < 28; j++) { lg[j] = __expf(lg[j]-m); sum += lg[j]; }
        float inv = 1.f/sum;
        #pragma unroll
        for (int j = 0; j < 28; j++)
            attn[(((size_t)b*8 + h)*28 + i)*28 + j] = lg[j]*inv;
    }
}

// x1 = attn-applied + residual; 8 rows per barrier interval
__global__ void k_apply(const float* __restrict__ x, const float* __restrict__ kv,
                        const float* __restrict__ attn, float* __restrict__ x1) {
    int chunk = blockIdx.x, b = blockIdx.y;
    __shared__ float att[6272];
    __shared__ float vr[8][224];
    int tid = threadIdx.x;   // 224
    for (int idx = tid; idx < 6272; idx += 224) att[idx] = attn[(size_t)b*6272 + idx];
    int h = tid / 28, i = tid % 28;
    for (int nn = 0; nn < 64; nn += 8) {
        size_t row0 = (size_t)b*1280 + chunk*64 + nn;
        __syncthreads();
        for (int idx = tid; idx < 1792; idx += 224) {
            int rr = idx / 224, cc = idx % 224;
            vr[rr][cc] = kv[(row0 + rr)*448 + 224 + cc];
        }
        __syncthreads();
        #pragma unroll
        for (int rr = 0; rr < 8; rr++) {
            float a = 0.f;
            #pragma unroll
            for (int j = 0; j < 28; j++) a += att[(h*28+i)*28 + j] * vr[rr][h*28 + j];
            size_t o = (row0 + rr)*224 + tid;
            x1[o] = x[o] + a;
        }
    }
}

// ---------------- transpose + LN into (b, L=8960, 32) ----------------
__global__ void k_ln1(const float* __restrict__ x1, const float* __restrict__ g,
                      const float* __restrict__ be, float* __restrict__ xn) {
    int ww = blockIdx.x, b = blockIdx.y;
    __shared__ float s[32*225];
    int tid = threadIdx.x;   // 256
    for (int idx = tid; idx < 32*224; idx += 256) {
        int m = idx / 224, cc = idx % 224;
        s[m*225 + cc] = x1[((size_t)b*1280 + m*40 + ww)*224 + cc];
    }
    __syncthreads();
    for (int cc = tid; cc < 224; cc += 256) {
        float mean = 0.f;
        #pragma unroll
        for (int m = 0; m < 32; m++) mean += s[m*225+cc];
        mean *= (1.f/32.f);
        float var = 0.f;
        #pragma unroll
        for (int m = 0; m < 32; m++) { float d = s[m*225+cc]-mean; var += d*d; }
        var *= (1.f/32.f);
        float inv = rsqrtf(var + 1e-5f);
        size_t ob = ((size_t)b*8960 + ww*224 + cc)*32;
        #pragma unroll
        for (int m = 0; m < 32; m++)
            xn[ob + m] = (s[m*225+cc]-mean)*inv*g[m] + be[m];
    }
}

// ---------------- mamba pieces ----------------
__global__ void k_conv1d(const float* __restrict__ xz, const float* __restrict__ cw,
                         const float* __restrict__ cb, float* __restrict__ xc) {
    size_t id = (size_t)blockIdx.x*256 + threadIdx.x;
    size_t row = id >> 6; int d = (int)(id & 63);
    size_t b = row / 8960; int l = (int)(row % 8960);
    float acc = cb[d];
    #pragma unroll
    for (int t = 0; t < 4; t++) {
        int ls = l - 3 + t;
        if (ls >= 0) acc += xz[((size_t)b*8960 + ls)*128 + d] * cw[d*4 + t];
    }
    xc[row*64 + d] = siluf(acc);
}

__global__ void k_dtbc(const float* __restrict__ xdbl, const float* __restrict__ dtW,
                       const float* __restrict__ dtb, float* __restrict__ dt,
                       float* __restrict__ Bm, float* __restrict__ Cm) {
    size_t id = (size_t)blockIdx.x*256 + threadIdx.x;
    size_t row = id / 96; int j = (int)(id % 96);
    const float* xd = xdbl + row*34;
    if (j < 64) {
        float v = xd[0]*dtW[j] + xd[1]*dtW[64+j] + dtb[j];
        dt[row*64 + j] = (v > 20.f) ? v : log1pf(__expf(v));
    } else if (j < 80) {
        Bm[row*16 + (j-64)] = xd[2 + (j-64)];
    } else {
        Cm[row*16 + (j-80)] = xd[18 + (j-80)];
    }
}

__global__ void k_scan1(const float* __restrict__ dt, const float* __restrict__ xc,
                        const float* __restrict__ Bm, const float* __restrict__ Alog,
                        float* __restrict__ S, float* __restrict__ sumdt) {
    int gw = (blockIdx.x*256 + threadIdx.x) >> 5;
    int lane = threadIdx.x & 31;
    int b = gw / 2240; int rem = gw % 2240;
    int chunk = rem >> 5; int dp = rem & 31;
    int d = dp*2 + (lane >> 4); int n = lane & 15;
    float Av = -__expf(Alog[d*16 + n]);
    float h = 0.f, sdt = 0.f;
    size_t base = (size_t)b*8960 + chunk*128;
    #pragma unroll 4
    for (int l = 0; l < 128; l++) {
        size_t row = base + l;
        float dtv = dt[row*64 + d];
        float u   = xc[row*64 + d];
        float Bn  = Bm[row*16 + n];
        h = __expf(Av*dtv)*h + dtv*u*Bn;
        sdt += dtv;
    }
    size_t idx = (size_t)(b*64 + d)*70 + chunk;
    S[idx*16 + n] = h;
    if (n == 0) sumdt[idx] = sdt;
}

__global__ void k_scan2(const float* __restrict__ S, const float* __restrict__ sumdt,
                        const float* __restrict__ Alog, float* __restrict__ H0) {
    int t = blockIdx.x*256 + threadIdx.x;
    int b = t >> 10; int d = (t >> 4) & 63; int n = t & 15;
    float Av = -__expf(Alog[d*16 + n]);
    float carry = 0.f;
    size_t base = (size_t)(b*64 + d)*70;
    for (int ch = 0; ch < 70; ch++) {
        size_t idx = base + ch;
        H0[idx*16 + n] = carry;
        carry = carry*__expf(Av*sumdt[idx]) + S[idx*16 + n];
    }
}

__global__ void k_scan3(const float* __restrict__ dt, const float* __restrict__ xc,
                        const float* __restrict__ Bm, const float* __restrict__ Cm,
                        const float* __restrict__ Alog, const float* __restrict__ H0,
                        float* __restrict__ y) {
    int gw = (blockIdx.x*256 + threadIdx.x) >> 5;
    int lane = threadIdx.x & 31;
    int b = gw / 2240; int rem = gw % 2240;
    int chunk = rem >> 5; int dp = rem & 31;
    int d = dp*2 + (lane >> 4); int n = lane & 15;
    float Av = -__expf(Alog[d*16 + n]);
    size_t idx = (size_t)(b*64 + d)*70 + chunk;
    float h = H0[idx*16 + n];
    size_t base = (size_t)b*8960 + chunk*128;
    #pragma unroll 4
    for (int l = 0; l < 128; l++) {
        size_t row = base + l;
        float dtv = dt[row*64 + d];
        float u   = xc[row*64 + d];
        float Bn  = Bm[row*16 + n];
        h = __expf(Av*dtv)*h + dtv*u*Bn;
        float yv = h * Cm[row*16 + n];
        yv += __shfl_xor_sync(0xffffffffu, yv, 8);
        yv += __shfl_xor_sync(0xffffffffu, yv, 4);
        yv += __shfl_xor_sync(0xffffffffu, yv, 2);
        yv += __shfl_xor_sync(0xffffffffu, yv, 1);
        if (n == 0) y[row*64 + d] = yv;
    }
}

// gate + out_proj + skip + LN + proj; each warp handles 8 rows
__global__ void k_final(const float* __restrict__ y, const float* __restrict__ xc,
                        const float* __restrict__ xz, const float* __restrict__ xn,
                        const float* __restrict__ Dp, const float* __restrict__ opW,
                        const float* __restrict__ skipp, const float* __restrict__ g,
                        const float* __restrict__ be, const float* __restrict__ projW,
                        const float* __restrict__ projb, float* __restrict__ xm2) {
    __shared__ float sop[2048], spj[1024];
    int tid = threadIdx.x;   // 256
    for (int i = tid; i < 2048; i += 256) sop[i] = opW[i];
    for (int i = tid; i < 1024; i += 256) spj[i] = projW[i];
    __syncthreads();
    int warp = tid >> 5, lane = tid & 31;
    float skip = skipp[0];
    float dpl = Dp[lane], dph = Dp[32+lane];
    float gl = g[lane], bel = be[lane], pbl = projb[lane];
    #pragma unroll
    for (int t = 0; t < 8; t++) {
        size_t r = ((size_t)blockIdx.x*8 + warp)*8 + t;
        float y0 = y[r*64 + lane],      y1 = y[r*64 + 32 + lane];
        float c0 = xc[r*64 + lane],     c1 = xc[r*64 + 32 + lane];
        float z0 = xz[r*128 + 64 + lane], z1 = xz[r*128 + 96 + lane];
        float yy0 = (y0 + c0*dpl) * siluf(z0);
        float yy1 = (y1 + c1*dph) * siluf(z1);
        float acc = 0.f;
        #pragma unroll
        for (int d = 0; d < 32; d++) acc += __shfl_sync(0xffffffffu, yy0, d) * sop[d*32 + lane];
        #pragma unroll
        for (int d = 0; d < 32; d++) acc += __shfl_sync(0xffffffffu, yy1, d) * sop[(d+32)*32 + lane];
        float xm = acc + skip * xn[r*32 + lane];
        float mean = xm;
        #pragma unroll
        for (int o = 16; o; o >>= 1) mean += __shfl_xor_sync(0xffffffffu, mean, o);
        mean *= (1.f/32.f);
        float dv = xm - mean, var = dv*dv;
        #pragma unroll
        for (int o = 16; o; o >>= 1) var += __shfl_xor_sync(0xffffffffu, var, o);
        var *= (1.f/32.f);
        float v = dv * rsqrtf(var + 1e-5f) * gl + bel;
        float acc2 = pbl;
        #pragma unroll
        for (int mm = 0; mm < 32; mm++) acc2 += __shfl_sync(0xffffffffu, v, mm) * spj[mm*32 + lane];
        xm2[r*32 + lane] = acc2;
    }
}

__global__ void k_addback(const float* __restrict__ x1, const float* __restrict__ xm2,
                          float* __restrict__ x2) {
    int ww = blockIdx.x, b = blockIdx.y;
    __shared__ float s[224*33];
    int tid = threadIdx.x;   // 256
    for (int idx = tid; idx < 224*32; idx += 256) {
        int cc = idx >> 5, m = idx & 31;
        s[cc*33 + m] = xm2[((size_t)b*8960 + ww*224 + cc)*32 + m];
    }
    __syncthreads();
    for (int idx = tid; idx < 32*224; idx += 256) {
        int m = idx / 224, cc = idx % 224;
        size_t o = ((size_t)b*1280 + m*40 + ww)*224 + cc;
        x2[o] = x1[o] + s[cc*33 + m];
    }
}

// ---------------- conv3d 5x5x5, pad 2, smem-tiled per ky-plane ----------------
__global__ void k_conv3d(const float* __restrict__ x2, const float* __restrict__ cw,
                         const float* __restrict__ cb, float* __restrict__ x3) {
    int y = blockIdx.x, b = blockIdx.y;
    int xx = threadIdx.x;   // 224
    __shared__ float ws[125];
    __shared__ float sp[32][228];
    if (xx < 125) ws[xx] = cw[xx];
    if (xx < 32) { sp[xx][0]=0.f; sp[xx][1]=0.f; sp[xx][226]=0.f; sp[xx][227]=0.f; }
    float acc[32];
    #pragma unroll
    for (int d = 0; d < 32; d++) acc[d] = 0.f;
    for (int ky = 0; ky < 5; ky++) {
        int yy = y + ky - 2;
        if (yy < 0 || yy >= 40) continue;
        __syncthreads();
        for (int i = 0; i < 32; i++)
            sp[i][xx+2] = x2[(((size_t)b*32 + i)*40 + yy)*224 + xx];
        __syncthreads();
        #pragma unroll
        for (int kx = 0; kx < 5; kx++) {
            float v[36];
            v[0]=v[1]=v[34]=v[35]=0.f;
            #pragma unroll
            for (int i = 0; i < 32; i++) v[i+2] = sp[i][xx + kx];
            #pragma unroll
            for (int kz = 0; kz < 5; kz++) {
                float wv = ws[(kz*5 + ky)*5 + kx];
                #pragma unroll
                for (int d = 0; d < 32; d++) acc[d] += v[d+kz]*wv;
            }
        }
    }
    float bias = cb[0];
    #pragma unroll
    for (int d = 0; d < 32; d++)
        x3[(((size_t)b*32 + d)*40 + y)*224 + xx] = acc[d] + bias;
}

// ---------------- DWT + reflect-pad + window pack ----------------
__global__ void k_dwt(const float* __restrict__ x3, float* __restrict__ xw) {
    size_t id = (size_t)blockIdx.x*256 + threadIdx.x;   // 11010048
    int c = (int)(id % 224); size_t r = id / 224;
    int sub = (int)(r / 12288); int rw = (int)(r % 12288);
    int win = rw >> 6, tok = rw & 63;
    int bb = win / 6, w6 = win % 6;
    int wi = w6 / 3, wj = w6 % 3;
    int ti = tok >> 3, tj = tok & 7;
    int i2 = wi*8 + ti;
    int j2 = wj*8 + tj;
    int j = (j2 < 20) ? j2 : 38 - j2;   // reflect pad
    size_t base = (((size_t)bb*32 + 2*i2)*40 + 2*j)*224 + c;
    float a  = x3[base],        bv = x3[base + 224];
    float c2 = x3[base + 8960], d2 = x3[base + 9184];
    float val;
    if      (sub == 0) val = a + bv + c2 + d2;
    else if (sub == 1) val = a + bv - c2 - d2;
    else if (sub == 2) val = a - bv + c2 - d2;
    else               val = a - bv - c2 + d2;
    xw[id] = 0.5f * val;
}

// ---------------- window attention (float4 smem reads) ----------------
__global__ void k_wattn(const float* __restrict__ qkvw, const float* __restrict__ pe,
                        float* __restrict__ obuf) {
    int win = blockIdx.x, head = blockIdx.y;
    __shared__ __align__(16) float qs[64*28], ks[64*28], vs[64*28];
    __shared__ float lgs[64*65];
    int tid = threadIdx.x;   // 64
    size_t wbase = (size_t)win * 64;
    for (int idx = tid; idx < 1792; idx += 64) {
        int tok = idx / 28, dd = idx % 28;
        size_t rb = (wbase + tok)*672 + head*28 + dd;
        qs[idx] = qkvw[rb] * 0.18898223650461363f;
        ks[idx] = qkvw[rb + 224];
        vs[idx] = qkvw[rb + 448];
    }
    __syncthreads();
    int i = tid;
    float qr[28];
    #pragma unroll
    for (int dd = 0; dd < 28; dd++) qr[dd] = qs[i*28 + dd];
    const float* per = pe + ((size_t)head*64 + i)*64;
    float m = -1e30f;
    for (int j = 0; j < 64; j++) {
        const float4* k4 = (const float4*)&ks[j*28];
        float dot = 0.f;
        #pragma unroll
        for (int q4 = 0; q4 < 7; q4++) {
            float4 kk = k4[q4];
            dot += qr[q4*4+0]*kk.x + qr[q4*4+1]*kk.y
                 + qr[q4*4+2]*kk.z + qr[q4*4+3]*kk.w;
        }
        float l = dot + per[j];
        lgs[i*65 + j] = l;
        m = fmaxf(m, l);
    }
    float sum = 0.f;
    for (int j = 0; j < 64; j++) {
        float e = __expf(lgs[i*65 + j] - m);
        lgs[i*65 + j] = e;
        sum += e;
    }
    float inv = 1.f / sum;
    float acc[28];
    #pragma unroll
    for (int dd = 0; dd < 28; dd++) acc[dd] = 0.f;
    for (int j = 0; j < 64; j++) {
        float a = lgs[i*65 + j] * inv;
        const float4* v4 = (const float4*)&vs[j*28];
        #pragma unroll
        for (int q4 = 0; q4 < 7; q4++) {
            float4 vv = v4[q4];
            acc[q4*4+0] += a*vv.x; acc[q4*4+1] += a*vv.y;
            acc[q4*4+2] += a*vv.z; acc[q4*4+3] += a*vv.w;
        }
    }
    size_t ob = (wbase + i)*224 + head*28;
    #pragma unroll
    for (int dd = 0; dd < 28; dd++) obuf[ob + dd] = acc[dd];
}

// ---------------- IWT + crop + final layout ----------------
__global__ void k_iwt(const float* __restrict__ oproj, float* __restrict__ out) {
    size_t id = (size_t)blockIdx.x*256 + threadIdx.x;   // 2293760
    int c = (int)(id % 224); size_t r = id / 224;
    int j = (int)(r % 20); r /= 20;
    int i = (int)(r % 16); int bb = (int)(r / 16);
    int wi = i >> 3, ti = i & 7, wj = j >> 3, tj = j & 7;
    size_t row0 = ((size_t)(bb*6 + wi*3 + wj))*64 + ti*8 + tj;
    float A  = oproj[row0*224 + c];
    float Hh = oproj[(row0 + 12288)*224 + c];
    float V  = oproj[(row0 + 24576)*224 + c];
    float D  = oproj[(row0 + 36864)*224 + c];
    size_t oo = (((size_t)bb*32 + 2*i)*40 + 2*j)*224 + c;
    out[oo]          = 0.5f*(A + Hh + V + D);
    out[oo + 224]    = 0.5f*(A + Hh - V - D);
    out[oo + 8960]   = 0.5f*(A - Hh + V - D);
    out[oo + 9184]   = 0.5f*(A - Hh - V + D);
}

// ---------------- launcher ----------------
extern "C" void kernel_launch(void* const* d_in, const int* in_sizes, int n_in,
                              void* d_out, int out_size) {
    const float* x       = (const float*)d_in[0];
    const float* Wq      = (const float*)d_in[1];
    const float* Wkv     = (const float*)d_in[2];
    const float* ln_g    = (const float*)d_in[3];
    const float* ln_b    = (const float*)d_in[4];
    const float* in_proj = (const float*)d_in[5];
    const float* conv1dW = (const float*)d_in[6];
    const float* conv1db = (const float*)d_in[7];
    const float* x_projW = (const float*)d_in[8];
    const float* dt_projW= (const float*)d_in[9];
    const float* dt_projb= (const float*)d_in[10];
    const float* A_log   = (const float*)d_in[11];
    const float* Dp      = (const float*)d_in[12];
    const float* out_projW=(const float*)d_in[13];
    const float* skip    = (const float*)d_in[14];
    const float* projW   = (const float*)d_in[15];
    const float* projb   = (const float*)d_in[16];
    const float* conv3dW = (const float*)d_in[17];
    const float* conv3db = (const float*)d_in[18];
    const float* Wq1     = (const float*)d_in[19];
    const float* Wkv1    = (const float*)d_in[20];
    const float* pos_emb = (const float*)d_in[21];
    GemmPtrs4 po;
    po.B[0] = (const float*)d_in[22]; po.bias[0] = (const float*)d_in[23];
    po.B[1] = (const float*)d_in[24]; po.bias[1] = (const float*)d_in[25];
    po.B[2] = (const float*)d_in[26]; po.bias[2] = (const float*)d_in[27];
    po.B[3] = (const float*)d_in[28]; po.bias[3] = (const float*)d_in[29];
    float* out = (float*)d_out;

    float *p_q, *p_kv, *p_attn, *p_x1, *p_xn, *p_xz, *p_xc, *p_xdbl, *p_dt,
          *p_Bm, *p_Cm, *p_y, *p_S, *p_sd, *p_H0, *p_xm2, *p_x2, *p_x3,
          *p_xw, *p_qkvw, *p_obuf, *p_oproj;
    cudaGetSymbolAddress((void**)&p_q,    g_q);
    cudaGetSymbolAddress((void**)&p_kv,   g_kv);
    cudaGetSymbolAddress((void**)&p_attn, g_attn);
    cudaGetSymbolAddress((void**)&p_x1,   g_x1);
    cudaGetSymbolAddress((void**)&p_xn,   g_xn);
    cudaGetSymbolAddress((void**)&p_xz,   g_xz);
    cudaGetSymbolAddress((void**)&p_xc,   g_xc);
    cudaGetSymbolAddress((void**)&p_xdbl, g_xdbl);
    cudaGetSymbolAddress((void**)&p_dt,   g_dt);
    cudaGetSymbolAddress((void**)&p_Bm,   g_Bm);
    cudaGetSymbolAddress((void**)&p_Cm,   g_Cm);
    cudaGetSymbolAddress((void**)&p_y,    g_y);
    cudaGetSymbolAddress((void**)&p_S,    g_S);
    cudaGetSymbolAddress((void**)&p_sd,   g_sumdt);
    cudaGetSymbolAddress((void**)&p_H0,   g_H0);
    cudaGetSymbolAddress((void**)&p_xm2,  g_xm2);
    cudaGetSymbolAddress((void**)&p_x2,   g_x2);
    cudaGetSymbolAddress((void**)&p_x3,   g_x3);
    cudaGetSymbolAddress((void**)&p_xw,   g_xw);
    cudaGetSymbolAddress((void**)&p_qkvw, g_qkvw);
    cudaGetSymbolAddress((void**)&p_obuf, g_obuf);
    cudaGetSymbolAddress((void**)&p_oproj,g_oproj);

    // stage 1: q/kv GEMMs (tensor core), gram+softmax, apply
    tgemm<<<dim3(4, 320), 256>>>(x, Wq,  p_q,  nullptr, 224, 224, 224, 224, 224);
    tgemm<<<dim3(7, 320), 256>>>(x, Wkv, p_kv, nullptr, 448, 224, 224, 448, 448);
    k_gram <<<dim3(32, 8), 256>>>(p_q, p_kv, p_attn);
    k_apply<<<dim3(20, 32), 224>>>(x, p_kv, p_attn, p_x1);

    // stage 2: mamba
    k_ln1<<<dim3(40, 32), 256>>>(p_x1, ln_g, ln_b, p_xn);
    tgemm<<<dim3(2, 2240), 256>>>(p_xn, in_proj, p_xz, nullptr, 128, 32, 32, 128, 128);
    k_conv1d<<<71680, 256>>>(p_xz, conv1dW, conv1db, p_xc);
    tgemm<<<dim3(1, 2240), 256>>>(p_xc, x_projW, p_xdbl, nullptr, 34, 64, 64, 34, 34);
    k_dtbc<<<107520, 256>>>(p_xdbl, dt_projW, dt_projb, p_dt, p_Bm, p_Cm);
    k_scan1<<<8960, 256>>>(p_dt, p_xc, p_Bm, A_log, p_S, p_sd);
    k_scan2<<<128, 256>>>(p_S, p_sd, A_log, p_H0);
    k_scan3<<<8960, 256>>>(p_dt, p_xc, p_Bm, p_Cm, A_log, p_H0, p_y);
    k_final<<<4480, 256>>>(p_y, p_xc, p_xz, p_xn, Dp, out_projW, skip,
                           ln_g, ln_b, projW, projb, p_xm2);
    k_addback<<<dim3(40, 32), 256>>>(p_x1, p_xm2, p_x2);

    // stage 3: conv3d
    k_conv3d<<<dim3(40, 32), 224>>>(p_x2, conv3dW, conv3db, p_x3);

    // stage 4: DWT + window attention
    k_dwt<<<43008, 256>>>(p_x3, p_xw);
    tgemm<<<dim3(4, 384), 256>>>(p_xw, Wq1,  p_qkvw,       nullptr, 224, 224, 224, 224, 672);
    tgemm<<<dim3(7, 384), 256>>>(p_xw, Wkv1, p_qkvw + 224, nullptr, 448, 224, 224, 448, 672);
    k_wattn<<<dim3(768, 8), 64>>>(p_qkvw, pos_emb, p_obuf);
    tgemm_b4<<<dim3(4, 96, 4), 256>>>(p_obuf, po, p_oproj,
                                      224, 224, 224, 224, 224,
                                      (long long)12288*224, (long long)12288*224);

    // stage 5: IWT + output
    k_iwt<<<8960, 256>>>(p_oproj, out);
}

// round 8
// speedup vs baseline: 1.1965x; 1.1965x over previous
#include <cuda_runtime.h>
#include <math.h>
#include <stdint.h>

// ---------------- static scratch (16B aligned) ----------------
__device__ __align__(16) float g_q    [40960u*224u];
__device__ __align__(16) float g_kv   [40960u*448u];
__device__ __align__(16) float g_attn [32*8*28*28];
__device__ __align__(16) float g_x1   [9175040];
__device__ __align__(16) float g_xn   [9175040];      // 286720 x 32
__device__ __align__(16) float g_xz   [36700160];     // 286720 x 128
__device__ __align__(16) float g_xc   [18350080];     // 286720 x 64
__device__ __align__(16) float g_xdbl [9748480];      // 286720 x 34
__device__ __align__(16) float g_dt   [18350080];
__device__ __align__(16) float g_Bm   [4587520];
__device__ __align__(16) float g_Cm   [4587520];
__device__ __align__(16) float g_y    [18350080];
__device__ __align__(16) float g_S    [2293760];      // 32*64*70*16
__device__ __align__(16) float g_sumdt[143360];       // 32*64*70
__device__ __align__(16) float g_H0   [2293760];
__device__ __align__(16) float g_xm2  [9175040];      // 286720 x 32
__device__ __align__(16) float g_x2   [9175040];
__device__ __align__(16) float g_x3   [9175040];
__device__ __align__(16) float g_xw   [11010048];     // 49152 x 224
__device__ __align__(16) float g_qkvw [33030144];     // 49152 x 672
__device__ __align__(16) float g_obuf [11010048];
__device__ __align__(16) float g_oproj[11010048];

__device__ __forceinline__ float siluf(float v){ return v / (1.f + __expf(-v)); }

struct GemmPtrs4 { const float* B[4]; const float* bias[4]; };

// ---------------- SGEMM: 128x64 tile, 8x4 micro, BK=16, DOUBLE-BUFFERED ------
// Requires M % 128 == 0, K % 16 == 0, lda % 4 == 0, A 16B-aligned. N predicated.
__device__ __forceinline__ void sgemm_core(
    const float* __restrict__ A, const float* __restrict__ B,
    float* __restrict__ C, const float* __restrict__ bias,
    int N, int K, int lda, int ldb, int ldc,
    float (*As)[16][128], float (*Bs)[16][64])
{
    const int bm = blockIdx.y * 128, bn = blockIdx.x * 64;
    const int tid = threadIdx.x;
    const int tr = tid >> 4, tc = tid & 15;
    const int br = tid >> 4, bc0 = (tid & 15) * 4;   // B loader
    float acc[8][4];
    #pragma unroll
    for (int i = 0; i < 8; i++)
        #pragma unroll
        for (int j = 0; j < 4; j++) acc[i][j] = 0.f;

    // prefetch tile 0 into regs, store to buffer 0
    float4 ra[2]; float rb[4];
    #pragma unroll
    for (int i = 0; i < 2; i++) {
        int idx = tid + i * 256;
        int r = idx >> 2, c4 = (idx & 3) * 4;
        ra[i] = *(const float4*)(A + (size_t)(bm + r) * lda + c4);
    }
    #pragma unroll
    for (int i = 0; i < 4; i++) {
        int n = bn + bc0 + i;
        rb[i] = (n < N) ? B[(size_t)br * ldb + n] : 0.f;
    }
    int buf = 0;
    #pragma unroll
    for (int i = 0; i < 2; i++) {
        int idx = tid + i * 256;
        int r = idx >> 2, c4 = (idx & 3) * 4;
        As[0][c4+0][r]=ra[i].x; As[0][c4+1][r]=ra[i].y;
        As[0][c4+2][r]=ra[i].z; As[0][c4+3][r]=ra[i].w;
    }
    #pragma unroll
    for (int i = 0; i < 4; i++) Bs[0][br][bc0+i] = rb[i];
    __syncthreads();

    for (int k0 = 0; k0 < K; k0 += 16) {
        const bool more = (k0 + 16) < K;
        float4 ra2[2]; float rb2[4];
        if (more) {
            #pragma unroll
            for (int i = 0; i < 2; i++) {
                int idx = tid + i * 256;
                int r = idx >> 2, c4 = (idx & 3) * 4;
                ra2[i] = *(const float4*)(A + (size_t)(bm + r) * lda + k0 + 16 + c4);
            }
            #pragma unroll
            for (int i = 0; i < 4; i++) {
                int n = bn + bc0 + i;
                rb2[i] = (n < N) ? B[(size_t)(k0 + 16 + br) * ldb + n] : 0.f;
            }
        }
        #pragma unroll
        for (int kk = 0; kk < 16; kk++) {
            float4 a0 = *(const float4*)&As[buf][kk][tr*8];
            float4 a1 = *(const float4*)&As[buf][kk][tr*8+4];
            float4 b0 = *(const float4*)&Bs[buf][kk][tc*4];
            float a[8] = {a0.x,a0.y,a0.z,a0.w,a1.x,a1.y,a1.z,a1.w};
            float b[4] = {b0.x,b0.y,b0.z,b0.w};
            #pragma unroll
            for (int i = 0; i < 8; i++)
                #pragma unroll
                for (int j = 0; j < 4; j++) acc[i][j] += a[i]*b[j];
        }
        if (more) {
            int nb = buf ^ 1;
            #pragma unroll
            for (int i = 0; i < 2; i++) {
                int idx = tid + i * 256;
                int r = idx >> 2, c4 = (idx & 3) * 4;
                As[nb][c4+0][r]=ra2[i].x; As[nb][c4+1][r]=ra2[i].y;
                As[nb][c4+2][r]=ra2[i].z; As[nb][c4+3][r]=ra2[i].w;
            }
            #pragma unroll
            for (int i = 0; i < 4; i++) Bs[nb][br][bc0+i] = rb2[i];
            __syncthreads();
            buf = nb;
        }
    }
    #pragma unroll
    for (int i = 0; i < 8; i++) {
        int m = bm + tr*8 + i;
        #pragma unroll
        for (int j = 0; j < 4; j++) {
            int n = bn + tc*4 + j;
            if (n < N) {
                float v = acc[i][j];
                if (bias) v += bias[n];
                C[(size_t)m * ldc + n] = v;
            }
        }
    }
}

__global__ __launch_bounds__(256) void sgemm_k(
    const float* __restrict__ A, const float* __restrict__ B,
    float* __restrict__ C, const float* __restrict__ bias,
    int N, int K, int lda, int ldb, int ldc) {
    __shared__ float As[2][16][128];
    __shared__ float Bs[2][16][64];
    sgemm_core(A, B, C, bias, N, K, lda, ldb, ldc, As, Bs);
}

// batched variant: per-z B/bias, A and C strided by z
__global__ __launch_bounds__(256) void sgemm_b4(
    const float* __restrict__ A, GemmPtrs4 p, float* __restrict__ C,
    int N, int K, int lda, int ldb, int ldc,
    long long strideA, long long strideC) {
    __shared__ float As[2][16][128];
    __shared__ float Bs[2][16][64];
    int z = blockIdx.z;
    sgemm_core(A + (size_t)z * strideA, p.B[z], C + (size_t)z * strideC,
               p.bias[z], N, K, lda, ldb, ldc, As, Bs);
}

// ---------------- stage 1: channel attention ----------------
__global__ void k_gram(const float* __restrict__ q, const float* __restrict__ kv,
                       float* __restrict__ attn) {
    int b = blockIdx.x, h = blockIdx.y;
    __shared__ float kt[32][28], qt[32][28];
    __shared__ float G[840];
    int tid = threadIdx.x;   // 256
    float acc[4] = {0.f,0.f,0.f,0.f};
    for (int nt = 0; nt < 40; nt++) {
        for (int idx = tid; idx < 896; idx += 256) {
            int n = idx / 28, i = idx % 28;
            size_t row = (size_t)b*1280 + nt*32 + n;
            kt[n][i] = kv[row*448 + h*28 + i];
            qt[n][i] = q [row*224 + h*28 + i];
        }
        __syncthreads();
        #pragma unroll
        for (int s = 0; s < 4; s++) {
            int w = tid + 256*s;
            if (w < 784) {
                int i = w/28, j = w%28; float a = acc[s];
                #pragma unroll
                for (int n = 0; n < 32; n++) a += kt[n][i]*qt[n][j];
                acc[s] = a;
            } else if (w < 812) {
                int i = w - 784; float a = acc[s];
                #pragma unroll
                for (int n = 0; n < 32; n++) a += kt[n][i]*kt[n][i];
                acc[s] = a;
            } else if (w < 840) {
                int j = w - 812; float a = acc[s];
                #pragma unroll
                for (int n = 0; n < 32; n++) a += qt[n][j]*qt[n][j];
                acc[s] = a;
            }
        }
        __syncthreads();
    }
    #pragma unroll
    for (int s = 0; s < 4; s++) { int w = tid + 256*s; if (w < 840) G[w] = acc[s]; }
    __syncthreads();
    if (tid < 28) {
        int i = tid;
        float nk = fmaxf(sqrtf(G[784+i]), 1e-12f);
        float lg[28], m = -1e30f;
        #pragma unroll
        for (int j = 0; j < 28; j++) {
            float nq = fmaxf(sqrtf(G[812+j]), 1e-12f);
            lg[j] = G[i*28+j] / (nk*nq) * 0.18898223650461363f;
            m = fmaxf(m, lg[j]);
        }
        float sum = 0.f;
        #pragma unroll
        for (int j = 0; j < 28; j++) { lg[j] = __expf(lg[j]-m); sum += lg[j]; }
        float inv = 1.f/sum;
        #pragma unroll
        for (int j = 0; j < 28; j++)
            attn[(((size_t)b*8 + h)*28 + i)*28 + j] = lg[j]*inv;
    }
}

// x1 = attn-applied + residual; 8 rows per barrier interval
__global__ void k_apply(const float* __restrict__ x, const float* __restrict__ kv,
                        const float* __restrict__ attn, float* __restrict__ x1) {
    int chunk = blockIdx.x, b = blockIdx.y;
    __shared__ float att[6272];
    __shared__ float vr[8][224];
    int tid = threadIdx.x;   // 224
    for (int idx = tid; idx < 6272; idx += 224) att[idx] = attn[(size_t)b*6272 + idx];
    int h = tid / 28, i = tid % 28;
    for (int nn = 0; nn < 64; nn += 8) {
        size_t row0 = (size_t)b*1280 + chunk*64 + nn;
        __syncthreads();
        for (int idx = tid; idx < 1792; idx += 224) {
            int rr = idx / 224, cc = idx % 224;
            vr[rr][cc] = kv[(row0 + rr)*448 + 224 + cc];
        }
        __syncthreads();
        #pragma unroll
        for (int rr = 0; rr < 8; rr++) {
            float a = 0.f;
            #pragma unroll
            for (int j = 0; j < 28; j++) a += att[(h*28+i)*28 + j] * vr[rr][h*28 + j];
            size_t o = (row0 + rr)*224 + tid;
            x1[o] = x[o] + a;
        }
    }
}

// ---------------- transpose + LN into (b, L=8960, 32) ----------------
__global__ void k_ln1(const float* __restrict__ x1, const float* __restrict__ g,
                      const float* __restrict__ be, float* __restrict__ xn) {
    int ww = blockIdx.x, b = blockIdx.y;
    __shared__ float s[32*225];
    int tid = threadIdx.x;   // 256
    for (int idx = tid; idx < 32*224; idx += 256) {
        int m = idx / 224, cc = idx % 224;
        s[m*225 + cc] = x1[((size_t)b*1280 + m*40 + ww)*224 + cc];
    }
    __syncthreads();
    for (int cc = tid; cc < 224; cc += 256) {
        float mean = 0.f;
        #pragma unroll
        for (int m = 0; m < 32; m++) mean += s[m*225+cc];
        mean *= (1.f/32.f);
        float var = 0.f;
        #pragma unroll
        for (int m = 0; m < 32; m++) { float d = s[m*225+cc]-mean; var += d*d; }
        var *= (1.f/32.f);
        float inv = rsqrtf(var + 1e-5f);
        size_t ob = ((size_t)b*8960 + ww*224 + cc)*32;
        #pragma unroll
        for (int m = 0; m < 32; m++)
            xn[ob + m] = (s[m*225+cc]-mean)*inv*g[m] + be[m];
    }
}

// ---------------- mamba pieces ----------------
__global__ void k_conv1d(const float* __restrict__ xz, const float* __restrict__ cw,
                         const float* __restrict__ cb, float* __restrict__ xc) {
    size_t id = (size_t)blockIdx.x*256 + threadIdx.x;
    size_t row = id >> 6; int d = (int)(id & 63);
    size_t b = row / 8960; int l = (int)(row % 8960);
    float acc = cb[d];
    #pragma unroll
    for (int t = 0; t < 4; t++) {
        int ls = l - 3 + t;
        if (ls >= 0) acc += xz[((size_t)b*8960 + ls)*128 + d] * cw[d*4 + t];
    }
    xc[row*64 + d] = siluf(acc);
}

__global__ void k_dtbc(const float* __restrict__ xdbl, const float* __restrict__ dtW,
                       const float* __restrict__ dtb, float* __restrict__ dt,
                       float* __restrict__ Bm, float* __restrict__ Cm) {
    size_t id = (size_t)blockIdx.x*256 + threadIdx.x;
    size_t row = id / 96; int j = (int)(id % 96);
    const float* xd = xdbl + row*34;
    if (j < 64) {
        float v = xd[0]*dtW[j] + xd[1]*dtW[64+j] + dtb[j];
        dt[row*64 + j] = (v > 20.f) ? v : log1pf(__expf(v));
    } else if (j < 80) {
        Bm[row*16 + (j-64)] = xd[2 + (j-64)];
    } else {
        Cm[row*16 + (j-80)] = xd[18 + (j-80)];
    }
}

__global__ void k_scan1(const float* __restrict__ dt, const float* __restrict__ xc,
                        const float* __restrict__ Bm, const float* __restrict__ Alog,
                        float* __restrict__ S, float* __restrict__ sumdt) {
    int gw = (blockIdx.x*256 + threadIdx.x) >> 5;
    int lane = threadIdx.x & 31;
    int b = gw / 2240; int rem = gw % 2240;
    int chunk = rem >> 5; int dp = rem & 31;
    int d = dp*2 + (lane >> 4); int n = lane & 15;
    float Av = -__expf(Alog[d*16 + n]);
    float h = 0.f, sdt = 0.f;
    size_t base = (size_t)b*8960 + chunk*128;
    #pragma unroll 4
    for (int l = 0; l < 128; l++) {
        size_t row = base + l;
        float dtv = dt[row*64 + d];
        float u   = xc[row*64 + d];
        float Bn  = Bm[row*16 + n];
        h = __expf(Av*dtv)*h + dtv*u*Bn;
        sdt += dtv;
    }
    size_t idx = (size_t)(b*64 + d)*70 + chunk;
    S[idx*16 + n] = h;
    if (n == 0) sumdt[idx] = sdt;
}

__global__ void k_scan2(const float* __restrict__ S, const float* __restrict__ sumdt,
                        const float* __restrict__ Alog, float* __restrict__ H0) {
    int t = blockIdx.x*256 + threadIdx.x;
    int b = t >> 10; int d = (t >> 4) & 63; int n = t & 15;
    float Av = -__expf(Alog[d*16 + n]);
    float carry = 0.f;
    size_t base = (size_t)(b*64 + d)*70;
    for (int ch = 0; ch < 70; ch++) {
        size_t idx = base + ch;
        H0[idx*16 + n] = carry;
        carry = carry*__expf(Av*sumdt[idx]) + S[idx*16 + n];
    }
}

__global__ void k_scan3(const float* __restrict__ dt, const float* __restrict__ xc,
                        const float* __restrict__ Bm, const float* __restrict__ Cm,
                        const float* __restrict__ Alog, const float* __restrict__ H0,
                        float* __restrict__ y) {
    int gw = (blockIdx.x*256 + threadIdx.x) >> 5;
    int lane = threadIdx.x & 31;
    int b = gw / 2240; int rem = gw % 2240;
    int chunk = rem >> 5; int dp = rem & 31;
    int d = dp*2 + (lane >> 4); int n = lane & 15;
    float Av = -__expf(Alog[d*16 + n]);
    size_t idx = (size_t)(b*64 + d)*70 + chunk;
    float h = H0[idx*16 + n];
    size_t base = (size_t)b*8960 + chunk*128;
    #pragma unroll 4
    for (int l = 0; l < 128; l++) {
        size_t row = base + l;
        float dtv = dt[row*64 + d];
        float u   = xc[row*64 + d];
        float Bn  = Bm[row*16 + n];
        h = __expf(Av*dtv)*h + dtv*u*Bn;
        float yv = h * Cm[row*16 + n];
        yv += __shfl_xor_sync(0xffffffffu, yv, 8);
        yv += __shfl_xor_sync(0xffffffffu, yv, 4);
        yv += __shfl_xor_sync(0xffffffffu, yv, 2);
        yv += __shfl_xor_sync(0xffffffffu, yv, 1);
        if (n == 0) y[row*64 + d] = yv;
    }
}

// gate + out_proj + skip + LN + proj; each warp handles 8 rows
__global__ void k_final(const float* __restrict__ y, const float* __restrict__ xc,
                        const float* __restrict__ xz, const float* __restrict__ xn,
                        const float* __restrict__ Dp, const float* __restrict__ opW,
                        const float* __restrict__ skipp, const float* __restrict__ g,
                        const float* __restrict__ be, const float* __restrict__ projW,
                        const float* __restrict__ projb, float* __restrict__ xm2) {
    __shared__ float sop[2048], spj[1024];
    int tid = threadIdx.x;   // 256
    for (int i = tid; i < 2048; i += 256) sop[i] = opW[i];
    for (int i = tid; i < 1024; i += 256) spj[i] = projW[i];
    __syncthreads();
    int warp = tid >> 5, lane = tid & 31;
    float skip = skipp[0];
    float dpl = Dp[lane], dph = Dp[32+lane];
    float gl = g[lane], bel = be[lane], pbl = projb[lane];
    #pragma unroll
    for (int t = 0; t < 8; t++) {
        size_t r = ((size_t)blockIdx.x*8 + warp)*8 + t;
        float y0 = y[r*64 + lane],      y1 = y[r*64 + 32 + lane];
        float c0 = xc[r*64 + lane],     c1 = xc[r*64 + 32 + lane];
        float z0 = xz[r*128 + 64 + lane], z1 = xz[r*128 + 96 + lane];
        float yy0 = (y0 + c0*dpl) * siluf(z0);
        float yy1 = (y1 + c1*dph) * siluf(z1);
        float acc = 0.f;
        #pragma unroll
        for (int d = 0; d < 32; d++) acc += __shfl_sync(0xffffffffu, yy0, d) * sop[d*32 + lane];
        #pragma unroll
        for (int d = 0; d < 32; d++) acc += __shfl_sync(0xffffffffu, yy1, d) * sop[(d+32)*32 + lane];
        float xm = acc + skip * xn[r*32 + lane];
        float mean = xm;
        #pragma unroll
        for (int o = 16; o; o >>= 1) mean += __shfl_xor_sync(0xffffffffu, mean, o);
        mean *= (1.f/32.f);
        float dv = xm - mean, var = dv*dv;
        #pragma unroll
        for (int o = 16; o; o >>= 1) var += __shfl_xor_sync(0xffffffffu, var, o);
        var *= (1.f/32.f);
        float v = dv * rsqrtf(var + 1e-5f) * gl + bel;
        float acc2 = pbl;
        #pragma unroll
        for (int mm = 0; mm < 32; mm++) acc2 += __shfl_sync(0xffffffffu, v, mm) * spj[mm*32 + lane];
        xm2[r*32 + lane] = acc2;
    }
}

__global__ void k_addback(const float* __restrict__ x1, const float* __restrict__ xm2,
                          float* __restrict__ x2) {
    int ww = blockIdx.x, b = blockIdx.y;
    __shared__ float s[224*33];
    int tid = threadIdx.x;   // 256
    for (int idx = tid; idx < 224*32; idx += 256) {
        int cc = idx >> 5, m = idx & 31;
        s[cc*33 + m] = xm2[((size_t)b*8960 + ww*224 + cc)*32 + m];
    }
    __syncthreads();
    for (int idx = tid; idx < 32*224; idx += 256) {
        int m = idx / 224, cc = idx % 224;
        size_t o = ((size_t)b*1280 + m*40 + ww)*224 + cc;
        x2[o] = x1[o] + s[cc*33 + m];
    }
}

// ---------------- conv3d 5x5x5, pad 2, smem-tiled per ky-plane ----------------
__global__ void k_conv3d(const float* __restrict__ x2, const float* __restrict__ cw,
                         const float* __restrict__ cb, float* __restrict__ x3) {
    int y = blockIdx.x, b = blockIdx.y;
    int xx = threadIdx.x;   // 224
    __shared__ float ws[125];
    __shared__ float sp[32][228];
    if (xx < 125) ws[xx] = cw[xx];
    if (xx < 32) { sp[xx][0]=0.f; sp[xx][1]=0.f; sp[xx][226]=0.f; sp[xx][227]=0.f; }
    float acc[32];
    #pragma unroll
    for (int d = 0; d < 32; d++) acc[d] = 0.f;
    for (int ky = 0; ky < 5; ky++) {
        int yy = y + ky - 2;
        if (yy < 0 || yy >= 40) continue;
        __syncthreads();
        for (int i = 0; i < 32; i++)
            sp[i][xx+2] = x2[(((size_t)b*32 + i)*40 + yy)*224 + xx];
        __syncthreads();
        #pragma unroll
        for (int kx = 0; kx < 5; kx++) {
            float v[36];
            v[0]=v[1]=v[34]=v[35]=0.f;
            #pragma unroll
            for (int i = 0; i < 32; i++) v[i+2] = sp[i][xx + kx];
            #pragma unroll
            for (int kz = 0; kz < 5; kz++) {
                float wv = ws[(kz*5 + ky)*5 + kx];
                #pragma unroll
                for (int d = 0; d < 32; d++) acc[d] += v[d+kz]*wv;
            }
        }
    }
    float bias = cb[0];
    #pragma unroll
    for (int d = 0; d < 32; d++)
        x3[(((size_t)b*32 + d)*40 + y)*224 + xx] = acc[d] + bias;
}

// ---------------- DWT: all 4 subbands per thread (reads once, writes 4) ------
__global__ void k_dwt(const float* __restrict__ x3, float* __restrict__ xw) {
    size_t id = (size_t)blockIdx.x*256 + threadIdx.x;   // 2752512
    int c = (int)(id % 224); size_t rw = id / 224;
    int win = (int)(rw >> 6), tok = (int)(rw & 63);
    int bb = win / 6, w6 = win % 6;
    int wi = w6 / 3, wj = w6 % 3;
    int ti = tok >> 3, tj = tok & 7;
    int i2 = wi*8 + ti;
    int j2 = wj*8 + tj;
    int j = (j2 < 20) ? j2 : 38 - j2;   // reflect pad
    size_t base = (((size_t)bb*32 + 2*i2)*40 + 2*j)*224 + c;
    float a  = x3[base],        bv = x3[base + 224];
    float c2 = x3[base + 8960], d2 = x3[base + 9184];
    const size_t SS = (size_t)12288*224;
    xw[id]        = 0.5f*(a + bv + c2 + d2);
    xw[id + SS]   = 0.5f*(a + bv - c2 - d2);
    xw[id + 2*SS] = 0.5f*(a - bv + c2 - d2);
    xw[id + 3*SS] = 0.5f*(a - bv - c2 + d2);
}

// ---------------- window attention (float4 smem reads) ----------------
__global__ void k_wattn(const float* __restrict__ qkvw, const float* __restrict__ pe,
                        float* __restrict__ obuf) {
    int win = blockIdx.x, head = blockIdx.y;
    __shared__ __align__(16) float qs[64*28], ks[64*28], vs[64*28];
    __shared__ float lgs[64*65];
    int tid = threadIdx.x;   // 64
    size_t wbase = (size_t)win * 64;
    for (int idx = tid; idx < 1792; idx += 64) {
        int tok = idx / 28, dd = idx % 28;
        size_t rb = (wbase + tok)*672 + head*28 + dd;
        qs[idx] = qkvw[rb] * 0.18898223650461363f;
        ks[idx] = qkvw[rb + 224];
        vs[idx] = qkvw[rb + 448];
    }
    __syncthreads();
    int i = tid;
    float qr[28];
    #pragma unroll
    for (int dd = 0; dd < 28; dd++) qr[dd] = qs[i*28 + dd];
    const float* per = pe + ((size_t)head*64 + i)*64;
    float m = -1e30f;
    for (int j = 0; j < 64; j++) {
        const float4* k4 = (const float4*)&ks[j*28];
        float dot = 0.f;
        #pragma unroll
        for (int q4 = 0; q4 < 7; q4++) {
            float4 kk = k4[q4];
            dot += qr[q4*4+0]*kk.x + qr[q4*4+1]*kk.y
                 + qr[q4*4+2]*kk.z + qr[q4*4+3]*kk.w;
        }
        float l = dot + per[j];
        lgs[i*65 + j] = l;
        m = fmaxf(m, l);
    }
    float sum = 0.f;
    for (int j = 0; j < 64; j++) {
        float e = __expf(lgs[i*65 + j] - m);
        lgs[i*65 + j] = e;
        sum += e;
    }
    float inv = 1.f / sum;
    float acc[28];
    #pragma unroll
    for (int dd = 0; dd < 28; dd++) acc[dd] = 0.f;
    for (int j = 0; j < 64; j++) {
        float a = lgs[i*65 + j] * inv;
        const float4* v4 = (const float4*)&vs[j*28];
        #pragma unroll
        for (int q4 = 0; q4 < 7; q4++) {
            float4 vv = v4[q4];
            acc[q4*4+0] += a*vv.x; acc[q4*4+1] += a*vv.y;
            acc[q4*4+2] += a*vv.z; acc[q4*4+3] += a*vv.w;
        }
    }
    size_t ob = (wbase + i)*224 + head*28;
    #pragma unroll
    for (int dd = 0; dd < 28; dd++) obuf[ob + dd] = acc[dd];
}

// ---------------- IWT + crop + final layout ----------------
__global__ void k_iwt(const float* __restrict__ oproj, float* __restrict__ out) {
    size_t id = (size_t)blockIdx.x*256 + threadIdx.x;   // 2293760
    int c = (int)(id % 224); size_t r = id / 224;
    int j = (int)(r % 20); r /= 20;
    int i = (int)(r % 16); int bb = (int)(r / 16);
    int wi = i >> 3, ti = i & 7, wj = j >> 3, tj = j & 7;
    size_t row0 = ((size_t)(bb*6 + wi*3 + wj))*64 + ti*8 + tj;
    float A  = oproj[row0*224 + c];
    float Hh = oproj[(row0 + 12288)*224 + c];
    float V  = oproj[(row0 + 24576)*224 + c];
    float D  = oproj[(row0 + 36864)*224 + c];
    size_t oo = (((size_t)bb*32 + 2*i)*40 + 2*j)*224 + c;
    out[oo]          = 0.5f*(A + Hh + V + D);
    out[oo + 224]    = 0.5f*(A + Hh - V - D);
    out[oo + 8960]   = 0.5f*(A - Hh + V - D);
    out[oo + 9184]   = 0.5f*(A - Hh - V + D);
}

// ---------------- launcher ----------------
extern "C" void kernel_launch(void* const* d_in, const int* in_sizes, int n_in,
                              void* d_out, int out_size) {
    const float* x       = (const float*)d_in[0];
    const float* Wq      = (const float*)d_in[1];
    const float* Wkv     = (const float*)d_in[2];
    const float* ln_g    = (const float*)d_in[3];
    const float* ln_b    = (const float*)d_in[4];
    const float* in_proj = (const float*)d_in[5];
    const float* conv1dW = (const float*)d_in[6];
    const float* conv1db = (const float*)d_in[7];
    const float* x_projW = (const float*)d_in[8];
    const float* dt_projW= (const float*)d_in[9];
    const float* dt_projb= (const float*)d_in[10];
    const float* A_log   = (const float*)d_in[11];
    const float* Dp      = (const float*)d_in[12];
    const float* out_projW=(const float*)d_in[13];
    const float* skip    = (const float*)d_in[14];
    const float* projW   = (const float*)d_in[15];
    const float* projb   = (const float*)d_in[16];
    const float* conv3dW = (const float*)d_in[17];
    const float* conv3db = (const float*)d_in[18];
    const float* Wq1     = (const float*)d_in[19];
    const float* Wkv1    = (const float*)d_in[20];
    const float* pos_emb = (const float*)d_in[21];
    GemmPtrs4 po;
    po.B[0] = (const float*)d_in[22]; po.bias[0] = (const float*)d_in[23];
    po.B[1] = (const float*)d_in[24]; po.bias[1] = (const float*)d_in[25];
    po.B[2] = (const float*)d_in[26]; po.bias[2] = (const float*)d_in[27];
    po.B[3] = (const float*)d_in[28]; po.bias[3] = (const float*)d_in[29];
    float* out = (float*)d_out;

    float *p_q, *p_kv, *p_attn, *p_x1, *p_xn, *p_xz, *p_xc, *p_xdbl, *p_dt,
          *p_Bm, *p_Cm, *p_y, *p_S, *p_sd, *p_H0, *p_xm2, *p_x2, *p_x3,
          *p_xw, *p_qkvw, *p_obuf, *p_oproj;
    cudaGetSymbolAddress((void**)&p_q,    g_q);
    cudaGetSymbolAddress((void**)&p_kv,   g_kv);
    cudaGetSymbolAddress((void**)&p_attn, g_attn);
    cudaGetSymbolAddress((void**)&p_x1,   g_x1);
    cudaGetSymbolAddress((void**)&p_xn,   g_xn);
    cudaGetSymbolAddress((void**)&p_xz,   g_xz);
    cudaGetSymbolAddress((void**)&p_xc,   g_xc);
    cudaGetSymbolAddress((void**)&p_xdbl, g_xdbl);
    cudaGetSymbolAddress((void**)&p_dt,   g_dt);
    cudaGetSymbolAddress((void**)&p_Bm,   g_Bm);
    cudaGetSymbolAddress((void**)&p_Cm,   g_Cm);
    cudaGetSymbolAddress((void**)&p_y,    g_y);
    cudaGetSymbolAddress((void**)&p_S,    g_S);
    cudaGetSymbolAddress((void**)&p_sd,   g_sumdt);
    cudaGetSymbolAddress((void**)&p_H0,   g_H0);
    cudaGetSymbolAddress((void**)&p_xm2,  g_xm2);
    cudaGetSymbolAddress((void**)&p_x2,   g_x2);
    cudaGetSymbolAddress((void**)&p_x3,   g_x3);
    cudaGetSymbolAddress((void**)&p_xw,   g_xw);
    cudaGetSymbolAddress((void**)&p_qkvw, g_qkvw);
    cudaGetSymbolAddress((void**)&p_obuf, g_obuf);
    cudaGetSymbolAddress((void**)&p_oproj,g_oproj);

    // stage 1: q/kv GEMMs, gram+softmax, apply
    sgemm_k<<<dim3(4, 320), 256>>>(x, Wq,  p_q,  nullptr, 224, 224, 224, 224, 224);
    sgemm_k<<<dim3(7, 320), 256>>>(x, Wkv, p_kv, nullptr, 448, 224, 224, 448, 448);
    k_gram <<<dim3(32, 8), 256>>>(p_q, p_kv, p_attn);
    k_apply<<<dim3(20, 32), 224>>>(x, p_kv, p_attn, p_x1);

    // stage 2: mamba
    k_ln1<<<dim3(40, 32), 256>>>(p_x1, ln_g, ln_b, p_xn);
    sgemm_k<<<dim3(2, 2240), 256>>>(p_xn, in_proj, p_xz, nullptr, 128, 32, 32, 128, 128);
    k_conv1d<<<71680, 256>>>(p_xz, conv1dW, conv1db, p_xc);
    sgemm_k<<<dim3(1, 2240), 256>>>(p_xc, x_projW, p_xdbl, nullptr, 34, 64, 64, 34, 34);
    k_dtbc<<<107520, 256>>>(p_xdbl, dt_projW, dt_projb, p_dt, p_Bm, p_Cm);
    k_scan1<<<8960, 256>>>(p_dt, p_xc, p_Bm, A_log, p_S, p_sd);
    k_scan2<<<128, 256>>>(p_S, p_sd, A_log, p_H0);
    k_scan3<<<8960, 256>>>(p_dt, p_xc, p_Bm, p_Cm, A_log, p_H0, p_y);
    k_final<<<4480, 256>>>(p_y, p_xc, p_xz, p_xn, Dp, out_projW, skip,
                           ln_g, ln_b, projW, projb, p_xm2);
    k_addback<<<dim3(40, 32), 256>>>(p_x1, p_xm2, p_x2);

    // stage 3: conv3d
    k_conv3d<<<dim3(40, 32), 224>>>(p_x2, conv3dW, conv3db, p_x3);

    // stage 4: DWT + window attention
    k_dwt<<<10752, 256>>>(p_x3, p_xw);
    sgemm_k<<<dim3(4, 384), 256>>>(p_xw, Wq1,  p_qkvw,       nullptr, 224, 224, 224, 224, 672);
    sgemm_k<<<dim3(7, 384), 256>>>(p_xw, Wkv1, p_qkvw + 224, nullptr, 448, 224, 224, 448, 672);
    k_wattn<<<dim3(768, 8), 64>>>(p_qkvw, pos_emb, p_obuf);
    sgemm_b4<<<dim3(4, 96, 4), 256>>>(p_obuf, po, p_oproj,
                                      224, 224, 224, 224, 224,
                                      (long long)12288*224, (long long)12288*224);

    // stage 5: IWT + output
    k_iwt<<<8960, 256>>>(p_oproj, out);
}

// round 9
// speedup vs baseline: 1.2816x; 1.0712x over previous
#include <cuda_runtime.h>
#include <math.h>
#include <stdint.h>

// ---------------- static scratch (16B aligned) ----------------
__device__ __align__(16) float g_q    [40960u*224u];
__device__ __align__(16) float g_kv   [40960u*448u];
__device__ __align__(16) float g_attn [32*8*28*28];
__device__ __align__(16) float g_x1   [9175040];
__device__ __align__(16) float g_xn   [9175040];      // 286720 x 32
__device__ __align__(16) float g_xz   [36700160];     // 286720 x 128
__device__ __align__(16) float g_xc   [18350080];     // 286720 x 64
__device__ __align__(16) float g_xdbl [9748480];      // 286720 x 34
__device__ __align__(16) float g_dt   [18350080];
__device__ __align__(16) float g_Bm   [4587520];
__device__ __align__(16) float g_Cm   [4587520];
__device__ __align__(16) float g_y    [18350080];
__device__ __align__(16) float g_S    [2293760];      // 32*64*70*16
__device__ __align__(16) float g_sumdt[143360];       // 32*64*70
__device__ __align__(16) float g_H0   [2293760];
__device__ __align__(16) float g_xm2  [9175040];      // 286720 x 32
__device__ __align__(16) float g_x2   [9175040];
__device__ __align__(16) float g_x3   [9175040];
__device__ __align__(16) float g_xw   [11010048];     // 49152 x 224
__device__ __align__(16) float g_qkvw [33030144];     // 49152 x 672
__device__ __align__(16) float g_obuf [11010048];
__device__ __align__(16) float g_oproj[11010048];

__device__ __forceinline__ float siluf(float v){ return v / (1.f + __expf(-v)); }

struct GemmPtrs4 { const float* B[4]; const float* bias[4]; };

// ---------------- SGEMM: 128x64 tile, 8x4 micro, BK=16, DOUBLE-BUFFERED ------
__device__ __forceinline__ void sgemm_core(
    const float* __restrict__ A, const float* __restrict__ B,
    float* __restrict__ C, const float* __restrict__ bias,
    int N, int K, int lda, int ldb, int ldc,
    float (*As)[16][128], float (*Bs)[16][64])
{
    const int bm = blockIdx.y * 128, bn = blockIdx.x * 64;
    const int tid = threadIdx.x;
    const int tr = tid >> 4, tc = tid & 15;
    const int br = tid >> 4, bc0 = (tid & 15) * 4;   // B loader
    float acc[8][4];
    #pragma unroll
    for (int i = 0; i < 8; i++)
        #pragma unroll
        for (int j = 0; j < 4; j++) acc[i][j] = 0.f;

    float4 ra[2]; float rb[4];
    #pragma unroll
    for (int i = 0; i < 2; i++) {
        int idx = tid + i * 256;
        int r = idx >> 2, c4 = (idx & 3) * 4;
        ra[i] = *(const float4*)(A + (size_t)(bm + r) * lda + c4);
    }
    #pragma unroll
    for (int i = 0; i < 4; i++) {
        int n = bn + bc0 + i;
        rb[i] = (n < N) ? B[(size_t)br * ldb + n] : 0.f;
    }
    int buf = 0;
    #pragma unroll
    for (int i = 0; i < 2; i++) {
        int idx = tid + i * 256;
        int r = idx >> 2, c4 = (idx & 3) * 4;
        As[0][c4+0][r]=ra[i].x; As[0][c4+1][r]=ra[i].y;
        As[0][c4+2][r]=ra[i].z; As[0][c4+3][r]=ra[i].w;
    }
    #pragma unroll
    for (int i = 0; i < 4; i++) Bs[0][br][bc0+i] = rb[i];
    __syncthreads();

    for (int k0 = 0; k0 < K; k0 += 16) {
        const bool more = (k0 + 16) < K;
        float4 ra2[2]; float rb2[4];
        if (more) {
            #pragma unroll
            for (int i = 0; i < 2; i++) {
                int idx = tid + i * 256;
                int r = idx >> 2, c4 = (idx & 3) * 4;
                ra2[i] = *(const float4*)(A + (size_t)(bm + r) * lda + k0 + 16 + c4);
            }
            #pragma unroll
            for (int i = 0; i < 4; i++) {
                int n = bn + bc0 + i;
                rb2[i] = (n < N) ? B[(size_t)(k0 + 16 + br) * ldb + n] : 0.f;
            }
        }
        #pragma unroll
        for (int kk = 0; kk < 16; kk++) {
            float4 a0 = *(const float4*)&As[buf][kk][tr*8];
            float4 a1 = *(const float4*)&As[buf][kk][tr*8+4];
            float4 b0 = *(const float4*)&Bs[buf][kk][tc*4];
            float a[8] = {a0.x,a0.y,a0.z,a0.w,a1.x,a1.y,a1.z,a1.w};
            float b[4] = {b0.x,b0.y,b0.z,b0.w};
            #pragma unroll
            for (int i = 0; i < 8; i++)
                #pragma unroll
                for (int j = 0; j < 4; j++) acc[i][j] += a[i]*b[j];
        }
        if (more) {
            int nb = buf ^ 1;
            #pragma unroll
            for (int i = 0; i < 2; i++) {
                int idx = tid + i * 256;
                int r = idx >> 2, c4 = (idx & 3) * 4;
                As[nb][c4+0][r]=ra2[i].x; As[nb][c4+1][r]=ra2[i].y;
                As[nb][c4+2][r]=ra2[i].z; As[nb][c4+3][r]=ra2[i].w;
            }
            #pragma unroll
            for (int i = 0; i < 4; i++) Bs[nb][br][bc0+i] = rb2[i];
            __syncthreads();
            buf = nb;
        }
    }
    #pragma unroll
    for (int i = 0; i < 8; i++) {
        int m = bm + tr*8 + i;
        #pragma unroll
        for (int j = 0; j < 4; j++) {
            int n = bn + tc*4 + j;
            if (n < N) {
                float v = acc[i][j];
                if (bias) v += bias[n];
                C[(size_t)m * ldc + n] = v;
            }
        }
    }
}

__global__ __launch_bounds__(256) void sgemm_k(
    const float* __restrict__ A, const float* __restrict__ B,
    float* __restrict__ C, const float* __restrict__ bias,
    int N, int K, int lda, int ldb, int ldc) {
    __shared__ float As[2][16][128];
    __shared__ float Bs[2][16][64];
    sgemm_core(A, B, C, bias, N, K, lda, ldb, ldc, As, Bs);
}

__global__ __launch_bounds__(256) void sgemm_b4(
    const float* __restrict__ A, GemmPtrs4 p, float* __restrict__ C,
    int N, int K, int lda, int ldb, int ldc,
    long long strideA, long long strideC) {
    __shared__ float As[2][16][128];
    __shared__ float Bs[2][16][64];
    int z = blockIdx.z;
    sgemm_core(A + (size_t)z * strideA, p.B[z], C + (size_t)z * strideC,
               p.bias[z], N, K, lda, ldb, ldc, As, Bs);
}

// ---------------- stage 1: channel attention ----------------
__global__ void k_gram(const float* __restrict__ q, const float* __restrict__ kv,
                       float* __restrict__ attn) {
    int b = blockIdx.x, h = blockIdx.y;
    __shared__ float kt[32][28], qt[32][28];
    __shared__ float G[840];
    int tid = threadIdx.x;   // 256
    float acc[4] = {0.f,0.f,0.f,0.f};
    for (int nt = 0; nt < 40; nt++) {
        for (int idx = tid; idx < 896; idx += 256) {
            int n = idx / 28, i = idx % 28;
            size_t row = (size_t)b*1280 + nt*32 + n;
            kt[n][i] = kv[row*448 + h*28 + i];
            qt[n][i] = q [row*224 + h*28 + i];
        }
        __syncthreads();
        #pragma unroll
        for (int s = 0; s < 4; s++) {
            int w = tid + 256*s;
            if (w < 784) {
                int i = w/28, j = w%28; float a = acc[s];
                #pragma unroll
                for (int n = 0; n < 32; n++) a += kt[n][i]*qt[n][j];
                acc[s] = a;
            } else if (w < 812) {
                int i = w - 784; float a = acc[s];
                #pragma unroll
                for (int n = 0; n < 32; n++) a += kt[n][i]*kt[n][i];
                acc[s] = a;
            } else if (w < 840) {
                int j = w - 812; float a = acc[s];
                #pragma unroll
                for (int n = 0; n < 32; n++) a += qt[n][j]*qt[n][j];
                acc[s] = a;
            }
        }
        __syncthreads();
    }
    #pragma unroll
    for (int s = 0; s < 4; s++) { int w = tid + 256*s; if (w < 840) G[w] = acc[s]; }
    __syncthreads();
    if (tid < 28) {
        int i = tid;
        float nk = fmaxf(sqrtf(G[784+i]), 1e-12f);
        float lg[28], m = -1e30f;
        #pragma unroll
        for (int j = 0; j < 28; j++) {
            float nq = fmaxf(sqrtf(G[812+j]), 1e-12f);
            lg[j] = G[i*28+j] / (nk*nq) * 0.18898223650461363f;
            m = fmaxf(m, lg[j]);
        }
        float sum = 0.f;
        #pragma unroll
        for (int j = 0; j < 28; j++) { lg[j] = __expf(lg[j]-m); sum += lg[j]; }
        float inv = 1.f/sum;
        #pragma unroll
        for (int j = 0; j < 28; j++)
            attn[(((size_t)b*8 + h)*28 + i)*28 + j] = lg[j]*inv;
    }
}

// x1 = attn-applied + residual; 8 rows per barrier interval
__global__ void k_apply(const float* __restrict__ x, const float* __restrict__ kv,
                        const float* __restrict__ attn, float* __restrict__ x1) {
    int chunk = blockIdx.x, b = blockIdx.y;
    __shared__ float att[6272];
    __shared__ float vr[8][224];
    int tid = threadIdx.x;   // 224
    for (int idx = tid; idx < 6272; idx += 224) att[idx] = attn[(size_t)b*6272 + idx];
    int h = tid / 28, i = tid % 28;
    for (int nn = 0; nn < 64; nn += 8) {
        size_t row0 = (size_t)b*1280 + chunk*64 + nn;
        __syncthreads();
        for (int idx = tid; idx < 1792; idx += 224) {
            int rr = idx / 224, cc = idx % 224;
            vr[rr][cc] = kv[(row0 + rr)*448 + 224 + cc];
        }
        __syncthreads();
        #pragma unroll
        for (int rr = 0; rr < 8; rr++) {
            float a = 0.f;
            #pragma unroll
            for (int j = 0; j < 28; j++) a += att[(h*28+i)*28 + j] * vr[rr][h*28 + j];
            size_t o = (row0 + rr)*224 + tid;
            x1[o] = x[o] + a;
        }
    }
}

// ---------------- transpose + LN into (b, L=8960, 32) ----------------
__global__ void k_ln1(const float* __restrict__ x1, const float* __restrict__ g,
                      const float* __restrict__ be, float* __restrict__ xn) {
    int ww = blockIdx.x, b = blockIdx.y;
    __shared__ float s[32*225];
    int tid = threadIdx.x;   // 256
    for (int idx = tid; idx < 32*224; idx += 256) {
        int m = idx / 224, cc = idx % 224;
        s[m*225 + cc] = x1[((size_t)b*1280 + m*40 + ww)*224 + cc];
    }
    __syncthreads();
    for (int cc = tid; cc < 224; cc += 256) {
        float mean = 0.f;
        #pragma unroll
        for (int m = 0; m < 32; m++) mean += s[m*225+cc];
        mean *= (1.f/32.f);
        float var = 0.f;
        #pragma unroll
        for (int m = 0; m < 32; m++) { float d = s[m*225+cc]-mean; var += d*d; }
        var *= (1.f/32.f);
        float inv = rsqrtf(var + 1e-5f);
        size_t ob = ((size_t)b*8960 + ww*224 + cc)*32;
        #pragma unroll
        for (int m = 0; m < 32; m++)
            xn[ob + m] = (s[m*225+cc]-mean)*inv*g[m] + be[m];
    }
}

// ---------------- mamba pieces ----------------
// 2 outputs per thread via float2
__global__ void k_conv1d(const float* __restrict__ xz, const float* __restrict__ cw,
                         const float* __restrict__ cb, float* __restrict__ xc) {
    size_t id = (size_t)blockIdx.x*256 + threadIdx.x;   // 286720*32
    size_t row = id >> 5; int d2 = (int)(id & 31) * 2;
    size_t b = row / 8960; int l = (int)(row % 8960);
    float ax = cb[d2], ay = cb[d2+1];
    #pragma unroll
    for (int t = 0; t < 4; t++) {
        int ls = l - 3 + t;
        if (ls >= 0) {
            float2 v = *(const float2*)(xz + ((size_t)b*8960 + ls)*128 + d2);
            ax += v.x * cw[d2*4 + t];
            ay += v.y * cw[(d2+1)*4 + t];
        }
    }
    float2 o; o.x = siluf(ax); o.y = siluf(ay);
    *(float2*)(xc + row*64 + d2) = o;
}

__global__ void k_dtbc(const float* __restrict__ xdbl, const float* __restrict__ dtW,
                       const float* __restrict__ dtb, float* __restrict__ dt,
                       float* __restrict__ Bm, float* __restrict__ Cm) {
    size_t id = (size_t)blockIdx.x*256 + threadIdx.x;
    size_t row = id / 96; int j = (int)(id % 96);
    const float* xd = xdbl + row*34;
    if (j < 64) {
        float v = xd[0]*dtW[j] + xd[1]*dtW[64+j] + dtb[j];
        dt[row*64 + j] = (v > 20.f) ? v : log1pf(__expf(v));
    } else if (j < 80) {
        Bm[row*16 + (j-64)] = xd[2 + (j-64)];
    } else {
        Cm[row*16 + (j-80)] = xd[18 + (j-80)];
    }
}

// staged scan pass 1: block = (b, chunk, d-group of 16), 256 threads
__global__ __launch_bounds__(256) void k_scan1(
    const float* __restrict__ dt, const float* __restrict__ xc,
    const float* __restrict__ Bm, const float* __restrict__ Alog,
    float* __restrict__ S, float* __restrict__ sumdt) {
    int bx = blockIdx.x;                 // 8960
    int b = bx / 280, rem = bx % 280;
    int chunk = rem >> 2, dg = rem & 3;
    int tid = threadIdx.x, warp = tid >> 5, lane = tid & 31;
    int dloc = 2*warp + (lane >> 4), n = lane & 15;
    int d = dg*16 + dloc;
    __shared__ float sdt[16][16], sxc[16][16], sbm[16][16];
    float Av = -__expf(Alog[d*16 + n]);
    float h = 0.f, sdsum = 0.f;
    size_t rowbase = (size_t)b*8960 + chunk*128;
    int lr = tid >> 4, lc = tid & 15;
    for (int s = 0; s < 8; s++) {
        size_t r0 = rowbase + s*16;
        __syncthreads();
        sdt[lr][lc] = dt[(r0 + lr)*64 + dg*16 + lc];
        sxc[lr][lc] = xc[(r0 + lr)*64 + dg*16 + lc];
        sbm[lr][lc] = Bm[(r0 + lr)*16 + lc];
        __syncthreads();
        #pragma unroll
        for (int l = 0; l < 16; l++) {
            float dtv = sdt[l][dloc];
            float u   = sxc[l][dloc];
            float Bn  = sbm[l][n];
            h = __expf(Av*dtv)*h + dtv*u*Bn;
            sdsum += dtv;
        }
    }
    size_t idx = (size_t)(b*64 + d)*70 + chunk;
    S[idx*16 + n] = h;
    if (n == 0) sumdt[idx] = sdsum;
}

__global__ void k_scan2(const float* __restrict__ S, const float* __restrict__ sumdt,
                        const float* __restrict__ Alog, float* __restrict__ H0) {
    int t = blockIdx.x*256 + threadIdx.x;
    int b = t >> 10; int d = (t >> 4) & 63; int n = t & 15;
    float Av = -__expf(Alog[d*16 + n]);
    float carry = 0.f;
    size_t base = (size_t)(b*64 + d)*70;
    for (int ch = 0; ch < 70; ch++) {
        size_t idx = base + ch;
        H0[idx*16 + n] = carry;
        carry = carry*__expf(Av*sumdt[idx]) + S[idx*16 + n];
    }
}

// staged scan pass 3: same decomposition; y staged through smem
__global__ __launch_bounds__(256) void k_scan3(
    const float* __restrict__ dt, const float* __restrict__ xc,
    const float* __restrict__ Bm, const float* __restrict__ Cm,
    const float* __restrict__ Alog, const float* __restrict__ H0,
    float* __restrict__ y) {
    int bx = blockIdx.x;
    int b = bx / 280, rem = bx % 280;
    int chunk = rem >> 2, dg = rem & 3;
    int tid = threadIdx.x, warp = tid >> 5, lane = tid & 31;
    int dloc = 2*warp + (lane >> 4), n = lane & 15;
    int d = dg*16 + dloc;
    __shared__ float sdt[16][16], sxc[16][16], sbm[16][16], scm[16][16], sy[16][16];
    float Av = -__expf(Alog[d*16 + n]);
    size_t idx = (size_t)(b*64 + d)*70 + chunk;
    float h = H0[idx*16 + n];
    size_t rowbase = (size_t)b*8960 + chunk*128;
    int lr = tid >> 4, lc = tid & 15;
    for (int s = 0; s < 8; s++) {
        size_t r0 = rowbase + s*16;
        __syncthreads();
        sdt[lr][lc] = dt[(r0 + lr)*64 + dg*16 + lc];
        sxc[lr][lc] = xc[(r0 + lr)*64 + dg*16 + lc];
        sbm[lr][lc] = Bm[(r0 + lr)*16 + lc];
        scm[lr][lc] = Cm[(r0 + lr)*16 + lc];
        __syncthreads();
        #pragma unroll
        for (int l = 0; l < 16; l++) {
            float dtv = sdt[l][dloc];
            float u   = sxc[l][dloc];
            float Bn  = sbm[l][n];
            h = __expf(Av*dtv)*h + dtv*u*Bn;
            float yv = h * scm[l][n];
            yv += __shfl_xor_sync(0xffffffffu, yv, 8);
            yv += __shfl_xor_sync(0xffffffffu, yv, 4);
            yv += __shfl_xor_sync(0xffffffffu, yv, 2);
            yv += __shfl_xor_sync(0xffffffffu, yv, 1);
            if (n == 0) sy[l][dloc] = yv;
        }
        __syncthreads();
        y[(r0 + lr)*64 + dg*16 + lc] = sy[lr][lc];
    }
}

// gate + out_proj + skip + LN + proj; each warp handles 8 rows
__global__ void k_final(const float* __restrict__ y, const float* __restrict__ xc,
                        const float* __restrict__ xz, const float* __restrict__ xn,
                        const float* __restrict__ Dp, const float* __restrict__ opW,
                        const float* __restrict__ skipp, const float* __restrict__ g,
                        const float* __restrict__ be, const float* __restrict__ projW,
                        const float* __restrict__ projb, float* __restrict__ xm2) {
    __shared__ float sop[2048], spj[1024];
    int tid = threadIdx.x;   // 256
    for (int i = tid; i < 2048; i += 256) sop[i] = opW[i];
    for (int i = tid; i < 1024; i += 256) spj[i] = projW[i];
    __syncthreads();
    int warp = tid >> 5, lane = tid & 31;
    float skip = skipp[0];
    float dpl = Dp[lane], dph = Dp[32+lane];
    float gl = g[lane], bel = be[lane], pbl = projb[lane];
    #pragma unroll
    for (int t = 0; t < 8; t++) {
        size_t r = ((size_t)blockIdx.x*8 + warp)*8 + t;
        float y0 = y[r*64 + lane],      y1 = y[r*64 + 32 + lane];
        float c0 = xc[r*64 + lane],     c1 = xc[r*64 + 32 + lane];
        float z0 = xz[r*128 + 64 + lane], z1 = xz[r*128 + 96 + lane];
        float yy0 = (y0 + c0*dpl) * siluf(z0);
        float yy1 = (y1 + c1*dph) * siluf(z1);
        float acc = 0.f;
        #pragma unroll
        for (int d = 0; d < 32; d++) acc += __shfl_sync(0xffffffffu, yy0, d) * sop[d*32 + lane];
        #pragma unroll
        for (int d = 0; d < 32; d++) acc += __shfl_sync(0xffffffffu, yy1, d) * sop[(d+32)*32 + lane];
        float xm = acc + skip * xn[r*32 + lane];
        float mean = xm;
        #pragma unroll
        for (int o = 16; o; o >>= 1) mean += __shfl_xor_sync(0xffffffffu, mean, o);
        mean *= (1.f/32.f);
        float dv = xm - mean, var = dv*dv;
        #pragma unroll
        for (int o = 16; o; o >>= 1) var += __shfl_xor_sync(0xffffffffu, var, o);
        var *= (1.f/32.f);
        float v = dv * rsqrtf(var + 1e-5f) * gl + bel;
        float acc2 = pbl;
        #pragma unroll
        for (int mm = 0; mm < 32; mm++) acc2 += __shfl_sync(0xffffffffu, v, mm) * spj[mm*32 + lane];
        xm2[r*32 + lane] = acc2;
    }
}

__global__ void k_addback(const float* __restrict__ x1, const float* __restrict__ xm2,
                          float* __restrict__ x2) {
    int ww = blockIdx.x, b = blockIdx.y;
    __shared__ float s[224*33];
    int tid = threadIdx.x;   // 256
    for (int idx = tid; idx < 224*32; idx += 256) {
        int cc = idx >> 5, m = idx & 31;
        s[cc*33 + m] = xm2[((size_t)b*8960 + ww*224 + cc)*32 + m];
    }
    __syncthreads();
    for (int idx = tid; idx < 32*224; idx += 256) {
        int m = idx / 224, cc = idx % 224;
        size_t o = ((size_t)b*1280 + m*40 + ww)*224 + cc;
        x2[o] = x1[o] + s[cc*33 + m];
    }
}

// ---------------- conv3d 5x5x5, pad 2, smem-tiled per ky-plane ----------------
__global__ void k_conv3d(const float* __restrict__ x2, const float* __restrict__ cw,
                         const float* __restrict__ cb, float* __restrict__ x3) {
    int y = blockIdx.x, b = blockIdx.y;
    int xx = threadIdx.x;   // 224
    __shared__ float ws[125];
    __shared__ float sp[32][228];
    if (xx < 125) ws[xx] = cw[xx];
    if (xx < 32) { sp[xx][0]=0.f; sp[xx][1]=0.f; sp[xx][226]=0.f; sp[xx][227]=0.f; }
    float acc[32];
    #pragma unroll
    for (int d = 0; d < 32; d++) acc[d] = 0.f;
    for (int ky = 0; ky < 5; ky++) {
        int yy = y + ky - 2;
        if (yy < 0 || yy >= 40) continue;
        __syncthreads();
        for (int i = 0; i < 32; i++)
            sp[i][xx+2] = x2[(((size_t)b*32 + i)*40 + yy)*224 + xx];
        __syncthreads();
        #pragma unroll
        for (int kx = 0; kx < 5; kx++) {
            float v[36];
            v[0]=v[1]=v[34]=v[35]=0.f;
            #pragma unroll
            for (int i = 0; i < 32; i++) v[i+2] = sp[i][xx + kx];
            #pragma unroll
            for (int kz = 0; kz < 5; kz++) {
                float wv = ws[(kz*5 + ky)*5 + kx];
                #pragma unroll
                for (int d = 0; d < 32; d++) acc[d] += v[d+kz]*wv;
            }
        }
    }
    float bias = cb[0];
    #pragma unroll
    for (int d = 0; d < 32; d++)
        x3[(((size_t)b*32 + d)*40 + y)*224 + xx] = acc[d] + bias;
}

// ---------------- DWT: all 4 subbands per thread ----------------
__global__ void k_dwt(const float* __restrict__ x3, float* __restrict__ xw) {
    size_t id = (size_t)blockIdx.x*256 + threadIdx.x;   // 2752512
    int c = (int)(id % 224); size_t rw = id / 224;
    int win = (int)(rw >> 6), tok = (int)(rw & 63);
    int bb = win / 6, w6 = win % 6;
    int wi = w6 / 3, wj = w6 % 3;
    int ti = tok >> 3, tj = tok & 7;
    int i2 = wi*8 + ti;
    int j2 = wj*8 + tj;
    int j = (j2 < 20) ? j2 : 38 - j2;   // reflect pad
    size_t base = (((size_t)bb*32 + 2*i2)*40 + 2*j)*224 + c;
    float a  = x3[base],        bv = x3[base + 224];
    float c2 = x3[base + 8960], d2 = x3[base + 9184];
    const size_t SS = (size_t)12288*224;
    xw[id]        = 0.5f*(a + bv + c2 + d2);
    xw[id + SS]   = 0.5f*(a + bv - c2 - d2);
    xw[id + 2*SS] = 0.5f*(a - bv + c2 - d2);
    xw[id + 3*SS] = 0.5f*(a - bv - c2 + d2);
}

// ---------------- window attention: online softmax, q in regs ----------------
__global__ void k_wattn(const float* __restrict__ qkvw, const float* __restrict__ pe,
                        float* __restrict__ obuf) {
    int win = blockIdx.x, head = blockIdx.y;
    __shared__ __align__(16) float ks[64*28], vs[64*28];
    int tid = threadIdx.x;   // 64
    size_t wbase = (size_t)win * 64;
    for (int idx = tid; idx < 1792; idx += 64) {
        int tok = idx / 28, dd = idx % 28;
        size_t rb = (wbase + tok)*672 + head*28 + dd;
        ks[idx] = qkvw[rb + 224];
        vs[idx] = qkvw[rb + 448];
    }
    // q row direct to registers (scaled)
    float qr[28];
    {
        const float4* qp = (const float4*)(qkvw + (wbase + tid)*672 + head*28);
        #pragma unroll
        for (int q4 = 0; q4 < 7; q4++) {
            float4 v = qp[q4];
            qr[q4*4+0] = v.x * 0.18898223650461363f;
            qr[q4*4+1] = v.y * 0.18898223650461363f;
            qr[q4*4+2] = v.z * 0.18898223650461363f;
            qr[q4*4+3] = v.w * 0.18898223650461363f;
        }
    }
    __syncthreads();
    const float* per = pe + ((size_t)head*64 + tid)*64;
    float m = -1e30f, sum = 0.f;
    float acc[28];
    #pragma unroll
    for (int dd = 0; dd < 28; dd++) acc[dd] = 0.f;
    for (int j = 0; j < 64; j++) {
        const float4* k4 = (const float4*)&ks[j*28];
        float dot = 0.f;
        #pragma unroll
        for (int q4 = 0; q4 < 7; q4++) {
            float4 kk = k4[q4];
            dot += qr[q4*4+0]*kk.x + qr[q4*4+1]*kk.y
                 + qr[q4*4+2]*kk.z + qr[q4*4+3]*kk.w;
        }
        dot += per[j];
        if (dot > m) {
            float corr = __expf(m - dot);   // exp(-1e30-x) underflows to 0 first time
            sum *= corr;
            #pragma unroll
            for (int dd = 0; dd < 28; dd++) acc[dd] *= corr;
            m = dot;
        }
        float e = __expf(dot - m);
        sum += e;
        const float4* v4 = (const float4*)&vs[j*28];
        #pragma unroll
        for (int q4 = 0; q4 < 7; q4++) {
            float4 vv = v4[q4];
            acc[q4*4+0] += e*vv.x; acc[q4*4+1] += e*vv.y;
            acc[q4*4+2] += e*vv.z; acc[q4*4+3] += e*vv.w;
        }
    }
    float inv = 1.f / sum;
    size_t ob = (wbase + tid)*224 + head*28;
    #pragma unroll
    for (int dd = 0; dd < 28; dd++) obuf[ob + dd] = acc[dd] * inv;
}

// ---------------- IWT + crop + final layout ----------------
__global__ void k_iwt(const float* __restrict__ oproj, float* __restrict__ out) {
    size_t id = (size_t)blockIdx.x*256 + threadIdx.x;   // 2293760
    int c = (int)(id % 224); size_t r = id / 224;
    int j = (int)(r % 20); r /= 20;
    int i = (int)(r % 16); int bb = (int)(r / 16);
    int wi = i >> 3, ti = i & 7, wj = j >> 3, tj = j & 7;
    size_t row0 = ((size_t)(bb*6 + wi*3 + wj))*64 + ti*8 + tj;
    float A  = oproj[row0*224 + c];
    float Hh = oproj[(row0 + 12288)*224 + c];
    float V  = oproj[(row0 + 24576)*224 + c];
    float D  = oproj[(row0 + 36864)*224 + c];
    size_t oo = (((size_t)bb*32 + 2*i)*40 + 2*j)*224 + c;
    out[oo]          = 0.5f*(A + Hh + V + D);
    out[oo + 224]    = 0.5f*(A + Hh - V - D);
    out[oo + 8960]   = 0.5f*(A - Hh + V - D);
    out[oo + 9184]   = 0.5f*(A - Hh - V + D);
}

// ---------------- launcher ----------------
extern "C" void kernel_launch(void* const* d_in, const int* in_sizes, int n_in,
                              void* d_out, int out_size) {
    const float* x       = (const float*)d_in[0];
    const float* Wq      = (const float*)d_in[1];
    const float* Wkv     = (const float*)d_in[2];
    const float* ln_g    = (const float*)d_in[3];
    const float* ln_b    = (const float*)d_in[4];
    const float* in_proj = (const float*)d_in[5];
    const float* conv1dW = (const float*)d_in[6];
    const float* conv1db = (const float*)d_in[7];
    const float* x_projW = (const float*)d_in[8];
    const float* dt_projW= (const float*)d_in[9];
    const float* dt_projb= (const float*)d_in[10];
    const float* A_log   = (const float*)d_in[11];
    const float* Dp      = (const float*)d_in[12];
    const float* out_projW=(const float*)d_in[13];
    const float* skip    = (const float*)d_in[14];
    const float* projW   = (const float*)d_in[15];
    const float* projb   = (const float*)d_in[16];
    const float* conv3dW = (const float*)d_in[17];
    const float* conv3db = (const float*)d_in[18];
    const float* Wq1     = (const float*)d_in[19];
    const float* Wkv1    = (const float*)d_in[20];
    const float* pos_emb = (const float*)d_in[21];
    GemmPtrs4 po;
    po.B[0] = (const float*)d_in[22]; po.bias[0] = (const float*)d_in[23];
    po.B[1] = (const float*)d_in[24]; po.bias[1] = (const float*)d_in[25];
    po.B[2] = (const float*)d_in[26]; po.bias[2] = (const float*)d_in[27];
    po.B[3] = (const float*)d_in[28]; po.bias[3] = (const float*)d_in[29];
    float* out = (float*)d_out;

    float *p_q, *p_kv, *p_attn, *p_x1, *p_xn, *p_xz, *p_xc, *p_xdbl, *p_dt,
          *p_Bm, *p_Cm, *p_y, *p_S, *p_sd, *p_H0, *p_xm2, *p_x2, *p_x3,
          *p_xw, *p_qkvw, *p_obuf, *p_oproj;
    cudaGetSymbolAddress((void**)&p_q,    g_q);
    cudaGetSymbolAddress((void**)&p_kv,   g_kv);
    cudaGetSymbolAddress((void**)&p_attn, g_attn);
    cudaGetSymbolAddress((void**)&p_x1,   g_x1);
    cudaGetSymbolAddress((void**)&p_xn,   g_xn);
    cudaGetSymbolAddress((void**)&p_xz,   g_xz);
    cudaGetSymbolAddress((void**)&p_xc,   g_xc);
    cudaGetSymbolAddress((void**)&p_xdbl, g_xdbl);
    cudaGetSymbolAddress((void**)&p_dt,   g_dt);
    cudaGetSymbolAddress((void**)&p_Bm,   g_Bm);
    cudaGetSymbolAddress((void**)&p_Cm,   g_Cm);
    cudaGetSymbolAddress((void**)&p_y,    g_y);
    cudaGetSymbolAddress((void**)&p_S,    g_S);
    cudaGetSymbolAddress((void**)&p_sd,   g_sumdt);
    cudaGetSymbolAddress((void**)&p_H0,   g_H0);
    cudaGetSymbolAddress((void**)&p_xm2,  g_xm2);
    cudaGetSymbolAddress((void**)&p_x2,   g_x2);
    cudaGetSymbolAddress((void**)&p_x3,   g_x3);
    cudaGetSymbolAddress((void**)&p_xw,   g_xw);
    cudaGetSymbolAddress((void**)&p_qkvw, g_qkvw);
    cudaGetSymbolAddress((void**)&p_obuf, g_obuf);
    cudaGetSymbolAddress((void**)&p_oproj,g_oproj);

    // stage 1
    sgemm_k<<<dim3(4, 320), 256>>>(x, Wq,  p_q,  nullptr, 224, 224, 224, 224, 224);
    sgemm_k<<<dim3(7, 320), 256>>>(x, Wkv, p_kv, nullptr, 448, 224, 224, 448, 448);
    k_gram <<<dim3(32, 8), 256>>>(p_q, p_kv, p_attn);
    k_apply<<<dim3(20, 32), 224>>>(x, p_kv, p_attn, p_x1);

    // stage 2: mamba
    k_ln1<<<dim3(40, 32), 256>>>(p_x1, ln_g, ln_b, p_xn);
    sgemm_k<<<dim3(2, 2240), 256>>>(p_xn, in_proj, p_xz, nullptr, 128, 32, 32, 128, 128);
    k_conv1d<<<35840, 256>>>(p_xz, conv1dW, conv1db, p_xc);
    sgemm_k<<<dim3(1, 2240), 256>>>(p_xc, x_projW, p_xdbl, nullptr, 34, 64, 64, 34, 34);
    k_dtbc<<<107520, 256>>>(p_xdbl, dt_projW, dt_projb, p_dt, p_Bm, p_Cm);
    k_scan1<<<8960, 256>>>(p_dt, p_xc, p_Bm, A_log, p_S, p_sd);
    k_scan2<<<128, 256>>>(p_S, p_sd, A_log, p_H0);
    k_scan3<<<8960, 256>>>(p_dt, p_xc, p_Bm, p_Cm, A_log, p_H0, p_y);
    k_final<<<4480, 256>>>(p_y, p_xc, p_xz, p_xn, Dp, out_projW, skip,
                           ln_g, ln_b, projW, projb, p_xm2);
    k_addback<<<dim3(40, 32), 256>>>(p_x1, p_xm2, p_x2);

    // stage 3: conv3d
    k_conv3d<<<dim3(40, 32), 224>>>(p_x2, conv3dW, conv3db, p_x3);

    // stage 4: DWT + window attention
    k_dwt<<<10752, 256>>>(p_x3, p_xw);
    sgemm_k<<<dim3(4, 384), 256>>>(p_xw, Wq1,  p_qkvw,       nullptr, 224, 224, 224, 224, 672);
    sgemm_k<<<dim3(7, 384), 256>>>(p_xw, Wkv1, p_qkvw + 224, nullptr, 448, 224, 224, 448, 672);
    k_wattn<<<dim3(768, 8), 64>>>(p_qkvw, pos_emb, p_obuf);
    sgemm_b4<<<dim3(4, 96, 4), 256>>>(p_obuf, po, p_oproj,
                                      224, 224, 224, 224, 224,
                                      (long long)12288*224, (long long)12288*224);

    // stage 5: IWT + output
    k_iwt<<<8960, 256>>>(p_oproj, out);
}

// round 10
// speedup vs baseline: 1.3157x; 1.0266x over previous
#include <cuda_runtime.h>
#include <math.h>
#include <stdint.h>

// ---------------- static scratch (16B aligned) ----------------
__device__ __align__(16) float g_q    [40960u*224u];
__device__ __align__(16) float g_kv   [40960u*448u];
__device__ __align__(16) float g_attn [32*8*28*28];
__device__ __align__(16) float g_x1   [9175040];
__device__ __align__(16) float g_xn   [9175040];      // 286720 x 32
__device__ __align__(16) float g_xz   [36700160];     // 286720 x 128
__device__ __align__(16) float g_xc   [18350080];     // 286720 x 64
__device__ __align__(16) float g_dt   [18350080];
__device__ __align__(16) float g_Bm   [4587520];
__device__ __align__(16) float g_Cm   [4587520];
__device__ __align__(16) float g_y    [18350080];
__device__ __align__(16) float g_S    [2293760];      // 32*64*70*16
__device__ __align__(16) float g_sumdt[143360];       // 32*64*70
__device__ __align__(16) float g_H0   [2293760];
__device__ __align__(16) float g_xm2  [9175040];      // 286720 x 32
__device__ __align__(16) float g_x2   [9175040];
__device__ __align__(16) float g_x3   [9175040];
__device__ __align__(16) float g_xw   [11010048];     // 49152 x 224
__device__ __align__(16) float g_qkvw [33030144];     // 49152 x 672
__device__ __align__(16) float g_obuf [11010048];
__device__ __align__(16) float g_oproj[11010048];

__device__ __forceinline__ float siluf(float v){ return v / (1.f + __expf(-v)); }

struct GemmPtrs4 { const float* B[4]; const float* bias[4]; };

// ---------------- SGEMM: 128x64 tile, 8x4 micro, BK=16, DOUBLE-BUFFERED ------
__device__ __forceinline__ void sgemm_core(
    const float* __restrict__ A, const float* __restrict__ B,
    float* __restrict__ C, const float* __restrict__ bias,
    int N, int K, int lda, int ldb, int ldc,
    float (*As)[16][128], float (*Bs)[16][64])
{
    const int bm = blockIdx.y * 128, bn = blockIdx.x * 64;
    const int tid = threadIdx.x;
    const int tr = tid >> 4, tc = tid & 15;
    const int br = tid >> 4, bc0 = (tid & 15) * 4;   // B loader
    float acc[8][4];
    #pragma unroll
    for (int i = 0; i < 8; i++)
        #pragma unroll
        for (int j = 0; j < 4; j++) acc[i][j] = 0.f;

    float4 ra[2]; float rb[4];
    #pragma unroll
    for (int i = 0; i < 2; i++) {
        int idx = tid + i * 256;
        int r = idx >> 2, c4 = (idx & 3) * 4;
        ra[i] = *(const float4*)(A + (size_t)(bm + r) * lda + c4);
    }
    #pragma unroll
    for (int i = 0; i < 4; i++) {
        int n = bn + bc0 + i;
        rb[i] = (n < N) ? B[(size_t)br * ldb + n] : 0.f;
    }
    int buf = 0;
    #pragma unroll
    for (int i = 0; i < 2; i++) {
        int idx = tid + i * 256;
        int r = idx >> 2, c4 = (idx & 3) * 4;
        As[0][c4+0][r]=ra[i].x; As[0][c4+1][r]=ra[i].y;
        As[0][c4+2][r]=ra[i].z; As[0][c4+3][r]=ra[i].w;
    }
    #pragma unroll
    for (int i = 0; i < 4; i++) Bs[0][br][bc0+i] = rb[i];
    __syncthreads();

    for (int k0 = 0; k0 < K; k0 += 16) {
        const bool more = (k0 + 16) < K;
        float4 ra2[2]; float rb2[4];
        if (more) {
            #pragma unroll
            for (int i = 0; i < 2; i++) {
                int idx = tid + i * 256;
                int r = idx >> 2, c4 = (idx & 3) * 4;
                ra2[i] = *(const float4*)(A + (size_t)(bm + r) * lda + k0 + 16 + c4);
            }
            #pragma unroll
            for (int i = 0; i < 4; i++) {
                int n = bn + bc0 + i;
                rb2[i] = (n < N) ? B[(size_t)(k0 + 16 + br) * ldb + n] : 0.f;
            }
        }
        #pragma unroll
        for (int kk = 0; kk < 16; kk++) {
            float4 a0 = *(const float4*)&As[buf][kk][tr*8];
            float4 a1 = *(const float4*)&As[buf][kk][tr*8+4];
            float4 b0 = *(const float4*)&Bs[buf][kk][tc*4];
            float a[8] = {a0.x,a0.y,a0.z,a0.w,a1.x,a1.y,a1.z,a1.w};
            float b[4] = {b0.x,b0.y,b0.z,b0.w};
            #pragma unroll
            for (int i = 0; i < 8; i++)
                #pragma unroll
                for (int j = 0; j < 4; j++) acc[i][j] += a[i]*b[j];
        }
        if (more) {
            int nb = buf ^ 1;
            #pragma unroll
            for (int i = 0; i < 2; i++) {
                int idx = tid + i * 256;
                int r = idx >> 2, c4 = (idx & 3) * 4;
                As[nb][c4+0][r]=ra2[i].x; As[nb][c4+1][r]=ra2[i].y;
                As[nb][c4+2][r]=ra2[i].z; As[nb][c4+3][r]=ra2[i].w;
            }
            #pragma unroll
            for (int i = 0; i < 4; i++) Bs[nb][br][bc0+i] = rb2[i];
            __syncthreads();
            buf = nb;
        }
    }
    #pragma unroll
    for (int i = 0; i < 8; i++) {
        int m = bm + tr*8 + i;
        #pragma unroll
        for (int j = 0; j < 4; j++) {
            int n = bn + tc*4 + j;
            if (n < N) {
                float v = acc[i][j];
                if (bias) v += bias[n];
                C[(size_t)m * ldc + n] = v;
            }
        }
    }
}

__global__ __launch_bounds__(256) void sgemm_k(
    const float* __restrict__ A, const float* __restrict__ B,
    float* __restrict__ C, const float* __restrict__ bias,
    int N, int K, int lda, int ldb, int ldc) {
    __shared__ float As[2][16][128];
    __shared__ float Bs[2][16][64];
    sgemm_core(A, B, C, bias, N, K, lda, ldb, ldc, As, Bs);
}

__global__ __launch_bounds__(256) void sgemm_b4(
    const float* __restrict__ A, GemmPtrs4 p, float* __restrict__ C,
    int N, int K, int lda, int ldb, int ldc,
    long long strideA, long long strideC) {
    __shared__ float As[2][16][128];
    __shared__ float Bs[2][16][64];
    int z = blockIdx.z;
    sgemm_core(A + (size_t)z * strideA, p.B[z], C + (size_t)z * strideC,
               p.bias[z], N, K, lda, ldb, ldc, As, Bs);
}

// ---------------- fused x_proj GEMM (M=128/block, N=34, K=64) + dt/B/C split --
__global__ __launch_bounds__(256) void sgemm_xproj(
    const float* __restrict__ A, const float* __restrict__ B,
    const float* __restrict__ dtW, const float* __restrict__ dtb,
    float* __restrict__ dt, float* __restrict__ Bm, float* __restrict__ Cm)
{
    __shared__ float As[2][16][128];
    __shared__ float Bs[2][16][64];
    __shared__ float St[128][36];
    __shared__ float sdtW[128], sdtb[64];
    const int N = 34, K = 64, lda = 64, ldb = 34;
    const int bm = blockIdx.y * 128;
    const int tid = threadIdx.x;
    const int tr = tid >> 4, tc = tid & 15;
    const int br = tid >> 4, bc0 = (tid & 15) * 4;
    if (tid < 128) sdtW[tid] = dtW[tid];
    if (tid >= 128 && tid < 192) sdtb[tid-128] = dtb[tid-128];
    float acc[8][4];
    #pragma unroll
    for (int i = 0; i < 8; i++)
        #pragma unroll
        for (int j = 0; j < 4; j++) acc[i][j] = 0.f;

    float4 ra[2]; float rb[4];
    #pragma unroll
    for (int i = 0; i < 2; i++) {
        int idx = tid + i * 256;
        int r = idx >> 2, c4 = (idx & 3) * 4;
        ra[i] = *(const float4*)(A + (size_t)(bm + r) * lda + c4);
    }
    #pragma unroll
    for (int i = 0; i < 4; i++) {
        int n = bc0 + i;
        rb[i] = (n < N) ? B[(size_t)br * ldb + n] : 0.f;
    }
    int buf = 0;
    #pragma unroll
    for (int i = 0; i < 2; i++) {
        int idx = tid + i * 256;
        int r = idx >> 2, c4 = (idx & 3) * 4;
        As[0][c4+0][r]=ra[i].x; As[0][c4+1][r]=ra[i].y;
        As[0][c4+2][r]=ra[i].z; As[0][c4+3][r]=ra[i].w;
    }
    #pragma unroll
    for (int i = 0; i < 4; i++) Bs[0][br][bc0+i] = rb[i];
    __syncthreads();

    for (int k0 = 0; k0 < K; k0 += 16) {
        const bool more = (k0 + 16) < K;
        float4 ra2[2]; float rb2[4];
        if (more) {
            #pragma unroll
            for (int i = 0; i < 2; i++) {
                int idx = tid + i * 256;
                int r = idx >> 2, c4 = (idx & 3) * 4;
                ra2[i] = *(const float4*)(A + (size_t)(bm + r) * lda + k0 + 16 + c4);
            }
            #pragma unroll
            for (int i = 0; i < 4; i++) {
                int n = bc0 + i;
                rb2[i] = (n < N) ? B[(size_t)(k0 + 16 + br) * ldb + n] : 0.f;
            }
        }
        #pragma unroll
        for (int kk = 0; kk < 16; kk++) {
            float4 a0 = *(const float4*)&As[buf][kk][tr*8];
            float4 a1 = *(const float4*)&As[buf][kk][tr*8+4];
            float4 b0 = *(const float4*)&Bs[buf][kk][tc*4];
            float a[8] = {a0.x,a0.y,a0.z,a0.w,a1.x,a1.y,a1.z,a1.w};
            float b[4] = {b0.x,b0.y,b0.z,b0.w};
            #pragma unroll
            for (int i = 0; i < 8; i++)
                #pragma unroll
                for (int j = 0; j < 4; j++) acc[i][j] += a[i]*b[j];
        }
        if (more) {
            int nb = buf ^ 1;
            #pragma unroll
            for (int i = 0; i < 2; i++) {
                int idx = tid + i * 256;
                int r = idx >> 2, c4 = (idx & 3) * 4;
                As[nb][c4+0][r]=ra2[i].x; As[nb][c4+1][r]=ra2[i].y;
                As[nb][c4+2][r]=ra2[i].z; As[nb][c4+3][r]=ra2[i].w;
            }
            #pragma unroll
            for (int i = 0; i < 4; i++) Bs[nb][br][bc0+i] = rb2[i];
            __syncthreads();
            buf = nb;
        }
    }
    // stage the 128x34 result tile
    #pragma unroll
    for (int i = 0; i < 8; i++) {
        #pragma unroll
        for (int j = 0; j < 4; j++) {
            int n = tc*4 + j;
            if (n < N) St[tr*8 + i][n] = acc[i][j];
        }
    }
    __syncthreads();
    // dt = softplus(St[:,0:2] @ dtW + dtb)
    for (int idx = tid; idx < 128*64; idx += 256) {
        int r = idx >> 6, d = idx & 63;
        float v = St[r][0]*sdtW[d] + St[r][1]*sdtW[64+d] + sdtb[d];
        dt[(size_t)(bm + r)*64 + d] = (v > 20.f) ? v : log1pf(__expf(v));
    }
    // Bm/Cm split
    for (int idx = tid; idx < 128*16; idx += 256) {
        int r = idx >> 4, n = idx & 15;
        Bm[(size_t)(bm + r)*16 + n] = St[r][2 + n];
        Cm[(size_t)(bm + r)*16 + n] = St[r][18 + n];
    }
}

// ---------------- stage 1: channel attention ----------------
__global__ void k_gram(const float* __restrict__ q, const float* __restrict__ kv,
                       float* __restrict__ attn) {
    int b = blockIdx.x, h = blockIdx.y;
    __shared__ float kt[32][28], qt[32][28];
    __shared__ float G[840];
    int tid = threadIdx.x;   // 256
    float acc[4] = {0.f,0.f,0.f,0.f};
    for (int nt = 0; nt < 40; nt++) {
        for (int idx = tid; idx < 896; idx += 256) {
            int n = idx / 28, i = idx % 28;
            size_t row = (size_t)b*1280 + nt*32 + n;
            kt[n][i] = kv[row*448 + h*28 + i];
            qt[n][i] = q [row*224 + h*28 + i];
        }
        __syncthreads();
        #pragma unroll
        for (int s = 0; s < 4; s++) {
            int w = tid + 256*s;
            if (w < 784) {
                int i = w/28, j = w%28; float a = acc[s];
                #pragma unroll
                for (int n = 0; n < 32; n++) a += kt[n][i]*qt[n][j];
                acc[s] = a;
            } else if (w < 812) {
                int i = w - 784; float a = acc[s];
                #pragma unroll
                for (int n = 0; n < 32; n++) a += kt[n][i]*kt[n][i];
                acc[s] = a;
            } else if (w < 840) {
                int j = w - 812; float a = acc[s];
                #pragma unroll
                for (int n = 0; n < 32; n++) a += qt[n][j]*qt[n][j];
                acc[s] = a;
            }
        }
        __syncthreads();
    }
    #pragma unroll
    for (int s = 0; s < 4; s++) { int w = tid + 256*s; if (w < 840) G[w] = acc[s]; }
    __syncthreads();
    if (tid < 28) {
        int i = tid;
        float nk = fmaxf(sqrtf(G[784+i]), 1e-12f);
        float lg[28], m = -1e30f;
        #pragma unroll
        for (int j = 0; j < 28; j++) {
            float nq = fmaxf(sqrtf(G[812+j]), 1e-12f);
            lg[j] = G[i*28+j] / (nk*nq) * 0.18898223650461363f;
            m = fmaxf(m, lg[j]);
        }
        float sum = 0.f;
        #pragma unroll
        for (int j = 0; j < 28; j++) { lg[j] = __expf(lg[j]-m); sum += lg[j]; }
        float inv = 1.f/sum;
        #pragma unroll
        for (int j = 0; j < 28; j++)
            attn[(((size_t)b*8 + h)*28 + i)*28 + j] = lg[j]*inv;
    }
}

// x1 = attn-applied + residual; attention row in REGISTERS
__global__ void k_apply(const float* __restrict__ x, const float* __restrict__ kv,
                        const float* __restrict__ attn, float* __restrict__ x1) {
    int chunk = blockIdx.x, b = blockIdx.y;
    __shared__ float vr[8][224];
    int tid = threadIdx.x;   // 224
    int h = tid / 28, i = tid % 28;
    float att[28];
    {
        const float4* ap = (const float4*)(attn + (((size_t)b*8 + h)*28 + i)*28);
        #pragma unroll
        for (int q4 = 0; q4 < 7; q4++) {
            float4 v = ap[q4];
            att[q4*4+0]=v.x; att[q4*4+1]=v.y; att[q4*4+2]=v.z; att[q4*4+3]=v.w;
        }
    }
    for (int nn = 0; nn < 64; nn += 8) {
        size_t row0 = (size_t)b*1280 + chunk*64 + nn;
        __syncthreads();
        for (int idx = tid; idx < 1792; idx += 224) {
            int rr = idx / 224, cc = idx % 224;
            vr[rr][cc] = kv[(row0 + rr)*448 + 224 + cc];
        }
        __syncthreads();
        #pragma unroll
        for (int rr = 0; rr < 8; rr++) {
            float a = 0.f;
            #pragma unroll
            for (int j = 0; j < 28; j++) a += att[j] * vr[rr][h*28 + j];
            size_t o = (row0 + rr)*224 + tid;
            x1[o] = x[o] + a;
        }
    }
}

// ---------------- transpose + LN into (b, L=8960, 32) ----------------
__global__ void k_ln1(const float* __restrict__ x1, const float* __restrict__ g,
                      const float* __restrict__ be, float* __restrict__ xn) {
    int ww = blockIdx.x, b = blockIdx.y;
    __shared__ float s[32*225];
    int tid = threadIdx.x;   // 256
    for (int idx = tid; idx < 32*224; idx += 256) {
        int m = idx / 224, cc = idx % 224;
        s[m*225 + cc] = x1[((size_t)b*1280 + m*40 + ww)*224 + cc];
    }
    __syncthreads();
    for (int cc = tid; cc < 224; cc += 256) {
        float mean = 0.f;
        #pragma unroll
        for (int m = 0; m < 32; m++) mean += s[m*225+cc];
        mean *= (1.f/32.f);
        float var = 0.f;
        #pragma unroll
        for (int m = 0; m < 32; m++) { float d = s[m*225+cc]-mean; var += d*d; }
        var *= (1.f/32.f);
        float inv = rsqrtf(var + 1e-5f);
        size_t ob = ((size_t)b*8960 + ww*224 + cc)*32;
        #pragma unroll
        for (int m = 0; m < 32; m++)
            xn[ob + m] = (s[m*225+cc]-mean)*inv*g[m] + be[m];
    }
}

// ---------------- mamba pieces ----------------
// 4 outputs per thread via float4
__global__ void k_conv1d(const float* __restrict__ xz, const float* __restrict__ cw,
                         const float* __restrict__ cb, float* __restrict__ xc) {
    size_t id = (size_t)blockIdx.x*256 + threadIdx.x;   // 286720*16
    size_t row = id >> 4; int d4 = (int)(id & 15) * 4;
    size_t b = row / 8960; int l = (int)(row % 8960);
    float a0 = cb[d4], a1 = cb[d4+1], a2 = cb[d4+2], a3 = cb[d4+3];
    #pragma unroll
    for (int t = 0; t < 4; t++) {
        int ls = l - 3 + t;
        if (ls >= 0) {
            float4 v = *(const float4*)(xz + ((size_t)b*8960 + ls)*128 + d4);
            a0 += v.x * cw[d4*4 + t];
            a1 += v.y * cw[(d4+1)*4 + t];
            a2 += v.z * cw[(d4+2)*4 + t];
            a3 += v.w * cw[(d4+3)*4 + t];
        }
    }
    float4 o; o.x = siluf(a0); o.y = siluf(a1); o.z = siluf(a2); o.w = siluf(a3);
    *(float4*)(xc + row*64 + d4) = o;
}

// staged scan pass 1: block = (b, chunk, d-group of 16), 256 threads
__global__ __launch_bounds__(256) void k_scan1(
    const float* __restrict__ dt, const float* __restrict__ xc,
    const float* __restrict__ Bm, const float* __restrict__ Alog,
    float* __restrict__ S, float* __restrict__ sumdt) {
    int bx = blockIdx.x;                 // 8960
    int b = bx / 280, rem = bx % 280;
    int chunk = rem >> 2, dg = rem & 3;
    int tid = threadIdx.x, warp = tid >> 5, lane = tid & 31;
    int dloc = 2*warp + (lane >> 4), n = lane & 15;
    int d = dg*16 + dloc;
    __shared__ float sdt[16][16], sxc[16][16], sbm[16][16];
    float Av = -__expf(Alog[d*16 + n]);
    float h = 0.f, sdsum = 0.f;
    size_t rowbase = (size_t)b*8960 + chunk*128;
    int lr = tid >> 4, lc = tid & 15;
    for (int s = 0; s < 8; s++) {
        size_t r0 = rowbase + s*16;
        __syncthreads();
        sdt[lr][lc] = dt[(r0 + lr)*64 + dg*16 + lc];
        sxc[lr][lc] = xc[(r0 + lr)*64 + dg*16 + lc];
        sbm[lr][lc] = Bm[(r0 + lr)*16 + lc];
        __syncthreads();
        #pragma unroll
        for (int l = 0; l < 16; l++) {
            float dtv = sdt[l][dloc];
            float u   = sxc[l][dloc];
            float Bn  = sbm[l][n];
            h = __expf(Av*dtv)*h + dtv*u*Bn;
            sdsum += dtv;
        }
    }
    size_t idx = (size_t)(b*64 + d)*70 + chunk;
    S[idx*16 + n] = h;
    if (n == 0) sumdt[idx] = sdsum;
}

__global__ void k_scan2(const float* __restrict__ S, const float* __restrict__ sumdt,
                        const float* __restrict__ Alog, float* __restrict__ H0) {
    int t = blockIdx.x*256 + threadIdx.x;
    int b = t >> 10; int d = (t >> 4) & 63; int n = t & 15;
    float Av = -__expf(Alog[d*16 + n]);
    float carry = 0.f;
    size_t base = (size_t)(b*64 + d)*70;
    for (int ch = 0; ch < 70; ch++) {
        size_t idx = base + ch;
        H0[idx*16 + n] = carry;
        carry = carry*__expf(Av*sumdt[idx]) + S[idx*16 + n];
    }
}

// staged scan pass 3: same decomposition; y staged through smem
__global__ __launch_bounds__(256) void k_scan3(
    const float* __restrict__ dt, const float* __restrict__ xc,
    const float* __restrict__ Bm, const float* __restrict__ Cm,
    const float* __restrict__ Alog, const float* __restrict__ H0,
    float* __restrict__ y) {
    int bx = blockIdx.x;
    int b = bx / 280, rem = bx % 280;
    int chunk = rem >> 2, dg = rem & 3;
    int tid = threadIdx.x, warp = tid >> 5, lane = tid & 31;
    int dloc = 2*warp + (lane >> 4), n = lane & 15;
    int d = dg*16 + dloc;
    __shared__ float sdt[16][16], sxc[16][16], sbm[16][16], scm[16][16], sy[16][16];
    float Av = -__expf(Alog[d*16 + n]);
    size_t idx = (size_t)(b*64 + d)*70 + chunk;
    float h = H0[idx*16 + n];
    size_t rowbase = (size_t)b*8960 + chunk*128;
    int lr = tid >> 4, lc = tid & 15;
    for (int s = 0; s < 8; s++) {
        size_t r0 = rowbase + s*16;
        __syncthreads();
        sdt[lr][lc] = dt[(r0 + lr)*64 + dg*16 + lc];
        sxc[lr][lc] = xc[(r0 + lr)*64 + dg*16 + lc];
        sbm[lr][lc] = Bm[(r0 + lr)*16 + lc];
        scm[lr][lc] = Cm[(r0 + lr)*16 + lc];
        __syncthreads();
        #pragma unroll
        for (int l = 0; l < 16; l++) {
            float dtv = sdt[l][dloc];
            float u   = sxc[l][dloc];
            float Bn  = sbm[l][n];
            h = __expf(Av*dtv)*h + dtv*u*Bn;
            float yv = h * scm[l][n];
            yv += __shfl_xor_sync(0xffffffffu, yv, 8);
            yv += __shfl_xor_sync(0xffffffffu, yv, 4);
            yv += __shfl_xor_sync(0xffffffffu, yv, 2);
            yv += __shfl_xor_sync(0xffffffffu, yv, 1);
            if (n == 0) sy[l][dloc] = yv;
        }
        __syncthreads();
        y[(r0 + lr)*64 + dg*16 + lc] = sy[lr][lc];
    }
}

// gate + out_proj + skip + LN + proj; each warp handles 8 rows
__global__ void k_final(const float* __restrict__ y, const float* __restrict__ xc,
                        const float* __restrict__ xz, const float* __restrict__ xn,
                        const float* __restrict__ Dp, const float* __restrict__ opW,
                        const float* __restrict__ skipp, const float* __restrict__ g,
                        const float* __restrict__ be, const float* __restrict__ projW,
                        const float* __restrict__ projb, float* __restrict__ xm2) {
    __shared__ float sop[2048], spj[1024];
    int tid = threadIdx.x;   // 256
    for (int i = tid; i < 2048; i += 256) sop[i] = opW[i];
    for (int i = tid; i < 1024; i += 256) spj[i] = projW[i];
    __syncthreads();
    int warp = tid >> 5, lane = tid & 31;
    float skip = skipp[0];
    float dpl = Dp[lane], dph = Dp[32+lane];
    float gl = g[lane], bel = be[lane], pbl = projb[lane];
    #pragma unroll
    for (int t = 0; t < 8; t++) {
        size_t r = ((size_t)blockIdx.x*8 + warp)*8 + t;
        float y0 = y[r*64 + lane],      y1 = y[r*64 + 32 + lane];
        float c0 = xc[r*64 + lane],     c1 = xc[r*64 + 32 + lane];
        float z0 = xz[r*128 + 64 + lane], z1 = xz[r*128 + 96 + lane];
        float yy0 = (y0 + c0*dpl) * siluf(z0);
        float yy1 = (y1 + c1*dph) * siluf(z1);
        float acc = 0.f;
        #pragma unroll
        for (int d = 0; d < 32; d++) acc += __shfl_sync(0xffffffffu, yy0, d) * sop[d*32 + lane];
        #pragma unroll
        for (int d = 0; d < 32; d++) acc += __shfl_sync(0xffffffffu, yy1, d) * sop[(d+32)*32 + lane];
        float xm = acc + skip * xn[r*32 + lane];
        float mean = xm;
        #pragma unroll
        for (int o = 16; o; o >>= 1) mean += __shfl_xor_sync(0xffffffffu, mean, o);
        mean *= (1.f/32.f);
        float dv = xm - mean, var = dv*dv;
        #pragma unroll
        for (int o = 16; o; o >>= 1) var += __shfl_xor_sync(0xffffffffu, var, o);
        var *= (1.f/32.f);
        float v = dv * rsqrtf(var + 1e-5f) * gl + bel;
        float acc2 = pbl;
        #pragma unroll
        for (int mm = 0; mm < 32; mm++) acc2 += __shfl_sync(0xffffffffu, v, mm) * spj[mm*32 + lane];
        xm2[r*32 + lane] = acc2;
    }
}

__global__ void k_addback(const float* __restrict__ x1, const float* __restrict__ xm2,
                          float* __restrict__ x2) {
    int ww = blockIdx.x, b = blockIdx.y;
    __shared__ float s[224*33];
    int tid = threadIdx.x;   // 256
    for (int idx = tid; idx < 224*32; idx += 256) {
        int cc = idx >> 5, m = idx & 31;
        s[cc*33 + m] = xm2[((size_t)b*8960 + ww*224 + cc)*32 + m];
    }
    __syncthreads();
    for (int idx = tid; idx < 32*224; idx += 256) {
        int m = idx / 224, cc = idx % 224;
        size_t o = ((size_t)b*1280 + m*40 + ww)*224 + cc;
        x2[o] = x1[o] + s[cc*33 + m];
    }
}

// ---------------- conv3d 5x5x5, pad 2, smem-tiled per ky-plane ----------------
__global__ void k_conv3d(const float* __restrict__ x2, const float* __restrict__ cw,
                         const float* __restrict__ cb, float* __restrict__ x3) {
    int y = blockIdx.x, b = blockIdx.y;
    int xx = threadIdx.x;   // 224
    __shared__ float ws[125];
    __shared__ float sp[32][228];
    if (xx < 125) ws[xx] = cw[xx];
    if (xx < 32) { sp[xx][0]=0.f; sp[xx][1]=0.f; sp[xx][226]=0.f; sp[xx][227]=0.f; }
    float acc[32];
    #pragma unroll
    for (int d = 0; d < 32; d++) acc[d] = 0.f;
    for (int ky = 0; ky < 5; ky++) {
        int yy = y + ky - 2;
        if (yy < 0 || yy >= 40) continue;
        __syncthreads();
        for (int i = 0; i < 32; i++)
            sp[i][xx+2] = x2[(((size_t)b*32 + i)*40 + yy)*224 + xx];
        __syncthreads();
        #pragma unroll
        for (int kx = 0; kx < 5; kx++) {
            float v[36];
            v[0]=v[1]=v[34]=v[35]=0.f;
            #pragma unroll
            for (int i = 0; i < 32; i++) v[i+2] = sp[i][xx + kx];
            #pragma unroll
            for (int kz = 0; kz < 5; kz++) {
                float wv = ws[(kz*5 + ky)*5 + kx];
                #pragma unroll
                for (int d = 0; d < 32; d++) acc[d] += v[d+kz]*wv;
            }
        }
    }
    float bias = cb[0];
    #pragma unroll
    for (int d = 0; d < 32; d++)
        x3[(((size_t)b*32 + d)*40 + y)*224 + xx] = acc[d] + bias;
}

// ---------------- DWT: all 4 subbands per thread ----------------
__global__ void k_dwt(const float* __restrict__ x3, float* __restrict__ xw) {
    size_t id = (size_t)blockIdx.x*256 + threadIdx.x;   // 2752512
    int c = (int)(id % 224); size_t rw = id / 224;
    int win = (int)(rw >> 6), tok = (int)(rw & 63);
    int bb = win / 6, w6 = win % 6;
    int wi = w6 / 3, wj = w6 % 3;
    int ti = tok >> 3, tj = tok & 7;
    int i2 = wi*8 + ti;
    int j2 = wj*8 + tj;
    int j = (j2 < 20) ? j2 : 38 - j2;   // reflect pad
    size_t base = (((size_t)bb*32 + 2*i2)*40 + 2*j)*224 + c;
    float a  = x3[base],        bv = x3[base + 224];
    float c2 = x3[base + 8960], d2 = x3[base + 9184];
    const size_t SS = (size_t)12288*224;
    xw[id]        = 0.5f*(a + bv + c2 + d2);
    xw[id + SS]   = 0.5f*(a + bv - c2 - d2);
    xw[id + 2*SS] = 0.5f*(a - bv + c2 - d2);
    xw[id + 3*SS] = 0.5f*(a - bv - c2 + d2);
}

// ---------------- window attention: online softmax, q in regs ----------------
__global__ void k_wattn(const float* __restrict__ qkvw, const float* __restrict__ pe,
                        float* __restrict__ obuf) {
    int win = blockIdx.x, head = blockIdx.y;
    __shared__ __align__(16) float ks[64*28], vs[64*28];
    int tid = threadIdx.x;   // 64
    size_t wbase = (size_t)win * 64;
    for (int idx = tid; idx < 1792; idx += 64) {
        int tok = idx / 28, dd = idx % 28;
        size_t rb = (wbase + tok)*672 + head*28 + dd;
        ks[idx] = qkvw[rb + 224];
        vs[idx] = qkvw[rb + 448];
    }
    float qr[28];
    {
        const float4* qp = (const float4*)(qkvw + (wbase + tid)*672 + head*28);
        #pragma unroll
        for (int q4 = 0; q4 < 7; q4++) {
            float4 v = qp[q4];
            qr[q4*4+0] = v.x * 0.18898223650461363f;
            qr[q4*4+1] = v.y * 0.18898223650461363f;
            qr[q4*4+2] = v.z * 0.18898223650461363f;
            qr[q4*4+3] = v.w * 0.18898223650461363f;
        }
    }
    __syncthreads();
    const float* per = pe + ((size_t)head*64 + tid)*64;
    float m = -1e30f, sum = 0.f;
    float acc[28];
    #pragma unroll
    for (int dd = 0; dd < 28; dd++) acc[dd] = 0.f;
    for (int j = 0; j < 64; j++) {
        const float4* k4 = (const float4*)&ks[j*28];
        float dot = 0.f;
        #pragma unroll
        for (int q4 = 0; q4 < 7; q4++) {
            float4 kk = k4[q4];
            dot += qr[q4*4+0]*kk.x + qr[q4*4+1]*kk.y
                 + qr[q4*4+2]*kk.z + qr[q4*4+3]*kk.w;
        }
        dot += per[j];
        if (dot > m) {
            float corr = __expf(m - dot);
            sum *= corr;
            #pragma unroll
            for (int dd = 0; dd < 28; dd++) acc[dd] *= corr;
            m = dot;
        }
        float e = __expf(dot - m);
        sum += e;
        const float4* v4 = (const float4*)&vs[j*28];
        #pragma unroll
        for (int q4 = 0; q4 < 7; q4++) {
            float4 vv = v4[q4];
            acc[q4*4+0] += e*vv.x; acc[q4*4+1] += e*vv.y;
            acc[q4*4+2] += e*vv.z; acc[q4*4+3] += e*vv.w;
        }
    }
    float inv = 1.f / sum;
    size_t ob = (wbase + tid)*224 + head*28;
    #pragma unroll
    for (int dd = 0; dd < 28; dd++) obuf[ob + dd] = acc[dd] * inv;
}

// ---------------- IWT + crop + final layout ----------------
__global__ void k_iwt(const float* __restrict__ oproj, float* __restrict__ out) {
    size_t id = (size_t)blockIdx.x*256 + threadIdx.x;   // 2293760
    int c = (int)(id % 224); size_t r = id / 224;
    int j = (int)(r % 20); r /= 20;
    int i = (int)(r % 16); int bb = (int)(r / 16);
    int wi = i >> 3, ti = i & 7, wj = j >> 3, tj = j & 7;
    size_t row0 = ((size_t)(bb*6 + wi*3 + wj))*64 + ti*8 + tj;
    float A  = oproj[row0*224 + c];
    float Hh = oproj[(row0 + 12288)*224 + c];
    float V  = oproj[(row0 + 24576)*224 + c];
    float D  = oproj[(row0 + 36864)*224 + c];
    size_t oo = (((size_t)bb*32 + 2*i)*40 + 2*j)*224 + c;
    out[oo]          = 0.5f*(A + Hh + V + D);
    out[oo + 224]    = 0.5f*(A + Hh - V - D);
    out[oo + 8960]   = 0.5f*(A - Hh + V - D);
    out[oo + 9184]   = 0.5f*(A - Hh - V + D);
}

// ---------------- launcher ----------------
extern "C" void kernel_launch(void* const* d_in, const int* in_sizes, int n_in,
                              void* d_out, int out_size) {
    const float* x       = (const float*)d_in[0];
    const float* Wq      = (const float*)d_in[1];
    const float* Wkv     = (const float*)d_in[2];
    const float* ln_g    = (const float*)d_in[3];
    const float* ln_b    = (const float*)d_in[4];
    const float* in_proj = (const float*)d_in[5];
    const float* conv1dW = (const float*)d_in[6];
    const float* conv1db = (const float*)d_in[7];
    const float* x_projW = (const float*)d_in[8];
    const float* dt_projW= (const float*)d_in[9];
    const float* dt_projb= (const float*)d_in[10];
    const float* A_log   = (const float*)d_in[11];
    const float* Dp      = (const float*)d_in[12];
    const float* out_projW=(const float*)d_in[13];
    const float* skip    = (const float*)d_in[14];
    const float* projW   = (const float*)d_in[15];
    const float* projb   = (const float*)d_in[16];
    const float* conv3dW = (const float*)d_in[17];
    const float* conv3db = (const float*)d_in[18];
    const float* Wq1     = (const float*)d_in[19];
    const float* Wkv1    = (const float*)d_in[20];
    const float* pos_emb = (const float*)d_in[21];
    GemmPtrs4 po;
    po.B[0] = (const float*)d_in[22]; po.bias[0] = (const float*)d_in[23];
    po.B[1] = (const float*)d_in[24]; po.bias[1] = (const float*)d_in[25];
    po.B[2] = (const float*)d_in[26]; po.bias[2] = (const float*)d_in[27];
    po.B[3] = (const float*)d_in[28]; po.bias[3] = (const float*)d_in[29];
    float* out = (float*)d_out;

    float *p_q, *p_kv, *p_attn, *p_x1, *p_xn, *p_xz, *p_xc, *p_dt,
          *p_Bm, *p_Cm, *p_y, *p_S, *p_sd, *p_H0, *p_xm2, *p_x2, *p_x3,
          *p_xw, *p_qkvw, *p_obuf, *p_oproj;
    cudaGetSymbolAddress((void**)&p_q,    g_q);
    cudaGetSymbolAddress((void**)&p_kv,   g_kv);
    cudaGetSymbolAddress((void**)&p_attn, g_attn);
    cudaGetSymbolAddress((void**)&p_x1,   g_x1);
    cudaGetSymbolAddress((void**)&p_xn,   g_xn);
    cudaGetSymbolAddress((void**)&p_xz,   g_xz);
    cudaGetSymbolAddress((void**)&p_xc,   g_xc);
    cudaGetSymbolAddress((void**)&p_dt,   g_dt);
    cudaGetSymbolAddress((void**)&p_Bm,   g_Bm);
    cudaGetSymbolAddress((void**)&p_Cm,   g_Cm);
    cudaGetSymbolAddress((void**)&p_y,    g_y);
    cudaGetSymbolAddress((void**)&p_S,    g_S);
    cudaGetSymbolAddress((void**)&p_sd,   g_sumdt);
    cudaGetSymbolAddress((void**)&p_H0,   g_H0);
    cudaGetSymbolAddress((void**)&p_xm2,  g_xm2);
    cudaGetSymbolAddress((void**)&p_x2,   g_x2);
    cudaGetSymbolAddress((void**)&p_x3,   g_x3);
    cudaGetSymbolAddress((void**)&p_xw,   g_xw);
    cudaGetSymbolAddress((void**)&p_qkvw, g_qkvw);
    cudaGetSymbolAddress((void**)&p_obuf, g_obuf);
    cudaGetSymbolAddress((void**)&p_oproj,g_oproj);

    // stage 1
    sgemm_k<<<dim3(4, 320), 256>>>(x, Wq,  p_q,  nullptr, 224, 224, 224, 224, 224);
    sgemm_k<<<dim3(7, 320), 256>>>(x, Wkv, p_kv, nullptr, 448, 224, 224, 448, 448);
    k_gram <<<dim3(32, 8), 256>>>(p_q, p_kv, p_attn);
    k_apply<<<dim3(20, 32), 224>>>(x, p_kv, p_attn, p_x1);

    // stage 2: mamba
    k_ln1<<<dim3(40, 32), 256>>>(p_x1, ln_g, ln_b, p_xn);
    sgemm_k<<<dim3(2, 2240), 256>>>(p_xn, in_proj, p_xz, nullptr, 128, 32, 32, 128, 128);
    k_conv1d<<<17920, 256>>>(p_xz, conv1dW, conv1db, p_xc);
    sgemm_xproj<<<dim3(1, 2240), 256>>>(p_xc, x_projW, dt_projW, dt_projb,
                                        p_dt, p_Bm, p_Cm);
    k_scan1<<<8960, 256>>>(p_dt, p_xc, p_Bm, A_log, p_S, p_sd);
    k_scan2<<<128, 256>>>(p_S, p_sd, A_log, p_H0);
    k_scan3<<<8960, 256>>>(p_dt, p_xc, p_Bm, p_Cm, A_log, p_H0, p_y);
    k_final<<<4480, 256>>>(p_y, p_xc, p_xz, p_xn, Dp, out_projW, skip,
                           ln_g, ln_b, projW, projb, p_xm2);
    k_addback<<<dim3(40, 32), 256>>>(p_x1, p_xm2, p_x2);

    // stage 3: conv3d
    k_conv3d<<<dim3(40, 32), 224>>>(p_x2, conv3dW, conv3db, p_x3);

    // stage 4: DWT + window attention
    k_dwt<<<10752, 256>>>(p_x3, p_xw);
    sgemm_k<<<dim3(4, 384), 256>>>(p_xw, Wq1,  p_qkvw,       nullptr, 224, 224, 224, 224, 672);
    sgemm_k<<<dim3(7, 384), 256>>>(p_xw, Wkv1, p_qkvw + 224, nullptr, 448, 224, 224, 448, 672);
    k_wattn<<<dim3(768, 8), 64>>>(p_qkvw, pos_emb, p_obuf);
    sgemm_b4<<<dim3(4, 96, 4), 256>>>(p_obuf, po, p_oproj,
                                      224, 224, 224, 224, 224,
                                      (long long)12288*224, (long long)12288*224);

    // stage 5: IWT + output
    k_iwt<<<8960, 256>>>(p_oproj, out);
}

// round 11
// speedup vs baseline: 1.4031x; 1.0665x over previous
#include <cuda_runtime.h>
#include <cuda_bf16.h>
#include <mma.h>
#include <math.h>
#include <stdint.h>

using namespace nvcuda;

// ---------------- static scratch ----------------
__device__ __align__(16) float g_q    [40960u*224u];
__device__ __align__(16) float g_kv   [40960u*448u];
__device__ __align__(16) float g_attn [32*8*28*28];
__device__ __align__(16) float g_x1   [9175040];
__device__ __align__(16) float g_xn   [9175040];      // 286720 x 32
__device__ __align__(16) float g_xz   [36700160];     // 286720 x 128
__device__ __align__(16) float g_xc   [18350080];     // 286720 x 64
__device__ __align__(16) float g_dt   [18350080];
__device__ __align__(16) float g_Bm   [4587520];
__device__ __align__(16) float g_Cm   [4587520];
__device__ __align__(16) float g_y    [18350080];
__device__ __align__(16) float g_S    [2293760];
__device__ __align__(16) float g_sumdt[143360];
__device__ __align__(16) float g_H0   [2293760];
__device__ __align__(16) float g_xm2  [9175040];
__device__ __align__(16) float g_x2   [9175040];
__device__ __align__(16) float g_x3   [9175040];
__device__ __align__(16) float g_qkvw [33030144];     // 49152 x 672
__device__ __align__(16) float g_oproj[11010048];

// bf16 hi/lo split scratch
__device__ __align__(16) __nv_bfloat16 g_xh  [9175040],  g_xlo  [9175040];
__device__ __align__(16) __nv_bfloat16 g_xnh [9175040],  g_xnl  [9175040];
__device__ __align__(16) __nv_bfloat16 g_xwh [11010048], g_xwl  [11010048];
__device__ __align__(16) __nv_bfloat16 g_obh [11010048], g_obl  [11010048];
__device__ __align__(16) __nv_bfloat16 g_Wqh [50176],  g_Wql [50176];
__device__ __align__(16) __nv_bfloat16 g_Wkvh[100352], g_Wkvl[100352];
__device__ __align__(16) __nv_bfloat16 g_iph [4096],   g_ipl [4096];
__device__ __align__(16) __nv_bfloat16 g_Wq1h[50176],  g_Wq1l[50176];
__device__ __align__(16) __nv_bfloat16 g_Wkv1h[100352],g_Wkv1l[100352];
__device__ __align__(16) __nv_bfloat16 g_Woh [200704], g_Wol [200704];

__device__ __forceinline__ float siluf(float v){ return v / (1.f + __expf(-v)); }
__device__ __forceinline__ void bfsplit(float v, __nv_bfloat16& h, __nv_bfloat16& l) {
    h = __float2bfloat16(v);
    l = __float2bfloat16(v - __bfloat162float(h));
}

struct BfPtrs4 { const __nv_bfloat16* Bh[4]; const __nv_bfloat16* Bl[4]; };

// ---------------- fp32 -> bf16 hi/lo split ----------------
__global__ void k_split(const float* __restrict__ in, __nv_bfloat16* __restrict__ hi,
                        __nv_bfloat16* __restrict__ lo, int n) {
    int i = blockIdx.x*256 + threadIdx.x;
    if (i < n) {
        __nv_bfloat16 h, l;
        bfsplit(in[i], h, l);
        hi[i] = h; lo[i] = l;
    }
}

// ---------------- bf16 split tensor-core GEMM ----------------
// C[M,N] = (Ah+Al)[M,K] @ (Bh+Bl)[K,N] with 3-term split, fp32 accum.
// M%128==0, K%16==0, N%16==0, lda/ldb even (16B rows), ldc%4==0.
__device__ __forceinline__ void tgemm_bf_core(
    const __nv_bfloat16* __restrict__ Ah, const __nv_bfloat16* __restrict__ Al,
    const __nv_bfloat16* __restrict__ Bh, const __nv_bfloat16* __restrict__ Bl,
    float* __restrict__ C, int N, int K, int lda, int ldb, int ldc,
    __nv_bfloat16* sAh, __nv_bfloat16* sAl, __nv_bfloat16* sBh, __nv_bfloat16* sBl)
{
    const int bm = blockIdx.y*128, bn = blockIdx.x*64;
    const int tid = threadIdx.x, warp = tid >> 5;
    const int wm = warp >> 1, wn = warp & 1;
    wmma::fragment<wmma::accumulator,16,16,16,float> acc[2][2];
    #pragma unroll
    for (int i = 0; i < 2; i++)
        #pragma unroll
        for (int j = 0; j < 2; j++) wmma::fill_fragment(acc[i][j], 0.f);

    const int ar = tid >> 1, ac = (tid & 1)*8;
    const int br = (tid & 127) >> 3, bs = ((tid & 127) & 7)*8;
    const int bcol = bn + bs;

    for (int k0 = 0; k0 < K; k0 += 16) {
        __syncthreads();
        *(uint4*)&sAh[ar*24 + ac] = *(const uint4*)&Ah[(size_t)(bm+ar)*lda + k0 + ac];
        *(uint4*)&sAl[ar*24 + ac] = *(const uint4*)&Al[(size_t)(bm+ar)*lda + k0 + ac];
        if (tid < 128) {
            uint4 v = make_uint4(0u,0u,0u,0u);
            if (bcol < N) v = *(const uint4*)&Bh[(size_t)(k0+br)*ldb + bcol];
            *(uint4*)&sBh[br*72 + bs] = v;
        } else {
            uint4 v = make_uint4(0u,0u,0u,0u);
            if (bcol < N) v = *(const uint4*)&Bl[(size_t)(k0+br)*ldb + bcol];
            *(uint4*)&sBl[br*72 + bs] = v;
        }
        __syncthreads();
        wmma::fragment<wmma::matrix_a,16,16,16,__nv_bfloat16,wmma::row_major> fah[2], fal[2];
        wmma::fragment<wmma::matrix_b,16,16,16,__nv_bfloat16,wmma::row_major> fbh[2], fbl[2];
        #pragma unroll
        for (int i = 0; i < 2; i++) {
            wmma::load_matrix_sync(fah[i], &sAh[(wm*32 + i*16)*24], 24);
            wmma::load_matrix_sync(fal[i], &sAl[(wm*32 + i*16)*24], 24);
        }
        #pragma unroll
        for (int j = 0; j < 2; j++) {
            wmma::load_matrix_sync(fbh[j], &sBh[wn*32 + j*16], 72);
            wmma::load_matrix_sync(fbl[j], &sBl[wn*32 + j*16], 72);
        }
        #pragma unroll
        for (int i = 0; i < 2; i++)
            #pragma unroll
            for (int j = 0; j < 2; j++) {
                wmma::mma_sync(acc[i][j], fah[i], fbh[j], acc[i][j]);
                wmma::mma_sync(acc[i][j], fah[i], fbl[j], acc[i][j]);
                wmma::mma_sync(acc[i][j], fal[i], fbh[j], acc[i][j]);
            }
    }
    #pragma unroll
    for (int i = 0; i < 2; i++)
        #pragma unroll
        for (int j = 0; j < 2; j++) {
            int n0 = bn + wn*32 + j*16;
            if (n0 < N)
                wmma::store_matrix_sync(C + (size_t)(bm + wm*32 + i*16)*ldc + n0,
                                        acc[i][j], ldc, wmma::mem_row_major);
        }
}

__global__ __launch_bounds__(256) void tgemm_bf(
    const __nv_bfloat16* __restrict__ Ah, const __nv_bfloat16* __restrict__ Al,
    const __nv_bfloat16* __restrict__ Bh, const __nv_bfloat16* __restrict__ Bl,
    float* __restrict__ C, int N, int K, int lda, int ldb, int ldc)
{
    __shared__ __align__(16) __nv_bfloat16 sAh[128*24], sAl[128*24];
    __shared__ __align__(16) __nv_bfloat16 sBh[16*72],  sBl[16*72];
    tgemm_bf_core(Ah, Al, Bh, Bl, C, N, K, lda, ldb, ldc, sAh, sAl, sBh, sBl);
}

__global__ __launch_bounds__(256) void tgemm_bf_b4(
    const __nv_bfloat16* __restrict__ Ah, const __nv_bfloat16* __restrict__ Al,
    BfPtrs4 p, float* __restrict__ C, int N, int K, int lda, int ldb, int ldc,
    long long strideA, long long strideC)
{
    __shared__ __align__(16) __nv_bfloat16 sAh[128*24], sAl[128*24];
    __shared__ __align__(16) __nv_bfloat16 sBh[16*72],  sBl[16*72];
    int z = blockIdx.z;
    tgemm_bf_core(Ah + (size_t)z*strideA, Al + (size_t)z*strideA,
                  p.Bh[z], p.Bl[z], C + (size_t)z*strideC,
                  N, K, lda, ldb, ldc, sAh, sAl, sBh, sBl);
}

// ---------------- fused x_proj GEMM (SIMT) + dt/B/C split ----------------
__global__ __launch_bounds__(256) void sgemm_xproj(
    const float* __restrict__ A, const float* __restrict__ B,
    const float* __restrict__ dtW, const float* __restrict__ dtb,
    float* __restrict__ dt, float* __restrict__ Bm, float* __restrict__ Cm)
{
    __shared__ float As[2][16][128];
    __shared__ float Bs[2][16][64];
    __shared__ float St[128][36];
    __shared__ float sdtW[128], sdtb[64];
    const int N = 34, K = 64, lda = 64, ldb = 34;
    const int bm = blockIdx.y * 128;
    const int tid = threadIdx.x;
    const int tr = tid >> 4, tc = tid & 15;
    const int br = tid >> 4, bc0 = (tid & 15) * 4;
    if (tid < 128) sdtW[tid] = dtW[tid];
    if (tid >= 128 && tid < 192) sdtb[tid-128] = dtb[tid-128];
    float acc[8][4];
    #pragma unroll
    for (int i = 0; i < 8; i++)
        #pragma unroll
        for (int j = 0; j < 4; j++) acc[i][j] = 0.f;

    float4 ra[2]; float rb[4];
    #pragma unroll
    for (int i = 0; i < 2; i++) {
        int idx = tid + i * 256;
        int r = idx >> 2, c4 = (idx & 3) * 4;
        ra[i] = *(const float4*)(A + (size_t)(bm + r) * lda + c4);
    }
    #pragma unroll
    for (int i = 0; i < 4; i++) {
        int n = bc0 + i;
        rb[i] = (n < N) ? B[(size_t)br * ldb + n] : 0.f;
    }
    int buf = 0;
    #pragma unroll
    for (int i = 0; i < 2; i++) {
        int idx = tid + i * 256;
        int r = idx >> 2, c4 = (idx & 3) * 4;
        As[0][c4+0][r]=ra[i].x; As[0][c4+1][r]=ra[i].y;
        As[0][c4+2][r]=ra[i].z; As[0][c4+3][r]=ra[i].w;
    }
    #pragma unroll
    for (int i = 0; i < 4; i++) Bs[0][br][bc0+i] = rb[i];
    __syncthreads();

    for (int k0 = 0; k0 < K; k0 += 16) {
        const bool more = (k0 + 16) < K;
        float4 ra2[2]; float rb2[4];
        if (more) {
            #pragma unroll
            for (int i = 0; i < 2; i++) {
                int idx = tid + i * 256;
                int r = idx >> 2, c4 = (idx & 3) * 4;
                ra2[i] = *(const float4*)(A + (size_t)(bm + r) * lda + k0 + 16 + c4);
            }
            #pragma unroll
            for (int i = 0; i < 4; i++) {
                int n = bc0 + i;
                rb2[i] = (n < N) ? B[(size_t)(k0 + 16 + br) * ldb + n] : 0.f;
            }
        }
        #pragma unroll
        for (int kk = 0; kk < 16; kk++) {
            float4 a0 = *(const float4*)&As[buf][kk][tr*8];
            float4 a1 = *(const float4*)&As[buf][kk][tr*8+4];
            float4 b0 = *(const float4*)&Bs[buf][kk][tc*4];
            float a[8] = {a0.x,a0.y,a0.z,a0.w,a1.x,a1.y,a1.z,a1.w};
            float b[4] = {b0.x,b0.y,b0.z,b0.w};
            #pragma unroll
            for (int i = 0; i < 8; i++)
                #pragma unroll
                for (int j = 0; j < 4; j++) acc[i][j] += a[i]*b[j];
        }
        if (more) {
            int nb = buf ^ 1;
            #pragma unroll
            for (int i = 0; i < 2; i++) {
                int idx = tid + i * 256;
                int r = idx >> 2, c4 = (idx & 3) * 4;
                As[nb][c4+0][r]=ra2[i].x; As[nb][c4+1][r]=ra2[i].y;
                As[nb][c4+2][r]=ra2[i].z; As[nb][c4+3][r]=ra2[i].w;
            }
            #pragma unroll
            for (int i = 0; i < 4; i++) Bs[nb][br][bc0+i] = rb2[i];
            __syncthreads();
            buf = nb;
        }
    }
    #pragma unroll
    for (int i = 0; i < 8; i++) {
        #pragma unroll
        for (int j = 0; j < 4; j++) {
            int n = tc*4 + j;
            if (n < N) St[tr*8 + i][n] = acc[i][j];
        }
    }
    __syncthreads();
    for (int idx = tid; idx < 128*64; idx += 256) {
        int r = idx >> 6, d = idx & 63;
        float v = St[r][0]*sdtW[d] + St[r][1]*sdtW[64+d] + sdtb[d];
        dt[(size_t)(bm + r)*64 + d] = (v > 20.f) ? v : log1pf(__expf(v));
    }
    for (int idx = tid; idx < 128*16; idx += 256) {
        int r = idx >> 4, n = idx & 15;
        Bm[(size_t)(bm + r)*16 + n] = St[r][2 + n];
        Cm[(size_t)(bm + r)*16 + n] = St[r][18 + n];
    }
}

// ---------------- stage 1: channel attention ----------------
__global__ void k_gram(const float* __restrict__ q, const float* __restrict__ kv,
                       float* __restrict__ attn) {
    int b = blockIdx.x, h = blockIdx.y;
    __shared__ float kt[32][28], qt[32][28];
    __shared__ float G[840];
    int tid = threadIdx.x;   // 256
    float acc[4] = {0.f,0.f,0.f,0.f};
    for (int nt = 0; nt < 40; nt++) {
        for (int idx = tid; idx < 896; idx += 256) {
            int n = idx / 28, i = idx % 28;
            size_t row = (size_t)b*1280 + nt*32 + n;
            kt[n][i] = kv[row*448 + h*28 + i];
            qt[n][i] = q [row*224 + h*28 + i];
        }
        __syncthreads();
        #pragma unroll
        for (int s = 0; s < 4; s++) {
            int w = tid + 256*s;
            if (w < 784) {
                int i = w/28, j = w%28; float a = acc[s];
                #pragma unroll
                for (int n = 0; n < 32; n++) a += kt[n][i]*qt[n][j];
                acc[s] = a;
            } else if (w < 812) {
                int i = w - 784; float a = acc[s];
                #pragma unroll
                for (int n = 0; n < 32; n++) a += kt[n][i]*kt[n][i];
                acc[s] = a;
            } else if (w < 840) {
                int j = w - 812; float a = acc[s];
                #pragma unroll
                for (int n = 0; n < 32; n++) a += qt[n][j]*qt[n][j];
                acc[s] = a;
            }
        }
        __syncthreads();
    }
    #pragma unroll
    for (int s = 0; s < 4; s++) { int w = tid + 256*s; if (w < 840) G[w] = acc[s]; }
    __syncthreads();
    if (tid < 28) {
        int i = tid;
        float nk = fmaxf(sqrtf(G[784+i]), 1e-12f);
        float lg[28], m = -1e30f;
        #pragma unroll
        for (int j = 0; j < 28; j++) {
            float nq = fmaxf(sqrtf(G[812+j]), 1e-12f);
            lg[j] = G[i*28+j] / (nk*nq) * 0.18898223650461363f;
            m = fmaxf(m, lg[j]);
        }
        float sum = 0.f;
        #pragma unroll
        for (int j = 0; j < 28; j++) { lg[j] = __expf(lg[j]-m); sum += lg[j]; }
        float inv = 1.f/sum;
        #pragma unroll
        for (int j = 0; j < 28; j++)
            attn[(((size_t)b*8 + h)*28 + i)*28 + j] = lg[j]*inv;
    }
}

// x1 = attn-applied + residual; attention row in registers
__global__ void k_apply(const float* __restrict__ x, const float* __restrict__ kv,
                        const float* __restrict__ attn, float* __restrict__ x1) {
    int chunk = blockIdx.x, b = blockIdx.y;
    __shared__ float vr[8][224];
    int tid = threadIdx.x;   // 224
    int h = tid / 28, i = tid % 28;
    float att[28];
    {
        const float4* ap = (const float4*)(attn + (((size_t)b*8 + h)*28 + i)*28);
        #pragma unroll
        for (int q4 = 0; q4 < 7; q4++) {
            float4 v = ap[q4];
            att[q4*4+0]=v.x; att[q4*4+1]=v.y; att[q4*4+2]=v.z; att[q4*4+3]=v.w;
        }
    }
    for (int nn = 0; nn < 64; nn += 8) {
        size_t row0 = (size_t)b*1280 + chunk*64 + nn;
        __syncthreads();
        for (int idx = tid; idx < 1792; idx += 224) {
            int rr = idx / 224, cc = idx % 224;
            vr[rr][cc] = kv[(row0 + rr)*448 + 224 + cc];
        }
        __syncthreads();
        #pragma unroll
        for (int rr = 0; rr < 8; rr++) {
            float a = 0.f;
            #pragma unroll
            for (int j = 0; j < 28; j++) a += att[j] * vr[rr][h*28 + j];
            size_t o = (row0 + rr)*224 + tid;
            x1[o] = x[o] + a;
        }
    }
}

// ---------------- transpose + LN; also emits bf16 hi/lo ----------------
__global__ void k_ln1(const float* __restrict__ x1, const float* __restrict__ g,
                      const float* __restrict__ be, float* __restrict__ xn,
                      __nv_bfloat16* __restrict__ xnh, __nv_bfloat16* __restrict__ xnl) {
    int ww = blockIdx.x, b = blockIdx.y;
    __shared__ float s[32*225];
    int tid = threadIdx.x;   // 256
    for (int idx = tid; idx < 32*224; idx += 256) {
        int m = idx / 224, cc = idx % 224;
        s[m*225 + cc] = x1[((size_t)b*1280 + m*40 + ww)*224 + cc];
    }
    __syncthreads();
    for (int cc = tid; cc < 224; cc += 256) {
        float mean = 0.f;
        #pragma unroll
        for (int m = 0; m < 32; m++) mean += s[m*225+cc];
        mean *= (1.f/32.f);
        float var = 0.f;
        #pragma unroll
        for (int m = 0; m < 32; m++) { float d = s[m*225+cc]-mean; var += d*d; }
        var *= (1.f/32.f);
        float inv = rsqrtf(var + 1e-5f);
        size_t ob = ((size_t)b*8960 + ww*224 + cc)*32;
        #pragma unroll
        for (int m = 0; m < 32; m++) {
            float v = (s[m*225+cc]-mean)*inv*g[m] + be[m];
            xn[ob + m] = v;
            __nv_bfloat16 h, l; bfsplit(v, h, l);
            xnh[ob + m] = h; xnl[ob + m] = l;
        }
    }
}

// ---------------- mamba pieces ----------------
__global__ void k_conv1d(const float* __restrict__ xz, const float* __restrict__ cw,
                         const float* __restrict__ cb, float* __restrict__ xc) {
    size_t id = (size_t)blockIdx.x*256 + threadIdx.x;   // 286720*16
    size_t row = id >> 4; int d4 = (int)(id & 15) * 4;
    size_t b = row / 8960; int l = (int)(row % 8960);
    float a0 = cb[d4], a1 = cb[d4+1], a2 = cb[d4+2], a3 = cb[d4+3];
    #pragma unroll
    for (int t = 0; t < 4; t++) {
        int ls = l - 3 + t;
        if (ls >= 0) {
            float4 v = *(const float4*)(xz + ((size_t)b*8960 + ls)*128 + d4);
            a0 += v.x * cw[d4*4 + t];
            a1 += v.y * cw[(d4+1)*4 + t];
            a2 += v.z * cw[(d4+2)*4 + t];
            a3 += v.w * cw[(d4+3)*4 + t];
        }
    }
    float4 o; o.x = siluf(a0); o.y = siluf(a1); o.z = siluf(a2); o.w = siluf(a3);
    *(float4*)(xc + row*64 + d4) = o;
}

__global__ __launch_bounds__(256) void k_scan1(
    const float* __restrict__ dt, const float* __restrict__ xc,
    const float* __restrict__ Bm, const float* __restrict__ Alog,
    float* __restrict__ S, float* __restrict__ sumdt) {
    int bx = blockIdx.x;                 // 8960
    int b = bx / 280, rem = bx % 280;
    int chunk = rem >> 2, dg = rem & 3;
    int tid = threadIdx.x, warp = tid >> 5, lane = tid & 31;
    int dloc = 2*warp + (lane >> 4), n = lane & 15;
    int d = dg*16 + dloc;
    __shared__ float sdt[16][16], sxc[16][16], sbm[16][16];
    float Av = -__expf(Alog[d*16 + n]);
    float h = 0.f, sdsum = 0.f;
    size_t rowbase = (size_t)b*8960 + chunk*128;
    int lr = tid >> 4, lc = tid & 15;
    for (int s = 0; s < 8; s++) {
        size_t r0 = rowbase + s*16;
        __syncthreads();
        sdt[lr][lc] = dt[(r0 + lr)*64 + dg*16 + lc];
        sxc[lr][lc] = xc[(r0 + lr)*64 + dg*16 + lc];
        sbm[lr][lc] = Bm[(r0 + lr)*16 + lc];
        __syncthreads();
        #pragma unroll
        for (int l = 0; l < 16; l++) {
            float dtv = sdt[l][dloc];
            float u   = sxc[l][dloc];
            float Bn  = sbm[l][n];
            h = __expf(Av*dtv)*h + dtv*u*Bn;
            sdsum += dtv;
        }
    }
    size_t idx = (size_t)(b*64 + d)*70 + chunk;
    S[idx*16 + n] = h;
    if (n == 0) sumdt[idx] = sdsum;
}

__global__ void k_scan2(const float* __restrict__ S, const float* __restrict__ sumdt,
                        const float* __restrict__ Alog, float* __restrict__ H0) {
    int t = blockIdx.x*256 + threadIdx.x;
    int b = t >> 10; int d = (t >> 4) & 63; int n = t & 15;
    float Av = -__expf(Alog[d*16 + n]);
    float carry = 0.f;
    size_t base = (size_t)(b*64 + d)*70;
    for (int ch = 0; ch < 70; ch++) {
        size_t idx = base + ch;
        H0[idx*16 + n] = carry;
        carry = carry*__expf(Av*sumdt[idx]) + S[idx*16 + n];
    }
}

__global__ __launch_bounds__(256) void k_scan3(
    const float* __restrict__ dt, const float* __restrict__ xc,
    const float* __restrict__ Bm, const float* __restrict__ Cm,
    const float* __restrict__ Alog, const float* __restrict__ H0,
    float* __restrict__ y) {
    int bx = blockIdx.x;
    int b = bx / 280, rem = bx % 280;
    int chunk = rem >> 2, dg = rem & 3;
    int tid = threadIdx.x, warp = tid >> 5, lane = tid & 31;
    int dloc = 2*warp + (lane >> 4), n = lane & 15;
    int d = dg*16 + dloc;
    __shared__ float sdt[16][16], sxc[16][16], sbm[16][16], scm[16][16], sy[16][16];
    float Av = -__expf(Alog[d*16 + n]);
    size_t idx = (size_t)(b*64 + d)*70 + chunk;
    float h = H0[idx*16 + n];
    size_t rowbase = (size_t)b*8960 + chunk*128;
    int lr = tid >> 4, lc = tid & 15;
    for (int s = 0; s < 8; s++) {
        size_t r0 = rowbase + s*16;
        __syncthreads();
        sdt[lr][lc] = dt[(r0 + lr)*64 + dg*16 + lc];
        sxc[lr][lc] = xc[(r0 + lr)*64 + dg*16 + lc];
        sbm[lr][lc] = Bm[(r0 + lr)*16 + lc];
        scm[lr][lc] = Cm[(r0 + lr)*16 + lc];
        __syncthreads();
        #pragma unroll
        for (int l = 0; l < 16; l++) {
            float dtv = sdt[l][dloc];
            float u   = sxc[l][dloc];
            float Bn  = sbm[l][n];
            h = __expf(Av*dtv)*h + dtv*u*Bn;
            float yv = h * scm[l][n];
            yv += __shfl_xor_sync(0xffffffffu, yv, 8);
            yv += __shfl_xor_sync(0xffffffffu, yv, 4);
            yv += __shfl_xor_sync(0xffffffffu, yv, 2);
            yv += __shfl_xor_sync(0xffffffffu, yv, 1);
            if (n == 0) sy[l][dloc] = yv;
        }
        __syncthreads();
        y[(r0 + lr)*64 + dg*16 + lc] = sy[lr][lc];
    }
}

__global__ void k_final(const float* __restrict__ y, const float* __restrict__ xc,
                        const float* __restrict__ xz, const float* __restrict__ xn,
                        const float* __restrict__ Dp, const float* __restrict__ opW,
                        const float* __restrict__ skipp, const float* __restrict__ g,
                        const float* __restrict__ be, const float* __restrict__ projW,
                        const float* __restrict__ projb, float* __restrict__ xm2) {
    __shared__ float sop[2048], spj[1024];
    int tid = threadIdx.x;   // 256
    for (int i = tid; i < 2048; i += 256) sop[i] = opW[i];
    for (int i = tid; i < 1024; i += 256) spj[i] = projW[i];
    __syncthreads();
    int warp = tid >> 5, lane = tid & 31;
    float skip = skipp[0];
    float dpl = Dp[lane], dph = Dp[32+lane];
    float gl = g[lane], bel = be[lane], pbl = projb[lane];
    #pragma unroll
    for (int t = 0; t < 8; t++) {
        size_t r = ((size_t)blockIdx.x*8 + warp)*8 + t;
        float y0 = y[r*64 + lane],      y1 = y[r*64 + 32 + lane];
        float c0 = xc[r*64 + lane],     c1 = xc[r*64 + 32 + lane];
        float z0 = xz[r*128 + 64 + lane], z1 = xz[r*128 + 96 + lane];
        float yy0 = (y0 + c0*dpl) * siluf(z0);
        float yy1 = (y1 + c1*dph) * siluf(z1);
        float acc = 0.f;
        #pragma unroll
        for (int d = 0; d < 32; d++) acc += __shfl_sync(0xffffffffu, yy0, d) * sop[d*32 + lane];
        #pragma unroll
        for (int d = 0; d < 32; d++) acc += __shfl_sync(0xffffffffu, yy1, d) * sop[(d+32)*32 + lane];
        float xm = acc + skip * xn[r*32 + lane];
        float mean = xm;
        #pragma unroll
        for (int o = 16; o; o >>= 1) mean += __shfl_xor_sync(0xffffffffu, mean, o);
        mean *= (1.f/32.f);
        float dv = xm - mean, var = dv*dv;
        #pragma unroll
        for (int o = 16; o; o >>= 1) var += __shfl_xor_sync(0xffffffffu, var, o);
        var *= (1.f/32.f);
        float v = dv * rsqrtf(var + 1e-5f) * gl + bel;
        float acc2 = pbl;
        #pragma unroll
        for (int mm = 0; mm < 32; mm++) acc2 += __shfl_sync(0xffffffffu, v, mm) * spj[mm*32 + lane];
        xm2[r*32 + lane] = acc2;
    }
}

__global__ void k_addback(const float* __restrict__ x1, const float* __restrict__ xm2,
                          float* __restrict__ x2) {
    int ww = blockIdx.x, b = blockIdx.y;
    __shared__ float s[224*33];
    int tid = threadIdx.x;   // 256
    for (int idx = tid; idx < 224*32; idx += 256) {
        int cc = idx >> 5, m = idx & 31;
        s[cc*33 + m] = xm2[((size_t)b*8960 + ww*224 + cc)*32 + m];
    }
    __syncthreads();
    for (int idx = tid; idx < 32*224; idx += 256) {
        int m = idx / 224, cc = idx % 224;
        size_t o = ((size_t)b*1280 + m*40 + ww)*224 + cc;
        x2[o] = x1[o] + s[cc*33 + m];
    }
}

// ---------------- conv3d 5x5x5, pad 2, smem-tiled per ky-plane ----------------
__global__ void k_conv3d(const float* __restrict__ x2, const float* __restrict__ cw,
                         const float* __restrict__ cb, float* __restrict__ x3) {
    int y = blockIdx.x, b = blockIdx.y;
    int xx = threadIdx.x;   // 224
    __shared__ float ws[125];
    __shared__ float sp[32][228];
    if (xx < 125) ws[xx] = cw[xx];
    if (xx < 32) { sp[xx][0]=0.f; sp[xx][1]=0.f; sp[xx][226]=0.f; sp[xx][227]=0.f; }
    float acc[32];
    #pragma unroll
    for (int d = 0; d < 32; d++) acc[d] = 0.f;
    for (int ky = 0; ky < 5; ky++) {
        int yy = y + ky - 2;
        if (yy < 0 || yy >= 40) continue;
        __syncthreads();
        for (int i = 0; i < 32; i++)
            sp[i][xx+2] = x2[(((size_t)b*32 + i)*40 + yy)*224 + xx];
        __syncthreads();
        #pragma unroll
        for (int kx = 0; kx < 5; kx++) {
            float v[36];
            v[0]=v[1]=v[34]=v[35]=0.f;
            #pragma unroll
            for (int i = 0; i < 32; i++) v[i+2] = sp[i][xx + kx];
            #pragma unroll
            for (int kz = 0; kz < 5; kz++) {
                float wv = ws[(kz*5 + ky)*5 + kx];
                #pragma unroll
                for (int d = 0; d < 32; d++) acc[d] += v[d+kz]*wv;
            }
        }
    }
    float bias = cb[0];
    #pragma unroll
    for (int d = 0; d < 32; d++)
        x3[(((size_t)b*32 + d)*40 + y)*224 + xx] = acc[d] + bias;
}

// ---------------- DWT: 4 subbands per thread, emits bf16 hi/lo ----------------
__global__ void k_dwt(const float* __restrict__ x3,
                      __nv_bfloat16* __restrict__ xwh, __nv_bfloat16* __restrict__ xwl) {
    size_t id = (size_t)blockIdx.x*256 + threadIdx.x;   // 2752512
    int c = (int)(id % 224); size_t rw = id / 224;
    int win = (int)(rw >> 6), tok = (int)(rw & 63);
    int bb = win / 6, w6 = win % 6;
    int wi = w6 / 3, wj = w6 % 3;
    int ti = tok >> 3, tj = tok & 7;
    int i2 = wi*8 + ti;
    int j2 = wj*8 + tj;
    int j = (j2 < 20) ? j2 : 38 - j2;   // reflect pad
    size_t base = (((size_t)bb*32 + 2*i2)*40 + 2*j)*224 + c;
    float a  = x3[base],        bv = x3[base + 224];
    float c2 = x3[base + 8960], d2 = x3[base + 9184];
    const size_t SS = (size_t)12288*224;
    float v0 = 0.5f*(a + bv + c2 + d2);
    float v1 = 0.5f*(a + bv - c2 - d2);
    float v2 = 0.5f*(a - bv + c2 - d2);
    float v3 = 0.5f*(a - bv - c2 + d2);
    __nv_bfloat16 h, l;
    bfsplit(v0, h, l); xwh[id]        = h; xwl[id]        = l;
    bfsplit(v1, h, l); xwh[id + SS]   = h; xwl[id + SS]   = l;
    bfsplit(v2, h, l); xwh[id + 2*SS] = h; xwl[id + 2*SS] = l;
    bfsplit(v3, h, l); xwh[id + 3*SS] = h; xwl[id + 3*SS] = l;
}

// ---------------- window attention: online softmax, emits bf16 hi/lo --------
__global__ void k_wattn(const float* __restrict__ qkvw, const float* __restrict__ pe,
                        __nv_bfloat16* __restrict__ obh, __nv_bfloat16* __restrict__ obl) {
    int win = blockIdx.x, head = blockIdx.y;
    __shared__ __align__(16) float ks[64*28], vs[64*28];
    int tid = threadIdx.x;   // 64
    size_t wbase = (size_t)win * 64;
    for (int idx = tid; idx < 1792; idx += 64) {
        int tok = idx / 28, dd = idx % 28;
        size_t rb = (wbase + tok)*672 + head*28 + dd;
        ks[idx] = qkvw[rb + 224];
        vs[idx] = qkvw[rb + 448];
    }
    float qr[28];
    {
        const float4* qp = (const float4*)(qkvw + (wbase + tid)*672 + head*28);
        #pragma unroll
        for (int q4 = 0; q4 < 7; q4++) {
            float4 v = qp[q4];
            qr[q4*4+0] = v.x * 0.18898223650461363f;
            qr[q4*4+1] = v.y * 0.18898223650461363f;
            qr[q4*4+2] = v.z * 0.18898223650461363f;
            qr[q4*4+3] = v.w * 0.18898223650461363f;
        }
    }
    __syncthreads();
    const float* per = pe + ((size_t)head*64 + tid)*64;
    float m = -1e30f, sum = 0.f;
    float acc[28];
    #pragma unroll
    for (int dd = 0; dd < 28; dd++) acc[dd] = 0.f;
    for (int j = 0; j < 64; j++) {
        const float4* k4 = (const float4*)&ks[j*28];
        float dot = 0.f;
        #pragma unroll
        for (int q4 = 0; q4 < 7; q4++) {
            float4 kk = k4[q4];
            dot += qr[q4*4+0]*kk.x + qr[q4*4+1]*kk.y
                 + qr[q4*4+2]*kk.z + qr[q4*4+3]*kk.w;
        }
        dot += per[j];
        if (dot > m) {
            float corr = __expf(m - dot);
            sum *= corr;
            #pragma unroll
            for (int dd = 0; dd < 28; dd++) acc[dd] *= corr;
            m = dot;
        }
        float e = __expf(dot - m);
        sum += e;
        const float4* v4 = (const float4*)&vs[j*28];
        #pragma unroll
        for (int q4 = 0; q4 < 7; q4++) {
            float4 vv = v4[q4];
            acc[q4*4+0] += e*vv.x; acc[q4*4+1] += e*vv.y;
            acc[q4*4+2] += e*vv.z; acc[q4*4+3] += e*vv.w;
        }
    }
    float inv = 1.f / sum;
    size_t ob = (wbase + tid)*224 + head*28;
    #pragma unroll
    for (int dd = 0; dd < 28; dd++) {
        __nv_bfloat16 h, l;
        bfsplit(acc[dd] * inv, h, l);
        obh[ob + dd] = h; obl[ob + dd] = l;
    }
}

// ---------------- IWT + biases + crop + final layout ----------------
__global__ void k_iwt(const float* __restrict__ oproj,
                      const float* __restrict__ b1, const float* __restrict__ b2,
                      const float* __restrict__ b3, const float* __restrict__ b4,
                      float* __restrict__ out) {
    size_t id = (size_t)blockIdx.x*256 + threadIdx.x;   // 2293760
    int c = (int)(id % 224); size_t r = id / 224;
    int j = (int)(r % 20); r /= 20;
    int i = (int)(r % 16); int bb = (int)(r / 16);
    int wi = i >> 3, ti = i & 7, wj = j >> 3, tj = j & 7;
    size_t row0 = ((size_t)(bb*6 + wi*3 + wj))*64 + ti*8 + tj;
    float A  = oproj[row0*224 + c]           + b1[c];
    float Hh = oproj[(row0 + 12288)*224 + c] + b2[c];
    float V  = oproj[(row0 + 24576)*224 + c] + b3[c];
    float D  = oproj[(row0 + 36864)*224 + c] + b4[c];
    size_t oo = (((size_t)bb*32 + 2*i)*40 + 2*j)*224 + c;
    out[oo]          = 0.5f*(A + Hh + V + D);
    out[oo + 224]    = 0.5f*(A + Hh - V - D);
    out[oo + 8960]   = 0.5f*(A - Hh + V - D);
    out[oo + 9184]   = 0.5f*(A - Hh - V + D);
}

// ---------------- launcher ----------------
extern "C" void kernel_launch(void* const* d_in, const int* in_sizes, int n_in,
                              void* d_out, int out_size) {
    const float* x       = (const float*)d_in[0];
    const float* Wq      = (const float*)d_in[1];
    const float* Wkv     = (const float*)d_in[2];
    const float* ln_g    = (const float*)d_in[3];
    const float* ln_b    = (const float*)d_in[4];
    const float* in_proj = (const float*)d_in[5];
    const float* conv1dW = (const float*)d_in[6];
    const float* conv1db = (const float*)d_in[7];
    const float* x_projW = (const float*)d_in[8];
    const float* dt_projW= (const float*)d_in[9];
    const float* dt_projb= (const float*)d_in[10];
    const float* A_log   = (const float*)d_in[11];
    const float* Dp      = (const float*)d_in[12];
    const float* out_projW=(const float*)d_in[13];
    const float* skip    = (const float*)d_in[14];
    const float* projW   = (const float*)d_in[15];
    const float* projb   = (const float*)d_in[16];
    const float* conv3dW = (const float*)d_in[17];
    const float* conv3db = (const float*)d_in[18];
    const float* Wq1     = (const float*)d_in[19];
    const float* Wkv1    = (const float*)d_in[20];
    const float* pos_emb = (const float*)d_in[21];
    const float* Wo[4]   = {(const float*)d_in[22],(const float*)d_in[24],
                            (const float*)d_in[26],(const float*)d_in[28]};
    const float* bo[4]   = {(const float*)d_in[23],(const float*)d_in[25],
                            (const float*)d_in[27],(const float*)d_in[29]};
    float* out = (float*)d_out;

    float *p_q, *p_kv, *p_attn, *p_x1, *p_xn, *p_xz, *p_xc, *p_dt,
          *p_Bm, *p_Cm, *p_y, *p_S, *p_sd, *p_H0, *p_xm2, *p_x2, *p_x3,
          *p_qkvw, *p_oproj;
    cudaGetSymbolAddress((void**)&p_q,    g_q);
    cudaGetSymbolAddress((void**)&p_kv,   g_kv);
    cudaGetSymbolAddress((void**)&p_attn, g_attn);
    cudaGetSymbolAddress((void**)&p_x1,   g_x1);
    cudaGetSymbolAddress((void**)&p_xn,   g_xn);
    cudaGetSymbolAddress((void**)&p_xz,   g_xz);
    cudaGetSymbolAddress((void**)&p_xc,   g_xc);
    cudaGetSymbolAddress((void**)&p_dt,   g_dt);
    cudaGetSymbolAddress((void**)&p_Bm,   g_Bm);
    cudaGetSymbolAddress((void**)&p_Cm,   g_Cm);
    cudaGetSymbolAddress((void**)&p_y,    g_y);
    cudaGetSymbolAddress((void**)&p_S,    g_S);
    cudaGetSymbolAddress((void**)&p_sd,   g_sumdt);
    cudaGetSymbolAddress((void**)&p_H0,   g_H0);
    cudaGetSymbolAddress((void**)&p_xm2,  g_xm2);
    cudaGetSymbolAddress((void**)&p_x2,   g_x2);
    cudaGetSymbolAddress((void**)&p_x3,   g_x3);
    cudaGetSymbolAddress((void**)&p_qkvw, g_qkvw);
    cudaGetSymbolAddress((void**)&p_oproj,g_oproj);

    __nv_bfloat16 *p_xh,*p_xl,*p_xnh,*p_xnl,*p_xwh,*p_xwl,*p_obh,*p_obl,
        *p_Wqh,*p_Wql,*p_Wkvh,*p_Wkvl,*p_iph,*p_ipl,*p_Wq1h,*p_Wq1l,
        *p_Wkv1h,*p_Wkv1l,*p_Woh,*p_Wol;
    cudaGetSymbolAddress((void**)&p_xh,   g_xh);
    cudaGetSymbolAddress((void**)&p_xl,   g_xlo);
    cudaGetSymbolAddress((void**)&p_xnh,  g_xnh);
    cudaGetSymbolAddress((void**)&p_xnl,  g_xnl);
    cudaGetSymbolAddress((void**)&p_xwh,  g_xwh);
    cudaGetSymbolAddress((void**)&p_xwl,  g_xwl);
    cudaGetSymbolAddress((void**)&p_obh,  g_obh);
    cudaGetSymbolAddress((void**)&p_obl,  g_obl);
    cudaGetSymbolAddress((void**)&p_Wqh,  g_Wqh);
    cudaGetSymbolAddress((void**)&p_Wql,  g_Wql);
    cudaGetSymbolAddress((void**)&p_Wkvh, g_Wkvh);
    cudaGetSymbolAddress((void**)&p_Wkvl, g_Wkvl);
    cudaGetSymbolAddress((void**)&p_iph,  g_iph);
    cudaGetSymbolAddress((void**)&p_ipl,  g_ipl);
    cudaGetSymbolAddress((void**)&p_Wq1h, g_Wq1h);
    cudaGetSymbolAddress((void**)&p_Wq1l, g_Wq1l);
    cudaGetSymbolAddress((void**)&p_Wkv1h,g_Wkv1h);
    cudaGetSymbolAddress((void**)&p_Wkv1l,g_Wkv1l);
    cudaGetSymbolAddress((void**)&p_Woh,  g_Woh);
    cudaGetSymbolAddress((void**)&p_Wol,  g_Wol);

    // ---- weight + input splits ----
    k_split<<<(9175040+255)/256, 256>>>(x, p_xh, p_xl, 9175040);
    k_split<<<(50176+255)/256,  256>>>(Wq,      p_Wqh,   p_Wql,   50176);
    k_split<<<(100352+255)/256, 256>>>(Wkv,     p_Wkvh,  p_Wkvl,  100352);
    k_split<<<(4096+255)/256,   256>>>(in_proj, p_iph,   p_ipl,   4096);
    k_split<<<(50176+255)/256,  256>>>(Wq1,     p_Wq1h,  p_Wq1l,  50176);
    k_split<<<(100352+255)/256, 256>>>(Wkv1,    p_Wkv1h, p_Wkv1l, 100352);
    for (int s = 0; s < 4; s++)
        k_split<<<(50176+255)/256, 256>>>(Wo[s], p_Woh + s*50176, p_Wol + s*50176, 50176);

    // stage 1: q/kv GEMMs (tensor core), gram+softmax, apply
    tgemm_bf<<<dim3(4, 320), 256>>>(p_xh, p_xl, p_Wqh,  p_Wql,  p_q,  224, 224, 224, 224, 224);
    tgemm_bf<<<dim3(7, 320), 256>>>(p_xh, p_xl, p_Wkvh, p_Wkvl, p_kv, 448, 224, 224, 448, 448);
    k_gram <<<dim3(32, 8), 256>>>(p_q, p_kv, p_attn);
    k_apply<<<dim3(20, 32), 224>>>(x, p_kv, p_attn, p_x1);

    // stage 2: mamba
    k_ln1<<<dim3(40, 32), 256>>>(p_x1, ln_g, ln_b, p_xn, p_xnh, p_xnl);
    tgemm_bf<<<dim3(2, 2240), 256>>>(p_xnh, p_xnl, p_iph, p_ipl, p_xz, 128, 32, 32, 128, 128);
    k_conv1d<<<17920, 256>>>(p_xz, conv1dW, conv1db, p_xc);
    sgemm_xproj<<<dim3(1, 2240), 256>>>(p_xc, x_projW, dt_projW, dt_projb,
                                        p_dt, p_Bm, p_Cm);
    k_scan1<<<8960, 256>>>(p_dt, p_xc, p_Bm, A_log, p_S, p_sd);
    k_scan2<<<128, 256>>>(p_S, p_sd, A_log, p_H0);
    k_scan3<<<8960, 256>>>(p_dt, p_xc, p_Bm, p_Cm, A_log, p_H0, p_y);
    k_final<<<4480, 256>>>(p_y, p_xc, p_xz, p_xn, Dp, out_projW, skip,
                           ln_g, ln_b, projW, projb, p_xm2);
    k_addback<<<dim3(40, 32), 256>>>(p_x1, p_xm2, p_x2);

    // stage 3: conv3d
    k_conv3d<<<dim3(40, 32), 224>>>(p_x2, conv3dW, conv3db, p_x3);

    // stage 4: DWT + window attention
    k_dwt<<<10752, 256>>>(p_x3, p_xwh, p_xwl);
    tgemm_bf<<<dim3(4, 384), 256>>>(p_xwh, p_xwl, p_Wq1h,  p_Wq1l,  p_qkvw,       224, 224, 224, 224, 672);
    tgemm_bf<<<dim3(7, 384), 256>>>(p_xwh, p_xwl, p_Wkv1h, p_Wkv1l, p_qkvw + 224, 448, 224, 224, 448, 672);
    k_wattn<<<dim3(768, 8), 64>>>(p_qkvw, pos_emb, p_obh, p_obl);
    BfPtrs4 po;
    for (int s = 0; s < 4; s++) { po.Bh[s] = p_Woh + s*50176; po.Bl[s] = p_Wol + s*50176; }
    tgemm_bf_b4<<<dim3(4, 96, 4), 256>>>(p_obh, p_obl, po, p_oproj,
                                         224, 224, 224, 224, 224,
                                         (long long)12288*224, (long long)12288*224);

    // stage 5: IWT + biases + output
    k_iwt<<<8960, 256>>>(p_oproj, bo[0], bo[1], bo[2], bo[3], out);
}

// round 12
// speedup vs baseline: 1.4830x; 1.0569x over previous
#include <cuda_runtime.h>
#include <cuda_bf16.h>
#include <mma.h>
#include <math.h>
#include <stdint.h>

using namespace nvcuda;

// ---------------- static scratch ----------------
__device__ __align__(16) float g_q    [40960u*224u];
__device__ __align__(16) float g_kv   [40960u*448u];
__device__ __align__(16) float g_attn [32*8*28*28];
__device__ __align__(16) float g_x1   [9175040];
__device__ __align__(16) float g_xn   [9175040];      // 286720 x 32
__device__ __align__(16) float g_xz   [36700160];     // 286720 x 128
__device__ __align__(16) float g_xc   [18350080];     // 286720 x 64
__device__ __align__(16) float g_dt   [18350080];
__device__ __align__(16) float g_Bm   [4587520];
__device__ __align__(16) float g_Cm   [4587520];
__device__ __align__(16) float g_y    [18350080];
__device__ __align__(16) float g_S    [2293760];
__device__ __align__(16) float g_sumdt[143360];
__device__ __align__(16) float g_H0   [2293760];
__device__ __align__(16) float g_xm2  [9175040];
__device__ __align__(16) float g_x2   [9175040];
__device__ __align__(16) float g_x3   [9175040];
__device__ __align__(16) float g_qkvw [33030144];     // 49152 x 672
__device__ __align__(16) float g_oproj[11010048];

// bf16 hi/lo split scratch
__device__ __align__(16) __nv_bfloat16 g_xh  [9175040],  g_xlo  [9175040];
__device__ __align__(16) __nv_bfloat16 g_xnh [9175040],  g_xnl  [9175040];
__device__ __align__(16) __nv_bfloat16 g_xwh [11010048], g_xwl  [11010048];
__device__ __align__(16) __nv_bfloat16 g_obh [11010048], g_obl  [11010048];
__device__ __align__(16) __nv_bfloat16 g_Wqh [50176],  g_Wql [50176];
__device__ __align__(16) __nv_bfloat16 g_Wkvh[100352], g_Wkvl[100352];
__device__ __align__(16) __nv_bfloat16 g_iph [4096],   g_ipl [4096];
__device__ __align__(16) __nv_bfloat16 g_Wq1h[50176],  g_Wq1l[50176];
__device__ __align__(16) __nv_bfloat16 g_Wkv1h[100352],g_Wkv1l[100352];
__device__ __align__(16) __nv_bfloat16 g_Woh [200704], g_Wol [200704];

__device__ __forceinline__ float siluf(float v){ return v / (1.f + __expf(-v)); }
__device__ __forceinline__ void bfsplit(float v, __nv_bfloat16& h, __nv_bfloat16& l) {
    h = __float2bfloat16(v);
    l = __float2bfloat16(v - __bfloat162float(h));
}

struct BfPtrs4 { const __nv_bfloat16* Bh[4]; const __nv_bfloat16* Bl[4]; };

// ---------------- fp32 -> bf16 hi/lo split ----------------
__global__ void k_split(const float* __restrict__ in, __nv_bfloat16* __restrict__ hi,
                        __nv_bfloat16* __restrict__ lo, int n) {
    int i = blockIdx.x*256 + threadIdx.x;
    if (i < n) {
        __nv_bfloat16 h, l;
        bfsplit(in[i], h, l);
        hi[i] = h; lo[i] = l;
    }
}

struct SplitSeg { const float* src; __nv_bfloat16* hi; __nv_bfloat16* lo; int n; };
struct SplitArgs { SplitSeg s[10]; };

__global__ void k_split_multi(SplitArgs a) {
    SplitSeg seg = a.s[blockIdx.y];
    int i = blockIdx.x*256 + threadIdx.x;
    if (i < seg.n) {
        __nv_bfloat16 h, l;
        bfsplit(seg.src[i], h, l);
        seg.hi[i] = h; seg.lo[i] = l;
    }
}

// ---------------- bf16 split tensor-core GEMM: 128x128 tile, double-buffered --
// C[M,N] = (Ah+Al)@(Bh+Bl), 3-term split, fp32 accum.
// M%128==0, K%16==0, N%8==0 (col-predicated at 16 granularity), lda/ldb%8==0.
#define APITCH 24
#define BPITCH 136
__device__ __forceinline__ void tgemm_bf_core(
    const __nv_bfloat16* __restrict__ Ah, const __nv_bfloat16* __restrict__ Al,
    const __nv_bfloat16* __restrict__ Bh, const __nv_bfloat16* __restrict__ Bl,
    float* __restrict__ C, int N, int K, int lda, int ldb, int ldc,
    __nv_bfloat16* sAh, __nv_bfloat16* sAl, __nv_bfloat16* sBh, __nv_bfloat16* sBl)
{
    const int bm = blockIdx.y*128, bn = blockIdx.x*128;
    const int tid = threadIdx.x, warp = tid >> 5;
    const int wm = warp >> 2, wn = warp & 3;   // 2 x 4 warps; warp tile 64x32
    wmma::fragment<wmma::accumulator,16,16,16,float> acc[4][2];
    #pragma unroll
    for (int i = 0; i < 4; i++)
        #pragma unroll
        for (int j = 0; j < 2; j++) wmma::fill_fragment(acc[i][j], 0.f);

    // A loader: 128 rows x 16 cols, one uint4 (8 bf16) per thread, x2 (hi/lo)
    const int ar = tid >> 1, ac = (tid & 1)*8;
    // B loader: 16 rows x 128 cols, one uint4 per thread, x2
    const int brr = tid >> 4, bcc = (tid & 15)*8;
    const int bcol = bn + bcc;

    uint4 rah, ral, rbh, rbl;
    rah = *(const uint4*)&Ah[(size_t)(bm+ar)*lda + ac];
    ral = *(const uint4*)&Al[(size_t)(bm+ar)*lda + ac];
    rbh = make_uint4(0u,0u,0u,0u); rbl = rbh;
    if (bcol < N) {
        rbh = *(const uint4*)&Bh[(size_t)brr*ldb + bcol];
        rbl = *(const uint4*)&Bl[(size_t)brr*ldb + bcol];
    }
    int buf = 0;
    __nv_bfloat16* pAh = sAh; __nv_bfloat16* pAl = sAl;
    __nv_bfloat16* pBh = sBh; __nv_bfloat16* pBl = sBl;
    const int ASZ = 128*APITCH, BSZ = 16*BPITCH;
    *(uint4*)&pAh[ar*APITCH + ac] = rah;
    *(uint4*)&pAl[ar*APITCH + ac] = ral;
    *(uint4*)&pBh[brr*BPITCH + bcc] = rbh;
    *(uint4*)&pBl[brr*BPITCH + bcc] = rbl;
    __syncthreads();

    for (int k0 = 0; k0 < K; k0 += 16) {
        const bool more = (k0 + 16) < K;
        if (more) {
            rah = *(const uint4*)&Ah[(size_t)(bm+ar)*lda + k0 + 16 + ac];
            ral = *(const uint4*)&Al[(size_t)(bm+ar)*lda + k0 + 16 + ac];
            if (bcol < N) {
                rbh = *(const uint4*)&Bh[(size_t)(k0+16+brr)*ldb + bcol];
                rbl = *(const uint4*)&Bl[(size_t)(k0+16+brr)*ldb + bcol];
            }
        }
        __nv_bfloat16* cAh = sAh + buf*ASZ; __nv_bfloat16* cAl = sAl + buf*ASZ;
        __nv_bfloat16* cBh = sBh + buf*BSZ; __nv_bfloat16* cBl = sBl + buf*BSZ;
        wmma::fragment<wmma::matrix_b,16,16,16,__nv_bfloat16,wmma::row_major> fbh[2], fbl[2];
        #pragma unroll
        for (int j = 0; j < 2; j++) {
            wmma::load_matrix_sync(fbh[j], &cBh[wn*32 + j*16], BPITCH);
            wmma::load_matrix_sync(fbl[j], &cBl[wn*32 + j*16], BPITCH);
        }
        #pragma unroll
        for (int i = 0; i < 4; i++) {
            wmma::fragment<wmma::matrix_a,16,16,16,__nv_bfloat16,wmma::row_major> fah, fal;
            wmma::load_matrix_sync(fah, &cAh[(wm*64 + i*16)*APITCH], APITCH);
            wmma::load_matrix_sync(fal, &cAl[(wm*64 + i*16)*APITCH], APITCH);
            #pragma unroll
            for (int j = 0; j < 2; j++) {
                wmma::mma_sync(acc[i][j], fah, fbh[j], acc[i][j]);
                wmma::mma_sync(acc[i][j], fah, fbl[j], acc[i][j]);
                wmma::mma_sync(acc[i][j], fal, fbh[j], acc[i][j]);
            }
        }
        if (more) {
            int nb = buf ^ 1;
            *(uint4*)&sAh[nb*ASZ + ar*APITCH + ac] = rah;
            *(uint4*)&sAl[nb*ASZ + ar*APITCH + ac] = ral;
            *(uint4*)&sBh[nb*BSZ + brr*BPITCH + bcc] = rbh;
            *(uint4*)&sBl[nb*BSZ + brr*BPITCH + bcc] = rbl;
            __syncthreads();
            buf = nb;
        }
    }
    #pragma unroll
    for (int i = 0; i < 4; i++)
        #pragma unroll
        for (int j = 0; j < 2; j++) {
            int n0 = bn + wn*32 + j*16;
            if (n0 < N)
                wmma::store_matrix_sync(C + (size_t)(bm + wm*64 + i*16)*ldc + n0,
                                        acc[i][j], ldc, wmma::mem_row_major);
        }
}

__global__ __launch_bounds__(256) void tgemm_bf(
    const __nv_bfloat16* __restrict__ Ah, const __nv_bfloat16* __restrict__ Al,
    const __nv_bfloat16* __restrict__ Bh, const __nv_bfloat16* __restrict__ Bl,
    float* __restrict__ C, int N, int K, int lda, int ldb, int ldc)
{
    __shared__ __align__(16) __nv_bfloat16 sAh[2*128*APITCH], sAl[2*128*APITCH];
    __shared__ __align__(16) __nv_bfloat16 sBh[2*16*BPITCH],  sBl[2*16*BPITCH];
    tgemm_bf_core(Ah, Al, Bh, Bl, C, N, K, lda, ldb, ldc, sAh, sAl, sBh, sBl);
}

__global__ __launch_bounds__(256) void tgemm_bf_b4(
    const __nv_bfloat16* __restrict__ Ah, const __nv_bfloat16* __restrict__ Al,
    BfPtrs4 p, float* __restrict__ C, int N, int K, int lda, int ldb, int ldc,
    long long strideA, long long strideC)
{
    __shared__ __align__(16) __nv_bfloat16 sAh[2*128*APITCH], sAl[2*128*APITCH];
    __shared__ __align__(16) __nv_bfloat16 sBh[2*16*BPITCH],  sBl[2*16*BPITCH];
    int z = blockIdx.z;
    tgemm_bf_core(Ah + (size_t)z*strideA, Al + (size_t)z*strideA,
                  p.Bh[z], p.Bl[z], C + (size_t)z*strideC,
                  N, K, lda, ldb, ldc, sAh, sAl, sBh, sBl);
}

// ---------------- fused x_proj GEMM (SIMT) + dt/B/C split ----------------
__global__ __launch_bounds__(256) void sgemm_xproj(
    const float* __restrict__ A, const float* __restrict__ B,
    const float* __restrict__ dtW, const float* __restrict__ dtb,
    float* __restrict__ dt, float* __restrict__ Bm, float* __restrict__ Cm)
{
    __shared__ float As[2][16][128];
    __shared__ float Bs[2][16][64];
    __shared__ float St[128][36];
    __shared__ float sdtW[128], sdtb[64];
    const int N = 34, K = 64, lda = 64, ldb = 34;
    const int bm = blockIdx.y * 128;
    const int tid = threadIdx.x;
    const int tr = tid >> 4, tc = tid & 15;
    const int br = tid >> 4, bc0 = (tid & 15) * 4;
    if (tid < 128) sdtW[tid] = dtW[tid];
    if (tid >= 128 && tid < 192) sdtb[tid-128] = dtb[tid-128];
    float acc[8][4];
    #pragma unroll
    for (int i = 0; i < 8; i++)
        #pragma unroll
        for (int j = 0; j < 4; j++) acc[i][j] = 0.f;

    float4 ra[2]; float rb[4];
    #pragma unroll
    for (int i = 0; i < 2; i++) {
        int idx = tid + i * 256;
        int r = idx >> 2, c4 = (idx & 3) * 4;
        ra[i] = *(const float4*)(A + (size_t)(bm + r) * lda + c4);
    }
    #pragma unroll
    for (int i = 0; i < 4; i++) {
        int n = bc0 + i;
        rb[i] = (n < N) ? B[(size_t)br * ldb + n] : 0.f;
    }
    int buf = 0;
    #pragma unroll
    for (int i = 0; i < 2; i++) {
        int idx = tid + i * 256;
        int r = idx >> 2, c4 = (idx & 3) * 4;
        As[0][c4+0][r]=ra[i].x; As[0][c4+1][r]=ra[i].y;
        As[0][c4+2][r]=ra[i].z; As[0][c4+3][r]=ra[i].w;
    }
    #pragma unroll
    for (int i = 0; i < 4; i++) Bs[0][br][bc0+i] = rb[i];
    __syncthreads();

    for (int k0 = 0; k0 < K; k0 += 16) {
        const bool more = (k0 + 16) < K;
        float4 ra2[2]; float rb2[4];
        if (more) {
            #pragma unroll
            for (int i = 0; i < 2; i++) {
                int idx = tid + i * 256;
                int r = idx >> 2, c4 = (idx & 3) * 4;
                ra2[i] = *(const float4*)(A + (size_t)(bm + r) * lda + k0 + 16 + c4);
            }
            #pragma unroll
            for (int i = 0; i < 4; i++) {
                int n = bc0 + i;
                rb2[i] = (n < N) ? B[(size_t)(k0 + 16 + br) * ldb + n] : 0.f;
            }
        }
        #pragma unroll
        for (int kk = 0; kk < 16; kk++) {
            float4 a0 = *(const float4*)&As[buf][kk][tr*8];
            float4 a1 = *(const float4*)&As[buf][kk][tr*8+4];
            float4 b0 = *(const float4*)&Bs[buf][kk][tc*4];
            float a[8] = {a0.x,a0.y,a0.z,a0.w,a1.x,a1.y,a1.z,a1.w};
            float b[4] = {b0.x,b0.y,b0.z,b0.w};
            #pragma unroll
            for (int i = 0; i < 8; i++)
                #pragma unroll
                for (int j = 0; j < 4; j++) acc[i][j] += a[i]*b[j];
        }
        if (more) {
            int nb = buf ^ 1;
            #pragma unroll
            for (int i = 0; i < 2; i++) {
                int idx = tid + i * 256;
                int r = idx >> 2, c4 = (idx & 3) * 4;
                As[nb][c4+0][r]=ra2[i].x; As[nb][c4+1][r]=ra2[i].y;
                As[nb][c4+2][r]=ra2[i].z; As[nb][c4+3][r]=ra2[i].w;
            }
            #pragma unroll
            for (int i = 0; i < 4; i++) Bs[nb][br][bc0+i] = rb2[i];
            __syncthreads();
            buf = nb;
        }
    }
    #pragma unroll
    for (int i = 0; i < 8; i++) {
        #pragma unroll
        for (int j = 0; j < 4; j++) {
            int n = tc*4 + j;
            if (n < N) St[tr*8 + i][n] = acc[i][j];
        }
    }
    __syncthreads();
    for (int idx = tid; idx < 128*64; idx += 256) {
        int r = idx >> 6, d = idx & 63;
        float v = St[r][0]*sdtW[d] + St[r][1]*sdtW[64+d] + sdtb[d];
        dt[(size_t)(bm + r)*64 + d] = (v > 20.f) ? v : log1pf(__expf(v));
    }
    for (int idx = tid; idx < 128*16; idx += 256) {
        int r = idx >> 4, n = idx & 15;
        Bm[(size_t)(bm + r)*16 + n] = St[r][2 + n];
        Cm[(size_t)(bm + r)*16 + n] = St[r][18 + n];
    }
}

// ---------------- stage 1: channel attention ----------------
__global__ void k_gram(const float* __restrict__ q, const float* __restrict__ kv,
                       float* __restrict__ attn) {
    int b = blockIdx.x, h = blockIdx.y;
    __shared__ float kt[32][28], qt[32][28];
    __shared__ float G[840];
    int tid = threadIdx.x;   // 256
    float acc[4] = {0.f,0.f,0.f,0.f};
    for (int nt = 0; nt < 40; nt++) {
        for (int idx = tid; idx < 896; idx += 256) {
            int n = idx / 28, i = idx % 28;
            size_t row = (size_t)b*1280 + nt*32 + n;
            kt[n][i] = kv[row*448 + h*28 + i];
            qt[n][i] = q [row*224 + h*28 + i];
        }
        __syncthreads();
        #pragma unroll
        for (int s = 0; s < 4; s++) {
            int w = tid + 256*s;
            if (w < 784) {
                int i = w/28, j = w%28; float a = acc[s];
                #pragma unroll
                for (int n = 0; n < 32; n++) a += kt[n][i]*qt[n][j];
                acc[s] = a;
            } else if (w < 812) {
                int i = w - 784; float a = acc[s];
                #pragma unroll
                for (int n = 0; n < 32; n++) a += kt[n][i]*kt[n][i];
                acc[s] = a;
            } else if (w < 840) {
                int j = w - 812; float a = acc[s];
                #pragma unroll
                for (int n = 0; n < 32; n++) a += qt[n][j]*qt[n][j];
                acc[s] = a;
            }
        }
        __syncthreads();
    }
    #pragma unroll
    for (int s = 0; s < 4; s++) { int w = tid + 256*s; if (w < 840) G[w] = acc[s]; }
    __syncthreads();
    if (tid < 28) {
        int i = tid;
        float nk = fmaxf(sqrtf(G[784+i]), 1e-12f);
        float lg[28], m = -1e30f;
        #pragma unroll
        for (int j = 0; j < 28; j++) {
            float nq = fmaxf(sqrtf(G[812+j]), 1e-12f);
            lg[j] = G[i*28+j] / (nk*nq) * 0.18898223650461363f;
            m = fmaxf(m, lg[j]);
        }
        float sum = 0.f;
        #pragma unroll
        for (int j = 0; j < 28; j++) { lg[j] = __expf(lg[j]-m); sum += lg[j]; }
        float inv = 1.f/sum;
        #pragma unroll
        for (int j = 0; j < 28; j++)
            attn[(((size_t)b*8 + h)*28 + i)*28 + j] = lg[j]*inv;
    }
}

// x1 = attn-applied + residual; attention row in registers
__global__ void k_apply(const float* __restrict__ x, const float* __restrict__ kv,
                        const float* __restrict__ attn, float* __restrict__ x1) {
    int chunk = blockIdx.x, b = blockIdx.y;
    __shared__ float vr[8][224];
    int tid = threadIdx.x;   // 224
    int h = tid / 28, i = tid % 28;
    float att[28];
    {
        const float4* ap = (const float4*)(attn + (((size_t)b*8 + h)*28 + i)*28);
        #pragma unroll
        for (int q4 = 0; q4 < 7; q4++) {
            float4 v = ap[q4];
            att[q4*4+0]=v.x; att[q4*4+1]=v.y; att[q4*4+2]=v.z; att[q4*4+3]=v.w;
        }
    }
    for (int nn = 0; nn < 64; nn += 8) {
        size_t row0 = (size_t)b*1280 + chunk*64 + nn;
        __syncthreads();
        for (int idx = tid; idx < 1792; idx += 224) {
            int rr = idx / 224, cc = idx % 224;
            vr[rr][cc] = kv[(row0 + rr)*448 + 224 + cc];
        }
        __syncthreads();
        #pragma unroll
        for (int rr = 0; rr < 8; rr++) {
            float a = 0.f;
            #pragma unroll
            for (int j = 0; j < 28; j++) a += att[j] * vr[rr][h*28 + j];
            size_t o = (row0 + rr)*224 + tid;
            x1[o] = x[o] + a;
        }
    }
}

// ---------------- transpose + LN; also emits bf16 hi/lo ----------------
__global__ void k_ln1(const float* __restrict__ x1, const float* __restrict__ g,
                      const float* __restrict__ be, float* __restrict__ xn,
                      __nv_bfloat16* __restrict__ xnh, __nv_bfloat16* __restrict__ xnl) {
    int ww = blockIdx.x, b = blockIdx.y;
    __shared__ float s[32*225];
    int tid = threadIdx.x;   // 256
    for (int idx = tid; idx < 32*224; idx += 256) {
        int m = idx / 224, cc = idx % 224;
        s[m*225 + cc] = x1[((size_t)b*1280 + m*40 + ww)*224 + cc];
    }
    __syncthreads();
    for (int cc = tid; cc < 224; cc += 256) {
        float mean = 0.f;
        #pragma unroll
        for (int m = 0; m < 32; m++) mean += s[m*225+cc];
        mean *= (1.f/32.f);
        float var = 0.f;
        #pragma unroll
        for (int m = 0; m < 32; m++) { float d = s[m*225+cc]-mean; var += d*d; }
        var *= (1.f/32.f);
        float inv = rsqrtf(var + 1e-5f);
        size_t ob = ((size_t)b*8960 + ww*224 + cc)*32;
        #pragma unroll
        for (int m = 0; m < 32; m++) {
            float v = (s[m*225+cc]-mean)*inv*g[m] + be[m];
            xn[ob + m] = v;
            __nv_bfloat16 h, l; bfsplit(v, h, l);
            xnh[ob + m] = h; xnl[ob + m] = l;
        }
    }
}

// ---------------- mamba pieces ----------------
__global__ void k_conv1d(const float* __restrict__ xz, const float* __restrict__ cw,
                         const float* __restrict__ cb, float* __restrict__ xc) {
    size_t id = (size_t)blockIdx.x*256 + threadIdx.x;   // 286720*16
    size_t row = id >> 4; int d4 = (int)(id & 15) * 4;
    size_t b = row / 8960; int l = (int)(row % 8960);
    float a0 = cb[d4], a1 = cb[d4+1], a2 = cb[d4+2], a3 = cb[d4+3];
    #pragma unroll
    for (int t = 0; t < 4; t++) {
        int ls = l - 3 + t;
        if (ls >= 0) {
            float4 v = *(const float4*)(xz + ((size_t)b*8960 + ls)*128 + d4);
            a0 += v.x * cw[d4*4 + t];
            a1 += v.y * cw[(d4+1)*4 + t];
            a2 += v.z * cw[(d4+2)*4 + t];
            a3 += v.w * cw[(d4+3)*4 + t];
        }
    }
    float4 o; o.x = siluf(a0); o.y = siluf(a1); o.z = siluf(a2); o.w = siluf(a3);
    *(float4*)(xc + row*64 + d4) = o;
}

__global__ __launch_bounds__(256) void k_scan1(
    const float* __restrict__ dt, const float* __restrict__ xc,
    const float* __restrict__ Bm, const float* __restrict__ Alog,
    float* __restrict__ S, float* __restrict__ sumdt) {
    int bx = blockIdx.x;                 // 8960
    int b = bx / 280, rem = bx % 280;
    int chunk = rem >> 2, dg = rem & 3;
    int tid = threadIdx.x, warp = tid >> 5, lane = tid & 31;
    int dloc = 2*warp + (lane >> 4), n = lane & 15;
    int d = dg*16 + dloc;
    __shared__ float sdt[16][16], sxc[16][16], sbm[16][16];
    float Av = -__expf(Alog[d*16 + n]);
    float h = 0.f, sdsum = 0.f;
    size_t rowbase = (size_t)b*8960 + chunk*128;
    int lr = tid >> 4, lc = tid & 15;
    for (int s = 0; s < 8; s++) {
        size_t r0 = rowbase + s*16;
        __syncthreads();
        sdt[lr][lc] = dt[(r0 + lr)*64 + dg*16 + lc];
        sxc[lr][lc] = xc[(r0 + lr)*64 + dg*16 + lc];
        sbm[lr][lc] = Bm[(r0 + lr)*16 + lc];
        __syncthreads();
        #pragma unroll
        for (int l = 0; l < 16; l++) {
            float dtv = sdt[l][dloc];
            float u   = sxc[l][dloc];
            float Bn  = sbm[l][n];
            h = __expf(Av*dtv)*h + dtv*u*Bn;
            sdsum += dtv;
        }
    }
    size_t idx = (size_t)(b*64 + d)*70 + chunk;
    S[idx*16 + n] = h;
    if (n == 0) sumdt[idx] = sdsum;
}

__global__ void k_scan2(const float* __restrict__ S, const float* __restrict__ sumdt,
                        const float* __restrict__ Alog, float* __restrict__ H0) {
    int t = blockIdx.x*256 + threadIdx.x;
    int b = t >> 10; int d = (t >> 4) & 63; int n = t & 15;
    float Av = -__expf(Alog[d*16 + n]);
    float carry = 0.f;
    size_t base = (size_t)(b*64 + d)*70;
    for (int ch = 0; ch < 70; ch++) {
        size_t idx = base + ch;
        H0[idx*16 + n] = carry;
        carry = carry*__expf(Av*sumdt[idx]) + S[idx*16 + n];
    }
}

__global__ __launch_bounds__(256) void k_scan3(
    const float* __restrict__ dt, const float* __restrict__ xc,
    const float* __restrict__ Bm, const float* __restrict__ Cm,
    const float* __restrict__ Alog, const float* __restrict__ H0,
    float* __restrict__ y) {
    int bx = blockIdx.x;
    int b = bx / 280, rem = bx % 280;
    int chunk = rem >> 2, dg = rem & 3;
    int tid = threadIdx.x, warp = tid >> 5, lane = tid & 31;
    int dloc = 2*warp + (lane >> 4), n = lane & 15;
    int d = dg*16 + dloc;
    __shared__ float sdt[16][16], sxc[16][16], sbm[16][16], scm[16][16], sy[16][16];
    float Av = -__expf(Alog[d*16 + n]);
    size_t idx = (size_t)(b*64 + d)*70 + chunk;
    float h = H0[idx*16 + n];
    size_t rowbase = (size_t)b*8960 + chunk*128;
    int lr = tid >> 4, lc = tid & 15;
    for (int s = 0; s < 8; s++) {
        size_t r0 = rowbase + s*16;
        __syncthreads();
        sdt[lr][lc] = dt[(r0 + lr)*64 + dg*16 + lc];
        sxc[lr][lc] = xc[(r0 + lr)*64 + dg*16 + lc];
        sbm[lr][lc] = Bm[(r0 + lr)*16 + lc];
        scm[lr][lc] = Cm[(r0 + lr)*16 + lc];
        __syncthreads();
        #pragma unroll
        for (int l = 0; l < 16; l++) {
            float dtv = sdt[l][dloc];
            float u   = sxc[l][dloc];
            float Bn  = sbm[l][n];
            h = __expf(Av*dtv)*h + dtv*u*Bn;
            float yv = h * scm[l][n];
            yv += __shfl_xor_sync(0xffffffffu, yv, 8);
            yv += __shfl_xor_sync(0xffffffffu, yv, 4);
            yv += __shfl_xor_sync(0xffffffffu, yv, 2);
            yv += __shfl_xor_sync(0xffffffffu, yv, 1);
            if (n == 0) sy[l][dloc] = yv;
        }
        __syncthreads();
        y[(r0 + lr)*64 + dg*16 + lc] = sy[lr][lc];
    }
}

__global__ void k_final(const float* __restrict__ y, const float* __restrict__ xc,
                        const float* __restrict__ xz, const float* __restrict__ xn,
                        const float* __restrict__ Dp, const float* __restrict__ opW,
                        const float* __restrict__ skipp, const float* __restrict__ g,
                        const float* __restrict__ be, const float* __restrict__ projW,
                        const float* __restrict__ projb, float* __restrict__ xm2) {
    __shared__ float sop[2048], spj[1024];
    int tid = threadIdx.x;   // 256
    for (int i = tid; i < 2048; i += 256) sop[i] = opW[i];
    for (int i = tid; i < 1024; i += 256) spj[i] = projW[i];
    __syncthreads();
    int warp = tid >> 5, lane = tid & 31;
    float skip = skipp[0];
    float dpl = Dp[lane], dph = Dp[32+lane];
    float gl = g[lane], bel = be[lane], pbl = projb[lane];
    #pragma unroll
    for (int t = 0; t < 8; t++) {
        size_t r = ((size_t)blockIdx.x*8 + warp)*8 + t;
        float y0 = y[r*64 + lane],      y1 = y[r*64 + 32 + lane];
        float c0 = xc[r*64 + lane],     c1 = xc[r*64 + 32 + lane];
        float z0 = xz[r*128 + 64 + lane], z1 = xz[r*128 + 96 + lane];
        float yy0 = (y0 + c0*dpl) * siluf(z0);
        float yy1 = (y1 + c1*dph) * siluf(z1);
        float acc = 0.f;
        #pragma unroll
        for (int d = 0; d < 32; d++) acc += __shfl_sync(0xffffffffu, yy0, d) * sop[d*32 + lane];
        #pragma unroll
        for (int d = 0; d < 32; d++) acc += __shfl_sync(0xffffffffu, yy1, d) * sop[(d+32)*32 + lane];
        float xm = acc + skip * xn[r*32 + lane];
        float mean = xm;
        #pragma unroll
        for (int o = 16; o; o >>= 1) mean += __shfl_xor_sync(0xffffffffu, mean, o);
        mean *= (1.f/32.f);
        float dv = xm - mean, var = dv*dv;
        #pragma unroll
        for (int o = 16; o; o >>= 1) var += __shfl_xor_sync(0xffffffffu, var, o);
        var *= (1.f/32.f);
        float v = dv * rsqrtf(var + 1e-5f) * gl + bel;
        float acc2 = pbl;
        #pragma unroll
        for (int mm = 0; mm < 32; mm++) acc2 += __shfl_sync(0xffffffffu, v, mm) * spj[mm*32 + lane];
        xm2[r*32 + lane] = acc2;
    }
}

__global__ void k_addback(const float* __restrict__ x1, const float* __restrict__ xm2,
                          float* __restrict__ x2) {
    int ww = blockIdx.x, b = blockIdx.y;
    __shared__ float s[224*33];
    int tid = threadIdx.x;   // 256
    for (int idx = tid; idx < 224*32; idx += 256) {
        int cc = idx >> 5, m = idx & 31;
        s[cc*33 + m] = xm2[((size_t)b*8960 + ww*224 + cc)*32 + m];
    }
    __syncthreads();
    for (int idx = tid; idx < 32*224; idx += 256) {
        int m = idx / 224, cc = idx % 224;
        size_t o = ((size_t)b*1280 + m*40 + ww)*224 + cc;
        x2[o] = x1[o] + s[cc*33 + m];
    }
}

// ---------------- conv3d 5x5x5, pad 2, smem-tiled per ky-plane ----------------
__global__ void k_conv3d(const float* __restrict__ x2, const float* __restrict__ cw,
                         const float* __restrict__ cb, float* __restrict__ x3) {
    int y = blockIdx.x, b = blockIdx.y;
    int xx = threadIdx.x;   // 224
    __shared__ float ws[125];
    __shared__ float sp[32][228];
    if (xx < 125) ws[xx] = cw[xx];
    if (xx < 32) { sp[xx][0]=0.f; sp[xx][1]=0.f; sp[xx][226]=0.f; sp[xx][227]=0.f; }
    float acc[32];
    #pragma unroll
    for (int d = 0; d < 32; d++) acc[d] = 0.f;
    for (int ky = 0; ky < 5; ky++) {
        int yy = y + ky - 2;
        if (yy < 0 || yy >= 40) continue;
        __syncthreads();
        for (int i = 0; i < 32; i++)
            sp[i][xx+2] = x2[(((size_t)b*32 + i)*40 + yy)*224 + xx];
        __syncthreads();
        #pragma unroll
        for (int kx = 0; kx < 5; kx++) {
            float v[36];
            v[0]=v[1]=v[34]=v[35]=0.f;
            #pragma unroll
            for (int i = 0; i < 32; i++) v[i+2] = sp[i][xx + kx];
            #pragma unroll
            for (int kz = 0; kz < 5; kz++) {
                float wv = ws[(kz*5 + ky)*5 + kx];
                #pragma unroll
                for (int d = 0; d < 32; d++) acc[d] += v[d+kz]*wv;
            }
        }
    }
    float bias = cb[0];
    #pragma unroll
    for (int d = 0; d < 32; d++)
        x3[(((size_t)b*32 + d)*40 + y)*224 + xx] = acc[d] + bias;
}

// ---------------- DWT: 4 subbands per thread, emits bf16 hi/lo ----------------
__global__ void k_dwt(const float* __restrict__ x3,
                      __nv_bfloat16* __restrict__ xwh, __nv_bfloat16* __restrict__ xwl) {
    size_t id = (size_t)blockIdx.x*256 + threadIdx.x;   // 2752512
    int c = (int)(id % 224); size_t rw = id / 224;
    int win = (int)(rw >> 6), tok = (int)(rw & 63);
    int bb = win / 6, w6 = win % 6;
    int wi = w6 / 3, wj = w6 % 3;
    int ti = tok >> 3, tj = tok & 7;
    int i2 = wi*8 + ti;
    int j2 = wj*8 + tj;
    int j = (j2 < 20) ? j2 : 38 - j2;   // reflect pad
    size_t base = (((size_t)bb*32 + 2*i2)*40 + 2*j)*224 + c;
    float a  = x3[base],        bv = x3[base + 224];
    float c2 = x3[base + 8960], d2 = x3[base + 9184];
    const size_t SS = (size_t)12288*224;
    float v0 = 0.5f*(a + bv + c2 + d2);
    float v1 = 0.5f*(a + bv - c2 - d2);
    float v2 = 0.5f*(a - bv + c2 - d2);
    float v3 = 0.5f*(a - bv - c2 + d2);
    __nv_bfloat16 h, l;
    bfsplit(v0, h, l); xwh[id]        = h; xwl[id]        = l;
    bfsplit(v1, h, l); xwh[id + SS]   = h; xwl[id + SS]   = l;
    bfsplit(v2, h, l); xwh[id + 2*SS] = h; xwl[id + 2*SS] = l;
    bfsplit(v3, h, l); xwh[id + 3*SS] = h; xwl[id + 3*SS] = l;
}

// ---------------- window attention: online softmax, emits bf16 hi/lo --------
__global__ void k_wattn(const float* __restrict__ qkvw, const float* __restrict__ pe,
                        __nv_bfloat16* __restrict__ obh, __nv_bfloat16* __restrict__ obl) {
    int win = blockIdx.x, head = blockIdx.y;
    __shared__ __align__(16) float ks[64*28], vs[64*28];
    int tid = threadIdx.x;   // 64
    size_t wbase = (size_t)win * 64;
    for (int idx = tid; idx < 1792; idx += 64) {
        int tok = idx / 28, dd = idx % 28;
        size_t rb = (wbase + tok)*672 + head*28 + dd;
        ks[idx] = qkvw[rb + 224];
        vs[idx] = qkvw[rb + 448];
    }
    float qr[28];
    {
        const float4* qp = (const float4*)(qkvw + (wbase + tid)*672 + head*28);
        #pragma unroll
        for (int q4 = 0; q4 < 7; q4++) {
            float4 v = qp[q4];
            qr[q4*4+0] = v.x * 0.18898223650461363f;
            qr[q4*4+1] = v.y * 0.18898223650461363f;
            qr[q4*4+2] = v.z * 0.18898223650461363f;
            qr[q4*4+3] = v.w * 0.18898223650461363f;
        }
    }
    __syncthreads();
    const float* per = pe + ((size_t)head*64 + tid)*64;
    float m = -1e30f, sum = 0.f;
    float acc[28];
    #pragma unroll
    for (int dd = 0; dd < 28; dd++) acc[dd] = 0.f;
    for (int j = 0; j < 64; j++) {
        const float4* k4 = (const float4*)&ks[j*28];
        float dot = 0.f;
        #pragma unroll
        for (int q4 = 0; q4 < 7; q4++) {
            float4 kk = k4[q4];
            dot += qr[q4*4+0]*kk.x + qr[q4*4+1]*kk.y
                 + qr[q4*4+2]*kk.z + qr[q4*4+3]*kk.w;
        }
        dot += per[j];
        if (dot > m) {
            float corr = __expf(m - dot);
            sum *= corr;
            #pragma unroll
            for (int dd = 0; dd < 28; dd++) acc[dd] *= corr;
            m = dot;
        }
        float e = __expf(dot - m);
        sum += e;
        const float4* v4 = (const float4*)&vs[j*28];
        #pragma unroll
        for (int q4 = 0; q4 < 7; q4++) {
            float4 vv = v4[q4];
            acc[q4*4+0] += e*vv.x; acc[q4*4+1] += e*vv.y;
            acc[q4*4+2] += e*vv.z; acc[q4*4+3] += e*vv.w;
        }
    }
    float inv = 1.f / sum;
    size_t ob = (wbase + tid)*224 + head*28;
    #pragma unroll
    for (int dd = 0; dd < 28; dd++) {
        __nv_bfloat16 h, l;
        bfsplit(acc[dd] * inv, h, l);
        obh[ob + dd] = h; obl[ob + dd] = l;
    }
}

// ---------------- IWT + biases + crop + final layout ----------------
__global__ void k_iwt(const float* __restrict__ oproj,
                      const float* __restrict__ b1, const float* __restrict__ b2,
                      const float* __restrict__ b3, const float* __restrict__ b4,
                      float* __restrict__ out) {
    size_t id = (size_t)blockIdx.x*256 + threadIdx.x;   // 2293760
    int c = (int)(id % 224); size_t r = id / 224;
    int j = (int)(r % 20); r /= 20;
    int i = (int)(r % 16); int bb = (int)(r / 16);
    int wi = i >> 3, ti = i & 7, wj = j >> 3, tj = j & 7;
    size_t row0 = ((size_t)(bb*6 + wi*3 + wj))*64 + ti*8 + tj;
    float A  = oproj[row0*224 + c]           + b1[c];
    float Hh = oproj[(row0 + 12288)*224 + c] + b2[c];
    float V  = oproj[(row0 + 24576)*224 + c] + b3[c];
    float D  = oproj[(row0 + 36864)*224 + c] + b4[c];
    size_t oo = (((size_t)bb*32 + 2*i)*40 + 2*j)*224 + c;
    out[oo]          = 0.5f*(A + Hh + V + D);
    out[oo + 224]    = 0.5f*(A + Hh - V - D);
    out[oo + 8960]   = 0.5f*(A - Hh + V - D);
    out[oo + 9184]   = 0.5f*(A - Hh - V + D);
}

// ---------------- launcher ----------------
extern "C" void kernel_launch(void* const* d_in, const int* in_sizes, int n_in,
                              void* d_out, int out_size) {
    const float* x       = (const float*)d_in[0];
    const float* Wq      = (const float*)d_in[1];
    const float* Wkv     = (const float*)d_in[2];
    const float* ln_g    = (const float*)d_in[3];
    const float* ln_b    = (const float*)d_in[4];
    const float* in_proj = (const float*)d_in[5];
    const float* conv1dW = (const float*)d_in[6];
    const float* conv1db = (const float*)d_in[7];
    const float* x_projW = (const float*)d_in[8];
    const float* dt_projW= (const float*)d_in[9];
    const float* dt_projb= (const float*)d_in[10];
    const float* A_log   = (const float*)d_in[11];
    const float* Dp      = (const float*)d_in[12];
    const float* out_projW=(const float*)d_in[13];
    const float* skip    = (const float*)d_in[14];
    const float* projW   = (const float*)d_in[15];
    const float* projb   = (const float*)d_in[16];
    const float* conv3dW = (const float*)d_in[17];
    const float* conv3db = (const float*)d_in[18];
    const float* Wq1     = (const float*)d_in[19];
    const float* Wkv1    = (const float*)d_in[20];
    const float* pos_emb = (const float*)d_in[21];
    const float* Wo[4]   = {(const float*)d_in[22],(const float*)d_in[24],
                            (const float*)d_in[26],(const float*)d_in[28]};
    const float* bo[4]   = {(const float*)d_in[23],(const float*)d_in[25],
                            (const float*)d_in[27],(const float*)d_in[29]};
    float* out = (float*)d_out;

    float *p_q, *p_kv, *p_attn, *p_x1, *p_xn, *p_xz, *p_xc, *p_dt,
          *p_Bm, *p_Cm, *p_y, *p_S, *p_sd, *p_H0, *p_xm2, *p_x2, *p_x3,
          *p_qkvw, *p_oproj;
    cudaGetSymbolAddress((void**)&p_q,    g_q);
    cudaGetSymbolAddress((void**)&p_kv,   g_kv);
    cudaGetSymbolAddress((void**)&p_attn, g_attn);
    cudaGetSymbolAddress((void**)&p_x1,   g_x1);
    cudaGetSymbolAddress((void**)&p_xn,   g_xn);
    cudaGetSymbolAddress((void**)&p_xz,   g_xz);
    cudaGetSymbolAddress((void**)&p_xc,   g_xc);
    cudaGetSymbolAddress((void**)&p_dt,   g_dt);
    cudaGetSymbolAddress((void**)&p_Bm,   g_Bm);
    cudaGetSymbolAddress((void**)&p_Cm,   g_Cm);
    cudaGetSymbolAddress((void**)&p_y,    g_y);
    cudaGetSymbolAddress((void**)&p_S,    g_S);
    cudaGetSymbolAddress((void**)&p_sd,   g_sumdt);
    cudaGetSymbolAddress((void**)&p_H0,   g_H0);
    cudaGetSymbolAddress((void**)&p_xm2,  g_xm2);
    cudaGetSymbolAddress((void**)&p_x2,   g_x2);
    cudaGetSymbolAddress((void**)&p_x3,   g_x3);
    cudaGetSymbolAddress((void**)&p_qkvw, g_qkvw);
    cudaGetSymbolAddress((void**)&p_oproj,g_oproj);

    __nv_bfloat16 *p_xh,*p_xl,*p_xnh,*p_xnl,*p_xwh,*p_xwl,*p_obh,*p_obl,
        *p_Wqh,*p_Wql,*p_Wkvh,*p_Wkvl,*p_iph,*p_ipl,*p_Wq1h,*p_Wq1l,
        *p_Wkv1h,*p_Wkv1l,*p_Woh,*p_Wol;
    cudaGetSymbolAddress((void**)&p_xh,   g_xh);
    cudaGetSymbolAddress((void**)&p_xl,   g_xlo);
    cudaGetSymbolAddress((void**)&p_xnh,  g_xnh);
    cudaGetSymbolAddress((void**)&p_xnl,  g_xnl);
    cudaGetSymbolAddress((void**)&p_xwh,  g_xwh);
    cudaGetSymbolAddress((void**)&p_xwl,  g_xwl);
    cudaGetSymbolAddress((void**)&p_obh,  g_obh);
    cudaGetSymbolAddress((void**)&p_obl,  g_obl);
    cudaGetSymbolAddress((void**)&p_Wqh,  g_Wqh);
    cudaGetSymbolAddress((void**)&p_Wql,  g_Wql);
    cudaGetSymbolAddress((void**)&p_Wkvh, g_Wkvh);
    cudaGetSymbolAddress((void**)&p_Wkvl, g_Wkvl);
    cudaGetSymbolAddress((void**)&p_iph,  g_iph);
    cudaGetSymbolAddress((void**)&p_ipl,  g_ipl);
    cudaGetSymbolAddress((void**)&p_Wq1h, g_Wq1h);
    cudaGetSymbolAddress((void**)&p_Wq1l, g_Wq1l);
    cudaGetSymbolAddress((void**)&p_Wkv1h,g_Wkv1h);
    cudaGetSymbolAddress((void**)&p_Wkv1l,g_Wkv1l);
    cudaGetSymbolAddress((void**)&p_Woh,  g_Woh);
    cudaGetSymbolAddress((void**)&p_Wol,  g_Wol);

    // ---- splits: input (big) + all weights (one batched launch) ----
    k_split<<<(9175040+255)/256, 256>>>(x, p_xh, p_xl, 9175040);
    SplitArgs sa;
    sa.s[0] = {Wq,      p_Wqh,   p_Wql,   50176};
    sa.s[1] = {Wkv,     p_Wkvh,  p_Wkvl,  100352};
    sa.s[2] = {in_proj, p_iph,   p_ipl,   4096};
    sa.s[3] = {Wq1,     p_Wq1h,  p_Wq1l,  50176};
    sa.s[4] = {Wkv1,    p_Wkv1h, p_Wkv1l, 100352};
    sa.s[5] = {Wo[0], p_Woh,          p_Wol,          50176};
    sa.s[6] = {Wo[1], p_Woh + 50176,  p_Wol + 50176,  50176};
    sa.s[7] = {Wo[2], p_Woh + 100352, p_Wol + 100352, 50176};
    sa.s[8] = {Wo[3], p_Woh + 150528, p_Wol + 150528, 50176};
    sa.s[9] = {Wq, p_Wqh, p_Wql, 0};   // unused slot
    k_split_multi<<<dim3(392, 10), 256>>>(sa);

    // stage 1: q/kv GEMMs (tensor core), gram+softmax, apply
    tgemm_bf<<<dim3(2, 320), 256>>>(p_xh, p_xl, p_Wqh,  p_Wql,  p_q,  224, 224, 224, 224, 224);
    tgemm_bf<<<dim3(4, 320), 256>>>(p_xh, p_xl, p_Wkvh, p_Wkvl, p_kv, 448, 224, 224, 448, 448);
    k_gram <<<dim3(32, 8), 256>>>(p_q, p_kv, p_attn);
    k_apply<<<dim3(20, 32), 224>>>(x, p_kv, p_attn, p_x1);

    // stage 2: mamba
    k_ln1<<<dim3(40, 32), 256>>>(p_x1, ln_g, ln_b, p_xn, p_xnh, p_xnl);
    tgemm_bf<<<dim3(1, 2240), 256>>>(p_xnh, p_xnl, p_iph, p_ipl, p_xz, 128, 32, 32, 128, 128);
    k_conv1d<<<17920, 256>>>(p_xz, conv1dW, conv1db, p_xc);
    sgemm_xproj<<<dim3(1, 2240), 256>>>(p_xc, x_projW, dt_projW, dt_projb,
                                        p_dt, p_Bm, p_Cm);
    k_scan1<<<8960, 256>>>(p_dt, p_xc, p_Bm, A_log, p_S, p_sd);
    k_scan2<<<128, 256>>>(p_S, p_sd, A_log, p_H0);
    k_scan3<<<8960, 256>>>(p_dt, p_xc, p_Bm, p_Cm, A_log, p_H0, p_y);
    k_final<<<4480, 256>>>(p_y, p_xc, p_xz, p_xn, Dp, out_projW, skip,
                           ln_g, ln_b, projW, projb, p_xm2);
    k_addback<<<dim3(40, 32), 256>>>(p_x1, p_xm2, p_x2);

    // stage 3: conv3d
    k_conv3d<<<dim3(40, 32), 224>>>(p_x2, conv3dW, conv3db, p_x3);

    // stage 4: DWT + window attention
    k_dwt<<<10752, 256>>>(p_x3, p_xwh, p_xwl);
    tgemm_bf<<<dim3(2, 384), 256>>>(p_xwh, p_xwl, p_Wq1h,  p_Wq1l,  p_qkvw,       224, 224, 224, 224, 672);
    tgemm_bf<<<dim3(4, 384), 256>>>(p_xwh, p_xwl, p_Wkv1h, p_Wkv1l, p_qkvw + 224, 448, 224, 224, 448, 672);
    k_wattn<<<dim3(768, 8), 64>>>(p_qkvw, pos_emb, p_obh, p_obl);
    BfPtrs4 po;
    for (int s = 0; s < 4; s++) { po.Bh[s] = p_Woh + s*50176; po.Bl[s] = p_Wol + s*50176; }
    tgemm_bf_b4<<<dim3(2, 96, 4), 256>>>(p_obh, p_obl, po, p_oproj,
                                         224, 224, 224, 224, 224,
                                         (long long)12288*224, (long long)12288*224);

    // stage 5: IWT + biases + output
    k_iwt<<<8960, 256>>>(p_oproj, bo[0], bo[1], bo[2], bo[3], out);
}

// round 13
// speedup vs baseline: 1.6819x; 1.1341x over previous
#include <cuda_runtime.h>
#include <cuda_bf16.h>
#include <mma.h>
#include <math.h>
#include <stdint.h>

using namespace nvcuda;

// ---------------- static scratch ----------------
__device__ __align__(16) float g_attn [32*8*28*28];
__device__ __align__(16) float g_x1   [9175040];
__device__ __align__(16) float g_xn   [9175040];      // 286720 x 32
__device__ __align__(16) float g_xz   [36700160];     // 286720 x 128
__device__ __align__(16) float g_xc   [18350080];     // 286720 x 64
__device__ __align__(16) float g_dt   [18350080];
__device__ __align__(16) float g_Bm   [4587520];
__device__ __align__(16) float g_Cm   [4587520];
__device__ __align__(16) float g_y    [18350080];
__device__ __align__(16) float g_S    [2293760];
__device__ __align__(16) float g_sumdt[143360];
__device__ __align__(16) float g_H0   [2293760];
__device__ __align__(16) float g_xm2  [9175040];
__device__ __align__(16) float g_x2   [9175040];
__device__ __align__(16) float g_x3   [9175040];
__device__ __align__(16) float g_qkvw [33030144];     // 49152 x 672 (also stage-1 qkv 40960x672)
__device__ __align__(16) float g_oproj[11010048];

// bf16 hi/lo split scratch
__device__ __align__(16) __nv_bfloat16 g_xh  [9175040],  g_xlo  [9175040];
__device__ __align__(16) __nv_bfloat16 g_xnh [9175040],  g_xnl  [9175040];
__device__ __align__(16) __nv_bfloat16 g_xwh [11010048], g_xwl  [11010048];
__device__ __align__(16) __nv_bfloat16 g_obh [11010048], g_obl  [11010048];
__device__ __align__(16) __nv_bfloat16 g_Wc1h[150528], g_Wc1l[150528];   // [Wq|Wkv] 224x672
__device__ __align__(16) __nv_bfloat16 g_Wc2h[150528], g_Wc2l[150528];   // [Wq1|Wkv1]
__device__ __align__(16) __nv_bfloat16 g_iph [4096],   g_ipl [4096];
__device__ __align__(16) __nv_bfloat16 g_Woh [200704], g_Wol [200704];

__device__ __forceinline__ float siluf(float v){ return v / (1.f + __expf(-v)); }
__device__ __forceinline__ void bfsplit(float v, __nv_bfloat16& h, __nv_bfloat16& l) {
    h = __float2bfloat16(v);
    l = __float2bfloat16(v - __bfloat162float(h));
}
__device__ __forceinline__ uint32_t smem_u32(const void* p) {
    return (uint32_t)__cvta_generic_to_shared(p);
}
#define CPA16(saddr, gptr, nbytes) \
    asm volatile("cp.async.cg.shared.global [%0], [%1], 16, %2;" \
                 :: "r"(saddr), "l"(gptr), "r"(nbytes))
#define CPA_COMMIT() asm volatile("cp.async.commit_group;")
#define CPA_WAIT0()  asm volatile("cp.async.wait_group 0;")

struct BfPtrs4 { const __nv_bfloat16* Bh[4]; const __nv_bfloat16* Bl[4]; };

// ---------------- fp32 -> bf16 hi/lo splits ----------------
__global__ void k_split(const float* __restrict__ in, __nv_bfloat16* __restrict__ hi,
                        __nv_bfloat16* __restrict__ lo, int n) {
    int i = blockIdx.x*256 + threadIdx.x;
    if (i < n) {
        __nv_bfloat16 h, l;
        bfsplit(in[i], h, l);
        hi[i] = h; lo[i] = l;
    }
}

struct SplitSeg { const float* src; __nv_bfloat16* hi; __nv_bfloat16* lo;
                  int n; int srcW; int dstPitch; int dstOff; };
struct SplitArgs { SplitSeg s[10]; };

__global__ void k_split_multi(SplitArgs a) {
    SplitSeg seg = a.s[blockIdx.y];
    int i = blockIdx.x*256 + threadIdx.x;
    if (i < seg.n) {
        __nv_bfloat16 h, l;
        bfsplit(seg.src[i], h, l);
        int o = i;
        if (seg.srcW) {
            int k = i / seg.srcW, c = i - k*seg.srcW;
            o = k*seg.dstPitch + seg.dstOff + c;
        }
        seg.hi[o] = h; seg.lo[o] = l;
    }
}

// ---------------- bf16 split tensor-core GEMM: 128x128 tile, cp.async pipe ---
#define APITCH 24
#define BPITCH 136
__device__ __forceinline__ void tgemm_bf_core(
    const __nv_bfloat16* __restrict__ Ah, const __nv_bfloat16* __restrict__ Al,
    const __nv_bfloat16* __restrict__ Bh, const __nv_bfloat16* __restrict__ Bl,
    float* __restrict__ C, int N, int K, int lda, int ldb, int ldc,
    __nv_bfloat16* sAh, __nv_bfloat16* sAl, __nv_bfloat16* sBh, __nv_bfloat16* sBl)
{
    const int bm = blockIdx.y*128, bn = blockIdx.x*128;
    const int tid = threadIdx.x, warp = tid >> 5;
    const int wm = warp >> 2, wn = warp & 3;   // 2 x 4 warps; warp tile 64x32
    wmma::fragment<wmma::accumulator,16,16,16,float> acc[4][2];
    #pragma unroll
    for (int i = 0; i < 4; i++)
        #pragma unroll
        for (int j = 0; j < 2; j++) wmma::fill_fragment(acc[i][j], 0.f);

    const int ar = tid >> 1, ac = (tid & 1)*8;
    const int brr = tid >> 4, bcc = (tid & 15)*8;
    const int bcol = bn + bcc;
    const int bbytes = (bcol < N) ? 16 : 0;

    const uint32_t uAh = smem_u32(sAh), uAl = smem_u32(sAl);
    const uint32_t uBh = smem_u32(sBh), uBl = smem_u32(sBl);
    const int ASZ = 128*APITCH, BSZ = 16*BPITCH;       // elements
    const uint32_t aoffb = (uint32_t)(ar*APITCH + ac)*2;
    const uint32_t boffb = (uint32_t)(brr*BPITCH + bcc)*2;
    const __nv_bfloat16* gAh = Ah + (size_t)(bm+ar)*lda + ac;
    const __nv_bfloat16* gAl = Al + (size_t)(bm+ar)*lda + ac;
    const __nv_bfloat16* gBh = Bh + (size_t)brr*ldb + bcol;
    const __nv_bfloat16* gBl = Bl + (size_t)brr*ldb + bcol;

    // prologue: tile 0 -> buf 0
    CPA16(uAh + aoffb, gAh, 16);
    CPA16(uAl + aoffb, gAl, 16);
    CPA16(uBh + boffb, gBh, bbytes);
    CPA16(uBl + boffb, gBl, bbytes);
    CPA_COMMIT(); CPA_WAIT0();
    __syncthreads();
    int buf = 0;

    for (int k0 = 0; k0 < K; k0 += 16) {
        const bool more = (k0 + 16) < K;
        if (more) {
            int nb = buf ^ 1;
            CPA16(uAh + (uint32_t)nb*ASZ*2 + aoffb, gAh + k0 + 16, 16);
            CPA16(uAl + (uint32_t)nb*ASZ*2 + aoffb, gAl + k0 + 16, 16);
            CPA16(uBh + (uint32_t)nb*BSZ*2 + boffb, gBh + (size_t)(k0+16)*ldb, bbytes);
            CPA16(uBl + (uint32_t)nb*BSZ*2 + boffb, gBl + (size_t)(k0+16)*ldb, bbytes);
            CPA_COMMIT();
        }
        __nv_bfloat16* cAh = sAh + buf*ASZ; __nv_bfloat16* cAl = sAl + buf*ASZ;
        __nv_bfloat16* cBh = sBh + buf*BSZ; __nv_bfloat16* cBl = sBl + buf*BSZ;
        wmma::fragment<wmma::matrix_b,16,16,16,__nv_bfloat16,wmma::row_major> fbh[2], fbl[2];
        #pragma unroll
        for (int j = 0; j < 2; j++) {
            wmma::load_matrix_sync(fbh[j], &cBh[wn*32 + j*16], BPITCH);
            wmma::load_matrix_sync(fbl[j], &cBl[wn*32 + j*16], BPITCH);
        }
        #pragma unroll
        for (int i = 0; i < 4; i++) {
            wmma::fragment<wmma::matrix_a,16,16,16,__nv_bfloat16,wmma::row_major> fah, fal;
            wmma::load_matrix_sync(fah, &cAh[(wm*64 + i*16)*APITCH], APITCH);
            wmma::load_matrix_sync(fal, &cAl[(wm*64 + i*16)*APITCH], APITCH);
            #pragma unroll
            for (int j = 0; j < 2; j++) {
                wmma::mma_sync(acc[i][j], fah, fbh[j], acc[i][j]);
                wmma::mma_sync(acc[i][j], fah, fbl[j], acc[i][j]);
                wmma::mma_sync(acc[i][j], fal, fbh[j], acc[i][j]);
            }
        }
        if (more) {
            CPA_WAIT0();
            __syncthreads();
            buf ^= 1;
        }
    }
    #pragma unroll
    for (int i = 0; i < 4; i++)
        #pragma unroll
        for (int j = 0; j < 2; j++) {
            int n0 = bn + wn*32 + j*16;
            if (n0 < N)
                wmma::store_matrix_sync(C + (size_t)(bm + wm*64 + i*16)*ldc + n0,
                                        acc[i][j], ldc, wmma::mem_row_major);
        }
}

__global__ __launch_bounds__(256, 2) void tgemm_bf(
    const __nv_bfloat16* __restrict__ Ah, const __nv_bfloat16* __restrict__ Al,
    const __nv_bfloat16* __restrict__ Bh, const __nv_bfloat16* __restrict__ Bl,
    float* __restrict__ C, int N, int K, int lda, int ldb, int ldc)
{
    __shared__ __align__(16) __nv_bfloat16 sAh[2*128*APITCH], sAl[2*128*APITCH];
    __shared__ __align__(16) __nv_bfloat16 sBh[2*16*BPITCH],  sBl[2*16*BPITCH];
    tgemm_bf_core(Ah, Al, Bh, Bl, C, N, K, lda, ldb, ldc, sAh, sAl, sBh, sBl);
}

__global__ __launch_bounds__(256, 2) void tgemm_bf_b4(
    const __nv_bfloat16* __restrict__ Ah, const __nv_bfloat16* __restrict__ Al,
    BfPtrs4 p, float* __restrict__ C, int N, int K, int lda, int ldb, int ldc,
    long long strideA, long long strideC)
{
    __shared__ __align__(16) __nv_bfloat16 sAh[2*128*APITCH], sAl[2*128*APITCH];
    __shared__ __align__(16) __nv_bfloat16 sBh[2*16*BPITCH],  sBl[2*16*BPITCH];
    int z = blockIdx.z;
    tgemm_bf_core(Ah + (size_t)z*strideA, Al + (size_t)z*strideA,
                  p.Bh[z], p.Bl[z], C + (size_t)z*strideC,
                  N, K, lda, ldb, ldc, sAh, sAl, sBh, sBl);
}

// ---------------- fused x_proj GEMM (SIMT) + dt/B/C split ----------------
__global__ __launch_bounds__(256) void sgemm_xproj(
    const float* __restrict__ A, const float* __restrict__ B,
    const float* __restrict__ dtW, const float* __restrict__ dtb,
    float* __restrict__ dt, float* __restrict__ Bm, float* __restrict__ Cm)
{
    __shared__ float As[2][16][128];
    __shared__ float Bs[2][16][64];
    __shared__ float St[128][36];
    __shared__ float sdtW[128], sdtb[64];
    const int N = 34, K = 64, lda = 64, ldb = 34;
    const int bm = blockIdx.y * 128;
    const int tid = threadIdx.x;
    const int tr = tid >> 4, tc = tid & 15;
    const int br = tid >> 4, bc0 = (tid & 15) * 4;
    if (tid < 128) sdtW[tid] = dtW[tid];
    if (tid >= 128 && tid < 192) sdtb[tid-128] = dtb[tid-128];
    float acc[8][4];
    #pragma unroll
    for (int i = 0; i < 8; i++)
        #pragma unroll
        for (int j = 0; j < 4; j++) acc[i][j] = 0.f;

    float4 ra[2]; float rb[4];
    #pragma unroll
    for (int i = 0; i < 2; i++) {
        int idx = tid + i * 256;
        int r = idx >> 2, c4 = (idx & 3) * 4;
        ra[i] = *(const float4*)(A + (size_t)(bm + r) * lda + c4);
    }
    #pragma unroll
    for (int i = 0; i < 4; i++) {
        int n = bc0 + i;
        rb[i] = (n < N) ? B[(size_t)br * ldb + n] : 0.f;
    }
    int buf = 0;
    #pragma unroll
    for (int i = 0; i < 2; i++) {
        int idx = tid + i * 256;
        int r = idx >> 2, c4 = (idx & 3) * 4;
        As[0][c4+0][r]=ra[i].x; As[0][c4+1][r]=ra[i].y;
        As[0][c4+2][r]=ra[i].z; As[0][c4+3][r]=ra[i].w;
    }
    #pragma unroll
    for (int i = 0; i < 4; i++) Bs[0][br][bc0+i] = rb[i];
    __syncthreads();

    for (int k0 = 0; k0 < K; k0 += 16) {
        const bool more = (k0 + 16) < K;
        float4 ra2[2]; float rb2[4];
        if (more) {
            #pragma unroll
            for (int i = 0; i < 2; i++) {
                int idx = tid + i * 256;
                int r = idx >> 2, c4 = (idx & 3) * 4;
                ra2[i] = *(const float4*)(A + (size_t)(bm + r) * lda + k0 + 16 + c4);
            }
            #pragma unroll
            for (int i = 0; i < 4; i++) {
                int n = bc0 + i;
                rb2[i] = (n < N) ? B[(size_t)(k0 + 16 + br) * ldb + n] : 0.f;
            }
        }
        #pragma unroll
        for (int kk = 0; kk < 16; kk++) {
            float4 a0 = *(const float4*)&As[buf][kk][tr*8];
            float4 a1 = *(const float4*)&As[buf][kk][tr*8+4];
            float4 b0 = *(const float4*)&Bs[buf][kk][tc*4];
            float a[8] = {a0.x,a0.y,a0.z,a0.w,a1.x,a1.y,a1.z,a1.w};
            float b[4] = {b0.x,b0.y,b0.z,b0.w};
            #pragma unroll
            for (int i = 0; i < 8; i++)
                #pragma unroll
                for (int j = 0; j < 4; j++) acc[i][j] += a[i]*b[j];
        }
        if (more) {
            int nb = buf ^ 1;
            #pragma unroll
            for (int i = 0; i < 2; i++) {
                int idx = tid + i * 256;
                int r = idx >> 2, c4 = (idx & 3) * 4;
                As[nb][c4+0][r]=ra2[i].x; As[nb][c4+1][r]=ra2[i].y;
                As[nb][c4+2][r]=ra2[i].z; As[nb][c4+3][r]=ra2[i].w;
            }
            #pragma unroll
            for (int i = 0; i < 4; i++) Bs[nb][br][bc0+i] = rb2[i];
            __syncthreads();
            buf = nb;
        }
    }
    #pragma unroll
    for (int i = 0; i < 8; i++) {
        #pragma unroll
        for (int j = 0; j < 4; j++) {
            int n = tc*4 + j;
            if (n < N) St[tr*8 + i][n] = acc[i][j];
        }
    }
    __syncthreads();
    for (int idx = tid; idx < 128*64; idx += 256) {
        int r = idx >> 6, d = idx & 63;
        float v = St[r][0]*sdtW[d] + St[r][1]*sdtW[64+d] + sdtb[d];
        dt[(size_t)(bm + r)*64 + d] = (v > 20.f) ? v : log1pf(__expf(v));
    }
    for (int idx = tid; idx < 128*16; idx += 256) {
        int r = idx >> 4, n = idx & 15;
        Bm[(size_t)(bm + r)*16 + n] = St[r][2 + n];
        Cm[(size_t)(bm + r)*16 + n] = St[r][18 + n];
    }
}

// ---------------- stage 1: channel attention (reads combined qkv, ld=672) ----
__global__ void k_gram(const float* __restrict__ qc, float* __restrict__ attn) {
    int b = blockIdx.x, h = blockIdx.y;
    __shared__ float kt[32][28], qt[32][28];
    __shared__ float G[840];
    int tid = threadIdx.x;   // 256
    float acc[4] = {0.f,0.f,0.f,0.f};
    for (int nt = 0; nt < 40; nt++) {
        for (int idx = tid; idx < 896; idx += 256) {
            int n = idx / 28, i = idx % 28;
            size_t row = (size_t)b*1280 + nt*32 + n;
            kt[n][i] = qc[row*672 + 224 + h*28 + i];
            qt[n][i] = qc[row*672 + h*28 + i];
        }
        __syncthreads();
        #pragma unroll
        for (int s = 0; s < 4; s++) {
            int w = tid + 256*s;
            if (w < 784) {
                int i = w/28, j = w%28; float a = acc[s];
                #pragma unroll
                for (int n = 0; n < 32; n++) a += kt[n][i]*qt[n][j];
                acc[s] = a;
            } else if (w < 812) {
                int i = w - 784; float a = acc[s];
                #pragma unroll
                for (int n = 0; n < 32; n++) a += kt[n][i]*kt[n][i];
                acc[s] = a;
            } else if (w < 840) {
                int j = w - 812; float a = acc[s];
                #pragma unroll
                for (int n = 0; n < 32; n++) a += qt[n][j]*qt[n][j];
                acc[s] = a;
            }
        }
        __syncthreads();
    }
    #pragma unroll
    for (int s = 0; s < 4; s++) { int w = tid + 256*s; if (w < 840) G[w] = acc[s]; }
    __syncthreads();
    if (tid < 28) {
        int i = tid;
        float nk = fmaxf(sqrtf(G[784+i]), 1e-12f);
        float lg[28], m = -1e30f;
        #pragma unroll
        for (int j = 0; j < 28; j++) {
            float nq = fmaxf(sqrtf(G[812+j]), 1e-12f);
            lg[j] = G[i*28+j] / (nk*nq) * 0.18898223650461363f;
            m = fmaxf(m, lg[j]);
        }
        float sum = 0.f;
        #pragma unroll
        for (int j = 0; j < 28; j++) { lg[j] = __expf(lg[j]-m); sum += lg[j]; }
        float inv = 1.f/sum;
        #pragma unroll
        for (int j = 0; j < 28; j++)
            attn[(((size_t)b*8 + h)*28 + i)*28 + j] = lg[j]*inv;
    }
}

// x1 = attn-applied + residual; attention row in registers; v from combined qkv
__global__ void k_apply(const float* __restrict__ x, const float* __restrict__ qc,
                        const float* __restrict__ attn, float* __restrict__ x1) {
    int chunk = blockIdx.x, b = blockIdx.y;
    __shared__ float vr[8][224];
    int tid = threadIdx.x;   // 224
    int h = tid / 28, i = tid % 28;
    float att[28];
    {
        const float4* ap = (const float4*)(attn + (((size_t)b*8 + h)*28 + i)*28);
        #pragma unroll
        for (int q4 = 0; q4 < 7; q4++) {
            float4 v = ap[q4];
            att[q4*4+0]=v.x; att[q4*4+1]=v.y; att[q4*4+2]=v.z; att[q4*4+3]=v.w;
        }
    }
    for (int nn = 0; nn < 64; nn += 8) {
        size_t row0 = (size_t)b*1280 + chunk*64 + nn;
        __syncthreads();
        for (int idx = tid; idx < 1792; idx += 224) {
            int rr = idx / 224, cc = idx % 224;
            vr[rr][cc] = qc[(row0 + rr)*672 + 448 + cc];
        }
        __syncthreads();
        #pragma unroll
        for (int rr = 0; rr < 8; rr++) {
            float a = 0.f;
            #pragma unroll
            for (int j = 0; j < 28; j++) a += att[j] * vr[rr][h*28 + j];
            size_t o = (row0 + rr)*224 + tid;
            x1[o] = x[o] + a;
        }
    }
}

// ---------------- transpose + LN; coalesced fp32 + bf16 hi/lo output ---------
__global__ void k_ln1(const float* __restrict__ x1, const float* __restrict__ g,
                      const float* __restrict__ be, float* __restrict__ xn,
                      __nv_bfloat16* __restrict__ xnh, __nv_bfloat16* __restrict__ xnl) {
    int ww = blockIdx.x, b = blockIdx.y;
    __shared__ float s[32*225];
    __shared__ float sg[32], sb[32];
    int tid = threadIdx.x;   // 256
    if (tid < 32) { sg[tid] = g[tid]; sb[tid] = be[tid]; }
    for (int idx = tid; idx < 32*224; idx += 256) {
        int m = idx / 224, cc = idx % 224;
        s[m*225 + cc] = x1[((size_t)b*1280 + m*40 + ww)*224 + cc];
    }
    __syncthreads();
    float v[32];
    if (tid < 224) {
        float mean = 0.f;
        #pragma unroll
        for (int m = 0; m < 32; m++) { v[m] = s[m*225 + tid]; mean += v[m]; }
        mean *= (1.f/32.f);
        float var = 0.f;
        #pragma unroll
        for (int m = 0; m < 32; m++) { float d = v[m]-mean; var += d*d; }
        var *= (1.f/32.f);
        float inv = rsqrtf(var + 1e-5f);
        #pragma unroll
        for (int m = 0; m < 32; m++) v[m] = (v[m]-mean)*inv*sg[m] + sb[m];
    }
    __syncthreads();
    if (tid < 224) {
        #pragma unroll
        for (int m = 0; m < 32; m++) s[tid*32 + m] = v[m];
    }
    __syncthreads();
    size_t base = ((size_t)b*8960 + ww*224)*32;
    for (int idx = tid; idx < 7168; idx += 256) {
        float val = s[idx];
        xn[base + idx] = val;
        __nv_bfloat16 h, l; bfsplit(val, h, l);
        xnh[base + idx] = h; xnl[base + idx] = l;
    }
}

// ---------------- mamba pieces ----------------
__global__ void k_conv1d(const float* __restrict__ xz, const float* __restrict__ cw,
                         const float* __restrict__ cb, float* __restrict__ xc) {
    size_t id = (size_t)blockIdx.x*256 + threadIdx.x;   // 286720*16
    size_t row = id >> 4; int d4 = (int)(id & 15) * 4;
    size_t b = row / 8960; int l = (int)(row % 8960);
    float a0 = cb[d4], a1 = cb[d4+1], a2 = cb[d4+2], a3 = cb[d4+3];
    #pragma unroll
    for (int t = 0; t < 4; t++) {
        int ls = l - 3 + t;
        if (ls >= 0) {
            float4 v = *(const float4*)(xz + ((size_t)b*8960 + ls)*128 + d4);
            a0 += v.x * cw[d4*4 + t];
            a1 += v.y * cw[(d4+1)*4 + t];
            a2 += v.z * cw[(d4+2)*4 + t];
            a3 += v.w * cw[(d4+3)*4 + t];
        }
    }
    float4 o; o.x = siluf(a0); o.y = siluf(a1); o.z = siluf(a2); o.w = siluf(a3);
    *(float4*)(xc + row*64 + d4) = o;
}

__global__ __launch_bounds__(256) void k_scan1(
    const float* __restrict__ dt, const float* __restrict__ xc,
    const float* __restrict__ Bm, const float* __restrict__ Alog,
    float* __restrict__ S, float* __restrict__ sumdt) {
    int bx = blockIdx.x;                 // 8960
    int b = bx / 280, rem = bx % 280;
    int chunk = rem >> 2, dg = rem & 3;
    int tid = threadIdx.x, warp = tid >> 5, lane = tid & 31;
    int dloc = 2*warp + (lane >> 4), n = lane & 15;
    int d = dg*16 + dloc;
    __shared__ float sdt[16][16], sxc[16][16], sbm[16][16];
    float Av = -__expf(Alog[d*16 + n]);
    float h = 0.f, sdsum = 0.f;
    size_t rowbase = (size_t)b*8960 + chunk*128;
    int lr = tid >> 4, lc = tid & 15;
    for (int s = 0; s < 8; s++) {
        size_t r0 = rowbase + s*16;
        __syncthreads();
        sdt[lr][lc] = dt[(r0 + lr)*64 + dg*16 + lc];
        sxc[lr][lc] = xc[(r0 + lr)*64 + dg*16 + lc];
        sbm[lr][lc] = Bm[(r0 + lr)*16 + lc];
        __syncthreads();
        #pragma unroll
        for (int l = 0; l < 16; l++) {
            float dtv = sdt[l][dloc];
            float u   = sxc[l][dloc];
            float Bn  = sbm[l][n];
            h = __expf(Av*dtv)*h + dtv*u*Bn;
            sdsum += dtv;
        }
    }
    size_t idx = (size_t)(b*64 + d)*70 + chunk;
    S[idx*16 + n] = h;
    if (n == 0) sumdt[idx] = sdsum;
}

__global__ void k_scan2(const float* __restrict__ S, const float* __restrict__ sumdt,
                        const float* __restrict__ Alog, float* __restrict__ H0) {
    int t = blockIdx.x*256 + threadIdx.x;
    int b = t >> 10; int d = (t >> 4) & 63; int n = t & 15;
    float Av = -__expf(Alog[d*16 + n]);
    float carry = 0.f;
    size_t base = (size_t)(b*64 + d)*70;
    for (int ch = 0; ch < 70; ch++) {
        size_t idx = base + ch;
        H0[idx*16 + n] = carry;
        carry = carry*__expf(Av*sumdt[idx]) + S[idx*16 + n];
    }
}

__global__ __launch_bounds__(256) void k_scan3(
    const float* __restrict__ dt, const float* __restrict__ xc,
    const float* __restrict__ Bm, const float* __restrict__ Cm,
    const float* __restrict__ Alog, const float* __restrict__ H0,
    float* __restrict__ y) {
    int bx = blockIdx.x;
    int b = bx / 280, rem = bx % 280;
    int chunk = rem >> 2, dg = rem & 3;
    int tid = threadIdx.x, warp = tid >> 5, lane = tid & 31;
    int dloc = 2*warp + (lane >> 4), n = lane & 15;
    int d = dg*16 + dloc;
    __shared__ float sdt[16][16], sxc[16][16], sbm[16][16], scm[16][16], sy[16][16];
    float Av = -__expf(Alog[d*16 + n]);
    size_t idx = (size_t)(b*64 + d)*70 + chunk;
    float h = H0[idx*16 + n];
    size_t rowbase = (size_t)b*8960 + chunk*128;
    int lr = tid >> 4, lc = tid & 15;
    for (int s = 0; s < 8; s++) {
        size_t r0 = rowbase + s*16;
        __syncthreads();
        sdt[lr][lc] = dt[(r0 + lr)*64 + dg*16 + lc];
        sxc[lr][lc] = xc[(r0 + lr)*64 + dg*16 + lc];
        sbm[lr][lc] = Bm[(r0 + lr)*16 + lc];
        scm[lr][lc] = Cm[(r0 + lr)*16 + lc];
        __syncthreads();
        #pragma unroll
        for (int l = 0; l < 16; l++) {
            float dtv = sdt[l][dloc];
            float u   = sxc[l][dloc];
            float Bn  = sbm[l][n];
            h = __expf(Av*dtv)*h + dtv*u*Bn;
            float yv = h * scm[l][n];
            yv += __shfl_xor_sync(0xffffffffu, yv, 8);
            yv += __shfl_xor_sync(0xffffffffu, yv, 4);
            yv += __shfl_xor_sync(0xffffffffu, yv, 2);
            yv += __shfl_xor_sync(0xffffffffu, yv, 1);
            if (n == 0) sy[l][dloc] = yv;
        }
        __syncthreads();
        y[(r0 + lr)*64 + dg*16 + lc] = sy[lr][lc];
    }
}

__global__ void k_final(const float* __restrict__ y, const float* __restrict__ xc,
                        const float* __restrict__ xz, const float* __restrict__ xn,
                        const float* __restrict__ Dp, const float* __restrict__ opW,
                        const float* __restrict__ skipp, const float* __restrict__ g,
                        const float* __restrict__ be, const float* __restrict__ projW,
                        const float* __restrict__ projb, float* __restrict__ xm2) {
    __shared__ float sop[2048], spj[1024];
    int tid = threadIdx.x;   // 256
    for (int i = tid; i < 2048; i += 256) sop[i] = opW[i];
    for (int i = tid; i < 1024; i += 256) spj[i] = projW[i];
    __syncthreads();
    int warp = tid >> 5, lane = tid & 31;
    float skip = skipp[0];
    float dpl = Dp[lane], dph = Dp[32+lane];
    float gl = g[lane], bel = be[lane], pbl = projb[lane];
    #pragma unroll
    for (int t = 0; t < 8; t++) {
        size_t r = ((size_t)blockIdx.x*8 + warp)*8 + t;
        float y0 = y[r*64 + lane],      y1 = y[r*64 + 32 + lane];
        float c0 = xc[r*64 + lane],     c1 = xc[r*64 + 32 + lane];
        float z0 = xz[r*128 + 64 + lane], z1 = xz[r*128 + 96 + lane];
        float yy0 = (y0 + c0*dpl) * siluf(z0);
        float yy1 = (y1 + c1*dph) * siluf(z1);
        float acc = 0.f;
        #pragma unroll
        for (int d = 0; d < 32; d++) acc += __shfl_sync(0xffffffffu, yy0, d) * sop[d*32 + lane];
        #pragma unroll
        for (int d = 0; d < 32; d++) acc += __shfl_sync(0xffffffffu, yy1, d) * sop[(d+32)*32 + lane];
        float xm = acc + skip * xn[r*32 + lane];
        float mean = xm;
        #pragma unroll
        for (int o = 16; o; o >>= 1) mean += __shfl_xor_sync(0xffffffffu, mean, o);
        mean *= (1.f/32.f);
        float dv = xm - mean, var = dv*dv;
        #pragma unroll
        for (int o = 16; o; o >>= 1) var += __shfl_xor_sync(0xffffffffu, var, o);
        var *= (1.f/32.f);
        float v = dv * rsqrtf(var + 1e-5f) * gl + bel;
        float acc2 = pbl;
        #pragma unroll
        for (int mm = 0; mm < 32; mm++) acc2 += __shfl_sync(0xffffffffu, v, mm) * spj[mm*32 + lane];
        xm2[r*32 + lane] = acc2;
    }
}

__global__ void k_addback(const float* __restrict__ x1, const float* __restrict__ xm2,
                          float* __restrict__ x2) {
    int ww = blockIdx.x, b = blockIdx.y;
    __shared__ float s[224*33];
    int tid = threadIdx.x;   // 256
    for (int idx = tid; idx < 224*32; idx += 256) {
        int cc = idx >> 5, m = idx & 31;
        s[cc*33 + m] = xm2[((size_t)b*8960 + ww*224 + cc)*32 + m];
    }
    __syncthreads();
    for (int idx = tid; idx < 32*224; idx += 256) {
        int m = idx / 224, cc = idx % 224;
        size_t o = ((size_t)b*1280 + m*40 + ww)*224 + cc;
        x2[o] = x1[o] + s[cc*33 + m];
    }
}

// ---------------- conv3d 5x5x5, pad 2, smem-tiled per ky-plane ----------------
__global__ void k_conv3d(const float* __restrict__ x2, const float* __restrict__ cw,
                         const float* __restrict__ cb, float* __restrict__ x3) {
    int y = blockIdx.x, b = blockIdx.y;
    int xx = threadIdx.x;   // 224
    __shared__ float ws[125];
    __shared__ float sp[32][228];
    if (xx < 125) ws[xx] = cw[xx];
    if (xx < 32) { sp[xx][0]=0.f; sp[xx][1]=0.f; sp[xx][226]=0.f; sp[xx][227]=0.f; }
    float acc[32];
    #pragma unroll
    for (int d = 0; d < 32; d++) acc[d] = 0.f;
    for (int ky = 0; ky < 5; ky++) {
        int yy = y + ky - 2;
        if (yy < 0 || yy >= 40) continue;
        __syncthreads();
        for (int i = 0; i < 32; i++)
            sp[i][xx+2] = x2[(((size_t)b*32 + i)*40 + yy)*224 + xx];
        __syncthreads();
        #pragma unroll
        for (int kx = 0; kx < 5; kx++) {
            float v[36];
            v[0]=v[1]=v[34]=v[35]=0.f;
            #pragma unroll
            for (int i = 0; i < 32; i++) v[i+2] = sp[i][xx + kx];
            #pragma unroll
            for (int kz = 0; kz < 5; kz++) {
                float wv = ws[(kz*5 + ky)*5 + kx];
                #pragma unroll
                for (int d = 0; d < 32; d++) acc[d] += v[d+kz]*wv;
            }
        }
    }
    float bias = cb[0];
    #pragma unroll
    for (int d = 0; d < 32; d++)
        x3[(((size_t)b*32 + d)*40 + y)*224 + xx] = acc[d] + bias;
}

// ---------------- DWT: 4 subbands per thread, emits bf16 hi/lo ----------------
__global__ void k_dwt(const float* __restrict__ x3,
                      __nv_bfloat16* __restrict__ xwh, __nv_bfloat16* __restrict__ xwl) {
    size_t id = (size_t)blockIdx.x*256 + threadIdx.x;   // 2752512
    int c = (int)(id % 224); size_t rw = id / 224;
    int win = (int)(rw >> 6), tok = (int)(rw & 63);
    int bb = win / 6, w6 = win % 6;
    int wi = w6 / 3, wj = w6 % 3;
    int ti = tok >> 3, tj = tok & 7;
    int i2 = wi*8 + ti;
    int j2 = wj*8 + tj;
    int j = (j2 < 20) ? j2 : 38 - j2;   // reflect pad
    size_t base = (((size_t)bb*32 + 2*i2)*40 + 2*j)*224 + c;
    float a  = x3[base],        bv = x3[base + 224];
    float c2 = x3[base + 8960], d2 = x3[base + 9184];
    const size_t SS = (size_t)12288*224;
    float v0 = 0.5f*(a + bv + c2 + d2);
    float v1 = 0.5f*(a + bv - c2 - d2);
    float v2 = 0.5f*(a - bv + c2 - d2);
    float v3 = 0.5f*(a - bv - c2 + d2);
    __nv_bfloat16 h, l;
    bfsplit(v0, h, l); xwh[id]        = h; xwl[id]        = l;
    bfsplit(v1, h, l); xwh[id + SS]   = h; xwl[id + SS]   = l;
    bfsplit(v2, h, l); xwh[id + 2*SS] = h; xwl[id + 2*SS] = l;
    bfsplit(v3, h, l); xwh[id + 3*SS] = h; xwl[id + 3*SS] = l;
}

// ---------------- window attention: online softmax, staged bf16 hi/lo out ----
__global__ void k_wattn(const float* __restrict__ qkvw, const float* __restrict__ pe,
                        __nv_bfloat16* __restrict__ obh, __nv_bfloat16* __restrict__ obl) {
    int win = blockIdx.x, head = blockIdx.y;
    __shared__ __align__(16) float ks[64*28], vs[64*28];
    __shared__ __nv_bfloat16 oh[64*28], ol[64*28];
    int tid = threadIdx.x;   // 64
    size_t wbase = (size_t)win * 64;
    for (int idx = tid; idx < 1792; idx += 64) {
        int tok = idx / 28, dd = idx % 28;
        size_t rb = (wbase + tok)*672 + head*28 + dd;
        ks[idx] = qkvw[rb + 224];
        vs[idx] = qkvw[rb + 448];
    }
    float qr[28];
    {
        const float4* qp = (const float4*)(qkvw + (wbase + tid)*672 + head*28);
        #pragma unroll
        for (int q4 = 0; q4 < 7; q4++) {
            float4 v = qp[q4];
            qr[q4*4+0] = v.x * 0.18898223650461363f;
            qr[q4*4+1] = v.y * 0.18898223650461363f;
            qr[q4*4+2] = v.z * 0.18898223650461363f;
            qr[q4*4+3] = v.w * 0.18898223650461363f;
        }
    }
    __syncthreads();
    const float* per = pe + ((size_t)head*64 + tid)*64;
    float m = -1e30f, sum = 0.f;
    float acc[28];
    #pragma unroll
    for (int dd = 0; dd < 28; dd++) acc[dd] = 0.f;
    for (int j = 0; j < 64; j++) {
        const float4* k4 = (const float4*)&ks[j*28];
        float dot = 0.f;
        #pragma unroll
        for (int q4 = 0; q4 < 7; q4++) {
            float4 kk = k4[q4];
            dot += qr[q4*4+0]*kk.x + qr[q4*4+1]*kk.y
                 + qr[q4*4+2]*kk.z + qr[q4*4+3]*kk.w;
        }
        dot += per[j];
        if (dot > m) {
            float corr = __expf(m - dot);
            sum *= corr;
            #pragma unroll
            for (int dd = 0; dd < 28; dd++) acc[dd] *= corr;
            m = dot;
        }
        float e = __expf(dot - m);
        sum += e;
        const float4* v4 = (const float4*)&vs[j*28];
        #pragma unroll
        for (int q4 = 0; q4 < 7; q4++) {
            float4 vv = v4[q4];
            acc[q4*4+0] += e*vv.x; acc[q4*4+1] += e*vv.y;
            acc[q4*4+2] += e*vv.z; acc[q4*4+3] += e*vv.w;
        }
    }
    float inv = 1.f / sum;
    #pragma unroll
    for (int dd = 0; dd < 28; dd++) {
        __nv_bfloat16 h, l;
        bfsplit(acc[dd] * inv, h, l);
        oh[tid*28 + dd] = h; ol[tid*28 + dd] = l;
    }
    __syncthreads();
    for (int idx = tid; idx < 1792; idx += 64) {
        int tok = idx / 28, dd = idx % 28;
        size_t o = (wbase + tok)*224 + head*28 + dd;
        obh[o] = oh[idx]; obl[o] = ol[idx];
    }
}

// ---------------- IWT + biases + crop + final layout ----------------
__global__ void k_iwt(const float* __restrict__ oproj,
                      const float* __restrict__ b1, const float* __restrict__ b2,
                      const float* __restrict__ b3, const float* __restrict__ b4,
                      float* __restrict__ out) {
    size_t id = (size_t)blockIdx.x*256 + threadIdx.x;   // 2293760
    int c = (int)(id % 224); size_t r = id / 224;
    int j = (int)(r % 20); r /= 20;
    int i = (int)(r % 16); int bb = (int)(r / 16);
    int wi = i >> 3, ti = i & 7, wj = j >> 3, tj = j & 7;
    size_t row0 = ((size_t)(bb*6 + wi*3 + wj))*64 + ti*8 + tj;
    float A  = oproj[row0*224 + c]           + b1[c];
    float Hh = oproj[(row0 + 12288)*224 + c] + b2[c];
    float V  = oproj[(row0 + 24576)*224 + c] + b3[c];
    float D  = oproj[(row0 + 36864)*224 + c] + b4[c];
    size_t oo = (((size_t)bb*32 + 2*i)*40 + 2*j)*224 + c;
    out[oo]          = 0.5f*(A + Hh + V + D);
    out[oo + 224]    = 0.5f*(A + Hh - V - D);
    out[oo + 8960]   = 0.5f*(A - Hh + V - D);
    out[oo + 9184]   = 0.5f*(A - Hh - V + D);
}

// ---------------- launcher ----------------
extern "C" void kernel_launch(void* const* d_in, const int* in_sizes, int n_in,
                              void* d_out, int out_size) {
    const float* x       = (const float*)d_in[0];
    const float* Wq      = (const float*)d_in[1];
    const float* Wkv     = (const float*)d_in[2];
    const float* ln_g    = (const float*)d_in[3];
    const float* ln_b    = (const float*)d_in[4];
    const float* in_proj = (const float*)d_in[5];
    const float* conv1dW = (const float*)d_in[6];
    const float* conv1db = (const float*)d_in[7];
    const float* x_projW = (const float*)d_in[8];
    const float* dt_projW= (const float*)d_in[9];
    const float* dt_projb= (const float*)d_in[10];
    const float* A_log   = (const float*)d_in[11];
    const float* Dp      = (const float*)d_in[12];
    const float* out_projW=(const float*)d_in[13];
    const float* skip    = (const float*)d_in[14];
    const float* projW   = (const float*)d_in[15];
    const float* projb   = (const float*)d_in[16];
    const float* conv3dW = (const float*)d_in[17];
    const float* conv3db = (const float*)d_in[18];
    const float* Wq1     = (const float*)d_in[19];
    const float* Wkv1    = (const float*)d_in[20];
    const float* pos_emb = (const float*)d_in[21];
    const float* Wo[4]   = {(const float*)d_in[22],(const float*)d_in[24],
                            (const float*)d_in[26],(const float*)d_in[28]};
    const float* bo[4]   = {(const float*)d_in[23],(const float*)d_in[25],
                            (const float*)d_in[27],(const float*)d_in[29]};
    float* out = (float*)d_out;

    float *p_attn, *p_x1, *p_xn, *p_xz, *p_xc, *p_dt,
          *p_Bm, *p_Cm, *p_y, *p_S, *p_sd, *p_H0, *p_xm2, *p_x2, *p_x3,
          *p_qkvw, *p_oproj;
    cudaGetSymbolAddress((void**)&p_attn, g_attn);
    cudaGetSymbolAddress((void**)&p_x1,   g_x1);
    cudaGetSymbolAddress((void**)&p_xn,   g_xn);
    cudaGetSymbolAddress((void**)&p_xz,   g_xz);
    cudaGetSymbolAddress((void**)&p_xc,   g_xc);
    cudaGetSymbolAddress((void**)&p_dt,   g_dt);
    cudaGetSymbolAddress((void**)&p_Bm,   g_Bm);
    cudaGetSymbolAddress((void**)&p_Cm,   g_Cm);
    cudaGetSymbolAddress((void**)&p_y,    g_y);
    cudaGetSymbolAddress((void**)&p_S,    g_S);
    cudaGetSymbolAddress((void**)&p_sd,   g_sumdt);
    cudaGetSymbolAddress((void**)&p_H0,   g_H0);
    cudaGetSymbolAddress((void**)&p_xm2,  g_xm2);
    cudaGetSymbolAddress((void**)&p_x2,   g_x2);
    cudaGetSymbolAddress((void**)&p_x3,   g_x3);
    cudaGetSymbolAddress((void**)&p_qkvw, g_qkvw);
    cudaGetSymbolAddress((void**)&p_oproj,g_oproj);

    __nv_bfloat16 *p_xh,*p_xl,*p_xnh,*p_xnl,*p_xwh,*p_xwl,*p_obh,*p_obl,
        *p_Wc1h,*p_Wc1l,*p_Wc2h,*p_Wc2l,*p_iph,*p_ipl,*p_Woh,*p_Wol;
    cudaGetSymbolAddress((void**)&p_xh,   g_xh);
    cudaGetSymbolAddress((void**)&p_xl,   g_xlo);
    cudaGetSymbolAddress((void**)&p_xnh,  g_xnh);
    cudaGetSymbolAddress((void**)&p_xnl,  g_xnl);
    cudaGetSymbolAddress((void**)&p_xwh,  g_xwh);
    cudaGetSymbolAddress((void**)&p_xwl,  g_xwl);
    cudaGetSymbolAddress((void**)&p_obh,  g_obh);
    cudaGetSymbolAddress((void**)&p_obl,  g_obl);
    cudaGetSymbolAddress((void**)&p_Wc1h, g_Wc1h);
    cudaGetSymbolAddress((void**)&p_Wc1l, g_Wc1l);
    cudaGetSymbolAddress((void**)&p_Wc2h, g_Wc2h);
    cudaGetSymbolAddress((void**)&p_Wc2l, g_Wc2l);
    cudaGetSymbolAddress((void**)&p_iph,  g_iph);
    cudaGetSymbolAddress((void**)&p_ipl,  g_ipl);
    cudaGetSymbolAddress((void**)&p_Woh,  g_Woh);
    cudaGetSymbolAddress((void**)&p_Wol,  g_Wol);

    // ---- splits: input (big) + all weights (one batched launch) ----
    k_split<<<(9175040+255)/256, 256>>>(x, p_xh, p_xl, 9175040);
    SplitArgs sa;
    sa.s[0] = {Wq,      p_Wc1h, p_Wc1l, 50176,  224, 672, 0};
    sa.s[1] = {Wkv,     p_Wc1h, p_Wc1l, 100352, 448, 672, 224};
    sa.s[2] = {in_proj, p_iph,  p_ipl,  4096,   0, 0, 0};
    sa.s[3] = {Wq1,     p_Wc2h, p_Wc2l, 50176,  224, 672, 0};
    sa.s[4] = {Wkv1,    p_Wc2h, p_Wc2l, 100352, 448, 672, 224};
    sa.s[5] = {Wo[0], p_Woh,          p_Wol,          50176, 0, 0, 0};
    sa.s[6] = {Wo[1], p_Woh + 50176,  p_Wol + 50176,  50176, 0, 0, 0};
    sa.s[7] = {Wo[2], p_Woh + 100352, p_Wol + 100352, 50176, 0, 0, 0};
    sa.s[8] = {Wo[3], p_Woh + 150528, p_Wol + 150528, 50176, 0, 0, 0};
    sa.s[9] = {Wq, p_Wc1h, p_Wc1l, 0, 0, 0, 0};   // unused
    k_split_multi<<<dim3(392, 10), 256>>>(sa);

    // stage 1: combined qkv GEMM (N=672) into p_qkvw, gram+softmax, apply
    tgemm_bf<<<dim3(6, 320), 256>>>(p_xh, p_xl, p_Wc1h, p_Wc1l, p_qkvw,
                                    672, 224, 224, 672, 672);
    k_gram <<<dim3(32, 8), 256>>>(p_qkvw, p_attn);
    k_apply<<<dim3(20, 32), 224>>>(x, p_qkvw, p_attn, p_x1);

    // stage 2: mamba
    k_ln1<<<dim3(40, 32), 256>>>(p_x1, ln_g, ln_b, p_xn, p_xnh, p_xnl);
    tgemm_bf<<<dim3(1, 2240), 256>>>(p_xnh, p_xnl, p_iph, p_ipl, p_xz, 128, 32, 32, 128, 128);
    k_conv1d<<<17920, 256>>>(p_xz, conv1dW, conv1db, p_xc);
    sgemm_xproj<<<dim3(1, 2240), 256>>>(p_xc, x_projW, dt_projW, dt_projb,
                                        p_dt, p_Bm, p_Cm);
    k_scan1<<<8960, 256>>>(p_dt, p_xc, p_Bm, A_log, p_S, p_sd);
    k_scan2<<<128, 256>>>(p_S, p_sd, A_log, p_H0);
    k_scan3<<<8960, 256>>>(p_dt, p_xc, p_Bm, p_Cm, A_log, p_H0, p_y);
    k_final<<<4480, 256>>>(p_y, p_xc, p_xz, p_xn, Dp, out_projW, skip,
                           ln_g, ln_b, projW, projb, p_xm2);
    k_addback<<<dim3(40, 32), 256>>>(p_x1, p_xm2, p_x2);

    // stage 3: conv3d
    k_conv3d<<<dim3(40, 32), 224>>>(p_x2, conv3dW, conv3db, p_x3);

    // stage 4: DWT + combined window-qkv GEMM + window attention
    k_dwt<<<10752, 256>>>(p_x3, p_xwh, p_xwl);
    tgemm_bf<<<dim3(6, 384), 256>>>(p_xwh, p_xwl, p_Wc2h, p_Wc2l, p_qkvw,
                                    672, 224, 224, 672, 672);
    k_wattn<<<dim3(768, 8), 64>>>(p_qkvw, pos_emb, p_obh, p_obl);
    BfPtrs4 po;
    for (int s = 0; s < 4; s++) { po.Bh[s] = p_Woh + s*50176; po.Bl[s] = p_Wol + s*50176; }
    tgemm_bf_b4<<<dim3(2, 96, 4), 256>>>(p_obh, p_obl, po, p_oproj,
                                         224, 224, 224, 224, 224,
                                         (long long)12288*224, (long long)12288*224);

    // stage 5: IWT + biases + output
    k_iwt<<<8960, 256>>>(p_oproj, bo[0], bo[1], bo[2], bo[3], out);
}

// round 14
// speedup vs baseline: 1.7436x; 1.0367x over previous
#include <cuda_runtime.h>
#include <cuda_bf16.h>
#include <mma.h>
#include <math.h>
#include <stdint.h>

using namespace nvcuda;

// ---------------- static scratch ----------------
__device__ __align__(16) float g_attn [32*8*28*28];
__device__ __align__(16) float g_gpart[32*8*8*840];   // partial Gram sums
__device__ __align__(16) float g_x1   [9175040];
__device__ __align__(16) float g_xn   [9175040];      // 286720 x 32
__device__ __align__(16) float g_xz   [36700160];     // 286720 x 128
__device__ __align__(16) float g_xc   [18350080];     // 286720 x 64
__device__ __align__(16) float g_dt   [18350080];
__device__ __align__(16) float g_Bm   [4587520];
__device__ __align__(16) float g_Cm   [4587520];
__device__ __align__(16) float g_y    [18350080];
__device__ __align__(16) float g_S    [2293760];
__device__ __align__(16) float g_sumdt[143360];
__device__ __align__(16) float g_H0   [2293760];
__device__ __align__(16) float g_xm2  [9175040];
__device__ __align__(16) float g_x2   [9175040];
__device__ __align__(16) float g_x3   [9175040];
__device__ __align__(16) float g_qkvw [33030144];     // 49152 x 672 (also stage-1 qkv 40960x672)
__device__ __align__(16) float g_oproj[11010048];

// bf16 hi/lo split scratch
__device__ __align__(16) __nv_bfloat16 g_xh  [9175040],  g_xlo  [9175040];
__device__ __align__(16) __nv_bfloat16 g_xnh [9175040],  g_xnl  [9175040];
__device__ __align__(16) __nv_bfloat16 g_xwh [11010048], g_xwl  [11010048];
__device__ __align__(16) __nv_bfloat16 g_obh [11010048], g_obl  [11010048];
__device__ __align__(16) __nv_bfloat16 g_Wc1h[150528], g_Wc1l[150528];   // [Wq|Wkv] 224x672
__device__ __align__(16) __nv_bfloat16 g_Wc2h[150528], g_Wc2l[150528];   // [Wq1|Wkv1]
__device__ __align__(16) __nv_bfloat16 g_iph [4096],   g_ipl [4096];
__device__ __align__(16) __nv_bfloat16 g_Woh [200704], g_Wol [200704];

__device__ __forceinline__ float siluf(float v){ return v / (1.f + __expf(-v)); }
__device__ __forceinline__ void bfsplit(float v, __nv_bfloat16& h, __nv_bfloat16& l) {
    h = __float2bfloat16(v);
    l = __float2bfloat16(v - __bfloat162float(h));
}
__device__ __forceinline__ uint32_t smem_u32(const void* p) {
    return (uint32_t)__cvta_generic_to_shared(p);
}
#define CPA16(saddr, gptr, nbytes) \
    asm volatile("cp.async.cg.shared.global [%0], [%1], 16, %2;" \
                 :: "r"(saddr), "l"(gptr), "r"(nbytes))
#define CPA_COMMIT() asm volatile("cp.async.commit_group;")
#define CPA_WAIT0()  asm volatile("cp.async.wait_group 0;")

struct BfPtrs4 { const __nv_bfloat16* Bh[4]; const __nv_bfloat16* Bl[4]; };

// ---------------- fp32 -> bf16 hi/lo splits ----------------
__global__ void k_split(const float* __restrict__ in, __nv_bfloat16* __restrict__ hi,
                        __nv_bfloat16* __restrict__ lo, int n) {
    int i = blockIdx.x*256 + threadIdx.x;
    if (i < n) {
        __nv_bfloat16 h, l;
        bfsplit(in[i], h, l);
        hi[i] = h; lo[i] = l;
    }
}

struct SplitSeg { const float* src; __nv_bfloat16* hi; __nv_bfloat16* lo;
                  int n; int srcW; int dstPitch; int dstOff; };
struct SplitArgs { SplitSeg s[10]; };

__global__ void k_split_multi(SplitArgs a) {
    SplitSeg seg = a.s[blockIdx.y];
    int i = blockIdx.x*256 + threadIdx.x;
    if (i < seg.n) {
        __nv_bfloat16 h, l;
        bfsplit(seg.src[i], h, l);
        int o = i;
        if (seg.srcW) {
            int k = i / seg.srcW, c = i - k*seg.srcW;
            o = k*seg.dstPitch + seg.dstOff + c;
        }
        seg.hi[o] = h; seg.lo[o] = l;
    }
}

// ---------------- bf16 split tensor-core GEMM: 128x128 tile, cp.async pipe ---
#define APITCH 24
#define BPITCH 136
__device__ __forceinline__ void tgemm_bf_core(
    const __nv_bfloat16* __restrict__ Ah, const __nv_bfloat16* __restrict__ Al,
    const __nv_bfloat16* __restrict__ Bh, const __nv_bfloat16* __restrict__ Bl,
    float* __restrict__ C, int N, int K, int lda, int ldb, int ldc,
    __nv_bfloat16* sAh, __nv_bfloat16* sAl, __nv_bfloat16* sBh, __nv_bfloat16* sBl)
{
    const int bm = blockIdx.y*128, bn = blockIdx.x*128;
    const int tid = threadIdx.x, warp = tid >> 5;
    const int wm = warp >> 2, wn = warp & 3;   // 2 x 4 warps; warp tile 64x32
    wmma::fragment<wmma::accumulator,16,16,16,float> acc[4][2];
    #pragma unroll
    for (int i = 0; i < 4; i++)
        #pragma unroll
        for (int j = 0; j < 2; j++) wmma::fill_fragment(acc[i][j], 0.f);

    const int ar = tid >> 1, ac = (tid & 1)*8;
    const int brr = tid >> 4, bcc = (tid & 15)*8;
    const int bcol = bn + bcc;
    const int bbytes = (bcol < N) ? 16 : 0;

    const uint32_t uAh = smem_u32(sAh), uAl = smem_u32(sAl);
    const uint32_t uBh = smem_u32(sBh), uBl = smem_u32(sBl);
    const int ASZ = 128*APITCH, BSZ = 16*BPITCH;       // elements
    const uint32_t aoffb = (uint32_t)(ar*APITCH + ac)*2;
    const uint32_t boffb = (uint32_t)(brr*BPITCH + bcc)*2;
    const __nv_bfloat16* gAh = Ah + (size_t)(bm+ar)*lda + ac;
    const __nv_bfloat16* gAl = Al + (size_t)(bm+ar)*lda + ac;
    const __nv_bfloat16* gBh = Bh + (size_t)brr*ldb + bcol;
    const __nv_bfloat16* gBl = Bl + (size_t)brr*ldb + bcol;

    CPA16(uAh + aoffb, gAh, 16);
    CPA16(uAl + aoffb, gAl, 16);
    CPA16(uBh + boffb, gBh, bbytes);
    CPA16(uBl + boffb, gBl, bbytes);
    CPA_COMMIT(); CPA_WAIT0();
    __syncthreads();
    int buf = 0;

    for (int k0 = 0; k0 < K; k0 += 16) {
        const bool more = (k0 + 16) < K;
        if (more) {
            int nb = buf ^ 1;
            CPA16(uAh + (uint32_t)nb*ASZ*2 + aoffb, gAh + k0 + 16, 16);
            CPA16(uAl + (uint32_t)nb*ASZ*2 + aoffb, gAl + k0 + 16, 16);
            CPA16(uBh + (uint32_t)nb*BSZ*2 + boffb, gBh + (size_t)(k0+16)*ldb, bbytes);
            CPA16(uBl + (uint32_t)nb*BSZ*2 + boffb, gBl + (size_t)(k0+16)*ldb, bbytes);
            CPA_COMMIT();
        }
        __nv_bfloat16* cAh = sAh + buf*ASZ; __nv_bfloat16* cAl = sAl + buf*ASZ;
        __nv_bfloat16* cBh = sBh + buf*BSZ; __nv_bfloat16* cBl = sBl + buf*BSZ;
        wmma::fragment<wmma::matrix_b,16,16,16,__nv_bfloat16,wmma::row_major> fbh[2], fbl[2];
        #pragma unroll
        for (int j = 0; j < 2; j++) {
            wmma::load_matrix_sync(fbh[j], &cBh[wn*32 + j*16], BPITCH);
            wmma::load_matrix_sync(fbl[j], &cBl[wn*32 + j*16], BPITCH);
        }
        #pragma unroll
        for (int i = 0; i < 4; i++) {
            wmma::fragment<wmma::matrix_a,16,16,16,__nv_bfloat16,wmma::row_major> fah, fal;
            wmma::load_matrix_sync(fah, &cAh[(wm*64 + i*16)*APITCH], APITCH);
            wmma::load_matrix_sync(fal, &cAl[(wm*64 + i*16)*APITCH], APITCH);
            #pragma unroll
            for (int j = 0; j < 2; j++) {
                wmma::mma_sync(acc[i][j], fah, fbh[j], acc[i][j]);
                wmma::mma_sync(acc[i][j], fah, fbl[j], acc[i][j]);
                wmma::mma_sync(acc[i][j], fal, fbh[j], acc[i][j]);
            }
        }
        if (more) {
            CPA_WAIT0();
            __syncthreads();
            buf ^= 1;
        }
    }
    #pragma unroll
    for (int i = 0; i < 4; i++)
        #pragma unroll
        for (int j = 0; j < 2; j++) {
            int n0 = bn + wn*32 + j*16;
            if (n0 < N)
                wmma::store_matrix_sync(C + (size_t)(bm + wm*64 + i*16)*ldc + n0,
                                        acc[i][j], ldc, wmma::mem_row_major);
        }
}

__global__ __launch_bounds__(256, 2) void tgemm_bf(
    const __nv_bfloat16* __restrict__ Ah, const __nv_bfloat16* __restrict__ Al,
    const __nv_bfloat16* __restrict__ Bh, const __nv_bfloat16* __restrict__ Bl,
    float* __restrict__ C, int N, int K, int lda, int ldb, int ldc)
{
    __shared__ __align__(16) __nv_bfloat16 sAh[2*128*APITCH], sAl[2*128*APITCH];
    __shared__ __align__(16) __nv_bfloat16 sBh[2*16*BPITCH],  sBl[2*16*BPITCH];
    tgemm_bf_core(Ah, Al, Bh, Bl, C, N, K, lda, ldb, ldc, sAh, sAl, sBh, sBl);
}

__global__ __launch_bounds__(256, 2) void tgemm_bf_b4(
    const __nv_bfloat16* __restrict__ Ah, const __nv_bfloat16* __restrict__ Al,
    BfPtrs4 p, float* __restrict__ C, int N, int K, int lda, int ldb, int ldc,
    long long strideA, long long strideC)
{
    __shared__ __align__(16) __nv_bfloat16 sAh[2*128*APITCH], sAl[2*128*APITCH];
    __shared__ __align__(16) __nv_bfloat16 sBh[2*16*BPITCH],  sBl[2*16*BPITCH];
    int z = blockIdx.z;
    tgemm_bf_core(Ah + (size_t)z*strideA, Al + (size_t)z*strideA,
                  p.Bh[z], p.Bl[z], C + (size_t)z*strideC,
                  N, K, lda, ldb, ldc, sAh, sAl, sBh, sBl);
}

// ---------------- fused x_proj GEMM (SIMT) + dt/B/C split ----------------
__global__ __launch_bounds__(256) void sgemm_xproj(
    const float* __restrict__ A, const float* __restrict__ B,
    const float* __restrict__ dtW, const float* __restrict__ dtb,
    float* __restrict__ dt, float* __restrict__ Bm, float* __restrict__ Cm)
{
    __shared__ float As[2][16][128];
    __shared__ float Bs[2][16][64];
    __shared__ float St[128][36];
    __shared__ float sdtW[128], sdtb[64];
    const int N = 34, K = 64, lda = 64, ldb = 34;
    const int bm = blockIdx.y * 128;
    const int tid = threadIdx.x;
    const int tr = tid >> 4, tc = tid & 15;
    const int br = tid >> 4, bc0 = (tid & 15) * 4;
    if (tid < 128) sdtW[tid] = dtW[tid];
    if (tid >= 128 && tid < 192) sdtb[tid-128] = dtb[tid-128];
    float acc[8][4];
    #pragma unroll
    for (int i = 0; i < 8; i++)
        #pragma unroll
        for (int j = 0; j < 4; j++) acc[i][j] = 0.f;

    float4 ra[2]; float rb[4];
    #pragma unroll
    for (int i = 0; i < 2; i++) {
        int idx = tid + i * 256;
        int r = idx >> 2, c4 = (idx & 3) * 4;
        ra[i] = *(const float4*)(A + (size_t)(bm + r) * lda + c4);
    }
    #pragma unroll
    for (int i = 0; i < 4; i++) {
        int n = bc0 + i;
        rb[i] = (n < N) ? B[(size_t)br * ldb + n] : 0.f;
    }
    int buf = 0;
    #pragma unroll
    for (int i = 0; i < 2; i++) {
        int idx = tid + i * 256;
        int r = idx >> 2, c4 = (idx & 3) * 4;
        As[0][c4+0][r]=ra[i].x; As[0][c4+1][r]=ra[i].y;
        As[0][c4+2][r]=ra[i].z; As[0][c4+3][r]=ra[i].w;
    }
    #pragma unroll
    for (int i = 0; i < 4; i++) Bs[0][br][bc0+i] = rb[i];
    __syncthreads();

    for (int k0 = 0; k0 < K; k0 += 16) {
        const bool more = (k0 + 16) < K;
        float4 ra2[2]; float rb2[4];
        if (more) {
            #pragma unroll
            for (int i = 0; i < 2; i++) {
                int idx = tid + i * 256;
                int r = idx >> 2, c4 = (idx & 3) * 4;
                ra2[i] = *(const float4*)(A + (size_t)(bm + r) * lda + k0 + 16 + c4);
            }
            #pragma unroll
            for (int i = 0; i < 4; i++) {
                int n = bc0 + i;
                rb2[i] = (n < N) ? B[(size_t)(k0 + 16 + br) * ldb + n] : 0.f;
            }
        }
        #pragma unroll
        for (int kk = 0; kk < 16; kk++) {
            float4 a0 = *(const float4*)&As[buf][kk][tr*8];
            float4 a1 = *(const float4*)&As[buf][kk][tr*8+4];
            float4 b0 = *(const float4*)&Bs[buf][kk][tc*4];
            float a[8] = {a0.x,a0.y,a0.z,a0.w,a1.x,a1.y,a1.z,a1.w};
            float b[4] = {b0.x,b0.y,b0.z,b0.w};
            #pragma unroll
            for (int i = 0; i < 8; i++)
                #pragma unroll
                for (int j = 0; j < 4; j++) acc[i][j] += a[i]*b[j];
        }
        if (more) {
            int nb = buf ^ 1;
            #pragma unroll
            for (int i = 0; i < 2; i++) {
                int idx = tid + i * 256;
                int r = idx >> 2, c4 = (idx & 3) * 4;
                As[nb][c4+0][r]=ra2[i].x; As[nb][c4+1][r]=ra2[i].y;
                As[nb][c4+2][r]=ra2[i].z; As[nb][c4+3][r]=ra2[i].w;
            }
            #pragma unroll
            for (int i = 0; i < 4; i++) Bs[nb][br][bc0+i] = rb2[i];
            __syncthreads();
            buf = nb;
        }
    }
    #pragma unroll
    for (int i = 0; i < 8; i++) {
        #pragma unroll
        for (int j = 0; j < 4; j++) {
            int n = tc*4 + j;
            if (n < N) St[tr*8 + i][n] = acc[i][j];
        }
    }
    __syncthreads();
    for (int idx = tid; idx < 128*64; idx += 256) {
        int r = idx >> 6, d = idx & 63;
        float v = St[r][0]*sdtW[d] + St[r][1]*sdtW[64+d] + sdtb[d];
        dt[(size_t)(bm + r)*64 + d] = (v > 20.f) ? v : log1pf(__expf(v));
    }
    for (int idx = tid; idx < 128*16; idx += 256) {
        int r = idx >> 4, n = idx & 15;
        Bm[(size_t)(bm + r)*16 + n] = St[r][2 + n];
        Cm[(size_t)(bm + r)*16 + n] = St[r][18 + n];
    }
}

// ---------------- stage 1: channel attention, token-split Gram ----------------
// partial: block = (b, h, zslice of 5 token-tiles); writes 840 partial sums
__global__ void k_gram_part(const float* __restrict__ qc, float* __restrict__ gpart) {
    int b = blockIdx.x, h = blockIdx.y, z = blockIdx.z;
    __shared__ float kt[32][28], qt[32][28];
    int tid = threadIdx.x;   // 256
    float acc[4] = {0.f,0.f,0.f,0.f};
    for (int nt = z*5; nt < z*5 + 5; nt++) {
        for (int idx = tid; idx < 896; idx += 256) {
            int n = idx / 28, i = idx % 28;
            size_t row = (size_t)b*1280 + nt*32 + n;
            kt[n][i] = qc[row*672 + 224 + h*28 + i];
            qt[n][i] = qc[row*672 + h*28 + i];
        }
        __syncthreads();
        #pragma unroll
        for (int s = 0; s < 4; s++) {
            int w = tid + 256*s;
            if (w < 784) {
                int i = w/28, j = w%28; float a = acc[s];
                #pragma unroll
                for (int n = 0; n < 32; n++) a += kt[n][i]*qt[n][j];
                acc[s] = a;
            } else if (w < 812) {
                int i = w - 784; float a = acc[s];
                #pragma unroll
                for (int n = 0; n < 32; n++) a += kt[n][i]*kt[n][i];
                acc[s] = a;
            } else if (w < 840) {
                int j = w - 812; float a = acc[s];
                #pragma unroll
                for (int n = 0; n < 32; n++) a += qt[n][j]*qt[n][j];
                acc[s] = a;
            }
        }
        __syncthreads();
    }
    float* gp = gpart + (((size_t)(b*8 + h))*8 + z)*840;
    #pragma unroll
    for (int s = 0; s < 4; s++) { int w = tid + 256*s; if (w < 840) gp[w] = acc[s]; }
}

// finalize: sum 8 partials, norms + softmax
__global__ void k_gram_fin(const float* __restrict__ gpart, float* __restrict__ attn) {
    int b = blockIdx.x, h = blockIdx.y;
    __shared__ float G[840];
    int tid = threadIdx.x;   // 256
    const float* gp = gpart + ((size_t)(b*8 + h))*8*840;
    #pragma unroll
    for (int s = 0; s < 4; s++) {
        int w = tid + 256*s;
        if (w < 840) {
            float a = 0.f;
            #pragma unroll
            for (int z = 0; z < 8; z++) a += gp[z*840 + w];
            G[w] = a;
        }
    }
    __syncthreads();
    if (tid < 28) {
        int i = tid;
        float nk = fmaxf(sqrtf(G[784+i]), 1e-12f);
        float lg[28], m = -1e30f;
        #pragma unroll
        for (int j = 0; j < 28; j++) {
            float nq = fmaxf(sqrtf(G[812+j]), 1e-12f);
            lg[j] = G[i*28+j] / (nk*nq) * 0.18898223650461363f;
            m = fmaxf(m, lg[j]);
        }
        float sum = 0.f;
        #pragma unroll
        for (int j = 0; j < 28; j++) { lg[j] = __expf(lg[j]-m); sum += lg[j]; }
        float inv = 1.f/sum;
        #pragma unroll
        for (int j = 0; j < 28; j++)
            attn[(((size_t)b*8 + h)*28 + i)*28 + j] = lg[j]*inv;
    }
}

// x1 = attn-applied + residual; attention row in registers; v from combined qkv
__global__ void k_apply(const float* __restrict__ x, const float* __restrict__ qc,
                        const float* __restrict__ attn, float* __restrict__ x1) {
    int chunk = blockIdx.x, b = blockIdx.y;
    __shared__ float vr[8][224];
    int tid = threadIdx.x;   // 224
    int h = tid / 28, i = tid % 28;
    float att[28];
    {
        const float4* ap = (const float4*)(attn + (((size_t)b*8 + h)*28 + i)*28);
        #pragma unroll
        for (int q4 = 0; q4 < 7; q4++) {
            float4 v = ap[q4];
            att[q4*4+0]=v.x; att[q4*4+1]=v.y; att[q4*4+2]=v.z; att[q4*4+3]=v.w;
        }
    }
    for (int nn = 0; nn < 64; nn += 8) {
        size_t row0 = (size_t)b*1280 + chunk*64 + nn;
        __syncthreads();
        for (int idx = tid; idx < 1792; idx += 224) {
            int rr = idx / 224, cc = idx % 224;
            vr[rr][cc] = qc[(row0 + rr)*672 + 448 + cc];
        }
        __syncthreads();
        #pragma unroll
        for (int rr = 0; rr < 8; rr++) {
            float a = 0.f;
            #pragma unroll
            for (int j = 0; j < 28; j++) a += att[j] * vr[rr][h*28 + j];
            size_t o = (row0 + rr)*224 + tid;
            x1[o] = x[o] + a;
        }
    }
}

// ---------------- transpose + LN; coalesced fp32 + bf16 hi/lo output ---------
__global__ void k_ln1(const float* __restrict__ x1, const float* __restrict__ g,
                      const float* __restrict__ be, float* __restrict__ xn,
                      __nv_bfloat16* __restrict__ xnh, __nv_bfloat16* __restrict__ xnl) {
    int ww = blockIdx.x, b = blockIdx.y;
    __shared__ float s[32*225];
    __shared__ float sg[32], sb[32];
    int tid = threadIdx.x;   // 256
    if (tid < 32) { sg[tid] = g[tid]; sb[tid] = be[tid]; }
    for (int idx = tid; idx < 32*224; idx += 256) {
        int m = idx / 224, cc = idx % 224;
        s[m*225 + cc] = x1[((size_t)b*1280 + m*40 + ww)*224 + cc];
    }
    __syncthreads();
    float v[32];
    if (tid < 224) {
        float mean = 0.f;
        #pragma unroll
        for (int m = 0; m < 32; m++) { v[m] = s[m*225 + tid]; mean += v[m]; }
        mean *= (1.f/32.f);
        float var = 0.f;
        #pragma unroll
        for (int m = 0; m < 32; m++) { float d = v[m]-mean; var += d*d; }
        var *= (1.f/32.f);
        float inv = rsqrtf(var + 1e-5f);
        #pragma unroll
        for (int m = 0; m < 32; m++) v[m] = (v[m]-mean)*inv*sg[m] + sb[m];
    }
    __syncthreads();
    if (tid < 224) {
        #pragma unroll
        for (int m = 0; m < 32; m++) s[tid*32 + m] = v[m];
    }
    __syncthreads();
    size_t base = ((size_t)b*8960 + ww*224)*32;
    for (int idx = tid; idx < 7168; idx += 256) {
        float val = s[idx];
        xn[base + idx] = val;
        __nv_bfloat16 h, l; bfsplit(val, h, l);
        xnh[base + idx] = h; xnl[base + idx] = l;
    }
}

// ---------------- mamba pieces ----------------
__global__ void k_conv1d(const float* __restrict__ xz, const float* __restrict__ cw,
                         const float* __restrict__ cb, float* __restrict__ xc) {
    size_t id = (size_t)blockIdx.x*256 + threadIdx.x;   // 286720*16
    size_t row = id >> 4; int d4 = (int)(id & 15) * 4;
    size_t b = row / 8960; int l = (int)(row % 8960);
    float a0 = cb[d4], a1 = cb[d4+1], a2 = cb[d4+2], a3 = cb[d4+3];
    #pragma unroll
    for (int t = 0; t < 4; t++) {
        int ls = l - 3 + t;
        if (ls >= 0) {
            float4 v = *(const float4*)(xz + ((size_t)b*8960 + ls)*128 + d4);
            a0 += v.x * cw[d4*4 + t];
            a1 += v.y * cw[(d4+1)*4 + t];
            a2 += v.z * cw[(d4+2)*4 + t];
            a3 += v.w * cw[(d4+3)*4 + t];
        }
    }
    float4 o; o.x = siluf(a0); o.y = siluf(a1); o.z = siluf(a2); o.w = siluf(a3);
    *(float4*)(xc + row*64 + d4) = o;
}

__global__ __launch_bounds__(256) void k_scan1(
    const float* __restrict__ dt, const float* __restrict__ xc,
    const float* __restrict__ Bm, const float* __restrict__ Alog,
    float* __restrict__ S, float* __restrict__ sumdt) {
    int bx = blockIdx.x;                 // 8960
    int b = bx / 280, rem = bx % 280;
    int chunk = rem >> 2, dg = rem & 3;
    int tid = threadIdx.x, warp = tid >> 5, lane = tid & 31;
    int dloc = 2*warp + (lane >> 4), n = lane & 15;
    int d = dg*16 + dloc;
    __shared__ float sdt[16][16], sxc[16][16], sbm[16][16];
    float Av = -__expf(Alog[d*16 + n]);
    float h = 0.f, sdsum = 0.f;
    size_t rowbase = (size_t)b*8960 + chunk*128;
    int lr = tid >> 4, lc = tid & 15;
    for (int s = 0; s < 8; s++) {
        size_t r0 = rowbase + s*16;
        __syncthreads();
        sdt[lr][lc] = dt[(r0 + lr)*64 + dg*16 + lc];
        sxc[lr][lc] = xc[(r0 + lr)*64 + dg*16 + lc];
        sbm[lr][lc] = Bm[(r0 + lr)*16 + lc];
        __syncthreads();
        #pragma unroll
        for (int l = 0; l < 16; l++) {
            float dtv = sdt[l][dloc];
            float u   = sxc[l][dloc];
            float Bn  = sbm[l][n];
            h = __expf(Av*dtv)*h + dtv*u*Bn;
            sdsum += dtv;
        }
    }
    size_t idx = (size_t)(b*64 + d)*70 + chunk;
    S[idx*16 + n] = h;
    if (n == 0) sumdt[idx] = sdsum;
}

__global__ void k_scan2(const float* __restrict__ S, const float* __restrict__ sumdt,
                        const float* __restrict__ Alog, float* __restrict__ H0) {
    int t = blockIdx.x*256 + threadIdx.x;
    int b = t >> 10; int d = (t >> 4) & 63; int n = t & 15;
    float Av = -__expf(Alog[d*16 + n]);
    float carry = 0.f;
    size_t base = (size_t)(b*64 + d)*70;
    for (int ch = 0; ch < 70; ch++) {
        size_t idx = base + ch;
        H0[idx*16 + n] = carry;
        carry = carry*__expf(Av*sumdt[idx]) + S[idx*16 + n];
    }
}

__global__ __launch_bounds__(256) void k_scan3(
    const float* __restrict__ dt, const float* __restrict__ xc,
    const float* __restrict__ Bm, const float* __restrict__ Cm,
    const float* __restrict__ Alog, const float* __restrict__ H0,
    float* __restrict__ y) {
    int bx = blockIdx.x;
    int b = bx / 280, rem = bx % 280;
    int chunk = rem >> 2, dg = rem & 3;
    int tid = threadIdx.x, warp = tid >> 5, lane = tid & 31;
    int dloc = 2*warp + (lane >> 4), n = lane & 15;
    int d = dg*16 + dloc;
    __shared__ float sdt[16][16], sxc[16][16], sbm[16][16], scm[16][16], sy[16][16];
    float Av = -__expf(Alog[d*16 + n]);
    size_t idx = (size_t)(b*64 + d)*70 + chunk;
    float h = H0[idx*16 + n];
    size_t rowbase = (size_t)b*8960 + chunk*128;
    int lr = tid >> 4, lc = tid & 15;
    for (int s = 0; s < 8; s++) {
        size_t r0 = rowbase + s*16;
        __syncthreads();
        sdt[lr][lc] = dt[(r0 + lr)*64 + dg*16 + lc];
        sxc[lr][lc] = xc[(r0 + lr)*64 + dg*16 + lc];
        sbm[lr][lc] = Bm[(r0 + lr)*16 + lc];
        scm[lr][lc] = Cm[(r0 + lr)*16 + lc];
        __syncthreads();
        #pragma unroll
        for (int l = 0; l < 16; l++) {
            float dtv = sdt[l][dloc];
            float u   = sxc[l][dloc];
            float Bn  = sbm[l][n];
            h = __expf(Av*dtv)*h + dtv*u*Bn;
            float yv = h * scm[l][n];
            yv += __shfl_xor_sync(0xffffffffu, yv, 8);
            yv += __shfl_xor_sync(0xffffffffu, yv, 4);
            yv += __shfl_xor_sync(0xffffffffu, yv, 2);
            yv += __shfl_xor_sync(0xffffffffu, yv, 1);
            if (n == 0) sy[l][dloc] = yv;
        }
        __syncthreads();
        y[(r0 + lr)*64 + dg*16 + lc] = sy[lr][lc];
    }
}

__global__ void k_final(const float* __restrict__ y, const float* __restrict__ xc,
                        const float* __restrict__ xz, const float* __restrict__ xn,
                        const float* __restrict__ Dp, const float* __restrict__ opW,
                        const float* __restrict__ skipp, const float* __restrict__ g,
                        const float* __restrict__ be, const float* __restrict__ projW,
                        const float* __restrict__ projb, float* __restrict__ xm2) {
    __shared__ float sop[2048], spj[1024];
    int tid = threadIdx.x;   // 256
    for (int i = tid; i < 2048; i += 256) sop[i] = opW[i];
    for (int i = tid; i < 1024; i += 256) spj[i] = projW[i];
    __syncthreads();
    int warp = tid >> 5, lane = tid & 31;
    float skip = skipp[0];
    float dpl = Dp[lane], dph = Dp[32+lane];
    float gl = g[lane], bel = be[lane], pbl = projb[lane];
    #pragma unroll
    for (int t = 0; t < 8; t++) {
        size_t r = ((size_t)blockIdx.x*8 + warp)*8 + t;
        float y0 = y[r*64 + lane],      y1 = y[r*64 + 32 + lane];
        float c0 = xc[r*64 + lane],     c1 = xc[r*64 + 32 + lane];
        float z0 = xz[r*128 + 64 + lane], z1 = xz[r*128 + 96 + lane];
        float yy0 = (y0 + c0*dpl) * siluf(z0);
        float yy1 = (y1 + c1*dph) * siluf(z1);
        float acc = 0.f;
        #pragma unroll
        for (int d = 0; d < 32; d++) acc += __shfl_sync(0xffffffffu, yy0, d) * sop[d*32 + lane];
        #pragma unroll
        for (int d = 0; d < 32; d++) acc += __shfl_sync(0xffffffffu, yy1, d) * sop[(d+32)*32 + lane];
        float xm = acc + skip * xn[r*32 + lane];
        float mean = xm;
        #pragma unroll
        for (int o = 16; o; o >>= 1) mean += __shfl_xor_sync(0xffffffffu, mean, o);
        mean *= (1.f/32.f);
        float dv = xm - mean, var = dv*dv;
        #pragma unroll
        for (int o = 16; o; o >>= 1) var += __shfl_xor_sync(0xffffffffu, var, o);
        var *= (1.f/32.f);
        float v = dv * rsqrtf(var + 1e-5f) * gl + bel;
        float acc2 = pbl;
        #pragma unroll
        for (int mm = 0; mm < 32; mm++) acc2 += __shfl_sync(0xffffffffu, v, mm) * spj[mm*32 + lane];
        xm2[r*32 + lane] = acc2;
    }
}

__global__ void k_addback(const float* __restrict__ x1, const float* __restrict__ xm2,
                          float* __restrict__ x2) {
    int ww = blockIdx.x, b = blockIdx.y;
    __shared__ float s[224*33];
    int tid = threadIdx.x;   // 256
    for (int idx = tid; idx < 224*32; idx += 256) {
        int cc = idx >> 5, m = idx & 31;
        s[cc*33 + m] = xm2[((size_t)b*8960 + ww*224 + cc)*32 + m];
    }
    __syncthreads();
    for (int idx = tid; idx < 32*224; idx += 256) {
        int m = idx / 224, cc = idx % 224;
        size_t o = ((size_t)b*1280 + m*40 + ww)*224 + cc;
        x2[o] = x1[o] + s[cc*33 + m];
    }
}

// ---------------- conv3d 5x5x5, pad 2, smem-tiled per ky-plane ----------------
__global__ void k_conv3d(const float* __restrict__ x2, const float* __restrict__ cw,
                         const float* __restrict__ cb, float* __restrict__ x3) {
    int y = blockIdx.x, b = blockIdx.y;
    int xx = threadIdx.x;   // 224
    __shared__ float ws[125];
    __shared__ float sp[32][228];
    if (xx < 125) ws[xx] = cw[xx];
    if (xx < 32) { sp[xx][0]=0.f; sp[xx][1]=0.f; sp[xx][226]=0.f; sp[xx][227]=0.f; }
    float acc[32];
    #pragma unroll
    for (int d = 0; d < 32; d++) acc[d] = 0.f;
    for (int ky = 0; ky < 5; ky++) {
        int yy = y + ky - 2;
        if (yy < 0 || yy >= 40) continue;
        __syncthreads();
        for (int i = 0; i < 32; i++)
            sp[i][xx+2] = x2[(((size_t)b*32 + i)*40 + yy)*224 + xx];
        __syncthreads();
        #pragma unroll
        for (int kx = 0; kx < 5; kx++) {
            float v[36];
            v[0]=v[1]=v[34]=v[35]=0.f;
            #pragma unroll
            for (int i = 0; i < 32; i++) v[i+2] = sp[i][xx + kx];
            #pragma unroll
            for (int kz = 0; kz < 5; kz++) {
                float wv = ws[(kz*5 + ky)*5 + kx];
                #pragma unroll
                for (int d = 0; d < 32; d++) acc[d] += v[d+kz]*wv;
            }
        }
    }
    float bias = cb[0];
    #pragma unroll
    for (int d = 0; d < 32; d++)
        x3[(((size_t)b*32 + d)*40 + y)*224 + xx] = acc[d] + bias;
}

// ---------------- DWT: 4 subbands per thread, emits bf16 hi/lo ----------------
__global__ void k_dwt(const float* __restrict__ x3,
                      __nv_bfloat16* __restrict__ xwh, __nv_bfloat16* __restrict__ xwl) {
    size_t id = (size_t)blockIdx.x*256 + threadIdx.x;   // 2752512
    int c = (int)(id % 224); size_t rw = id / 224;
    int win = (int)(rw >> 6), tok = (int)(rw & 63);
    int bb = win / 6, w6 = win % 6;
    int wi = w6 / 3, wj = w6 % 3;
    int ti = tok >> 3, tj = tok & 7;
    int i2 = wi*8 + ti;
    int j2 = wj*8 + tj;
    int j = (j2 < 20) ? j2 : 38 - j2;   // reflect pad
    size_t base = (((size_t)bb*32 + 2*i2)*40 + 2*j)*224 + c;
    float a  = x3[base],        bv = x3[base + 224];
    float c2 = x3[base + 8960], d2 = x3[base + 9184];
    const size_t SS = (size_t)12288*224;
    float v0 = 0.5f*(a + bv + c2 + d2);
    float v1 = 0.5f*(a + bv - c2 - d2);
    float v2 = 0.5f*(a - bv + c2 - d2);
    float v3 = 0.5f*(a - bv - c2 + d2);
    __nv_bfloat16 h, l;
    bfsplit(v0, h, l); xwh[id]        = h; xwl[id]        = l;
    bfsplit(v1, h, l); xwh[id + SS]   = h; xwl[id + SS]   = l;
    bfsplit(v2, h, l); xwh[id + 2*SS] = h; xwl[id + 2*SS] = l;
    bfsplit(v3, h, l); xwh[id + 3*SS] = h; xwl[id + 3*SS] = l;
}

// ---------------- window attention: online softmax, staged bf16 hi/lo out ----
__global__ void k_wattn(const float* __restrict__ qkvw, const float* __restrict__ pe,
                        __nv_bfloat16* __restrict__ obh, __nv_bfloat16* __restrict__ obl) {
    int win = blockIdx.x, head = blockIdx.y;
    __shared__ __align__(16) float ks[64*28], vs[64*28];
    __shared__ __nv_bfloat16 oh[64*28], ol[64*28];
    int tid = threadIdx.x;   // 64
    size_t wbase = (size_t)win * 64;
    for (int idx = tid; idx < 1792; idx += 64) {
        int tok = idx / 28, dd = idx % 28;
        size_t rb = (wbase + tok)*672 + head*28 + dd;
        ks[idx] = qkvw[rb + 224];
        vs[idx] = qkvw[rb + 448];
    }
    float qr[28];
    {
        const float4* qp = (const float4*)(qkvw + (wbase + tid)*672 + head*28);
        #pragma unroll
        for (int q4 = 0; q4 < 7; q4++) {
            float4 v = qp[q4];
            qr[q4*4+0] = v.x * 0.18898223650461363f;
            qr[q4*4+1] = v.y * 0.18898223650461363f;
            qr[q4*4+2] = v.z * 0.18898223650461363f;
            qr[q4*4+3] = v.w * 0.18898223650461363f;
        }
    }
    __syncthreads();
    const float* per = pe + ((size_t)head*64 + tid)*64;
    float m = -1e30f, sum = 0.f;
    float acc[28];
    #pragma unroll
    for (int dd = 0; dd < 28; dd++) acc[dd] = 0.f;
    for (int j = 0; j < 64; j++) {
        const float4* k4 = (const float4*)&ks[j*28];
        float dot = 0.f;
        #pragma unroll
        for (int q4 = 0; q4 < 7; q4++) {
            float4 kk = k4[q4];
            dot += qr[q4*4+0]*kk.x + qr[q4*4+1]*kk.y
                 + qr[q4*4+2]*kk.z + qr[q4*4+3]*kk.w;
        }
        dot += per[j];
        if (dot > m) {
            float corr = __expf(m - dot);
            sum *= corr;
            #pragma unroll
            for (int dd = 0; dd < 28; dd++) acc[dd] *= corr;
            m = dot;
        }
        float e = __expf(dot - m);
        sum += e;
        const float4* v4 = (const float4*)&vs[j*28];
        #pragma unroll
        for (int q4 = 0; q4 < 7; q4++) {
            float4 vv = v4[q4];
            acc[q4*4+0] += e*vv.x; acc[q4*4+1] += e*vv.y;
            acc[q4*4+2] += e*vv.z; acc[q4*4+3] += e*vv.w;
        }
    }
    float inv = 1.f / sum;
    #pragma unroll
    for (int dd = 0; dd < 28; dd++) {
        __nv_bfloat16 h, l;
        bfsplit(acc[dd] * inv, h, l);
        oh[tid*28 + dd] = h; ol[tid*28 + dd] = l;
    }
    __syncthreads();
    for (int idx = tid; idx < 1792; idx += 64) {
        int tok = idx / 28, dd = idx % 28;
        size_t o = (wbase + tok)*224 + head*28 + dd;
        obh[o] = oh[idx]; obl[o] = ol[idx];
    }
}

// ---------------- IWT + biases + crop + final layout ----------------
__global__ void k_iwt(const float* __restrict__ oproj,
                      const float* __restrict__ b1, const float* __restrict__ b2,
                      const float* __restrict__ b3, const float* __restrict__ b4,
                      float* __restrict__ out) {
    size_t id = (size_t)blockIdx.x*256 + threadIdx.x;   // 2293760
    int c = (int)(id % 224); size_t r = id / 224;
    int j = (int)(r % 20); r /= 20;
    int i = (int)(r % 16); int bb = (int)(r / 16);
    int wi = i >> 3, ti = i & 7, wj = j >> 3, tj = j & 7;
    size_t row0 = ((size_t)(bb*6 + wi*3 + wj))*64 + ti*8 + tj;
    float A  = oproj[row0*224 + c]           + b1[c];
    float Hh = oproj[(row0 + 12288)*224 + c] + b2[c];
    float V  = oproj[(row0 + 24576)*224 + c] + b3[c];
    float D  = oproj[(row0 + 36864)*224 + c] + b4[c];
    size_t oo = (((size_t)bb*32 + 2*i)*40 + 2*j)*224 + c;
    out[oo]          = 0.5f*(A + Hh + V + D);
    out[oo + 224]    = 0.5f*(A + Hh - V - D);
    out[oo + 8960]   = 0.5f*(A - Hh + V - D);
    out[oo + 9184]   = 0.5f*(A - Hh - V + D);
}

// ---------------- launcher ----------------
extern "C" void kernel_launch(void* const* d_in, const int* in_sizes, int n_in,
                              void* d_out, int out_size) {
    const float* x       = (const float*)d_in[0];
    const float* Wq      = (const float*)d_in[1];
    const float* Wkv     = (const float*)d_in[2];
    const float* ln_g    = (const float*)d_in[3];
    const float* ln_b    = (const float*)d_in[4];
    const float* in_proj = (const float*)d_in[5];
    const float* conv1dW = (const float*)d_in[6];
    const float* conv1db = (const float*)d_in[7];
    const float* x_projW = (const float*)d_in[8];
    const float* dt_projW= (const float*)d_in[9];
    const float* dt_projb= (const float*)d_in[10];
    const float* A_log   = (const float*)d_in[11];
    const float* Dp      = (const float*)d_in[12];
    const float* out_projW=(const float*)d_in[13];
    const float* skip    = (const float*)d_in[14];
    const float* projW   = (const float*)d_in[15];
    const float* projb   = (const float*)d_in[16];
    const float* conv3dW = (const float*)d_in[17];
    const float* conv3db = (const float*)d_in[18];
    const float* Wq1     = (const float*)d_in[19];
    const float* Wkv1    = (const float*)d_in[20];
    const float* pos_emb = (const float*)d_in[21];
    const float* Wo[4]   = {(const float*)d_in[22],(const float*)d_in[24],
                            (const float*)d_in[26],(const float*)d_in[28]};
    const float* bo[4]   = {(const float*)d_in[23],(const float*)d_in[25],
                            (const float*)d_in[27],(const float*)d_in[29]};
    float* out = (float*)d_out;

    float *p_attn, *p_gp, *p_x1, *p_xn, *p_xz, *p_xc, *p_dt,
          *p_Bm, *p_Cm, *p_y, *p_S, *p_sd, *p_H0, *p_xm2, *p_x2, *p_x3,
          *p_qkvw, *p_oproj;
    cudaGetSymbolAddress((void**)&p_attn, g_attn);
    cudaGetSymbolAddress((void**)&p_gp,   g_gpart);
    cudaGetSymbolAddress((void**)&p_x1,   g_x1);
    cudaGetSymbolAddress((void**)&p_xn,   g_xn);
    cudaGetSymbolAddress((void**)&p_xz,   g_xz);
    cudaGetSymbolAddress((void**)&p_xc,   g_xc);
    cudaGetSymbolAddress((void**)&p_dt,   g_dt);
    cudaGetSymbolAddress((void**)&p_Bm,   g_Bm);
    cudaGetSymbolAddress((void**)&p_Cm,   g_Cm);
    cudaGetSymbolAddress((void**)&p_y,    g_y);
    cudaGetSymbolAddress((void**)&p_S,    g_S);
    cudaGetSymbolAddress((void**)&p_sd,   g_sumdt);
    cudaGetSymbolAddress((void**)&p_H0,   g_H0);
    cudaGetSymbolAddress((void**)&p_xm2,  g_xm2);
    cudaGetSymbolAddress((void**)&p_x2,   g_x2);
    cudaGetSymbolAddress((void**)&p_x3,   g_x3);
    cudaGetSymbolAddress((void**)&p_qkvw, g_qkvw);
    cudaGetSymbolAddress((void**)&p_oproj,g_oproj);

    __nv_bfloat16 *p_xh,*p_xl,*p_xnh,*p_xnl,*p_xwh,*p_xwl,*p_obh,*p_obl,
        *p_Wc1h,*p_Wc1l,*p_Wc2h,*p_Wc2l,*p_iph,*p_ipl,*p_Woh,*p_Wol;
    cudaGetSymbolAddress((void**)&p_xh,   g_xh);
    cudaGetSymbolAddress((void**)&p_xl,   g_xlo);
    cudaGetSymbolAddress((void**)&p_xnh,  g_xnh);
    cudaGetSymbolAddress((void**)&p_xnl,  g_xnl);
    cudaGetSymbolAddress((void**)&p_xwh,  g_xwh);
    cudaGetSymbolAddress((void**)&p_xwl,  g_xwl);
    cudaGetSymbolAddress((void**)&p_obh,  g_obh);
    cudaGetSymbolAddress((void**)&p_obl,  g_obl);
    cudaGetSymbolAddress((void**)&p_Wc1h, g_Wc1h);
    cudaGetSymbolAddress((void**)&p_Wc1l, g_Wc1l);
    cudaGetSymbolAddress((void**)&p_Wc2h, g_Wc2h);
    cudaGetSymbolAddress((void**)&p_Wc2l, g_Wc2l);
    cudaGetSymbolAddress((void**)&p_iph,  g_iph);
    cudaGetSymbolAddress((void**)&p_ipl,  g_ipl);
    cudaGetSymbolAddress((void**)&p_Woh,  g_Woh);
    cudaGetSymbolAddress((void**)&p_Wol,  g_Wol);

    // ---- splits: input (big) + all weights (one batched launch) ----
    k_split<<<(9175040+255)/256, 256>>>(x, p_xh, p_xl, 9175040);
    SplitArgs sa;
    sa.s[0] = {Wq,      p_Wc1h, p_Wc1l, 50176,  224, 672, 0};
    sa.s[1] = {Wkv,     p_Wc1h, p_Wc1l, 100352, 448, 672, 224};
    sa.s[2] = {in_proj, p_iph,  p_ipl,  4096,   0, 0, 0};
    sa.s[3] = {Wq1,     p_Wc2h, p_Wc2l, 50176,  224, 672, 0};
    sa.s[4] = {Wkv1,    p_Wc2h, p_Wc2l, 100352, 448, 672, 224};
    sa.s[5] = {Wo[0], p_Woh,          p_Wol,          50176, 0, 0, 0};
    sa.s[6] = {Wo[1], p_Woh + 50176,  p_Wol + 50176,  50176, 0, 0, 0};
    sa.s[7] = {Wo[2], p_Woh + 100352, p_Wol + 100352, 50176, 0, 0, 0};
    sa.s[8] = {Wo[3], p_Woh + 150528, p_Wol + 150528, 50176, 0, 0, 0};
    sa.s[9] = {Wq, p_Wc1h, p_Wc1l, 0, 0, 0, 0};   // unused
    k_split_multi<<<dim3(392, 10), 256>>>(sa);

    // stage 1: combined qkv GEMM (N=672), token-split gram, apply
    tgemm_bf<<<dim3(6, 320), 256>>>(p_xh, p_xl, p_Wc1h, p_Wc1l, p_qkvw,
                                    672, 224, 224, 672, 672);
    k_gram_part<<<dim3(32, 8, 8), 256>>>(p_qkvw, p_gp);
    k_gram_fin <<<dim3(32, 8), 256>>>(p_gp, p_attn);
    k_apply<<<dim3(20, 32), 224>>>(x, p_qkvw, p_attn, p_x1);

    // stage 2: mamba
    k_ln1<<<dim3(40, 32), 256>>>(p_x1, ln_g, ln_b, p_xn, p_xnh, p_xnl);
    tgemm_bf<<<dim3(1, 2240), 256>>>(p_xnh, p_xnl, p_iph, p_ipl, p_xz, 128, 32, 32, 128, 128);
    k_conv1d<<<17920, 256>>>(p_xz, conv1dW, conv1db, p_xc);
    sgemm_xproj<<<dim3(1, 2240), 256>>>(p_xc, x_projW, dt_projW, dt_projb,
                                        p_dt, p_Bm, p_Cm);
    k_scan1<<<8960, 256>>>(p_dt, p_xc, p_Bm, A_log, p_S, p_sd);
    k_scan2<<<128, 256>>>(p_S, p_sd, A_log, p_H0);
    k_scan3<<<8960, 256>>>(p_dt, p_xc, p_Bm, p_Cm, A_log, p_H0, p_y);
    k_final<<<4480, 256>>>(p_y, p_xc, p_xz, p_xn, Dp, out_projW, skip,
                           ln_g, ln_b, projW, projb, p_xm2);
    k_addback<<<dim3(40, 32), 256>>>(p_x1, p_xm2, p_x2);

    // stage 3: conv3d
    k_conv3d<<<dim3(40, 32), 224>>>(p_x2, conv3dW, conv3db, p_x3);

    // stage 4: DWT + combined window-qkv GEMM + window attention
    k_dwt<<<10752, 256>>>(p_x3, p_xwh, p_xwl);
    tgemm_bf<<<dim3(6, 384), 256>>>(p_xwh, p_xwl, p_Wc2h, p_Wc2l, p_qkvw,
                                    672, 224, 224, 672, 672);
    k_wattn<<<dim3(768, 8), 64>>>(p_qkvw, pos_emb, p_obh, p_obl);
    BfPtrs4 po;
    for (int s = 0; s < 4; s++) { po.Bh[s] = p_Woh + s*50176; po.Bl[s] = p_Wol + s*50176; }
    tgemm_bf_b4<<<dim3(2, 96, 4), 256>>>(p_obh, p_obl, po, p_oproj,
                                         224, 224, 224, 224, 224,
                                         (long long)12288*224, (long long)12288*224);

    // stage 5: IWT + biases + output
    k_iwt<<<8960, 256>>>(p_oproj, bo[0], bo[1], bo[2], bo[3], out);
}

// round 15
// speedup vs baseline: 1.7791x; 1.0204x over previous
#include <cuda_runtime.h>
#include <cuda_bf16.h>
#include <mma.h>
#include <math.h>
#include <stdint.h>

using namespace nvcuda;

// ---------------- static scratch ----------------
__device__ __align__(16) float g_attn [32*8*28*28];
__device__ __align__(16) float g_gpart[32*8*8*840];   // partial Gram sums
__device__ __align__(16) float g_x1   [9175040];
__device__ __align__(16) float g_xn   [9175040];      // 286720 x 32
__device__ __align__(16) float g_xz   [36700160];     // 286720 x 128
__device__ __align__(16) float g_xc   [18350080];     // 286720 x 64
__device__ __align__(16) float g_dt   [18350080];
__device__ __align__(16) float g_Bm   [4587520];
__device__ __align__(16) float g_Cm   [4587520];
__device__ __align__(16) float g_y    [18350080];
__device__ __align__(16) float g_S    [2293760];
__device__ __align__(16) float g_sumdt[143360];
__device__ __align__(16) float g_H0   [2293760];
__device__ __align__(16) float g_xm2  [9175040];
__device__ __align__(16) float g_x2   [9175040];
__device__ __align__(16) float g_x3   [9175040];
__device__ __align__(16) float g_qkvw [33030144];     // 49152 x 672 (also stage-1 qkv 40960x672)
__device__ __align__(16) float g_oproj[11010048];

// bf16 hi/lo split scratch
__device__ __align__(16) __nv_bfloat16 g_xh  [9175040],  g_xlo  [9175040];
__device__ __align__(16) __nv_bfloat16 g_xnh [9175040],  g_xnl  [9175040];
__device__ __align__(16) __nv_bfloat16 g_xwh [11010048], g_xwl  [11010048];
__device__ __align__(16) __nv_bfloat16 g_obh [11010048], g_obl  [11010048];
__device__ __align__(16) __nv_bfloat16 g_Wc1h[150528], g_Wc1l[150528];   // [Wq|Wkv] 224x672
__device__ __align__(16) __nv_bfloat16 g_Wc2h[150528], g_Wc2l[150528];   // [Wq1|Wkv1]
__device__ __align__(16) __nv_bfloat16 g_iph [4096],   g_ipl [4096];
__device__ __align__(16) __nv_bfloat16 g_Woh [200704], g_Wol [200704];

__device__ __forceinline__ float siluf(float v){ return v / (1.f + __expf(-v)); }
__device__ __forceinline__ void bfsplit(float v, __nv_bfloat16& h, __nv_bfloat16& l) {
    h = __float2bfloat16(v);
    l = __float2bfloat16(v - __bfloat162float(h));
}
__device__ __forceinline__ uint32_t smem_u32(const void* p) {
    return (uint32_t)__cvta_generic_to_shared(p);
}
#define CPA16(saddr, gptr, nbytes) \
    asm volatile("cp.async.cg.shared.global [%0], [%1], 16, %2;" \
                 :: "r"(saddr), "l"(gptr), "r"(nbytes))
#define CPA_COMMIT() asm volatile("cp.async.commit_group;")
#define CPA_WAIT0()  asm volatile("cp.async.wait_group 0;")

struct BfPtrs4 { const __nv_bfloat16* Bh[4]; const __nv_bfloat16* Bl[4]; };

// ---------------- fp32 -> bf16 hi/lo splits ----------------
__global__ void k_split(const float* __restrict__ in, __nv_bfloat16* __restrict__ hi,
                        __nv_bfloat16* __restrict__ lo, int n) {
    int i = blockIdx.x*256 + threadIdx.x;
    if (i < n) {
        __nv_bfloat16 h, l;
        bfsplit(in[i], h, l);
        hi[i] = h; lo[i] = l;
    }
}

struct SplitSeg { const float* src; __nv_bfloat16* hi; __nv_bfloat16* lo;
                  int n; int srcW; int dstPitch; int dstOff; };
struct SplitArgs { SplitSeg s[10]; };

__global__ void k_split_multi(SplitArgs a) {
    SplitSeg seg = a.s[blockIdx.y];
    int i = blockIdx.x*256 + threadIdx.x;
    if (i < seg.n) {
        __nv_bfloat16 h, l;
        bfsplit(seg.src[i], h, l);
        int o = i;
        if (seg.srcW) {
            int k = i / seg.srcW, c = i - k*seg.srcW;
            o = k*seg.dstPitch + seg.dstOff + c;
        }
        seg.hi[o] = h; seg.lo[o] = l;
    }
}

// ---------------- bf16 split tensor-core GEMM: 128x128 tile, cp.async pipe ---
#define APITCH 24
#define BPITCH 136
__device__ __forceinline__ void tgemm_bf_core(
    const __nv_bfloat16* __restrict__ Ah, const __nv_bfloat16* __restrict__ Al,
    const __nv_bfloat16* __restrict__ Bh, const __nv_bfloat16* __restrict__ Bl,
    float* __restrict__ C, int N, int K, int lda, int ldb, int ldc,
    __nv_bfloat16* sAh, __nv_bfloat16* sAl, __nv_bfloat16* sBh, __nv_bfloat16* sBl)
{
    const int bm = blockIdx.y*128, bn = blockIdx.x*128;
    const int tid = threadIdx.x, warp = tid >> 5;
    const int wm = warp >> 2, wn = warp & 3;   // 2 x 4 warps; warp tile 64x32
    wmma::fragment<wmma::accumulator,16,16,16,float> acc[4][2];
    #pragma unroll
    for (int i = 0; i < 4; i++)
        #pragma unroll
        for (int j = 0; j < 2; j++) wmma::fill_fragment(acc[i][j], 0.f);

    const int ar = tid >> 1, ac = (tid & 1)*8;
    const int brr = tid >> 4, bcc = (tid & 15)*8;
    const int bcol = bn + bcc;
    const int bbytes = (bcol < N) ? 16 : 0;

    const uint32_t uAh = smem_u32(sAh), uAl = smem_u32(sAl);
    const uint32_t uBh = smem_u32(sBh), uBl = smem_u32(sBl);
    const int ASZ = 128*APITCH, BSZ = 16*BPITCH;       // elements
    const uint32_t aoffb = (uint32_t)(ar*APITCH + ac)*2;
    const uint32_t boffb = (uint32_t)(brr*BPITCH + bcc)*2;
    const __nv_bfloat16* gAh = Ah + (size_t)(bm+ar)*lda + ac;
    const __nv_bfloat16* gAl = Al + (size_t)(bm+ar)*lda + ac;
    const __nv_bfloat16* gBh = Bh + (size_t)brr*ldb + bcol;
    const __nv_bfloat16* gBl = Bl + (size_t)brr*ldb + bcol;

    CPA16(uAh + aoffb, gAh, 16);
    CPA16(uAl + aoffb, gAl, 16);
    CPA16(uBh + boffb, gBh, bbytes);
    CPA16(uBl + boffb, gBl, bbytes);
    CPA_COMMIT(); CPA_WAIT0();
    __syncthreads();
    int buf = 0;

    for (int k0 = 0; k0 < K; k0 += 16) {
        const bool more = (k0 + 16) < K;
        if (more) {
            int nb = buf ^ 1;
            CPA16(uAh + (uint32_t)nb*ASZ*2 + aoffb, gAh + k0 + 16, 16);
            CPA16(uAl + (uint32_t)nb*ASZ*2 + aoffb, gAl + k0 + 16, 16);
            CPA16(uBh + (uint32_t)nb*BSZ*2 + boffb, gBh + (size_t)(k0+16)*ldb, bbytes);
            CPA16(uBl + (uint32_t)nb*BSZ*2 + boffb, gBl + (size_t)(k0+16)*ldb, bbytes);
            CPA_COMMIT();
        }
        __nv_bfloat16* cAh = sAh + buf*ASZ; __nv_bfloat16* cAl = sAl + buf*ASZ;
        __nv_bfloat16* cBh = sBh + buf*BSZ; __nv_bfloat16* cBl = sBl + buf*BSZ;
        wmma::fragment<wmma::matrix_b,16,16,16,__nv_bfloat16,wmma::row_major> fbh[2], fbl[2];
        #pragma unroll
        for (int j = 0; j < 2; j++) {
            wmma::load_matrix_sync(fbh[j], &cBh[wn*32 + j*16], BPITCH);
            wmma::load_matrix_sync(fbl[j], &cBl[wn*32 + j*16], BPITCH);
        }
        #pragma unroll
        for (int i = 0; i < 4; i++) {
            wmma::fragment<wmma::matrix_a,16,16,16,__nv_bfloat16,wmma::row_major> fah, fal;
            wmma::load_matrix_sync(fah, &cAh[(wm*64 + i*16)*APITCH], APITCH);
            wmma::load_matrix_sync(fal, &cAl[(wm*64 + i*16)*APITCH], APITCH);
            #pragma unroll
            for (int j = 0; j < 2; j++) {
                wmma::mma_sync(acc[i][j], fah, fbh[j], acc[i][j]);
                wmma::mma_sync(acc[i][j], fah, fbl[j], acc[i][j]);
                wmma::mma_sync(acc[i][j], fal, fbh[j], acc[i][j]);
            }
        }
        if (more) {
            CPA_WAIT0();
            __syncthreads();
            buf ^= 1;
        }
    }
    #pragma unroll
    for (int i = 0; i < 4; i++)
        #pragma unroll
        for (int j = 0; j < 2; j++) {
            int n0 = bn + wn*32 + j*16;
            if (n0 < N)
                wmma::store_matrix_sync(C + (size_t)(bm + wm*64 + i*16)*ldc + n0,
                                        acc[i][j], ldc, wmma::mem_row_major);
        }
}

__global__ __launch_bounds__(256, 2) void tgemm_bf(
    const __nv_bfloat16* __restrict__ Ah, const __nv_bfloat16* __restrict__ Al,
    const __nv_bfloat16* __restrict__ Bh, const __nv_bfloat16* __restrict__ Bl,
    float* __restrict__ C, int N, int K, int lda, int ldb, int ldc)
{
    __shared__ __align__(16) __nv_bfloat16 sAh[2*128*APITCH], sAl[2*128*APITCH];
    __shared__ __align__(16) __nv_bfloat16 sBh[2*16*BPITCH],  sBl[2*16*BPITCH];
    tgemm_bf_core(Ah, Al, Bh, Bl, C, N, K, lda, ldb, ldc, sAh, sAl, sBh, sBl);
}

__global__ __launch_bounds__(256, 2) void tgemm_bf_b4(
    const __nv_bfloat16* __restrict__ Ah, const __nv_bfloat16* __restrict__ Al,
    BfPtrs4 p, float* __restrict__ C, int N, int K, int lda, int ldb, int ldc,
    long long strideA, long long strideC)
{
    __shared__ __align__(16) __nv_bfloat16 sAh[2*128*APITCH], sAl[2*128*APITCH];
    __shared__ __align__(16) __nv_bfloat16 sBh[2*16*BPITCH],  sBl[2*16*BPITCH];
    int z = blockIdx.z;
    tgemm_bf_core(Ah + (size_t)z*strideA, Al + (size_t)z*strideA,
                  p.Bh[z], p.Bl[z], C + (size_t)z*strideC,
                  N, K, lda, ldb, ldc, sAh, sAl, sBh, sBl);
}

// ---------------- fused x_proj GEMM (SIMT) + dt/B/C split ----------------
__global__ __launch_bounds__(256) void sgemm_xproj(
    const float* __restrict__ A, const float* __restrict__ B,
    const float* __restrict__ dtW, const float* __restrict__ dtb,
    float* __restrict__ dt, float* __restrict__ Bm, float* __restrict__ Cm)
{
    __shared__ float As[2][16][128];
    __shared__ float Bs[2][16][64];
    __shared__ float St[128][36];
    __shared__ float sdtW[128], sdtb[64];
    const int N = 34, K = 64, lda = 64, ldb = 34;
    const int bm = blockIdx.y * 128;
    const int tid = threadIdx.x;
    const int tr = tid >> 4, tc = tid & 15;
    const int br = tid >> 4, bc0 = (tid & 15) * 4;
    if (tid < 128) sdtW[tid] = dtW[tid];
    if (tid >= 128 && tid < 192) sdtb[tid-128] = dtb[tid-128];
    float acc[8][4];
    #pragma unroll
    for (int i = 0; i < 8; i++)
        #pragma unroll
        for (int j = 0; j < 4; j++) acc[i][j] = 0.f;

    float4 ra[2]; float rb[4];
    #pragma unroll
    for (int i = 0; i < 2; i++) {
        int idx = tid + i * 256;
        int r = idx >> 2, c4 = (idx & 3) * 4;
        ra[i] = *(const float4*)(A + (size_t)(bm + r) * lda + c4);
    }
    #pragma unroll
    for (int i = 0; i < 4; i++) {
        int n = bc0 + i;
        rb[i] = (n < N) ? B[(size_t)br * ldb + n] : 0.f;
    }
    int buf = 0;
    #pragma unroll
    for (int i = 0; i < 2; i++) {
        int idx = tid + i * 256;
        int r = idx >> 2, c4 = (idx & 3) * 4;
        As[0][c4+0][r]=ra[i].x; As[0][c4+1][r]=ra[i].y;
        As[0][c4+2][r]=ra[i].z; As[0][c4+3][r]=ra[i].w;
    }
    #pragma unroll
    for (int i = 0; i < 4; i++) Bs[0][br][bc0+i] = rb[i];
    __syncthreads();

    for (int k0 = 0; k0 < K; k0 += 16) {
        const bool more = (k0 + 16) < K;
        float4 ra2[2]; float rb2[4];
        if (more) {
            #pragma unroll
            for (int i = 0; i < 2; i++) {
                int idx = tid + i * 256;
                int r = idx >> 2, c4 = (idx & 3) * 4;
                ra2[i] = *(const float4*)(A + (size_t)(bm + r) * lda + k0 + 16 + c4);
            }
            #pragma unroll
            for (int i = 0; i < 4; i++) {
                int n = bc0 + i;
                rb2[i] = (n < N) ? B[(size_t)(k0 + 16 + br) * ldb + n] : 0.f;
            }
        }
        #pragma unroll
        for (int kk = 0; kk < 16; kk++) {
            float4 a0 = *(const float4*)&As[buf][kk][tr*8];
            float4 a1 = *(const float4*)&As[buf][kk][tr*8+4];
            float4 b0 = *(const float4*)&Bs[buf][kk][tc*4];
            float a[8] = {a0.x,a0.y,a0.z,a0.w,a1.x,a1.y,a1.z,a1.w};
            float b[4] = {b0.x,b0.y,b0.z,b0.w};
            #pragma unroll
            for (int i = 0; i < 8; i++)
                #pragma unroll
                for (int j = 0; j < 4; j++) acc[i][j] += a[i]*b[j];
        }
        if (more) {
            int nb = buf ^ 1;
            #pragma unroll
            for (int i = 0; i < 2; i++) {
                int idx = tid + i * 256;
                int r = idx >> 2, c4 = (idx & 3) * 4;
                As[nb][c4+0][r]=ra2[i].x; As[nb][c4+1][r]=ra2[i].y;
                As[nb][c4+2][r]=ra2[i].z; As[nb][c4+3][r]=ra2[i].w;
            }
            #pragma unroll
            for (int i = 0; i < 4; i++) Bs[nb][br][bc0+i] = rb2[i];
            __syncthreads();
            buf = nb;
        }
    }
    #pragma unroll
    for (int i = 0; i < 8; i++) {
        #pragma unroll
        for (int j = 0; j < 4; j++) {
            int n = tc*4 + j;
            if (n < N) St[tr*8 + i][n] = acc[i][j];
        }
    }
    __syncthreads();
    for (int idx = tid; idx < 128*64; idx += 256) {
        int r = idx >> 6, d = idx & 63;
        float v = St[r][0]*sdtW[d] + St[r][1]*sdtW[64+d] + sdtb[d];
        dt[(size_t)(bm + r)*64 + d] = (v > 20.f) ? v : log1pf(__expf(v));
    }
    for (int idx = tid; idx < 128*16; idx += 256) {
        int r = idx >> 4, n = idx & 15;
        Bm[(size_t)(bm + r)*16 + n] = St[r][2 + n];
        Cm[(size_t)(bm + r)*16 + n] = St[r][18 + n];
    }
}

// ---------------- stage 1: channel attention, token-split Gram ----------------
// partial: block = (b, h, z of 5 token-tiles); 2x2 register microtile
__global__ void k_gram_part(const float* __restrict__ qc, float* __restrict__ gpart) {
    int b = blockIdx.x, h = blockIdx.y, z = blockIdx.z;
    __shared__ float kt[32][28], qt[32][28];
    int tid = threadIdx.x;   // 256
    float a00=0.f, a01=0.f, a10=0.f, a11=0.f;   // tile threads
    int i0 = 0, j0 = 0;
    if (tid < 196) { i0 = 2*(tid/14); j0 = 2*(tid%14); }
    for (int nt = z*5; nt < z*5 + 5; nt++) {
        for (int idx = tid; idx < 896; idx += 256) {
            int n = idx / 28, i = idx % 28;
            size_t row = (size_t)b*1280 + nt*32 + n;
            kt[n][i] = qc[row*672 + 224 + h*28 + i];
            qt[n][i] = qc[row*672 + h*28 + i];
        }
        __syncthreads();
        if (tid < 196) {
            #pragma unroll
            for (int n = 0; n < 32; n++) {
                float k0 = kt[n][i0], k1 = kt[n][i0+1];
                float q0 = qt[n][j0], q1 = qt[n][j0+1];
                a00 += k0*q0; a01 += k0*q1;
                a10 += k1*q0; a11 += k1*q1;
            }
        } else if (tid < 224) {
            int i = tid - 196;
            #pragma unroll
            for (int n = 0; n < 32; n++) { float v = kt[n][i]; a00 += v*v; }
        } else if (tid < 252) {
            int j = tid - 224;
            #pragma unroll
            for (int n = 0; n < 32; n++) { float v = qt[n][j]; a00 += v*v; }
        }
        __syncthreads();
    }
    float* gp = gpart + (((size_t)(b*8 + h))*8 + z)*840;
    if (tid < 196) {
        gp[i0*28 + j0]       = a00;
        gp[i0*28 + j0 + 1]   = a01;
        gp[(i0+1)*28 + j0]   = a10;
        gp[(i0+1)*28 + j0+1] = a11;
    } else if (tid < 224) {
        gp[784 + (tid - 196)] = a00;
    } else if (tid < 252) {
        gp[812 + (tid - 224)] = a00;
    }
}

// finalize: sum 8 partials, norms + softmax
__global__ void k_gram_fin(const float* __restrict__ gpart, float* __restrict__ attn) {
    int b = blockIdx.x, h = blockIdx.y;
    __shared__ float G[840];
    int tid = threadIdx.x;   // 256
    const float* gp = gpart + ((size_t)(b*8 + h))*8*840;
    #pragma unroll
    for (int s = 0; s < 4; s++) {
        int w = tid + 256*s;
        if (w < 840) {
            float a = 0.f;
            #pragma unroll
            for (int z = 0; z < 8; z++) a += gp[z*840 + w];
            G[w] = a;
        }
    }
    __syncthreads();
    if (tid < 28) {
        int i = tid;
        float nk = fmaxf(sqrtf(G[784+i]), 1e-12f);
        float lg[28], m = -1e30f;
        #pragma unroll
        for (int j = 0; j < 28; j++) {
            float nq = fmaxf(sqrtf(G[812+j]), 1e-12f);
            lg[j] = G[i*28+j] / (nk*nq) * 0.18898223650461363f;
            m = fmaxf(m, lg[j]);
        }
        float sum = 0.f;
        #pragma unroll
        for (int j = 0; j < 28; j++) { lg[j] = __expf(lg[j]-m); sum += lg[j]; }
        float inv = 1.f/sum;
        #pragma unroll
        for (int j = 0; j < 28; j++)
            attn[(((size_t)b*8 + h)*28 + i)*28 + j] = lg[j]*inv;
    }
}

// x1 = attn-applied + residual; 32 rows per block
__global__ void k_apply(const float* __restrict__ x, const float* __restrict__ qc,
                        const float* __restrict__ attn, float* __restrict__ x1) {
    int chunk = blockIdx.x, b = blockIdx.y;   // 40 chunks of 32 rows
    __shared__ float vr[8][224];
    int tid = threadIdx.x;   // 224
    int h = tid / 28, i = tid % 28;
    float att[28];
    {
        const float4* ap = (const float4*)(attn + (((size_t)b*8 + h)*28 + i)*28);
        #pragma unroll
        for (int q4 = 0; q4 < 7; q4++) {
            float4 v = ap[q4];
            att[q4*4+0]=v.x; att[q4*4+1]=v.y; att[q4*4+2]=v.z; att[q4*4+3]=v.w;
        }
    }
    for (int nn = 0; nn < 32; nn += 8) {
        size_t row0 = (size_t)b*1280 + chunk*32 + nn;
        __syncthreads();
        for (int idx = tid; idx < 1792; idx += 224) {
            int rr = idx / 224, cc = idx % 224;
            vr[rr][cc] = qc[(row0 + rr)*672 + 448 + cc];
        }
        __syncthreads();
        #pragma unroll
        for (int rr = 0; rr < 8; rr++) {
            float a = 0.f;
            #pragma unroll
            for (int j = 0; j < 28; j++) a += att[j] * vr[rr][h*28 + j];
            size_t o = (row0 + rr)*224 + tid;
            x1[o] = x[o] + a;
        }
    }
}

// ---------------- transpose + LN; coalesced fp32 + bf16 hi/lo output ---------
__global__ void k_ln1(const float* __restrict__ x1, const float* __restrict__ g,
                      const float* __restrict__ be, float* __restrict__ xn,
                      __nv_bfloat16* __restrict__ xnh, __nv_bfloat16* __restrict__ xnl) {
    int ww = blockIdx.x, b = blockIdx.y;
    __shared__ float s[32*225];
    __shared__ float sg[32], sb[32];
    int tid = threadIdx.x;   // 256
    if (tid < 32) { sg[tid] = g[tid]; sb[tid] = be[tid]; }
    for (int idx = tid; idx < 32*224; idx += 256) {
        int m = idx / 224, cc = idx % 224;
        s[m*225 + cc] = x1[((size_t)b*1280 + m*40 + ww)*224 + cc];
    }
    __syncthreads();
    float v[32];
    if (tid < 224) {
        float mean = 0.f;
        #pragma unroll
        for (int m = 0; m < 32; m++) { v[m] = s[m*225 + tid]; mean += v[m]; }
        mean *= (1.f/32.f);
        float var = 0.f;
        #pragma unroll
        for (int m = 0; m < 32; m++) { float d = v[m]-mean; var += d*d; }
        var *= (1.f/32.f);
        float inv = rsqrtf(var + 1e-5f);
        #pragma unroll
        for (int m = 0; m < 32; m++) v[m] = (v[m]-mean)*inv*sg[m] + sb[m];
    }
    __syncthreads();
    if (tid < 224) {
        #pragma unroll
        for (int m = 0; m < 32; m++) s[tid*32 + m] = v[m];
    }
    __syncthreads();
    size_t base = ((size_t)b*8960 + ww*224)*32;
    for (int idx = tid; idx < 7168; idx += 256) {
        float val = s[idx];
        xn[base + idx] = val;
        __nv_bfloat16 h, l; bfsplit(val, h, l);
        xnh[base + idx] = h; xnl[base + idx] = l;
    }
}

// ---------------- mamba pieces ----------------
__global__ void k_conv1d(const float* __restrict__ xz, const float* __restrict__ cw,
                         const float* __restrict__ cb, float* __restrict__ xc) {
    size_t id = (size_t)blockIdx.x*256 + threadIdx.x;   // 286720*16
    size_t row = id >> 4; int d4 = (int)(id & 15) * 4;
    size_t b = row / 8960; int l = (int)(row % 8960);
    float a0 = cb[d4], a1 = cb[d4+1], a2 = cb[d4+2], a3 = cb[d4+3];
    #pragma unroll
    for (int t = 0; t < 4; t++) {
        int ls = l - 3 + t;
        if (ls >= 0) {
            float4 v = *(const float4*)(xz + ((size_t)b*8960 + ls)*128 + d4);
            a0 += v.x * cw[d4*4 + t];
            a1 += v.y * cw[(d4+1)*4 + t];
            a2 += v.z * cw[(d4+2)*4 + t];
            a3 += v.w * cw[(d4+3)*4 + t];
        }
    }
    float4 o; o.x = siluf(a0); o.y = siluf(a1); o.z = siluf(a2); o.w = siluf(a3);
    *(float4*)(xc + row*64 + d4) = o;
}

__global__ __launch_bounds__(256) void k_scan1(
    const float* __restrict__ dt, const float* __restrict__ xc,
    const float* __restrict__ Bm, const float* __restrict__ Alog,
    float* __restrict__ S, float* __restrict__ sumdt) {
    int bx = blockIdx.x;                 // 8960
    int b = bx / 280, rem = bx % 280;
    int chunk = rem >> 2, dg = rem & 3;
    int tid = threadIdx.x, warp = tid >> 5, lane = tid & 31;
    int dloc = 2*warp + (lane >> 4), n = lane & 15;
    int d = dg*16 + dloc;
    __shared__ float sdt[16][16], sxc[16][16], sbm[16][16];
    float Av = -__expf(Alog[d*16 + n]);
    float h = 0.f, sdsum = 0.f;
    size_t rowbase = (size_t)b*8960 + chunk*128;
    int lr = tid >> 4, lc = tid & 15;
    for (int s = 0; s < 8; s++) {
        size_t r0 = rowbase + s*16;
        __syncthreads();
        sdt[lr][lc] = dt[(r0 + lr)*64 + dg*16 + lc];
        sxc[lr][lc] = xc[(r0 + lr)*64 + dg*16 + lc];
        sbm[lr][lc] = Bm[(r0 + lr)*16 + lc];
        __syncthreads();
        #pragma unroll
        for (int l = 0; l < 16; l++) {
            float dtv = sdt[l][dloc];
            float u   = sxc[l][dloc];
            float Bn  = sbm[l][n];
            h = __expf(Av*dtv)*h + dtv*u*Bn;
            sdsum += dtv;
        }
    }
    size_t idx = (size_t)(b*64 + d)*70 + chunk;
    S[idx*16 + n] = h;
    if (n == 0) sumdt[idx] = sdsum;
}

__global__ void k_scan2(const float* __restrict__ S, const float* __restrict__ sumdt,
                        const float* __restrict__ Alog, float* __restrict__ H0) {
    int t = blockIdx.x*256 + threadIdx.x;
    int b = t >> 10; int d = (t >> 4) & 63; int n = t & 15;
    float Av = -__expf(Alog[d*16 + n]);
    float carry = 0.f;
    size_t base = (size_t)(b*64 + d)*70;
    for (int ch = 0; ch < 70; ch++) {
        size_t idx = base + ch;
        H0[idx*16 + n] = carry;
        carry = carry*__expf(Av*sumdt[idx]) + S[idx*16 + n];
    }
}

__global__ __launch_bounds__(256) void k_scan3(
    const float* __restrict__ dt, const float* __restrict__ xc,
    const float* __restrict__ Bm, const float* __restrict__ Cm,
    const float* __restrict__ Alog, const float* __restrict__ H0,
    float* __restrict__ y) {
    int bx = blockIdx.x;
    int b = bx / 280, rem = bx % 280;
    int chunk = rem >> 2, dg = rem & 3;
    int tid = threadIdx.x, warp = tid >> 5, lane = tid & 31;
    int dloc = 2*warp + (lane >> 4), n = lane & 15;
    int d = dg*16 + dloc;
    __shared__ float sdt[16][16], sxc[16][16], sbm[16][16], scm[16][16], sy[16][16];
    float Av = -__expf(Alog[d*16 + n]);
    size_t idx = (size_t)(b*64 + d)*70 + chunk;
    float h = H0[idx*16 + n];
    size_t rowbase = (size_t)b*8960 + chunk*128;
    int lr = tid >> 4, lc = tid & 15;
    for (int s = 0; s < 8; s++) {
        size_t r0 = rowbase + s*16;
        __syncthreads();
        sdt[lr][lc] = dt[(r0 + lr)*64 + dg*16 + lc];
        sxc[lr][lc] = xc[(r0 + lr)*64 + dg*16 + lc];
        sbm[lr][lc] = Bm[(r0 + lr)*16 + lc];
        scm[lr][lc] = Cm[(r0 + lr)*16 + lc];
        __syncthreads();
        #pragma unroll
        for (int l = 0; l < 16; l++) {
            float dtv = sdt[l][dloc];
            float u   = sxc[l][dloc];
            float Bn  = sbm[l][n];
            h = __expf(Av*dtv)*h + dtv*u*Bn;
            float yv = h * scm[l][n];
            yv += __shfl_xor_sync(0xffffffffu, yv, 8);
            yv += __shfl_xor_sync(0xffffffffu, yv, 4);
            yv += __shfl_xor_sync(0xffffffffu, yv, 2);
            yv += __shfl_xor_sync(0xffffffffu, yv, 1);
            if (n == 0) sy[l][dloc] = yv;
        }
        __syncthreads();
        y[(r0 + lr)*64 + dg*16 + lc] = sy[lr][lc];
    }
}

__global__ void k_final(const float* __restrict__ y, const float* __restrict__ xc,
                        const float* __restrict__ xz, const float* __restrict__ xn,
                        const float* __restrict__ Dp, const float* __restrict__ opW,
                        const float* __restrict__ skipp, const float* __restrict__ g,
                        const float* __restrict__ be, const float* __restrict__ projW,
                        const float* __restrict__ projb, float* __restrict__ xm2) {
    __shared__ float sop[2048], spj[1024];
    int tid = threadIdx.x;   // 256
    for (int i = tid; i < 2048; i += 256) sop[i] = opW[i];
    for (int i = tid; i < 1024; i += 256) spj[i] = projW[i];
    __syncthreads();
    int warp = tid >> 5, lane = tid & 31;
    float skip = skipp[0];
    float dpl = Dp[lane], dph = Dp[32+lane];
    float gl = g[lane], bel = be[lane], pbl = projb[lane];
    #pragma unroll
    for (int t = 0; t < 8; t++) {
        size_t r = ((size_t)blockIdx.x*8 + warp)*8 + t;
        float y0 = y[r*64 + lane],      y1 = y[r*64 + 32 + lane];
        float c0 = xc[r*64 + lane],     c1 = xc[r*64 + 32 + lane];
        float z0 = xz[r*128 + 64 + lane], z1 = xz[r*128 + 96 + lane];
        float yy0 = (y0 + c0*dpl) * siluf(z0);
        float yy1 = (y1 + c1*dph) * siluf(z1);
        float acc = 0.f;
        #pragma unroll
        for (int d = 0; d < 32; d++) acc += __shfl_sync(0xffffffffu, yy0, d) * sop[d*32 + lane];
        #pragma unroll
        for (int d = 0; d < 32; d++) acc += __shfl_sync(0xffffffffu, yy1, d) * sop[(d+32)*32 + lane];
        float xm = acc + skip * xn[r*32 + lane];
        float mean = xm;
        #pragma unroll
        for (int o = 16; o; o >>= 1) mean += __shfl_xor_sync(0xffffffffu, mean, o);
        mean *= (1.f/32.f);
        float dv = xm - mean, var = dv*dv;
        #pragma unroll
        for (int o = 16; o; o >>= 1) var += __shfl_xor_sync(0xffffffffu, var, o);
        var *= (1.f/32.f);
        float v = dv * rsqrtf(var + 1e-5f) * gl + bel;
        float acc2 = pbl;
        #pragma unroll
        for (int mm = 0; mm < 32; mm++) acc2 += __shfl_sync(0xffffffffu, v, mm) * spj[mm*32 + lane];
        xm2[r*32 + lane] = acc2;
    }
}

__global__ void k_addback(const float* __restrict__ x1, const float* __restrict__ xm2,
                          float* __restrict__ x2) {
    int ww = blockIdx.x, b = blockIdx.y;
    __shared__ float s[224*33];
    int tid = threadIdx.x;   // 256
    for (int idx = tid; idx < 224*32; idx += 256) {
        int cc = idx >> 5, m = idx & 31;
        s[cc*33 + m] = xm2[((size_t)b*8960 + ww*224 + cc)*32 + m];
    }
    __syncthreads();
    for (int idx = tid; idx < 32*224; idx += 256) {
        int m = idx / 224, cc = idx % 224;
        size_t o = ((size_t)b*1280 + m*40 + ww)*224 + cc;
        x2[o] = x1[o] + s[cc*33 + m];
    }
}

// ---------------- conv3d 5x5x5, pad 2, smem-tiled per ky-plane ----------------
__global__ void k_conv3d(const float* __restrict__ x2, const float* __restrict__ cw,
                         const float* __restrict__ cb, float* __restrict__ x3) {
    int y = blockIdx.x, b = blockIdx.y;
    int xx = threadIdx.x;   // 224
    __shared__ float ws[125];
    __shared__ float sp[32][228];
    if (xx < 125) ws[xx] = cw[xx];
    if (xx < 32) { sp[xx][0]=0.f; sp[xx][1]=0.f; sp[xx][226]=0.f; sp[xx][227]=0.f; }
    float acc[32];
    #pragma unroll
    for (int d = 0; d < 32; d++) acc[d] = 0.f;
    for (int ky = 0; ky < 5; ky++) {
        int yy = y + ky - 2;
        if (yy < 0 || yy >= 40) continue;
        __syncthreads();
        for (int i = 0; i < 32; i++)
            sp[i][xx+2] = x2[(((size_t)b*32 + i)*40 + yy)*224 + xx];
        __syncthreads();
        #pragma unroll
        for (int kx = 0; kx < 5; kx++) {
            float v[36];
            v[0]=v[1]=v[34]=v[35]=0.f;
            #pragma unroll
            for (int i = 0; i < 32; i++) v[i+2] = sp[i][xx + kx];
            #pragma unroll
            for (int kz = 0; kz < 5; kz++) {
                float wv = ws[(kz*5 + ky)*5 + kx];
                #pragma unroll
                for (int d = 0; d < 32; d++) acc[d] += v[d+kz]*wv;
            }
        }
    }
    float bias = cb[0];
    #pragma unroll
    for (int d = 0; d < 32; d++)
        x3[(((size_t)b*32 + d)*40 + y)*224 + xx] = acc[d] + bias;
}

// ---------------- DWT: 4 subbands per thread, emits bf16 hi/lo ----------------
__global__ void k_dwt(const float* __restrict__ x3,
                      __nv_bfloat16* __restrict__ xwh, __nv_bfloat16* __restrict__ xwl) {
    size_t id = (size_t)blockIdx.x*256 + threadIdx.x;   // 2752512
    int c = (int)(id % 224); size_t rw = id / 224;
    int win = (int)(rw >> 6), tok = (int)(rw & 63);
    int bb = win / 6, w6 = win % 6;
    int wi = w6 / 3, wj = w6 % 3;
    int ti = tok >> 3, tj = tok & 7;
    int i2 = wi*8 + ti;
    int j2 = wj*8 + tj;
    int j = (j2 < 20) ? j2 : 38 - j2;   // reflect pad
    size_t base = (((size_t)bb*32 + 2*i2)*40 + 2*j)*224 + c;
    float a  = x3[base],        bv = x3[base + 224];
    float c2 = x3[base + 8960], d2 = x3[base + 9184];
    const size_t SS = (size_t)12288*224;
    float v0 = 0.5f*(a + bv + c2 + d2);
    float v1 = 0.5f*(a + bv - c2 - d2);
    float v2 = 0.5f*(a - bv + c2 - d2);
    float v3 = 0.5f*(a - bv - c2 + d2);
    __nv_bfloat16 h, l;
    bfsplit(v0, h, l); xwh[id]        = h; xwl[id]        = l;
    bfsplit(v1, h, l); xwh[id + SS]   = h; xwl[id + SS]   = l;
    bfsplit(v2, h, l); xwh[id + 2*SS] = h; xwl[id + 2*SS] = l;
    bfsplit(v3, h, l); xwh[id + 3*SS] = h; xwl[id + 3*SS] = l;
}

// ---------------- window attention: online softmax, staged bf16 hi/lo out ----
__global__ void k_wattn(const float* __restrict__ qkvw, const float* __restrict__ pe,
                        __nv_bfloat16* __restrict__ obh, __nv_bfloat16* __restrict__ obl) {
    int win = blockIdx.x, head = blockIdx.y;
    __shared__ __align__(16) float ks[64*28], vs[64*28];
    __shared__ __nv_bfloat16 oh[64*28], ol[64*28];
    int tid = threadIdx.x;   // 64
    size_t wbase = (size_t)win * 64;
    for (int idx = tid; idx < 1792; idx += 64) {
        int tok = idx / 28, dd = idx % 28;
        size_t rb = (wbase + tok)*672 + head*28 + dd;
        ks[idx] = qkvw[rb + 224];
        vs[idx] = qkvw[rb + 448];
    }
    float qr[28];
    {
        const float4* qp = (const float4*)(qkvw + (wbase + tid)*672 + head*28);
        #pragma unroll
        for (int q4 = 0; q4 < 7; q4++) {
            float4 v = qp[q4];
            qr[q4*4+0] = v.x * 0.18898223650461363f;
            qr[q4*4+1] = v.y * 0.18898223650461363f;
            qr[q4*4+2] = v.z * 0.18898223650461363f;
            qr[q4*4+3] = v.w * 0.18898223650461363f;
        }
    }
    __syncthreads();
    const float* per = pe + ((size_t)head*64 + tid)*64;
    float m = -1e30f, sum = 0.f;
    float acc[28];
    #pragma unroll
    for (int dd = 0; dd < 28; dd++) acc[dd] = 0.f;
    for (int j = 0; j < 64; j++) {
        const float4* k4 = (const float4*)&ks[j*28];
        float dot = 0.f;
        #pragma unroll
        for (int q4 = 0; q4 < 7; q4++) {
            float4 kk = k4[q4];
            dot += qr[q4*4+0]*kk.x + qr[q4*4+1]*kk.y
                 + qr[q4*4+2]*kk.z + qr[q4*4+3]*kk.w;
        }
        dot += per[j];
        if (dot > m) {
            float corr = __expf(m - dot);
            sum *= corr;
            #pragma unroll
            for (int dd = 0; dd < 28; dd++) acc[dd] *= corr;
            m = dot;
        }
        float e = __expf(dot - m);
        sum += e;
        const float4* v4 = (const float4*)&vs[j*28];
        #pragma unroll
        for (int q4 = 0; q4 < 7; q4++) {
            float4 vv = v4[q4];
            acc[q4*4+0] += e*vv.x; acc[q4*4+1] += e*vv.y;
            acc[q4*4+2] += e*vv.z; acc[q4*4+3] += e*vv.w;
        }
    }
    float inv = 1.f / sum;
    #pragma unroll
    for (int dd = 0; dd < 28; dd++) {
        __nv_bfloat16 h, l;
        bfsplit(acc[dd] * inv, h, l);
        oh[tid*28 + dd] = h; ol[tid*28 + dd] = l;
    }
    __syncthreads();
    for (int idx = tid; idx < 1792; idx += 64) {
        int tok = idx / 28, dd = idx % 28;
        size_t o = (wbase + tok)*224 + head*28 + dd;
        obh[o] = oh[idx]; obl[o] = ol[idx];
    }
}

// ---------------- IWT + biases + crop + final layout ----------------
__global__ void k_iwt(const float* __restrict__ oproj,
                      const float* __restrict__ b1, const float* __restrict__ b2,
                      const float* __restrict__ b3, const float* __restrict__ b4,
                      float* __restrict__ out) {
    size_t id = (size_t)blockIdx.x*256 + threadIdx.x;   // 2293760
    int c = (int)(id % 224); size_t r = id / 224;
    int j = (int)(r % 20); r /= 20;
    int i = (int)(r % 16); int bb = (int)(r / 16);
    int wi = i >> 3, ti = i & 7, wj = j >> 3, tj = j & 7;
    size_t row0 = ((size_t)(bb*6 + wi*3 + wj))*64 + ti*8 + tj;
    float A  = oproj[row0*224 + c]           + b1[c];
    float Hh = oproj[(row0 + 12288)*224 + c] + b2[c];
    float V  = oproj[(row0 + 24576)*224 + c] + b3[c];
    float D  = oproj[(row0 + 36864)*224 + c] + b4[c];
    size_t oo = (((size_t)bb*32 + 2*i)*40 + 2*j)*224 + c;
    out[oo]          = 0.5f*(A + Hh + V + D);
    out[oo + 224]    = 0.5f*(A + Hh - V - D);
    out[oo + 8960]   = 0.5f*(A - Hh + V - D);
    out[oo + 9184]   = 0.5f*(A - Hh - V + D);
}

// ---------------- launcher ----------------
extern "C" void kernel_launch(void* const* d_in, const int* in_sizes, int n_in,
                              void* d_out, int out_size) {
    const float* x       = (const float*)d_in[0];
    const float* Wq      = (const float*)d_in[1];
    const float* Wkv     = (const float*)d_in[2];
    const float* ln_g    = (const float*)d_in[3];
    const float* ln_b    = (const float*)d_in[4];
    const float* in_proj = (const float*)d_in[5];
    const float* conv1dW = (const float*)d_in[6];
    const float* conv1db = (const float*)d_in[7];
    const float* x_projW = (const float*)d_in[8];
    const float* dt_projW= (const float*)d_in[9];
    const float* dt_projb= (const float*)d_in[10];
    const float* A_log   = (const float*)d_in[11];
    const float* Dp      = (const float*)d_in[12];
    const float* out_projW=(const float*)d_in[13];
    const float* skip    = (const float*)d_in[14];
    const float* projW   = (const float*)d_in[15];
    const float* projb   = (const float*)d_in[16];
    const float* conv3dW = (const float*)d_in[17];
    const float* conv3db = (const float*)d_in[18];
    const float* Wq1     = (const float*)d_in[19];
    const float* Wkv1    = (const float*)d_in[20];
    const float* pos_emb = (const float*)d_in[21];
    const float* Wo[4]   = {(const float*)d_in[22],(const float*)d_in[24],
                            (const float*)d_in[26],(const float*)d_in[28]};
    const float* bo[4]   = {(const float*)d_in[23],(const float*)d_in[25],
                            (const float*)d_in[27],(const float*)d_in[29]};
    float* out = (float*)d_out;

    float *p_attn, *p_gp, *p_x1, *p_xn, *p_xz, *p_xc, *p_dt,
          *p_Bm, *p_Cm, *p_y, *p_S, *p_sd, *p_H0, *p_xm2, *p_x2, *p_x3,
          *p_qkvw, *p_oproj;
    cudaGetSymbolAddress((void**)&p_attn, g_attn);
    cudaGetSymbolAddress((void**)&p_gp,   g_gpart);
    cudaGetSymbolAddress((void**)&p_x1,   g_x1);
    cudaGetSymbolAddress((void**)&p_xn,   g_xn);
    cudaGetSymbolAddress((void**)&p_xz,   g_xz);
    cudaGetSymbolAddress((void**)&p_xc,   g_xc);
    cudaGetSymbolAddress((void**)&p_dt,   g_dt);
    cudaGetSymbolAddress((void**)&p_Bm,   g_Bm);
    cudaGetSymbolAddress((void**)&p_Cm,   g_Cm);
    cudaGetSymbolAddress((void**)&p_y,    g_y);
    cudaGetSymbolAddress((void**)&p_S,    g_S);
    cudaGetSymbolAddress((void**)&p_sd,   g_sumdt);
    cudaGetSymbolAddress((void**)&p_H0,   g_H0);
    cudaGetSymbolAddress((void**)&p_xm2,  g_xm2);
    cudaGetSymbolAddress((void**)&p_x2,   g_x2);
    cudaGetSymbolAddress((void**)&p_x3,   g_x3);
    cudaGetSymbolAddress((void**)&p_qkvw, g_qkvw);
    cudaGetSymbolAddress((void**)&p_oproj,g_oproj);

    __nv_bfloat16 *p_xh,*p_xl,*p_xnh,*p_xnl,*p_xwh,*p_xwl,*p_obh,*p_obl,
        *p_Wc1h,*p_Wc1l,*p_Wc2h,*p_Wc2l,*p_iph,*p_ipl,*p_Woh,*p_Wol;
    cudaGetSymbolAddress((void**)&p_xh,   g_xh);
    cudaGetSymbolAddress((void**)&p_xl,   g_xlo);
    cudaGetSymbolAddress((void**)&p_xnh,  g_xnh);
    cudaGetSymbolAddress((void**)&p_xnl,  g_xnl);
    cudaGetSymbolAddress((void**)&p_xwh,  g_xwh);
    cudaGetSymbolAddress((void**)&p_xwl,  g_xwl);
    cudaGetSymbolAddress((void**)&p_obh,  g_obh);
    cudaGetSymbolAddress((void**)&p_obl,  g_obl);
    cudaGetSymbolAddress((void**)&p_Wc1h, g_Wc1h);
    cudaGetSymbolAddress((void**)&p_Wc1l, g_Wc1l);
    cudaGetSymbolAddress((void**)&p_Wc2h, g_Wc2h);
    cudaGetSymbolAddress((void**)&p_Wc2l, g_Wc2l);
    cudaGetSymbolAddress((void**)&p_iph,  g_iph);
    cudaGetSymbolAddress((void**)&p_ipl,  g_ipl);
    cudaGetSymbolAddress((void**)&p_Woh,  g_Woh);
    cudaGetSymbolAddress((void**)&p_Wol,  g_Wol);

    // ---- splits: input (big) + all weights (one batched launch) ----
    k_split<<<(9175040+255)/256, 256>>>(x, p_xh, p_xl, 9175040);
    SplitArgs sa;
    sa.s[0] = {Wq,      p_Wc1h, p_Wc1l, 50176,  224, 672, 0};
    sa.s[1] = {Wkv,     p_Wc1h, p_Wc1l, 100352, 448, 672, 224};
    sa.s[2] = {in_proj, p_iph,  p_ipl,  4096,   0, 0, 0};
    sa.s[3] = {Wq1,     p_Wc2h, p_Wc2l, 50176,  224, 672, 0};
    sa.s[4] = {Wkv1,    p_Wc2h, p_Wc2l, 100352, 448, 672, 224};
    sa.s[5] = {Wo[0], p_Woh,          p_Wol,          50176, 0, 0, 0};
    sa.s[6] = {Wo[1], p_Woh + 50176,  p_Wol + 50176,  50176, 0, 0, 0};
    sa.s[7] = {Wo[2], p_Woh + 100352, p_Wol + 100352, 50176, 0, 0, 0};
    sa.s[8] = {Wo[3], p_Woh + 150528, p_Wol + 150528, 50176, 0, 0, 0};
    sa.s[9] = {Wq, p_Wc1h, p_Wc1l, 0, 0, 0, 0};   // unused
    k_split_multi<<<dim3(392, 10), 256>>>(sa);

    // stage 1: combined qkv GEMM (N=672), token-split gram (2x2 microtile), apply
    tgemm_bf<<<dim3(6, 320), 256>>>(p_xh, p_xl, p_Wc1h, p_Wc1l, p_qkvw,
                                    672, 224, 224, 672, 672);
    k_gram_part<<<dim3(32, 8, 8), 256>>>(p_qkvw, p_gp);
    k_gram_fin <<<dim3(32, 8), 256>>>(p_gp, p_attn);
    k_apply<<<dim3(40, 32), 224>>>(x, p_qkvw, p_attn, p_x1);

    // stage 2: mamba
    k_ln1<<<dim3(40, 32), 256>>>(p_x1, ln_g, ln_b, p_xn, p_xnh, p_xnl);
    tgemm_bf<<<dim3(1, 2240), 256>>>(p_xnh, p_xnl, p_iph, p_ipl, p_xz, 128, 32, 32, 128, 128);
    k_conv1d<<<17920, 256>>>(p_xz, conv1dW, conv1db, p_xc);
    sgemm_xproj<<<dim3(1, 2240), 256>>>(p_xc, x_projW, dt_projW, dt_projb,
                                        p_dt, p_Bm, p_Cm);
    k_scan1<<<8960, 256>>>(p_dt, p_xc, p_Bm, A_log, p_S, p_sd);
    k_scan2<<<128, 256>>>(p_S, p_sd, A_log, p_H0);
    k_scan3<<<8960, 256>>>(p_dt, p_xc, p_Bm, p_Cm, A_log, p_H0, p_y);
    k_final<<<4480, 256>>>(p_y, p_xc, p_xz, p_xn, Dp, out_projW, skip,
                           ln_g, ln_b, projW, projb, p_xm2);
    k_addback<<<dim3(40, 32), 256>>>(p_x1, p_xm2, p_x2);

    // stage 3: conv3d
    k_conv3d<<<dim3(40, 32), 224>>>(p_x2, conv3dW, conv3db, p_x3);

    // stage 4: DWT + combined window-qkv GEMM + window attention
    k_dwt<<<10752, 256>>>(p_x3, p_xwh, p_xwl);
    tgemm_bf<<<dim3(6, 384), 256>>>(p_xwh, p_xwl, p_Wc2h, p_Wc2l, p_qkvw,
                                    672, 224, 224, 672, 672);
    k_wattn<<<dim3(768, 8), 64>>>(p_qkvw, pos_emb, p_obh, p_obl);
    BfPtrs4 po;
    for (int s = 0; s < 4; s++) { po.Bh[s] = p_Woh + s*50176; po.Bl[s] = p_Wol + s*50176; }
    tgemm_bf_b4<<<dim3(2, 96, 4), 256>>>(p_obh, p_obl, po, p_oproj,
                                         224, 224, 224, 224, 224,
                                         (long long)12288*224, (long long)12288*224);

    // stage 5: IWT + biases + output
    k_iwt<<<8960, 256>>>(p_oproj, bo[0], bo[1], bo[2], bo[3], out);
}

// round 16
// speedup vs baseline: 1.8180x; 1.0219x over previous
#include <cuda_runtime.h>
#include <cuda_bf16.h>
#include <mma.h>
#include <math.h>
#include <stdint.h>

using namespace nvcuda;

// ---------------- static scratch ----------------
__device__ __align__(16) float g_attn [32*8*28*28];
__device__ __align__(16) float g_gpart[32*8*8*840];   // partial Gram sums
__device__ __align__(16) float g_x1   [9175040];
__device__ __align__(16) float g_xn   [9175040];      // 286720 x 32
__device__ __align__(16) float g_xz   [36700160];     // 286720 x 128
__device__ __align__(16) float g_xc   [18350080];     // 286720 x 64
__device__ __align__(16) float g_dt   [18350080];
__device__ __align__(16) float g_Bm   [4587520];
__device__ __align__(16) float g_Cm   [4587520];
__device__ __align__(16) float g_y    [18350080];
__device__ __align__(16) float g_S    [2293760];
__device__ __align__(16) float g_sumdt[143360];
__device__ __align__(16) float g_H0   [2293760];
__device__ __align__(16) float g_xm2  [9175040];
__device__ __align__(16) float g_x2   [9175040];
__device__ __align__(16) float g_x3   [9175040];
__device__ __align__(16) float g_qkvw [33030144];     // 49152 x 672 (also stage-1 qkv 40960x672)
__device__ __align__(16) float g_oproj[11010048];

// bf16 hi/lo split scratch
__device__ __align__(16) __nv_bfloat16 g_xh  [9175040],  g_xlo  [9175040];
__device__ __align__(16) __nv_bfloat16 g_xnh [9175040],  g_xnl  [9175040];
__device__ __align__(16) __nv_bfloat16 g_xwh [11010048], g_xwl  [11010048];
__device__ __align__(16) __nv_bfloat16 g_obh [11010048], g_obl  [11010048];
__device__ __align__(16) __nv_bfloat16 g_Wc1h[150528], g_Wc1l[150528];   // [Wq|Wkv] 224x672
__device__ __align__(16) __nv_bfloat16 g_Wc2h[150528], g_Wc2l[150528];   // [Wq1|Wkv1]
__device__ __align__(16) __nv_bfloat16 g_iph [4096],   g_ipl [4096];
__device__ __align__(16) __nv_bfloat16 g_Woh [200704], g_Wol [200704];

__device__ __forceinline__ float siluf(float v){ return v / (1.f + __expf(-v)); }
__device__ __forceinline__ void bfsplit(float v, __nv_bfloat16& h, __nv_bfloat16& l) {
    h = __float2bfloat16(v);
    l = __float2bfloat16(v - __bfloat162float(h));
}
__device__ __forceinline__ uint32_t smem_u32(const void* p) {
    return (uint32_t)__cvta_generic_to_shared(p);
}
#define CPA16(saddr, gptr, nbytes) \
    asm volatile("cp.async.cg.shared.global [%0], [%1], 16, %2;" \
                 :: "r"(saddr), "l"(gptr), "r"(nbytes))
#define CPA_COMMIT() asm volatile("cp.async.commit_group;")
#define CPA_WAIT0()  asm volatile("cp.async.wait_group 0;")
#define CPA_WAIT1()  asm volatile("cp.async.wait_group 1;")

struct BfPtrs4 { const __nv_bfloat16* Bh[4]; const __nv_bfloat16* Bl[4]; };

// ---------------- fp32 -> bf16 hi/lo splits ----------------
__global__ void k_split(const float* __restrict__ in, __nv_bfloat16* __restrict__ hi,
                        __nv_bfloat16* __restrict__ lo, int n) {
    int i = blockIdx.x*256 + threadIdx.x;
    if (i < n) {
        __nv_bfloat16 h, l;
        bfsplit(in[i], h, l);
        hi[i] = h; lo[i] = l;
    }
}

struct SplitSeg { const float* src; __nv_bfloat16* hi; __nv_bfloat16* lo;
                  int n; int srcW; int dstPitch; int dstOff; };
struct SplitArgs { SplitSeg s[10]; };

__global__ void k_split_multi(SplitArgs a) {
    SplitSeg seg = a.s[blockIdx.y];
    int i = blockIdx.x*256 + threadIdx.x;
    if (i < seg.n) {
        __nv_bfloat16 h, l;
        bfsplit(seg.src[i], h, l);
        int o = i;
        if (seg.srcW) {
            int k = i / seg.srcW, c = i - k*seg.srcW;
            o = k*seg.dstPitch + seg.dstOff + c;
        }
        seg.hi[o] = h; seg.lo[o] = l;
    }
}

// ---------------- bf16 split tensor-core GEMM: 128x128 tile, 3-stage cp.async
#define APITCH 24
#define BPITCH 136
__device__ __forceinline__ void tgemm_bf_core(
    const __nv_bfloat16* __restrict__ Ah, const __nv_bfloat16* __restrict__ Al,
    const __nv_bfloat16* __restrict__ Bh, const __nv_bfloat16* __restrict__ Bl,
    float* __restrict__ C, int N, int K, int lda, int ldb, int ldc,
    __nv_bfloat16* sAh, __nv_bfloat16* sAl, __nv_bfloat16* sBh, __nv_bfloat16* sBl)
{
    const int bm = blockIdx.y*128, bn = blockIdx.x*128;
    const int tid = threadIdx.x, warp = tid >> 5;
    const int wm = warp >> 2, wn = warp & 3;   // 2 x 4 warps; warp tile 64x32
    wmma::fragment<wmma::accumulator,16,16,16,float> acc[4][2];
    #pragma unroll
    for (int i = 0; i < 4; i++)
        #pragma unroll
        for (int j = 0; j < 2; j++) wmma::fill_fragment(acc[i][j], 0.f);

    const int ar = tid >> 1, ac = (tid & 1)*8;
    const int brr = tid >> 4, bcc = (tid & 15)*8;
    const int bcol = bn + bcc;
    const int bbytes = (bcol < N) ? 16 : 0;

    const uint32_t uAh = smem_u32(sAh), uAl = smem_u32(sAl);
    const uint32_t uBh = smem_u32(sBh), uBl = smem_u32(sBl);
    const int ASZ = 128*APITCH, BSZ = 16*BPITCH;       // elements
    const uint32_t aoffb = (uint32_t)(ar*APITCH + ac)*2;
    const uint32_t boffb = (uint32_t)(brr*BPITCH + bcc)*2;
    const __nv_bfloat16* gAh = Ah + (size_t)(bm+ar)*lda + ac;
    const __nv_bfloat16* gAl = Al + (size_t)(bm+ar)*lda + ac;
    const __nv_bfloat16* gBh = Bh + (size_t)brr*ldb + bcol;
    const __nv_bfloat16* gBl = Bl + (size_t)brr*ldb + bcol;

    const int T = K >> 4;

    // prologue: issue tiles 0 and 1
    {
        CPA16(uAh + aoffb, gAh, 16);
        CPA16(uAl + aoffb, gAl, 16);
        CPA16(uBh + boffb, gBh, bbytes);
        CPA16(uBl + boffb, gBl, bbytes);
        CPA_COMMIT();
    }
    if (T > 1) {
        CPA16(uAh + (uint32_t)ASZ*2 + aoffb, gAh + 16, 16);
        CPA16(uAl + (uint32_t)ASZ*2 + aoffb, gAl + 16, 16);
        CPA16(uBh + (uint32_t)BSZ*2 + boffb, gBh + (size_t)16*ldb, bbytes);
        CPA16(uBl + (uint32_t)BSZ*2 + boffb, gBl + (size_t)16*ldb, bbytes);
        CPA_COMMIT();
        CPA_WAIT1();
    } else {
        CPA_WAIT0();
    }
    __syncthreads();

    for (int t = 0; t < T; t++) {
        if (t + 2 < T) {
            int nb = (t + 2) % 3;
            int k2 = (t + 2) * 16;
            CPA16(uAh + (uint32_t)nb*ASZ*2 + aoffb, gAh + k2, 16);
            CPA16(uAl + (uint32_t)nb*ASZ*2 + aoffb, gAl + k2, 16);
            CPA16(uBh + (uint32_t)nb*BSZ*2 + boffb, gBh + (size_t)k2*ldb, bbytes);
            CPA16(uBl + (uint32_t)nb*BSZ*2 + boffb, gBl + (size_t)k2*ldb, bbytes);
            CPA_COMMIT();
        }
        int buf = t % 3;
        __nv_bfloat16* cAh = sAh + buf*ASZ; __nv_bfloat16* cAl = sAl + buf*ASZ;
        __nv_bfloat16* cBh = sBh + buf*BSZ; __nv_bfloat16* cBl = sBl + buf*BSZ;
        wmma::fragment<wmma::matrix_b,16,16,16,__nv_bfloat16,wmma::row_major> fbh[2], fbl[2];
        #pragma unroll
        for (int j = 0; j < 2; j++) {
            wmma::load_matrix_sync(fbh[j], &cBh[wn*32 + j*16], BPITCH);
            wmma::load_matrix_sync(fbl[j], &cBl[wn*32 + j*16], BPITCH);
        }
        #pragma unroll
        for (int i = 0; i < 4; i++) {
            wmma::fragment<wmma::matrix_a,16,16,16,__nv_bfloat16,wmma::row_major> fah, fal;
            wmma::load_matrix_sync(fah, &cAh[(wm*64 + i*16)*APITCH], APITCH);
            wmma::load_matrix_sync(fal, &cAl[(wm*64 + i*16)*APITCH], APITCH);
            #pragma unroll
            for (int j = 0; j < 2; j++) {
                wmma::mma_sync(acc[i][j], fah, fbh[j], acc[i][j]);
                wmma::mma_sync(acc[i][j], fah, fbl[j], acc[i][j]);
                wmma::mma_sync(acc[i][j], fal, fbh[j], acc[i][j]);
            }
        }
        if (t + 1 < T) {
            if (t + 2 < T) { CPA_WAIT1(); } else { CPA_WAIT0(); }
            __syncthreads();
        }
    }
    #pragma unroll
    for (int i = 0; i < 4; i++)
        #pragma unroll
        for (int j = 0; j < 2; j++) {
            int n0 = bn + wn*32 + j*16;
            if (n0 < N)
                wmma::store_matrix_sync(C + (size_t)(bm + wm*64 + i*16)*ldc + n0,
                                        acc[i][j], ldc, wmma::mem_row_major);
        }
}

__global__ __launch_bounds__(256, 2) void tgemm_bf(
    const __nv_bfloat16* __restrict__ Ah, const __nv_bfloat16* __restrict__ Al,
    const __nv_bfloat16* __restrict__ Bh, const __nv_bfloat16* __restrict__ Bl,
    float* __restrict__ C, int N, int K, int lda, int ldb, int ldc)
{
    __shared__ __align__(16) __nv_bfloat16 sAh[3*128*APITCH], sAl[3*128*APITCH];
    __shared__ __align__(16) __nv_bfloat16 sBh[3*16*BPITCH],  sBl[3*16*BPITCH];
    tgemm_bf_core(Ah, Al, Bh, Bl, C, N, K, lda, ldb, ldc, sAh, sAl, sBh, sBl);
}

__global__ __launch_bounds__(256, 2) void tgemm_bf_b4(
    const __nv_bfloat16* __restrict__ Ah, const __nv_bfloat16* __restrict__ Al,
    BfPtrs4 p, float* __restrict__ C, int N, int K, int lda, int ldb, int ldc,
    long long strideA, long long strideC)
{
    __shared__ __align__(16) __nv_bfloat16 sAh[3*128*APITCH], sAl[3*128*APITCH];
    __shared__ __align__(16) __nv_bfloat16 sBh[3*16*BPITCH],  sBl[3*16*BPITCH];
    int z = blockIdx.z;
    tgemm_bf_core(Ah + (size_t)z*strideA, Al + (size_t)z*strideA,
                  p.Bh[z], p.Bl[z], C + (size_t)z*strideC,
                  N, K, lda, ldb, ldc, sAh, sAl, sBh, sBl);
}

// ---------------- fused x_proj GEMM (SIMT) + dt/B/C split ----------------
__global__ __launch_bounds__(256) void sgemm_xproj(
    const float* __restrict__ A, const float* __restrict__ B,
    const float* __restrict__ dtW, const float* __restrict__ dtb,
    float* __restrict__ dt, float* __restrict__ Bm, float* __restrict__ Cm)
{
    __shared__ float As[2][16][128];
    __shared__ float Bs[2][16][64];
    __shared__ float St[128][36];
    __shared__ float sdtW[128], sdtb[64];
    const int N = 34, K = 64, lda = 64, ldb = 34;
    const int bm = blockIdx.y * 128;
    const int tid = threadIdx.x;
    const int tr = tid >> 4, tc = tid & 15;
    const int br = tid >> 4, bc0 = (tid & 15) * 4;
    if (tid < 128) sdtW[tid] = dtW[tid];
    if (tid >= 128 && tid < 192) sdtb[tid-128] = dtb[tid-128];
    float acc[8][4];
    #pragma unroll
    for (int i = 0; i < 8; i++)
        #pragma unroll
        for (int j = 0; j < 4; j++) acc[i][j] = 0.f;

    float4 ra[2]; float rb[4];
    #pragma unroll
    for (int i = 0; i < 2; i++) {
        int idx = tid + i * 256;
        int r = idx >> 2, c4 = (idx & 3) * 4;
        ra[i] = *(const float4*)(A + (size_t)(bm + r) * lda + c4);
    }
    #pragma unroll
    for (int i = 0; i < 4; i++) {
        int n = bc0 + i;
        rb[i] = (n < N) ? B[(size_t)br * ldb + n] : 0.f;
    }
    int buf = 0;
    #pragma unroll
    for (int i = 0; i < 2; i++) {
        int idx = tid + i * 256;
        int r = idx >> 2, c4 = (idx & 3) * 4;
        As[0][c4+0][r]=ra[i].x; As[0][c4+1][r]=ra[i].y;
        As[0][c4+2][r]=ra[i].z; As[0][c4+3][r]=ra[i].w;
    }
    #pragma unroll
    for (int i = 0; i < 4; i++) Bs[0][br][bc0+i] = rb[i];
    __syncthreads();

    for (int k0 = 0; k0 < K; k0 += 16) {
        const bool more = (k0 + 16) < K;
        float4 ra2[2]; float rb2[4];
        if (more) {
            #pragma unroll
            for (int i = 0; i < 2; i++) {
                int idx = tid + i * 256;
                int r = idx >> 2, c4 = (idx & 3) * 4;
                ra2[i] = *(const float4*)(A + (size_t)(bm + r) * lda + k0 + 16 + c4);
            }
            #pragma unroll
            for (int i = 0; i < 4; i++) {
                int n = bc0 + i;
                rb2[i] = (n < N) ? B[(size_t)(k0 + 16 + br) * ldb + n] : 0.f;
            }
        }
        #pragma unroll
        for (int kk = 0; kk < 16; kk++) {
            float4 a0 = *(const float4*)&As[buf][kk][tr*8];
            float4 a1 = *(const float4*)&As[buf][kk][tr*8+4];
            float4 b0 = *(const float4*)&Bs[buf][kk][tc*4];
            float a[8] = {a0.x,a0.y,a0.z,a0.w,a1.x,a1.y,a1.z,a1.w};
            float b[4] = {b0.x,b0.y,b0.z,b0.w};
            #pragma unroll
            for (int i = 0; i < 8; i++)
                #pragma unroll
                for (int j = 0; j < 4; j++) acc[i][j] += a[i]*b[j];
        }
        if (more) {
            int nb = buf ^ 1;
            #pragma unroll
            for (int i = 0; i < 2; i++) {
                int idx = tid + i * 256;
                int r = idx >> 2, c4 = (idx & 3) * 4;
                As[nb][c4+0][r]=ra2[i].x; As[nb][c4+1][r]=ra2[i].y;
                As[nb][c4+2][r]=ra2[i].z; As[nb][c4+3][r]=ra2[i].w;
            }
            #pragma unroll
            for (int i = 0; i < 4; i++) Bs[nb][br][bc0+i] = rb2[i];
            __syncthreads();
            buf = nb;
        }
    }
    #pragma unroll
    for (int i = 0; i < 8; i++) {
        #pragma unroll
        for (int j = 0; j < 4; j++) {
            int n = tc*4 + j;
            if (n < N) St[tr*8 + i][n] = acc[i][j];
        }
    }
    __syncthreads();
    for (int idx = tid; idx < 128*64; idx += 256) {
        int r = idx >> 6, d = idx & 63;
        float v = St[r][0]*sdtW[d] + St[r][1]*sdtW[64+d] + sdtb[d];
        dt[(size_t)(bm + r)*64 + d] = (v > 20.f) ? v : log1pf(__expf(v));
    }
    for (int idx = tid; idx < 128*16; idx += 256) {
        int r = idx >> 4, n = idx & 15;
        Bm[(size_t)(bm + r)*16 + n] = St[r][2 + n];
        Cm[(size_t)(bm + r)*16 + n] = St[r][18 + n];
    }
}

// ---------------- stage 1: channel attention, token-split Gram ----------------
__global__ void k_gram_part(const float* __restrict__ qc, float* __restrict__ gpart) {
    int b = blockIdx.x, h = blockIdx.y, z = blockIdx.z;
    __shared__ float kt[32][28], qt[32][28];
    int tid = threadIdx.x;   // 256
    float a00=0.f, a01=0.f, a10=0.f, a11=0.f;
    int i0 = 0, j0 = 0;
    if (tid < 196) { i0 = 2*(tid/14); j0 = 2*(tid%14); }
    for (int nt = z*5; nt < z*5 + 5; nt++) {
        for (int idx = tid; idx < 896; idx += 256) {
            int n = idx / 28, i = idx % 28;
            size_t row = (size_t)b*1280 + nt*32 + n;
            kt[n][i] = qc[row*672 + 224 + h*28 + i];
            qt[n][i] = qc[row*672 + h*28 + i];
        }
        __syncthreads();
        if (tid < 196) {
            #pragma unroll
            for (int n = 0; n < 32; n++) {
                float k0 = kt[n][i0], k1 = kt[n][i0+1];
                float q0 = qt[n][j0], q1 = qt[n][j0+1];
                a00 += k0*q0; a01 += k0*q1;
                a10 += k1*q0; a11 += k1*q1;
            }
        } else if (tid < 224) {
            int i = tid - 196;
            #pragma unroll
            for (int n = 0; n < 32; n++) { float v = kt[n][i]; a00 += v*v; }
        } else if (tid < 252) {
            int j = tid - 224;
            #pragma unroll
            for (int n = 0; n < 32; n++) { float v = qt[n][j]; a00 += v*v; }
        }
        __syncthreads();
    }
    float* gp = gpart + (((size_t)(b*8 + h))*8 + z)*840;
    if (tid < 196) {
        gp[i0*28 + j0]       = a00;
        gp[i0*28 + j0 + 1]   = a01;
        gp[(i0+1)*28 + j0]   = a10;
        gp[(i0+1)*28 + j0+1] = a11;
    } else if (tid < 224) {
        gp[784 + (tid - 196)] = a00;
    } else if (tid < 252) {
        gp[812 + (tid - 224)] = a00;
    }
}

__global__ void k_gram_fin(const float* __restrict__ gpart, float* __restrict__ attn) {
    int b = blockIdx.x, h = blockIdx.y;
    __shared__ float G[840];
    int tid = threadIdx.x;   // 256
    const float* gp = gpart + ((size_t)(b*8 + h))*8*840;
    #pragma unroll
    for (int s = 0; s < 4; s++) {
        int w = tid + 256*s;
        if (w < 840) {
            float a = 0.f;
            #pragma unroll
            for (int z = 0; z < 8; z++) a += gp[z*840 + w];
            G[w] = a;
        }
    }
    __syncthreads();
    if (tid < 28) {
        int i = tid;
        float nk = fmaxf(sqrtf(G[784+i]), 1e-12f);
        float lg[28], m = -1e30f;
        #pragma unroll
        for (int j = 0; j < 28; j++) {
            float nq = fmaxf(sqrtf(G[812+j]), 1e-12f);
            lg[j] = G[i*28+j] / (nk*nq) * 0.18898223650461363f;
            m = fmaxf(m, lg[j]);
        }
        float sum = 0.f;
        #pragma unroll
        for (int j = 0; j < 28; j++) { lg[j] = __expf(lg[j]-m); sum += lg[j]; }
        float inv = 1.f/sum;
        #pragma unroll
        for (int j = 0; j < 28; j++)
            attn[(((size_t)b*8 + h)*28 + i)*28 + j] = lg[j]*inv;
    }
}

// x1 = attn-applied + residual; 32 rows per block
__global__ void k_apply(const float* __restrict__ x, const float* __restrict__ qc,
                        const float* __restrict__ attn, float* __restrict__ x1) {
    int chunk = blockIdx.x, b = blockIdx.y;
    __shared__ float vr[8][224];
    int tid = threadIdx.x;   // 224
    int h = tid / 28, i = tid % 28;
    float att[28];
    {
        const float4* ap = (const float4*)(attn + (((size_t)b*8 + h)*28 + i)*28);
        #pragma unroll
        for (int q4 = 0; q4 < 7; q4++) {
            float4 v = ap[q4];
            att[q4*4+0]=v.x; att[q4*4+1]=v.y; att[q4*4+2]=v.z; att[q4*4+3]=v.w;
        }
    }
    for (int nn = 0; nn < 32; nn += 8) {
        size_t row0 = (size_t)b*1280 + chunk*32 + nn;
        __syncthreads();
        for (int idx = tid; idx < 1792; idx += 224) {
            int rr = idx / 224, cc = idx % 224;
            vr[rr][cc] = qc[(row0 + rr)*672 + 448 + cc];
        }
        __syncthreads();
        #pragma unroll
        for (int rr = 0; rr < 8; rr++) {
            float a = 0.f;
            #pragma unroll
            for (int j = 0; j < 28; j++) a += att[j] * vr[rr][h*28 + j];
            size_t o = (row0 + rr)*224 + tid;
            x1[o] = x[o] + a;
        }
    }
}

// ---------------- transpose + LN; coalesced fp32 + bf16 hi/lo output ---------
__global__ void k_ln1(const float* __restrict__ x1, const float* __restrict__ g,
                      const float* __restrict__ be, float* __restrict__ xn,
                      __nv_bfloat16* __restrict__ xnh, __nv_bfloat16* __restrict__ xnl) {
    int ww = blockIdx.x, b = blockIdx.y;
    __shared__ float s[32*225];
    __shared__ float sg[32], sb[32];
    int tid = threadIdx.x;   // 256
    if (tid < 32) { sg[tid] = g[tid]; sb[tid] = be[tid]; }
    for (int idx = tid; idx < 32*224; idx += 256) {
        int m = idx / 224, cc = idx % 224;
        s[m*225 + cc] = x1[((size_t)b*1280 + m*40 + ww)*224 + cc];
    }
    __syncthreads();
    float v[32];
    if (tid < 224) {
        float mean = 0.f;
        #pragma unroll
        for (int m = 0; m < 32; m++) { v[m] = s[m*225 + tid]; mean += v[m]; }
        mean *= (1.f/32.f);
        float var = 0.f;
        #pragma unroll
        for (int m = 0; m < 32; m++) { float d = v[m]-mean; var += d*d; }
        var *= (1.f/32.f);
        float inv = rsqrtf(var + 1e-5f);
        #pragma unroll
        for (int m = 0; m < 32; m++) v[m] = (v[m]-mean)*inv*sg[m] + sb[m];
    }
    __syncthreads();
    if (tid < 224) {
        #pragma unroll
        for (int m = 0; m < 32; m++) s[tid*32 + m] = v[m];
    }
    __syncthreads();
    size_t base = ((size_t)b*8960 + ww*224)*32;
    for (int idx = tid; idx < 7168; idx += 256) {
        float val = s[idx];
        xn[base + idx] = val;
        __nv_bfloat16 h, l; bfsplit(val, h, l);
        xnh[base + idx] = h; xnl[base + idx] = l;
    }
}

// ---------------- conv1d: smem-tiled, 128 rows x 64 d per block --------------
__global__ __launch_bounds__(256) void k_conv1d(
    const float* __restrict__ xz, const float* __restrict__ cw,
    const float* __restrict__ cb, float* __restrict__ xc) {
    __shared__ float sx[131][64];
    int bx = blockIdx.x;            // 2240 = 32 b * 70 chunks
    int b = bx / 70, chunk = bx % 70;
    int l0 = chunk * 128;
    int tid = threadIdx.x;
    // load halo+tile: rows l0-3 .. l0+127, first 64 channels of xz (pitch 128)
    for (int idx = tid; idx < 131*16; idx += 256) {
        int r = idx >> 4, c4 = (idx & 15) * 4;
        int l = l0 - 3 + r;
        float4 v = make_float4(0.f, 0.f, 0.f, 0.f);
        if (l >= 0) v = *(const float4*)(xz + ((size_t)b*8960 + l)*128 + c4);
        *(float4*)&sx[r][c4] = v;
    }
    __syncthreads();
    int r0 = (tid >> 4) * 8, d4 = (tid & 15) * 4;
    float w[4][4];
    #pragma unroll
    for (int dd = 0; dd < 4; dd++)
        #pragma unroll
        for (int t = 0; t < 4; t++) w[dd][t] = cw[(d4+dd)*4 + t];
    float b0 = cb[d4], b1 = cb[d4+1], b2 = cb[d4+2], b3 = cb[d4+3];
    #pragma unroll
    for (int s = 0; s < 8; s++) {
        int rr = r0 + s;                 // output row rr; smem rows rr..rr+3 = l-3..l
        float a0 = b0, a1 = b1, a2 = b2, a3 = b3;
        #pragma unroll
        for (int t = 0; t < 4; t++) {
            float4 v = *(const float4*)&sx[rr + t][d4];
            a0 += v.x * w[0][t];
            a1 += v.y * w[1][t];
            a2 += v.z * w[2][t];
            a3 += v.w * w[3][t];
        }
        float4 o; o.x = siluf(a0); o.y = siluf(a1); o.z = siluf(a2); o.w = siluf(a3);
        *(float4*)(xc + ((size_t)b*8960 + l0 + rr)*64 + d4) = o;
    }
}

__global__ __launch_bounds__(256) void k_scan1(
    const float* __restrict__ dt, const float* __restrict__ xc,
    const float* __restrict__ Bm, const float* __restrict__ Alog,
    float* __restrict__ S, float* __restrict__ sumdt) {
    int bx = blockIdx.x;                 // 8960
    int b = bx / 280, rem = bx % 280;
    int chunk = rem >> 2, dg = rem & 3;
    int tid = threadIdx.x, warp = tid >> 5, lane = tid & 31;
    int dloc = 2*warp + (lane >> 4), n = lane & 15;
    int d = dg*16 + dloc;
    __shared__ float sdt[16][16], sxc[16][16], sbm[16][16];
    float Av = -__expf(Alog[d*16 + n]);
    float h = 0.f, sdsum = 0.f;
    size_t rowbase = (size_t)b*8960 + chunk*128;
    int lr = tid >> 4, lc = tid & 15;
    for (int s = 0; s < 8; s++) {
        size_t r0 = rowbase + s*16;
        __syncthreads();
        sdt[lr][lc] = dt[(r0 + lr)*64 + dg*16 + lc];
        sxc[lr][lc] = xc[(r0 + lr)*64 + dg*16 + lc];
        sbm[lr][lc] = Bm[(r0 + lr)*16 + lc];
        __syncthreads();
        #pragma unroll
        for (int l = 0; l < 16; l++) {
            float dtv = sdt[l][dloc];
            float u   = sxc[l][dloc];
            float Bn  = sbm[l][n];
            h = __expf(Av*dtv)*h + dtv*u*Bn;
            sdsum += dtv;
        }
    }
    size_t idx = (size_t)(b*64 + d)*70 + chunk;
    S[idx*16 + n] = h;
    if (n == 0) sumdt[idx] = sdsum;
}

__global__ void k_scan2(const float* __restrict__ S, const float* __restrict__ sumdt,
                        const float* __restrict__ Alog, float* __restrict__ H0) {
    int t = blockIdx.x*256 + threadIdx.x;
    int b = t >> 10; int d = (t >> 4) & 63; int n = t & 15;
    float Av = -__expf(Alog[d*16 + n]);
    float carry = 0.f;
    size_t base = (size_t)(b*64 + d)*70;
    for (int ch = 0; ch < 70; ch++) {
        size_t idx = base + ch;
        H0[idx*16 + n] = carry;
        carry = carry*__expf(Av*sumdt[idx]) + S[idx*16 + n];
    }
}

__global__ __launch_bounds__(256) void k_scan3(
    const float* __restrict__ dt, const float* __restrict__ xc,
    const float* __restrict__ Bm, const float* __restrict__ Cm,
    const float* __restrict__ Alog, const float* __restrict__ H0,
    float* __restrict__ y) {
    int bx = blockIdx.x;
    int b = bx / 280, rem = bx % 280;
    int chunk = rem >> 2, dg = rem & 3;
    int tid = threadIdx.x, warp = tid >> 5, lane = tid & 31;
    int dloc = 2*warp + (lane >> 4), n = lane & 15;
    int d = dg*16 + dloc;
    __shared__ float sdt[16][16], sxc[16][16], sbm[16][16], scm[16][16], sy[16][16];
    float Av = -__expf(Alog[d*16 + n]);
    size_t idx = (size_t)(b*64 + d)*70 + chunk;
    float h = H0[idx*16 + n];
    size_t rowbase = (size_t)b*8960 + chunk*128;
    int lr = tid >> 4, lc = tid & 15;
    for (int s = 0; s < 8; s++) {
        size_t r0 = rowbase + s*16;
        __syncthreads();
        sdt[lr][lc] = dt[(r0 + lr)*64 + dg*16 + lc];
        sxc[lr][lc] = xc[(r0 + lr)*64 + dg*16 + lc];
        sbm[lr][lc] = Bm[(r0 + lr)*16 + lc];
        scm[lr][lc] = Cm[(r0 + lr)*16 + lc];
        __syncthreads();
        #pragma unroll
        for (int l = 0; l < 16; l++) {
            float dtv = sdt[l][dloc];
            float u   = sxc[l][dloc];
            float Bn  = sbm[l][n];
            h = __expf(Av*dtv)*h + dtv*u*Bn;
            float yv = h * scm[l][n];
            yv += __shfl_xor_sync(0xffffffffu, yv, 8);
            yv += __shfl_xor_sync(0xffffffffu, yv, 4);
            yv += __shfl_xor_sync(0xffffffffu, yv, 2);
            yv += __shfl_xor_sync(0xffffffffu, yv, 1);
            if (n == 0) sy[l][dloc] = yv;
        }
        __syncthreads();
        y[(r0 + lr)*64 + dg*16 + lc] = sy[lr][lc];
    }
}

__global__ void k_final(const float* __restrict__ y, const float* __restrict__ xc,
                        const float* __restrict__ xz, const float* __restrict__ xn,
                        const float* __restrict__ Dp, const float* __restrict__ opW,
                        const float* __restrict__ skipp, const float* __restrict__ g,
                        const float* __restrict__ be, const float* __restrict__ projW,
                        const float* __restrict__ projb, float* __restrict__ xm2) {
    __shared__ float sop[2048], spj[1024];
    int tid = threadIdx.x;   // 256
    for (int i = tid; i < 2048; i += 256) sop[i] = opW[i];
    for (int i = tid; i < 1024; i += 256) spj[i] = projW[i];
    __syncthreads();
    int warp = tid >> 5, lane = tid & 31;
    float skip = skipp[0];
    float dpl = Dp[lane], dph = Dp[32+lane];
    float gl = g[lane], bel = be[lane], pbl = projb[lane];
    #pragma unroll
    for (int t = 0; t < 8; t++) {
        size_t r = ((size_t)blockIdx.x*8 + warp)*8 + t;
        float y0 = y[r*64 + lane],      y1 = y[r*64 + 32 + lane];
        float c0 = xc[r*64 + lane],     c1 = xc[r*64 + 32 + lane];
        float z0 = xz[r*128 + 64 + lane], z1 = xz[r*128 + 96 + lane];
        float yy0 = (y0 + c0*dpl) * siluf(z0);
        float yy1 = (y1 + c1*dph) * siluf(z1);
        float acc = 0.f;
        #pragma unroll
        for (int d = 0; d < 32; d++) acc += __shfl_sync(0xffffffffu, yy0, d) * sop[d*32 + lane];
        #pragma unroll
        for (int d = 0; d < 32; d++) acc += __shfl_sync(0xffffffffu, yy1, d) * sop[(d+32)*32 + lane];
        float xm = acc + skip * xn[r*32 + lane];
        float mean = xm;
        #pragma unroll
        for (int o = 16; o; o >>= 1) mean += __shfl_xor_sync(0xffffffffu, mean, o);
        mean *= (1.f/32.f);
        float dv = xm - mean, var = dv*dv;
        #pragma unroll
        for (int o = 16; o; o >>= 1) var += __shfl_xor_sync(0xffffffffu, var, o);
        var *= (1.f/32.f);
        float v = dv * rsqrtf(var + 1e-5f) * gl + bel;
        float acc2 = pbl;
        #pragma unroll
        for (int mm = 0; mm < 32; mm++) acc2 += __shfl_sync(0xffffffffu, v, mm) * spj[mm*32 + lane];
        xm2[r*32 + lane] = acc2;
    }
}

__global__ void k_addback(const float* __restrict__ x1, const float* __restrict__ xm2,
                          float* __restrict__ x2) {
    int ww = blockIdx.x, b = blockIdx.y;
    __shared__ float s[224*33];
    int tid = threadIdx.x;   // 256
    for (int idx = tid; idx < 224*32; idx += 256) {
        int cc = idx >> 5, m = idx & 31;
        s[cc*33 + m] = xm2[((size_t)b*8960 + ww*224 + cc)*32 + m];
    }
    __syncthreads();
    for (int idx = tid; idx < 32*224; idx += 256) {
        int m = idx / 224, cc = idx % 224;
        size_t o = ((size_t)b*1280 + m*40 + ww)*224 + cc;
        x2[o] = x1[o] + s[cc*33 + m];
    }
}

// ---------------- conv3d 5x5x5, pad 2, smem-tiled per ky-plane ----------------
__global__ void k_conv3d(const float* __restrict__ x2, const float* __restrict__ cw,
                         const float* __restrict__ cb, float* __restrict__ x3) {
    int y = blockIdx.x, b = blockIdx.y;
    int xx = threadIdx.x;   // 224
    __shared__ float ws[125];
    __shared__ float sp[32][228];
    if (xx < 125) ws[xx] = cw[xx];
    if (xx < 32) { sp[xx][0]=0.f; sp[xx][1]=0.f; sp[xx][226]=0.f; sp[xx][227]=0.f; }
    float acc[32];
    #pragma unroll
    for (int d = 0; d < 32; d++) acc[d] = 0.f;
    for (int ky = 0; ky < 5; ky++) {
        int yy = y + ky - 2;
        if (yy < 0 || yy >= 40) continue;
        __syncthreads();
        for (int i = 0; i < 32; i++)
            sp[i][xx+2] = x2[(((size_t)b*32 + i)*40 + yy)*224 + xx];
        __syncthreads();
        #pragma unroll
        for (int kx = 0; kx < 5; kx++) {
            float v[36];
            v[0]=v[1]=v[34]=v[35]=0.f;
            #pragma unroll
            for (int i = 0; i < 32; i++) v[i+2] = sp[i][xx + kx];
            #pragma unroll
            for (int kz = 0; kz < 5; kz++) {
                float wv = ws[(kz*5 + ky)*5 + kx];
                #pragma unroll
                for (int d = 0; d < 32; d++) acc[d] += v[d+kz]*wv;
            }
        }
    }
    float bias = cb[0];
    #pragma unroll
    for (int d = 0; d < 32; d++)
        x3[(((size_t)b*32 + d)*40 + y)*224 + xx] = acc[d] + bias;
}

// ---------------- DWT: 4 subbands per thread, emits bf16 hi/lo ----------------
__global__ void k_dwt(const float* __restrict__ x3,
                      __nv_bfloat16* __restrict__ xwh, __nv_bfloat16* __restrict__ xwl) {
    size_t id = (size_t)blockIdx.x*256 + threadIdx.x;   // 2752512
    int c = (int)(id % 224); size_t rw = id / 224;
    int win = (int)(rw >> 6), tok = (int)(rw & 63);
    int bb = win / 6, w6 = win % 6;
    int wi = w6 / 3, wj = w6 % 3;
    int ti = tok >> 3, tj = tok & 7;
    int i2 = wi*8 + ti;
    int j2 = wj*8 + tj;
    int j = (j2 < 20) ? j2 : 38 - j2;   // reflect pad
    size_t base = (((size_t)bb*32 + 2*i2)*40 + 2*j)*224 + c;
    float a  = x3[base],        bv = x3[base + 224];
    float c2 = x3[base + 8960], d2 = x3[base + 9184];
    const size_t SS = (size_t)12288*224;
    float v0 = 0.5f*(a + bv + c2 + d2);
    float v1 = 0.5f*(a + bv - c2 - d2);
    float v2 = 0.5f*(a - bv + c2 - d2);
    float v3 = 0.5f*(a - bv - c2 + d2);
    __nv_bfloat16 h, l;
    bfsplit(v0, h, l); xwh[id]        = h; xwl[id]        = l;
    bfsplit(v1, h, l); xwh[id + SS]   = h; xwl[id + SS]   = l;
    bfsplit(v2, h, l); xwh[id + 2*SS] = h; xwl[id + 2*SS] = l;
    bfsplit(v3, h, l); xwh[id + 3*SS] = h; xwl[id + 3*SS] = l;
}

// ---------------- window attention: online softmax, staged bf16 hi/lo out ----
__global__ void k_wattn(const float* __restrict__ qkvw, const float* __restrict__ pe,
                        __nv_bfloat16* __restrict__ obh, __nv_bfloat16* __restrict__ obl) {
    int win = blockIdx.x, head = blockIdx.y;
    __shared__ __align__(16) float ks[64*28], vs[64*28];
    __shared__ __nv_bfloat16 oh[64*28], ol[64*28];
    int tid = threadIdx.x;   // 64
    size_t wbase = (size_t)win * 64;
    for (int idx = tid; idx < 1792; idx += 64) {
        int tok = idx / 28, dd = idx % 28;
        size_t rb = (wbase + tok)*672 + head*28 + dd;
        ks[idx] = qkvw[rb + 224];
        vs[idx] = qkvw[rb + 448];
    }
    float qr[28];
    {
        const float4* qp = (const float4*)(qkvw + (wbase + tid)*672 + head*28);
        #pragma unroll
        for (int q4 = 0; q4 < 7; q4++) {
            float4 v = qp[q4];
            qr[q4*4+0] = v.x * 0.18898223650461363f;
            qr[q4*4+1] = v.y * 0.18898223650461363f;
            qr[q4*4+2] = v.z * 0.18898223650461363f;
            qr[q4*4+3] = v.w * 0.18898223650461363f;
        }
    }
    __syncthreads();
    const float* per = pe + ((size_t)head*64 + tid)*64;
    float m = -1e30f, sum = 0.f;
    float acc[28];
    #pragma unroll
    for (int dd = 0; dd < 28; dd++) acc[dd] = 0.f;
    for (int j = 0; j < 64; j++) {
        const float4* k4 = (const float4*)&ks[j*28];
        float dot = 0.f;
        #pragma unroll
        for (int q4 = 0; q4 < 7; q4++) {
            float4 kk = k4[q4];
            dot += qr[q4*4+0]*kk.x + qr[q4*4+1]*kk.y
                 + qr[q4*4+2]*kk.z + qr[q4*4+3]*kk.w;
        }
        dot += per[j];
        if (dot > m) {
            float corr = __expf(m - dot);
            sum *= corr;
            #pragma unroll
            for (int dd = 0; dd < 28; dd++) acc[dd] *= corr;
            m = dot;
        }
        float e = __expf(dot - m);
        sum += e;
        const float4* v4 = (const float4*)&vs[j*28];
        #pragma unroll
        for (int q4 = 0; q4 < 7; q4++) {
            float4 vv = v4[q4];
            acc[q4*4+0] += e*vv.x; acc[q4*4+1] += e*vv.y;
            acc[q4*4+2] += e*vv.z; acc[q4*4+3] += e*vv.w;
        }
    }
    float inv = 1.f / sum;
    #pragma unroll
    for (int dd = 0; dd < 28; dd++) {
        __nv_bfloat16 h, l;
        bfsplit(acc[dd] * inv, h, l);
        oh[tid*28 + dd] = h; ol[tid*28 + dd] = l;
    }
    __syncthreads();
    for (int idx = tid; idx < 1792; idx += 64) {
        int tok = idx / 28, dd = idx % 28;
        size_t o = (wbase + tok)*224 + head*28 + dd;
        obh[o] = oh[idx]; obl[o] = ol[idx];
    }
}

// ---------------- IWT + biases + crop + final layout ----------------
__global__ void k_iwt(const float* __restrict__ oproj,
                      const float* __restrict__ b1, const float* __restrict__ b2,
                      const float* __restrict__ b3, const float* __restrict__ b4,
                      float* __restrict__ out) {
    size_t id = (size_t)blockIdx.x*256 + threadIdx.x;   // 2293760
    int c = (int)(id % 224); size_t r = id / 224;
    int j = (int)(r % 20); r /= 20;
    int i = (int)(r % 16); int bb = (int)(r / 16);
    int wi = i >> 3, ti = i & 7, wj = j >> 3, tj = j & 7;
    size_t row0 = ((size_t)(bb*6 + wi*3 + wj))*64 + ti*8 + tj;
    float A  = oproj[row0*224 + c]           + b1[c];
    float Hh = oproj[(row0 + 12288)*224 + c] + b2[c];
    float V  = oproj[(row0 + 24576)*224 + c] + b3[c];
    float D  = oproj[(row0 + 36864)*224 + c] + b4[c];
    size_t oo = (((size_t)bb*32 + 2*i)*40 + 2*j)*224 + c;
    out[oo]          = 0.5f*(A + Hh + V + D);
    out[oo + 224]    = 0.5f*(A + Hh - V - D);
    out[oo + 8960]   = 0.5f*(A - Hh + V - D);
    out[oo + 9184]   = 0.5f*(A - Hh - V + D);
}

// ---------------- launcher ----------------
extern "C" void kernel_launch(void* const* d_in, const int* in_sizes, int n_in,
                              void* d_out, int out_size) {
    const float* x       = (const float*)d_in[0];
    const float* Wq      = (const float*)d_in[1];
    const float* Wkv     = (const float*)d_in[2];
    const float* ln_g    = (const float*)d_in[3];
    const float* ln_b    = (const float*)d_in[4];
    const float* in_proj = (const float*)d_in[5];
    const float* conv1dW = (const float*)d_in[6];
    const float* conv1db = (const float*)d_in[7];
    const float* x_projW = (const float*)d_in[8];
    const float* dt_projW= (const float*)d_in[9];
    const float* dt_projb= (const float*)d_in[10];
    const float* A_log   = (const float*)d_in[11];
    const float* Dp      = (const float*)d_in[12];
    const float* out_projW=(const float*)d_in[13];
    const float* skip    = (const float*)d_in[14];
    const float* projW   = (const float*)d_in[15];
    const float* projb   = (const float*)d_in[16];
    const float* conv3dW = (const float*)d_in[17];
    const float* conv3db = (const float*)d_in[18];
    const float* Wq1     = (const float*)d_in[19];
    const float* Wkv1    = (const float*)d_in[20];
    const float* pos_emb = (const float*)d_in[21];
    const float* Wo[4]   = {(const float*)d_in[22],(const float*)d_in[24],
                            (const float*)d_in[26],(const float*)d_in[28]};
    const float* bo[4]   = {(const float*)d_in[23],(const float*)d_in[25],
                            (const float*)d_in[27],(const float*)d_in[29]};
    float* out = (float*)d_out;

    float *p_attn, *p_gp, *p_x1, *p_xn, *p_xz, *p_xc, *p_dt,
          *p_Bm, *p_Cm, *p_y, *p_S, *p_sd, *p_H0, *p_xm2, *p_x2, *p_x3,
          *p_qkvw, *p_oproj;
    cudaGetSymbolAddress((void**)&p_attn, g_attn);
    cudaGetSymbolAddress((void**)&p_gp,   g_gpart);
    cudaGetSymbolAddress((void**)&p_x1,   g_x1);
    cudaGetSymbolAddress((void**)&p_xn,   g_xn);
    cudaGetSymbolAddress((void**)&p_xz,   g_xz);
    cudaGetSymbolAddress((void**)&p_xc,   g_xc);
    cudaGetSymbolAddress((void**)&p_dt,   g_dt);
    cudaGetSymbolAddress((void**)&p_Bm,   g_Bm);
    cudaGetSymbolAddress((void**)&p_Cm,   g_Cm);
    cudaGetSymbolAddress((void**)&p_y,    g_y);
    cudaGetSymbolAddress((void**)&p_S,    g_S);
    cudaGetSymbolAddress((void**)&p_sd,   g_sumdt);
    cudaGetSymbolAddress((void**)&p_H0,   g_H0);
    cudaGetSymbolAddress((void**)&p_xm2,  g_xm2);
    cudaGetSymbolAddress((void**)&p_x2,   g_x2);
    cudaGetSymbolAddress((void**)&p_x3,   g_x3);
    cudaGetSymbolAddress((void**)&p_qkvw, g_qkvw);
    cudaGetSymbolAddress((void**)&p_oproj,g_oproj);

    __nv_bfloat16 *p_xh,*p_xl,*p_xnh,*p_xnl,*p_xwh,*p_xwl,*p_obh,*p_obl,
        *p_Wc1h,*p_Wc1l,*p_Wc2h,*p_Wc2l,*p_iph,*p_ipl,*p_Woh,*p_Wol;
    cudaGetSymbolAddress((void**)&p_xh,   g_xh);
    cudaGetSymbolAddress((void**)&p_xl,   g_xlo);
    cudaGetSymbolAddress((void**)&p_xnh,  g_xnh);
    cudaGetSymbolAddress((void**)&p_xnl,  g_xnl);
    cudaGetSymbolAddress((void**)&p_xwh,  g_xwh);
    cudaGetSymbolAddress((void**)&p_xwl,  g_xwl);
    cudaGetSymbolAddress((void**)&p_obh,  g_obh);
    cudaGetSymbolAddress((void**)&p_obl,  g_obl);
    cudaGetSymbolAddress((void**)&p_Wc1h, g_Wc1h);
    cudaGetSymbolAddress((void**)&p_Wc1l, g_Wc1l);
    cudaGetSymbolAddress((void**)&p_Wc2h, g_Wc2h);
    cudaGetSymbolAddress((void**)&p_Wc2l, g_Wc2l);
    cudaGetSymbolAddress((void**)&p_iph,  g_iph);
    cudaGetSymbolAddress((void**)&p_ipl,  g_ipl);
    cudaGetSymbolAddress((void**)&p_Woh,  g_Woh);
    cudaGetSymbolAddress((void**)&p_Wol,  g_Wol);

    // ---- splits: input (big) + all weights (one batched launch) ----
    k_split<<<(9175040+255)/256, 256>>>(x, p_xh, p_xl, 9175040);
    SplitArgs sa;
    sa.s[0] = {Wq,      p_Wc1h, p_Wc1l, 50176,  224, 672, 0};
    sa.s[1] = {Wkv,     p_Wc1h, p_Wc1l, 100352, 448, 672, 224};
    sa.s[2] = {in_proj, p_iph,  p_ipl,  4096,   0, 0, 0};
    sa.s[3] = {Wq1,     p_Wc2h, p_Wc2l, 50176,  224, 672, 0};
    sa.s[4] = {Wkv1,    p_Wc2h, p_Wc2l, 100352, 448, 672, 224};
    sa.s[5] = {Wo[0], p_Woh,          p_Wol,          50176, 0, 0, 0};
    sa.s[6] = {Wo[1], p_Woh + 50176,  p_Wol + 50176,  50176, 0, 0, 0};
    sa.s[7] = {Wo[2], p_Woh + 100352, p_Wol + 100352, 50176, 0, 0, 0};
    sa.s[8] = {Wo[3], p_Woh + 150528, p_Wol + 150528, 50176, 0, 0, 0};
    sa.s[9] = {Wq, p_Wc1h, p_Wc1l, 0, 0, 0, 0};   // unused
    k_split_multi<<<dim3(392, 10), 256>>>(sa);

    // stage 1: combined qkv GEMM (N=672), token-split gram, apply
    tgemm_bf<<<dim3(6, 320), 256>>>(p_xh, p_xl, p_Wc1h, p_Wc1l, p_qkvw,
                                    672, 224, 224, 672, 672);
    k_gram_part<<<dim3(32, 8, 8), 256>>>(p_qkvw, p_gp);
    k_gram_fin <<<dim3(32, 8), 256>>>(p_gp, p_attn);
    k_apply<<<dim3(40, 32), 224>>>(x, p_qkvw, p_attn, p_x1);

    // stage 2: mamba
    k_ln1<<<dim3(40, 32), 256>>>(p_x1, ln_g, ln_b, p_xn, p_xnh, p_xnl);
    tgemm_bf<<<dim3(1, 2240), 256>>>(p_xnh, p_xnl, p_iph, p_ipl, p_xz, 128, 32, 32, 128, 128);
    k_conv1d<<<2240, 256>>>(p_xz, conv1dW, conv1db, p_xc);
    sgemm_xproj<<<dim3(1, 2240), 256>>>(p_xc, x_projW, dt_projW, dt_projb,
                                        p_dt, p_Bm, p_Cm);
    k_scan1<<<8960, 256>>>(p_dt, p_xc, p_Bm, A_log, p_S, p_sd);
    k_scan2<<<128, 256>>>(p_S, p_sd, A_log, p_H0);
    k_scan3<<<8960, 256>>>(p_dt, p_xc, p_Bm, p_Cm, A_log, p_H0, p_y);
    k_final<<<4480, 256>>>(p_y, p_xc, p_xz, p_xn, Dp, out_projW, skip,
                           ln_g, ln_b, projW, projb, p_xm2);
    k_addback<<<dim3(40, 32), 256>>>(p_x1, p_xm2, p_x2);

    // stage 3: conv3d
    k_conv3d<<<dim3(40, 32), 224>>>(p_x2, conv3dW, conv3db, p_x3);

    // stage 4: DWT + combined window-qkv GEMM + window attention
    k_dwt<<<10752, 256>>>(p_x3, p_xwh, p_xwl);
    tgemm_bf<<<dim3(6, 384), 256>>>(p_xwh, p_xwl, p_Wc2h, p_Wc2l, p_qkvw,
                                    672, 224, 224, 672, 672);
    k_wattn<<<dim3(768, 8), 64>>>(p_qkvw, pos_emb, p_obh, p_obl);
    BfPtrs4 po;
    for (int s = 0; s < 4; s++) { po.Bh[s] = p_Woh + s*50176; po.Bl[s] = p_Wol + s*50176; }
    tgemm_bf_b4<<<dim3(2, 96, 4), 256>>>(p_obh, p_obl, po, p_oproj,
                                         224, 224, 224, 224, 224,
                                         (long long)12288*224, (long long)12288*224);

    // stage 5: IWT + biases + output
    k_iwt<<<8960, 256>>>(p_oproj, bo[0], bo[1], bo[2], bo[3], out);
}

// round 17
// speedup vs baseline: 1.8255x; 1.0041x over previous
#include <cuda_runtime.h>
#include <cuda_bf16.h>
#include <mma.h>
#include <math.h>
#include <stdint.h>

using namespace nvcuda;

// ---------------- static scratch ----------------
__device__ __align__(16) float g_attn [32*8*28*28];
__device__ __align__(16) float g_gpart[32*8*8*840];   // partial Gram sums
__device__ __align__(16) float g_x1   [9175040];
__device__ __align__(16) float g_xn   [9175040];      // 286720 x 32
__device__ __align__(16) float g_xz   [36700160];     // 286720 x 128
__device__ __align__(16) float g_xc   [18350080];     // 286720 x 64
__device__ __align__(16) float g_dt   [18350080];
__device__ __align__(16) float g_Bm   [4587520];
__device__ __align__(16) float g_Cm   [4587520];
__device__ __align__(16) float g_y    [18350080];
__device__ __align__(16) float g_S    [2293760];
__device__ __align__(16) float g_sumdt[143360];
__device__ __align__(16) float g_H0   [2293760];
__device__ __align__(16) float g_xm2  [9175040];
__device__ __align__(16) float g_x2   [9175040];
__device__ __align__(16) float g_x3   [9175040];
__device__ __align__(16) float g_qkvw [33030144];     // 49152 x 672 (also stage-1 qkv 40960x672)
__device__ __align__(16) float g_oproj[11010048];

// bf16 hi/lo split scratch
__device__ __align__(16) __nv_bfloat16 g_xh  [9175040],  g_xlo  [9175040];
__device__ __align__(16) __nv_bfloat16 g_xnh [9175040],  g_xnl  [9175040];
__device__ __align__(16) __nv_bfloat16 g_xwh [11010048], g_xwl  [11010048];
__device__ __align__(16) __nv_bfloat16 g_obh [11010048], g_obl  [11010048];
__device__ __align__(16) __nv_bfloat16 g_Wc1h[150528], g_Wc1l[150528];   // [Wq|Wkv] 224x672
__device__ __align__(16) __nv_bfloat16 g_Wc2h[150528], g_Wc2l[150528];   // [Wq1|Wkv1]
__device__ __align__(16) __nv_bfloat16 g_iph [4096],   g_ipl [4096];
__device__ __align__(16) __nv_bfloat16 g_Woh [200704], g_Wol [200704];

__device__ __forceinline__ float siluf(float v){ return v / (1.f + __expf(-v)); }
__device__ __forceinline__ void bfsplit(float v, __nv_bfloat16& h, __nv_bfloat16& l) {
    h = __float2bfloat16(v);
    l = __float2bfloat16(v - __bfloat162float(h));
}
__device__ __forceinline__ uint32_t smem_u32(const void* p) {
    return (uint32_t)__cvta_generic_to_shared(p);
}
#define CPA16(saddr, gptr, nbytes) \
    asm volatile("cp.async.cg.shared.global [%0], [%1], 16, %2;" \
                 :: "r"(saddr), "l"(gptr), "r"(nbytes))
#define CPA_COMMIT() asm volatile("cp.async.commit_group;")
#define CPA_WAIT0()  asm volatile("cp.async.wait_group 0;")
#define CPA_WAIT1()  asm volatile("cp.async.wait_group 1;")

struct BfPtrs4 { const __nv_bfloat16* Bh[4]; const __nv_bfloat16* Bl[4]; };

// ---------------- fp32 -> bf16 hi/lo splits ----------------
__global__ void k_split(const float* __restrict__ in, __nv_bfloat16* __restrict__ hi,
                        __nv_bfloat16* __restrict__ lo, int n) {
    int i = blockIdx.x*256 + threadIdx.x;
    if (i < n) {
        __nv_bfloat16 h, l;
        bfsplit(in[i], h, l);
        hi[i] = h; lo[i] = l;
    }
}

struct SplitSeg { const float* src; __nv_bfloat16* hi; __nv_bfloat16* lo;
                  int n; int srcW; int dstPitch; int dstOff; };
struct SplitArgs { SplitSeg s[10]; };

__global__ void k_split_multi(SplitArgs a) {
    SplitSeg seg = a.s[blockIdx.y];
    int i = blockIdx.x*256 + threadIdx.x;
    if (i < seg.n) {
        __nv_bfloat16 h, l;
        bfsplit(seg.src[i], h, l);
        int o = i;
        if (seg.srcW) {
            int k = i / seg.srcW, c = i - k*seg.srcW;
            o = k*seg.dstPitch + seg.dstOff + c;
        }
        seg.hi[o] = h; seg.lo[o] = l;
    }
}

// ---------------- bf16 split tensor-core GEMM: 128x128 tile, 3-stage cp.async
#define APITCH 24
#define BPITCH 136
__device__ __forceinline__ void tgemm_bf_core(
    const __nv_bfloat16* __restrict__ Ah, const __nv_bfloat16* __restrict__ Al,
    const __nv_bfloat16* __restrict__ Bh, const __nv_bfloat16* __restrict__ Bl,
    float* __restrict__ C, int N, int K, int lda, int ldb, int ldc,
    __nv_bfloat16* sAh, __nv_bfloat16* sAl, __nv_bfloat16* sBh, __nv_bfloat16* sBl)
{
    const int bm = blockIdx.y*128, bn = blockIdx.x*128;
    const int tid = threadIdx.x, warp = tid >> 5;
    const int wm = warp >> 2, wn = warp & 3;   // 2 x 4 warps; warp tile 64x32
    wmma::fragment<wmma::accumulator,16,16,16,float> acc[4][2];
    #pragma unroll
    for (int i = 0; i < 4; i++)
        #pragma unroll
        for (int j = 0; j < 2; j++) wmma::fill_fragment(acc[i][j], 0.f);

    const int ar = tid >> 1, ac = (tid & 1)*8;
    const int brr = tid >> 4, bcc = (tid & 15)*8;
    const int bcol = bn + bcc;
    const int bbytes = (bcol < N) ? 16 : 0;

    const uint32_t uAh = smem_u32(sAh), uAl = smem_u32(sAl);
    const uint32_t uBh = smem_u32(sBh), uBl = smem_u32(sBl);
    const int ASZ = 128*APITCH, BSZ = 16*BPITCH;       // elements
    const uint32_t aoffb = (uint32_t)(ar*APITCH + ac)*2;
    const uint32_t boffb = (uint32_t)(brr*BPITCH + bcc)*2;
    const __nv_bfloat16* gAh = Ah + (size_t)(bm+ar)*lda + ac;
    const __nv_bfloat16* gAl = Al + (size_t)(bm+ar)*lda + ac;
    const __nv_bfloat16* gBh = Bh + (size_t)brr*ldb + bcol;
    const __nv_bfloat16* gBl = Bl + (size_t)brr*ldb + bcol;

    const int T = K >> 4;

    {
        CPA16(uAh + aoffb, gAh, 16);
        CPA16(uAl + aoffb, gAl, 16);
        CPA16(uBh + boffb, gBh, bbytes);
        CPA16(uBl + boffb, gBl, bbytes);
        CPA_COMMIT();
    }
    if (T > 1) {
        CPA16(uAh + (uint32_t)ASZ*2 + aoffb, gAh + 16, 16);
        CPA16(uAl + (uint32_t)ASZ*2 + aoffb, gAl + 16, 16);
        CPA16(uBh + (uint32_t)BSZ*2 + boffb, gBh + (size_t)16*ldb, bbytes);
        CPA16(uBl + (uint32_t)BSZ*2 + boffb, gBl + (size_t)16*ldb, bbytes);
        CPA_COMMIT();
        CPA_WAIT1();
    } else {
        CPA_WAIT0();
    }
    __syncthreads();

    for (int t = 0; t < T; t++) {
        if (t + 2 < T) {
            int nb = (t + 2) % 3;
            int k2 = (t + 2) * 16;
            CPA16(uAh + (uint32_t)nb*ASZ*2 + aoffb, gAh + k2, 16);
            CPA16(uAl + (uint32_t)nb*ASZ*2 + aoffb, gAl + k2, 16);
            CPA16(uBh + (uint32_t)nb*BSZ*2 + boffb, gBh + (size_t)k2*ldb, bbytes);
            CPA16(uBl + (uint32_t)nb*BSZ*2 + boffb, gBl + (size_t)k2*ldb, bbytes);
            CPA_COMMIT();
        }
        int buf = t % 3;
        __nv_bfloat16* cAh = sAh + buf*ASZ; __nv_bfloat16* cAl = sAl + buf*ASZ;
        __nv_bfloat16* cBh = sBh + buf*BSZ; __nv_bfloat16* cBl = sBl + buf*BSZ;
        wmma::fragment<wmma::matrix_b,16,16,16,__nv_bfloat16,wmma::row_major> fbh[2], fbl[2];
        #pragma unroll
        for (int j = 0; j < 2; j++) {
            wmma::load_matrix_sync(fbh[j], &cBh[wn*32 + j*16], BPITCH);
            wmma::load_matrix_sync(fbl[j], &cBl[wn*32 + j*16], BPITCH);
        }
        #pragma unroll
        for (int i = 0; i < 4; i++) {
            wmma::fragment<wmma::matrix_a,16,16,16,__nv_bfloat16,wmma::row_major> fah, fal;
            wmma::load_matrix_sync(fah, &cAh[(wm*64 + i*16)*APITCH], APITCH);
            wmma::load_matrix_sync(fal, &cAl[(wm*64 + i*16)*APITCH], APITCH);
            #pragma unroll
            for (int j = 0; j < 2; j++) {
                wmma::mma_sync(acc[i][j], fah, fbh[j], acc[i][j]);
                wmma::mma_sync(acc[i][j], fah, fbl[j], acc[i][j]);
                wmma::mma_sync(acc[i][j], fal, fbh[j], acc[i][j]);
            }
        }
        if (t + 1 < T) {
            if (t + 2 < T) { CPA_WAIT1(); } else { CPA_WAIT0(); }
            __syncthreads();
        }
    }
    #pragma unroll
    for (int i = 0; i < 4; i++)
        #pragma unroll
        for (int j = 0; j < 2; j++) {
            int n0 = bn + wn*32 + j*16;
            if (n0 < N)
                wmma::store_matrix_sync(C + (size_t)(bm + wm*64 + i*16)*ldc + n0,
                                        acc[i][j], ldc, wmma::mem_row_major);
        }
}

__global__ __launch_bounds__(256, 2) void tgemm_bf(
    const __nv_bfloat16* __restrict__ Ah, const __nv_bfloat16* __restrict__ Al,
    const __nv_bfloat16* __restrict__ Bh, const __nv_bfloat16* __restrict__ Bl,
    float* __restrict__ C, int N, int K, int lda, int ldb, int ldc)
{
    __shared__ __align__(16) __nv_bfloat16 sAh[3*128*APITCH], sAl[3*128*APITCH];
    __shared__ __align__(16) __nv_bfloat16 sBh[3*16*BPITCH],  sBl[3*16*BPITCH];
    tgemm_bf_core(Ah, Al, Bh, Bl, C, N, K, lda, ldb, ldc, sAh, sAl, sBh, sBl);
}

__global__ __launch_bounds__(256, 2) void tgemm_bf_b4(
    const __nv_bfloat16* __restrict__ Ah, const __nv_bfloat16* __restrict__ Al,
    BfPtrs4 p, float* __restrict__ C, int N, int K, int lda, int ldb, int ldc,
    long long strideA, long long strideC)
{
    __shared__ __align__(16) __nv_bfloat16 sAh[3*128*APITCH], sAl[3*128*APITCH];
    __shared__ __align__(16) __nv_bfloat16 sBh[3*16*BPITCH],  sBl[3*16*BPITCH];
    int z = blockIdx.z;
    tgemm_bf_core(Ah + (size_t)z*strideA, Al + (size_t)z*strideA,
                  p.Bh[z], p.Bl[z], C + (size_t)z*strideC,
                  N, K, lda, ldb, ldc, sAh, sAl, sBh, sBl);
}

// ---------------- fused x_proj GEMM (SIMT) + dt/B/C split ----------------
__global__ __launch_bounds__(256) void sgemm_xproj(
    const float* __restrict__ A, const float* __restrict__ B,
    const float* __restrict__ dtW, const float* __restrict__ dtb,
    float* __restrict__ dt, float* __restrict__ Bm, float* __restrict__ Cm)
{
    __shared__ float As[2][16][128];
    __shared__ float Bs[2][16][64];
    __shared__ float St[128][36];
    __shared__ float sdtW[128], sdtb[64];
    const int N = 34, K = 64, lda = 64, ldb = 34;
    const int bm = blockIdx.y * 128;
    const int tid = threadIdx.x;
    const int tr = tid >> 4, tc = tid & 15;
    const int br = tid >> 4, bc0 = (tid & 15) * 4;
    if (tid < 128) sdtW[tid] = dtW[tid];
    if (tid >= 128 && tid < 192) sdtb[tid-128] = dtb[tid-128];
    float acc[8][4];
    #pragma unroll
    for (int i = 0; i < 8; i++)
        #pragma unroll
        for (int j = 0; j < 4; j++) acc[i][j] = 0.f;

    float4 ra[2]; float rb[4];
    #pragma unroll
    for (int i = 0; i < 2; i++) {
        int idx = tid + i * 256;
        int r = idx >> 2, c4 = (idx & 3) * 4;
        ra[i] = *(const float4*)(A + (size_t)(bm + r) * lda + c4);
    }
    #pragma unroll
    for (int i = 0; i < 4; i++) {
        int n = bc0 + i;
        rb[i] = (n < N) ? B[(size_t)br * ldb + n] : 0.f;
    }
    int buf = 0;
    #pragma unroll
    for (int i = 0; i < 2; i++) {
        int idx = tid + i * 256;
        int r = idx >> 2, c4 = (idx & 3) * 4;
        As[0][c4+0][r]=ra[i].x; As[0][c4+1][r]=ra[i].y;
        As[0][c4+2][r]=ra[i].z; As[0][c4+3][r]=ra[i].w;
    }
    #pragma unroll
    for (int i = 0; i < 4; i++) Bs[0][br][bc0+i] = rb[i];
    __syncthreads();

    for (int k0 = 0; k0 < K; k0 += 16) {
        const bool more = (k0 + 16) < K;
        float4 ra2[2]; float rb2[4];
        if (more) {
            #pragma unroll
            for (int i = 0; i < 2; i++) {
                int idx = tid + i * 256;
                int r = idx >> 2, c4 = (idx & 3) * 4;
                ra2[i] = *(const float4*)(A + (size_t)(bm + r) * lda + k0 + 16 + c4);
            }
            #pragma unroll
            for (int i = 0; i < 4; i++) {
                int n = bc0 + i;
                rb2[i] = (n < N) ? B[(size_t)(k0 + 16 + br) * ldb + n] : 0.f;
            }
        }
        #pragma unroll
        for (int kk = 0; kk < 16; kk++) {
            float4 a0 = *(const float4*)&As[buf][kk][tr*8];
            float4 a1 = *(const float4*)&As[buf][kk][tr*8+4];
            float4 b0 = *(const float4*)&Bs[buf][kk][tc*4];
            float a[8] = {a0.x,a0.y,a0.z,a0.w,a1.x,a1.y,a1.z,a1.w};
            float b[4] = {b0.x,b0.y,b0.z,b0.w};
            #pragma unroll
            for (int i = 0; i < 8; i++)
                #pragma unroll
                for (int j = 0; j < 4; j++) acc[i][j] += a[i]*b[j];
        }
        if (more) {
            int nb = buf ^ 1;
            #pragma unroll
            for (int i = 0; i < 2; i++) {
                int idx = tid + i * 256;
                int r = idx >> 2, c4 = (idx & 3) * 4;
                As[nb][c4+0][r]=ra2[i].x; As[nb][c4+1][r]=ra2[i].y;
                As[nb][c4+2][r]=ra2[i].z; As[nb][c4+3][r]=ra2[i].w;
            }
            #pragma unroll
            for (int i = 0; i < 4; i++) Bs[nb][br][bc0+i] = rb2[i];
            __syncthreads();
            buf = nb;
        }
    }
    #pragma unroll
    for (int i = 0; i < 8; i++) {
        #pragma unroll
        for (int j = 0; j < 4; j++) {
            int n = tc*4 + j;
            if (n < N) St[tr*8 + i][n] = acc[i][j];
        }
    }
    __syncthreads();
    for (int idx = tid; idx < 128*64; idx += 256) {
        int r = idx >> 6, d = idx & 63;
        float v = St[r][0]*sdtW[d] + St[r][1]*sdtW[64+d] + sdtb[d];
        dt[(size_t)(bm + r)*64 + d] = (v > 20.f) ? v : log1pf(__expf(v));
    }
    for (int idx = tid; idx < 128*16; idx += 256) {
        int r = idx >> 4, n = idx & 15;
        Bm[(size_t)(bm + r)*16 + n] = St[r][2 + n];
        Cm[(size_t)(bm + r)*16 + n] = St[r][18 + n];
    }
}

// ---------------- stage 1: channel attention, token-split Gram ----------------
__global__ void k_gram_part(const float* __restrict__ qc, float* __restrict__ gpart) {
    int b = blockIdx.x, h = blockIdx.y, z = blockIdx.z;
    __shared__ float kt[32][28], qt[32][28];
    int tid = threadIdx.x;   // 256
    float a00=0.f, a01=0.f, a10=0.f, a11=0.f;
    int i0 = 0, j0 = 0;
    if (tid < 196) { i0 = 2*(tid/14); j0 = 2*(tid%14); }
    for (int nt = z*5; nt < z*5 + 5; nt++) {
        for (int idx = tid; idx < 896; idx += 256) {
            int n = idx / 28, i = idx % 28;
            size_t row = (size_t)b*1280 + nt*32 + n;
            kt[n][i] = qc[row*672 + 224 + h*28 + i];
            qt[n][i] = qc[row*672 + h*28 + i];
        }
        __syncthreads();
        if (tid < 196) {
            #pragma unroll
            for (int n = 0; n < 32; n++) {
                float k0 = kt[n][i0], k1 = kt[n][i0+1];
                float q0 = qt[n][j0], q1 = qt[n][j0+1];
                a00 += k0*q0; a01 += k0*q1;
                a10 += k1*q0; a11 += k1*q1;
            }
        } else if (tid < 224) {
            int i = tid - 196;
            #pragma unroll
            for (int n = 0; n < 32; n++) { float v = kt[n][i]; a00 += v*v; }
        } else if (tid < 252) {
            int j = tid - 224;
            #pragma unroll
            for (int n = 0; n < 32; n++) { float v = qt[n][j]; a00 += v*v; }
        }
        __syncthreads();
    }
    float* gp = gpart + (((size_t)(b*8 + h))*8 + z)*840;
    if (tid < 196) {
        gp[i0*28 + j0]       = a00;
        gp[i0*28 + j0 + 1]   = a01;
        gp[(i0+1)*28 + j0]   = a10;
        gp[(i0+1)*28 + j0+1] = a11;
    } else if (tid < 224) {
        gp[784 + (tid - 196)] = a00;
    } else if (tid < 252) {
        gp[812 + (tid - 224)] = a00;
    }
}

__global__ void k_gram_fin(const float* __restrict__ gpart, float* __restrict__ attn) {
    int b = blockIdx.x, h = blockIdx.y;
    __shared__ float G[840];
    int tid = threadIdx.x;   // 256
    const float* gp = gpart + ((size_t)(b*8 + h))*8*840;
    #pragma unroll
    for (int s = 0; s < 4; s++) {
        int w = tid + 256*s;
        if (w < 840) {
            float a = 0.f;
            #pragma unroll
            for (int z = 0; z < 8; z++) a += gp[z*840 + w];
            G[w] = a;
        }
    }
    __syncthreads();
    if (tid < 28) {
        int i = tid;
        float nk = fmaxf(sqrtf(G[784+i]), 1e-12f);
        float lg[28], m = -1e30f;
        #pragma unroll
        for (int j = 0; j < 28; j++) {
            float nq = fmaxf(sqrtf(G[812+j]), 1e-12f);
            lg[j] = G[i*28+j] / (nk*nq) * 0.18898223650461363f;
            m = fmaxf(m, lg[j]);
        }
        float sum = 0.f;
        #pragma unroll
        for (int j = 0; j < 28; j++) { lg[j] = __expf(lg[j]-m); sum += lg[j]; }
        float inv = 1.f/sum;
        #pragma unroll
        for (int j = 0; j < 28; j++)
            attn[(((size_t)b*8 + h)*28 + i)*28 + j] = lg[j]*inv;
    }
}

// x1 = attn-applied + residual; 32 rows per block
__global__ void k_apply(const float* __restrict__ x, const float* __restrict__ qc,
                        const float* __restrict__ attn, float* __restrict__ x1) {
    int chunk = blockIdx.x, b = blockIdx.y;
    __shared__ float vr[8][224];
    int tid = threadIdx.x;   // 224
    int h = tid / 28, i = tid % 28;
    float att[28];
    {
        const float4* ap = (const float4*)(attn + (((size_t)b*8 + h)*28 + i)*28);
        #pragma unroll
        for (int q4 = 0; q4 < 7; q4++) {
            float4 v = ap[q4];
            att[q4*4+0]=v.x; att[q4*4+1]=v.y; att[q4*4+2]=v.z; att[q4*4+3]=v.w;
        }
    }
    for (int nn = 0; nn < 32; nn += 8) {
        size_t row0 = (size_t)b*1280 + chunk*32 + nn;
        __syncthreads();
        for (int idx = tid; idx < 1792; idx += 224) {
            int rr = idx / 224, cc = idx % 224;
            vr[rr][cc] = qc[(row0 + rr)*672 + 448 + cc];
        }
        __syncthreads();
        #pragma unroll
        for (int rr = 0; rr < 8; rr++) {
            float a = 0.f;
            #pragma unroll
            for (int j = 0; j < 28; j++) a += att[j] * vr[rr][h*28 + j];
            size_t o = (row0 + rr)*224 + tid;
            x1[o] = x[o] + a;
        }
    }
}

// ---------------- transpose + LN; coalesced fp32 + bf16 hi/lo output ---------
__global__ void k_ln1(const float* __restrict__ x1, const float* __restrict__ g,
                      const float* __restrict__ be, float* __restrict__ xn,
                      __nv_bfloat16* __restrict__ xnh, __nv_bfloat16* __restrict__ xnl) {
    int ww = blockIdx.x, b = blockIdx.y;
    __shared__ float s[32*225];
    __shared__ float sg[32], sb[32];
    int tid = threadIdx.x;   // 256
    if (tid < 32) { sg[tid] = g[tid]; sb[tid] = be[tid]; }
    for (int idx = tid; idx < 32*224; idx += 256) {
        int m = idx / 224, cc = idx % 224;
        s[m*225 + cc] = x1[((size_t)b*1280 + m*40 + ww)*224 + cc];
    }
    __syncthreads();
    float v[32];
    if (tid < 224) {
        float mean = 0.f;
        #pragma unroll
        for (int m = 0; m < 32; m++) { v[m] = s[m*225 + tid]; mean += v[m]; }
        mean *= (1.f/32.f);
        float var = 0.f;
        #pragma unroll
        for (int m = 0; m < 32; m++) { float d = v[m]-mean; var += d*d; }
        var *= (1.f/32.f);
        float inv = rsqrtf(var + 1e-5f);
        #pragma unroll
        for (int m = 0; m < 32; m++) v[m] = (v[m]-mean)*inv*sg[m] + sb[m];
    }
    __syncthreads();
    if (tid < 224) {
        #pragma unroll
        for (int m = 0; m < 32; m++) s[tid*32 + m] = v[m];
    }
    __syncthreads();
    size_t base = ((size_t)b*8960 + ww*224)*32;
    for (int idx = tid; idx < 7168; idx += 256) {
        float val = s[idx];
        xn[base + idx] = val;
        __nv_bfloat16 h, l; bfsplit(val, h, l);
        xnh[base + idx] = h; xnl[base + idx] = l;
    }
}

// ---------------- conv1d: smem-tiled, 128 rows x 64 d per block --------------
__global__ __launch_bounds__(256) void k_conv1d(
    const float* __restrict__ xz, const float* __restrict__ cw,
    const float* __restrict__ cb, float* __restrict__ xc) {
    __shared__ float sx[131][64];
    int bx = blockIdx.x;            // 2240 = 32 b * 70 chunks
    int b = bx / 70, chunk = bx % 70;
    int l0 = chunk * 128;
    int tid = threadIdx.x;
    for (int idx = tid; idx < 131*16; idx += 256) {
        int r = idx >> 4, c4 = (idx & 15) * 4;
        int l = l0 - 3 + r;
        float4 v = make_float4(0.f, 0.f, 0.f, 0.f);
        if (l >= 0) v = *(const float4*)(xz + ((size_t)b*8960 + l)*128 + c4);
        *(float4*)&sx[r][c4] = v;
    }
    __syncthreads();
    int r0 = (tid >> 4) * 8, d4 = (tid & 15) * 4;
    float w[4][4];
    #pragma unroll
    for (int dd = 0; dd < 4; dd++)
        #pragma unroll
        for (int t = 0; t < 4; t++) w[dd][t] = cw[(d4+dd)*4 + t];
    float b0 = cb[d4], b1 = cb[d4+1], b2 = cb[d4+2], b3 = cb[d4+3];
    #pragma unroll
    for (int s = 0; s < 8; s++) {
        int rr = r0 + s;
        float a0 = b0, a1 = b1, a2 = b2, a3 = b3;
        #pragma unroll
        for (int t = 0; t < 4; t++) {
            float4 v = *(const float4*)&sx[rr + t][d4];
            a0 += v.x * w[0][t];
            a1 += v.y * w[1][t];
            a2 += v.z * w[2][t];
            a3 += v.w * w[3][t];
        }
        float4 o; o.x = siluf(a0); o.y = siluf(a1); o.z = siluf(a2); o.w = siluf(a3);
        *(float4*)(xc + ((size_t)b*8960 + l0 + rr)*64 + d4) = o;
    }
}

// staged scan pass 1: 32-row stages (8 barriers instead of 16)
__global__ __launch_bounds__(256) void k_scan1(
    const float* __restrict__ dt, const float* __restrict__ xc,
    const float* __restrict__ Bm, const float* __restrict__ Alog,
    float* __restrict__ S, float* __restrict__ sumdt) {
    int bx = blockIdx.x;                 // 8960
    int b = bx / 280, rem = bx % 280;
    int chunk = rem >> 2, dg = rem & 3;
    int tid = threadIdx.x, warp = tid >> 5, lane = tid & 31;
    int dloc = 2*warp + (lane >> 4), n = lane & 15;
    int d = dg*16 + dloc;
    __shared__ float sdt[32][16], sxc[32][16], sbm[32][16];
    float Av = -__expf(Alog[d*16 + n]);
    float h = 0.f, sdsum = 0.f;
    size_t rowbase = (size_t)b*8960 + chunk*128;
    int lr = tid >> 4, lc = tid & 15;
    for (int s = 0; s < 4; s++) {
        size_t r0 = rowbase + s*32;
        __syncthreads();
        sdt[lr][lc]      = dt[(r0 + lr)*64 + dg*16 + lc];
        sdt[lr+16][lc]   = dt[(r0 + lr + 16)*64 + dg*16 + lc];
        sxc[lr][lc]      = xc[(r0 + lr)*64 + dg*16 + lc];
        sxc[lr+16][lc]   = xc[(r0 + lr + 16)*64 + dg*16 + lc];
        sbm[lr][lc]      = Bm[(r0 + lr)*16 + lc];
        sbm[lr+16][lc]   = Bm[(r0 + lr + 16)*16 + lc];
        __syncthreads();
        #pragma unroll
        for (int l = 0; l < 32; l++) {
            float dtv = sdt[l][dloc];
            float u   = sxc[l][dloc];
            float Bn  = sbm[l][n];
            h = __expf(Av*dtv)*h + dtv*u*Bn;
            sdsum += dtv;
        }
    }
    size_t idx = (size_t)(b*64 + d)*70 + chunk;
    S[idx*16 + n] = h;
    if (n == 0) sumdt[idx] = sdsum;
}

__global__ void k_scan2(const float* __restrict__ S, const float* __restrict__ sumdt,
                        const float* __restrict__ Alog, float* __restrict__ H0) {
    int t = blockIdx.x*256 + threadIdx.x;
    int b = t >> 10; int d = (t >> 4) & 63; int n = t & 15;
    float Av = -__expf(Alog[d*16 + n]);
    float carry = 0.f;
    size_t base = (size_t)(b*64 + d)*70;
    for (int ch = 0; ch < 70; ch++) {
        size_t idx = base + ch;
        H0[idx*16 + n] = carry;
        carry = carry*__expf(Av*sumdt[idx]) + S[idx*16 + n];
    }
}

// staged scan pass 3: 32-row stages
__global__ __launch_bounds__(256) void k_scan3(
    const float* __restrict__ dt, const float* __restrict__ xc,
    const float* __restrict__ Bm, const float* __restrict__ Cm,
    const float* __restrict__ Alog, const float* __restrict__ H0,
    float* __restrict__ y) {
    int bx = blockIdx.x;
    int b = bx / 280, rem = bx % 280;
    int chunk = rem >> 2, dg = rem & 3;
    int tid = threadIdx.x, warp = tid >> 5, lane = tid & 31;
    int dloc = 2*warp + (lane >> 4), n = lane & 15;
    int d = dg*16 + dloc;
    __shared__ float sdt[32][16], sxc[32][16], sbm[32][16], scm[32][16], sy[32][16];
    float Av = -__expf(Alog[d*16 + n]);
    size_t idx = (size_t)(b*64 + d)*70 + chunk;
    float h = H0[idx*16 + n];
    size_t rowbase = (size_t)b*8960 + chunk*128;
    int lr = tid >> 4, lc = tid & 15;
    for (int s = 0; s < 4; s++) {
        size_t r0 = rowbase + s*32;
        __syncthreads();
        sdt[lr][lc]      = dt[(r0 + lr)*64 + dg*16 + lc];
        sdt[lr+16][lc]   = dt[(r0 + lr + 16)*64 + dg*16 + lc];
        sxc[lr][lc]      = xc[(r0 + lr)*64 + dg*16 + lc];
        sxc[lr+16][lc]   = xc[(r0 + lr + 16)*64 + dg*16 + lc];
        sbm[lr][lc]      = Bm[(r0 + lr)*16 + lc];
        sbm[lr+16][lc]   = Bm[(r0 + lr + 16)*16 + lc];
        scm[lr][lc]      = Cm[(r0 + lr)*16 + lc];
        scm[lr+16][lc]   = Cm[(r0 + lr + 16)*16 + lc];
        __syncthreads();
        #pragma unroll
        for (int l = 0; l < 32; l++) {
            float dtv = sdt[l][dloc];
            float u   = sxc[l][dloc];
            float Bn  = sbm[l][n];
            h = __expf(Av*dtv)*h + dtv*u*Bn;
            float yv = h * scm[l][n];
            yv += __shfl_xor_sync(0xffffffffu, yv, 8);
            yv += __shfl_xor_sync(0xffffffffu, yv, 4);
            yv += __shfl_xor_sync(0xffffffffu, yv, 2);
            yv += __shfl_xor_sync(0xffffffffu, yv, 1);
            if (n == 0) sy[l][dloc] = yv;
        }
        __syncthreads();
        y[(r0 + lr)*64 + dg*16 + lc]      = sy[lr][lc];
        y[(r0 + lr + 16)*64 + dg*16 + lc] = sy[lr+16][lc];
    }
}

__global__ void k_final(const float* __restrict__ y, const float* __restrict__ xc,
                        const float* __restrict__ xz, const float* __restrict__ xn,
                        const float* __restrict__ Dp, const float* __restrict__ opW,
                        const float* __restrict__ skipp, const float* __restrict__ g,
                        const float* __restrict__ be, const float* __restrict__ projW,
                        const float* __restrict__ projb, float* __restrict__ xm2) {
    __shared__ float sop[2048], spj[1024];
    int tid = threadIdx.x;   // 256
    for (int i = tid; i < 2048; i += 256) sop[i] = opW[i];
    for (int i = tid; i < 1024; i += 256) spj[i] = projW[i];
    __syncthreads();
    int warp = tid >> 5, lane = tid & 31;
    float skip = skipp[0];
    float dpl = Dp[lane], dph = Dp[32+lane];
    float gl = g[lane], bel = be[lane], pbl = projb[lane];
    #pragma unroll
    for (int t = 0; t < 8; t++) {
        size_t r = ((size_t)blockIdx.x*8 + warp)*8 + t;
        float y0 = y[r*64 + lane],      y1 = y[r*64 + 32 + lane];
        float c0 = xc[r*64 + lane],     c1 = xc[r*64 + 32 + lane];
        float z0 = xz[r*128 + 64 + lane], z1 = xz[r*128 + 96 + lane];
        float yy0 = (y0 + c0*dpl) * siluf(z0);
        float yy1 = (y1 + c1*dph) * siluf(z1);
        float acc = 0.f;
        #pragma unroll
        for (int d = 0; d < 32; d++) acc += __shfl_sync(0xffffffffu, yy0, d) * sop[d*32 + lane];
        #pragma unroll
        for (int d = 0; d < 32; d++) acc += __shfl_sync(0xffffffffu, yy1, d) * sop[(d+32)*32 + lane];
        float xm = acc + skip * xn[r*32 + lane];
        float mean = xm;
        #pragma unroll
        for (int o = 16; o; o >>= 1) mean += __shfl_xor_sync(0xffffffffu, mean, o);
        mean *= (1.f/32.f);
        float dv = xm - mean, var = dv*dv;
        #pragma unroll
        for (int o = 16; o; o >>= 1) var += __shfl_xor_sync(0xffffffffu, var, o);
        var *= (1.f/32.f);
        float v = dv * rsqrtf(var + 1e-5f) * gl + bel;
        float acc2 = pbl;
        #pragma unroll
        for (int mm = 0; mm < 32; mm++) acc2 += __shfl_sync(0xffffffffu, v, mm) * spj[mm*32 + lane];
        xm2[r*32 + lane] = acc2;
    }
}

__global__ void k_addback(const float* __restrict__ x1, const float* __restrict__ xm2,
                          float* __restrict__ x2) {
    int ww = blockIdx.x, b = blockIdx.y;
    __shared__ float s[224*33];
    int tid = threadIdx.x;   // 256
    for (int idx = tid; idx < 224*32; idx += 256) {
        int cc = idx >> 5, m = idx & 31;
        s[cc*33 + m] = xm2[((size_t)b*8960 + ww*224 + cc)*32 + m];
    }
    __syncthreads();
    for (int idx = tid; idx < 32*224; idx += 256) {
        int m = idx / 224, cc = idx % 224;
        size_t o = ((size_t)b*1280 + m*40 + ww)*224 + cc;
        x2[o] = x1[o] + s[cc*33 + m];
    }
}

// ---------------- conv3d 5x5x5, pad 2, smem-tiled per ky-plane ----------------
__global__ void k_conv3d(const float* __restrict__ x2, const float* __restrict__ cw,
                         const float* __restrict__ cb, float* __restrict__ x3) {
    int y = blockIdx.x, b = blockIdx.y;
    int xx = threadIdx.x;   // 224
    __shared__ float ws[125];
    __shared__ float sp[32][228];
    if (xx < 125) ws[xx] = cw[xx];
    if (xx < 32) { sp[xx][0]=0.f; sp[xx][1]=0.f; sp[xx][226]=0.f; sp[xx][227]=0.f; }
    float acc[32];
    #pragma unroll
    for (int d = 0; d < 32; d++) acc[d] = 0.f;
    for (int ky = 0; ky < 5; ky++) {
        int yy = y + ky - 2;
        if (yy < 0 || yy >= 40) continue;
        __syncthreads();
        for (int i = 0; i < 32; i++)
            sp[i][xx+2] = x2[(((size_t)b*32 + i)*40 + yy)*224 + xx];
        __syncthreads();
        #pragma unroll
        for (int kx = 0; kx < 5; kx++) {
            float v[36];
            v[0]=v[1]=v[34]=v[35]=0.f;
            #pragma unroll
            for (int i = 0; i < 32; i++) v[i+2] = sp[i][xx + kx];
            #pragma unroll
            for (int kz = 0; kz < 5; kz++) {
                float wv = ws[(kz*5 + ky)*5 + kx];
                #pragma unroll
                for (int d = 0; d < 32; d++) acc[d] += v[d+kz]*wv;
            }
        }
    }
    float bias = cb[0];
    #pragma unroll
    for (int d = 0; d < 32; d++)
        x3[(((size_t)b*32 + d)*40 + y)*224 + xx] = acc[d] + bias;
}

// ---------------- DWT: 4 subbands per thread, emits bf16 hi/lo ----------------
__global__ void k_dwt(const float* __restrict__ x3,
                      __nv_bfloat16* __restrict__ xwh, __nv_bfloat16* __restrict__ xwl) {
    size_t id = (size_t)blockIdx.x*256 + threadIdx.x;   // 2752512
    int c = (int)(id % 224); size_t rw = id / 224;
    int win = (int)(rw >> 6), tok = (int)(rw & 63);
    int bb = win / 6, w6 = win % 6;
    int wi = w6 / 3, wj = w6 % 3;
    int ti = tok >> 3, tj = tok & 7;
    int i2 = wi*8 + ti;
    int j2 = wj*8 + tj;
    int j = (j2 < 20) ? j2 : 38 - j2;   // reflect pad
    size_t base = (((size_t)bb*32 + 2*i2)*40 + 2*j)*224 + c;
    float a  = x3[base],        bv = x3[base + 224];
    float c2 = x3[base + 8960], d2 = x3[base + 9184];
    const size_t SS = (size_t)12288*224;
    float v0 = 0.5f*(a + bv + c2 + d2);
    float v1 = 0.5f*(a + bv - c2 - d2);
    float v2 = 0.5f*(a - bv + c2 - d2);
    float v3 = 0.5f*(a - bv - c2 + d2);
    __nv_bfloat16 h, l;
    bfsplit(v0, h, l); xwh[id]        = h; xwl[id]        = l;
    bfsplit(v1, h, l); xwh[id + SS]   = h; xwl[id + SS]   = l;
    bfsplit(v2, h, l); xwh[id + 2*SS] = h; xwl[id + 2*SS] = l;
    bfsplit(v3, h, l); xwh[id + 3*SS] = h; xwl[id + 3*SS] = l;
}

// ---------------- window attention: 2 heads per block, online softmax --------
__global__ __launch_bounds__(128) void k_wattn(
    const float* __restrict__ qkvw, const float* __restrict__ pe,
    __nv_bfloat16* __restrict__ obh, __nv_bfloat16* __restrict__ obl) {
    int win = blockIdx.x;
    int tid = threadIdx.x;            // 128
    int hd = tid >> 6, wtid = tid & 63;
    int head = blockIdx.y*2 + hd;
    __shared__ __align__(16) float ks[2][64*28], vs[2][64*28];
    __shared__ __nv_bfloat16 oh[2][64*28], ol[2][64*28];
    size_t wbase = (size_t)win * 64;
    for (int idx = wtid; idx < 1792; idx += 64) {
        int tok = idx / 28, dd = idx % 28;
        size_t rb = (wbase + tok)*672 + head*28 + dd;
        ks[hd][idx] = qkvw[rb + 224];
        vs[hd][idx] = qkvw[rb + 448];
    }
    float qr[28];
    {
        const float4* qp = (const float4*)(qkvw + (wbase + wtid)*672 + head*28);
        #pragma unroll
        for (int q4 = 0; q4 < 7; q4++) {
            float4 v = qp[q4];
            qr[q4*4+0] = v.x * 0.18898223650461363f;
            qr[q4*4+1] = v.y * 0.18898223650461363f;
            qr[q4*4+2] = v.z * 0.18898223650461363f;
            qr[q4*4+3] = v.w * 0.18898223650461363f;
        }
    }
    __syncthreads();
    const float* per = pe + ((size_t)head*64 + wtid)*64;
    float m = -1e30f, sum = 0.f;
    float acc[28];
    #pragma unroll
    for (int dd = 0; dd < 28; dd++) acc[dd] = 0.f;
    for (int j = 0; j < 64; j++) {
        const float4* k4 = (const float4*)&ks[hd][j*28];
        float dot = 0.f;
        #pragma unroll
        for (int q4 = 0; q4 < 7; q4++) {
            float4 kk = k4[q4];
            dot += qr[q4*4+0]*kk.x + qr[q4*4+1]*kk.y
                 + qr[q4*4+2]*kk.z + qr[q4*4+3]*kk.w;
        }
        dot += per[j];
        if (dot > m) {
            float corr = __expf(m - dot);
            sum *= corr;
            #pragma unroll
            for (int dd = 0; dd < 28; dd++) acc[dd] *= corr;
            m = dot;
        }
        float e = __expf(dot - m);
        sum += e;
        const float4* v4 = (const float4*)&vs[hd][j*28];
        #pragma unroll
        for (int q4 = 0; q4 < 7; q4++) {
            float4 vv = v4[q4];
            acc[q4*4+0] += e*vv.x; acc[q4*4+1] += e*vv.y;
            acc[q4*4+2] += e*vv.z; acc[q4*4+3] += e*vv.w;
        }
    }
    float inv = 1.f / sum;
    #pragma unroll
    for (int dd = 0; dd < 28; dd++) {
        __nv_bfloat16 h, l;
        bfsplit(acc[dd] * inv, h, l);
        oh[hd][wtid*28 + dd] = h; ol[hd][wtid*28 + dd] = l;
    }
    __syncthreads();
    for (int idx = wtid; idx < 1792; idx += 64) {
        int tok = idx / 28, dd = idx % 28;
        size_t o = (wbase + tok)*224 + head*28 + dd;
        obh[o] = oh[hd][idx]; obl[o] = ol[hd][idx];
    }
}

// ---------------- IWT + biases + crop + final layout ----------------
__global__ void k_iwt(const float* __restrict__ oproj,
                      const float* __restrict__ b1, const float* __restrict__ b2,
                      const float* __restrict__ b3, const float* __restrict__ b4,
                      float* __restrict__ out) {
    size_t id = (size_t)blockIdx.x*256 + threadIdx.x;   // 2293760
    int c = (int)(id % 224); size_t r = id / 224;
    int j = (int)(r % 20); r /= 20;
    int i = (int)(r % 16); int bb = (int)(r / 16);
    int wi = i >> 3, ti = i & 7, wj = j >> 3, tj = j & 7;
    size_t row0 = ((size_t)(bb*6 + wi*3 + wj))*64 + ti*8 + tj;
    float A  = oproj[row0*224 + c]           + b1[c];
    float Hh = oproj[(row0 + 12288)*224 + c] + b2[c];
    float V  = oproj[(row0 + 24576)*224 + c] + b3[c];
    float D  = oproj[(row0 + 36864)*224 + c] + b4[c];
    size_t oo = (((size_t)bb*32 + 2*i)*40 + 2*j)*224 + c;
    out[oo]          = 0.5f*(A + Hh + V + D);
    out[oo + 224]    = 0.5f*(A + Hh - V - D);
    out[oo + 8960]   = 0.5f*(A - Hh + V - D);
    out[oo + 9184]   = 0.5f*(A - Hh - V + D);
}

// ---------------- launcher ----------------
extern "C" void kernel_launch(void* const* d_in, const int* in_sizes, int n_in,
                              void* d_out, int out_size) {
    const float* x       = (const float*)d_in[0];
    const float* Wq      = (const float*)d_in[1];
    const float* Wkv     = (const float*)d_in[2];
    const float* ln_g    = (const float*)d_in[3];
    const float* ln_b    = (const float*)d_in[4];
    const float* in_proj = (const float*)d_in[5];
    const float* conv1dW = (const float*)d_in[6];
    const float* conv1db = (const float*)d_in[7];
    const float* x_projW = (const float*)d_in[8];
    const float* dt_projW= (const float*)d_in[9];
    const float* dt_projb= (const float*)d_in[10];
    const float* A_log   = (const float*)d_in[11];
    const float* Dp      = (const float*)d_in[12];
    const float* out_projW=(const float*)d_in[13];
    const float* skip    = (const float*)d_in[14];
    const float* projW   = (const float*)d_in[15];
    const float* projb   = (const float*)d_in[16];
    const float* conv3dW = (const float*)d_in[17];
    const float* conv3db = (const float*)d_in[18];
    const float* Wq1     = (const float*)d_in[19];
    const float* Wkv1    = (const float*)d_in[20];
    const float* pos_emb = (const float*)d_in[21];
    const float* Wo[4]   = {(const float*)d_in[22],(const float*)d_in[24],
                            (const float*)d_in[26],(const float*)d_in[28]};
    const float* bo[4]   = {(const float*)d_in[23],(const float*)d_in[25],
                            (const float*)d_in[27],(const float*)d_in[29]};
    float* out = (float*)d_out;

    float *p_attn, *p_gp, *p_x1, *p_xn, *p_xz, *p_xc, *p_dt,
          *p_Bm, *p_Cm, *p_y, *p_S, *p_sd, *p_H0, *p_xm2, *p_x2, *p_x3,
          *p_qkvw, *p_oproj;
    cudaGetSymbolAddress((void**)&p_attn, g_attn);
    cudaGetSymbolAddress((void**)&p_gp,   g_gpart);
    cudaGetSymbolAddress((void**)&p_x1,   g_x1);
    cudaGetSymbolAddress((void**)&p_xn,   g_xn);
    cudaGetSymbolAddress((void**)&p_xz,   g_xz);
    cudaGetSymbolAddress((void**)&p_xc,   g_xc);
    cudaGetSymbolAddress((void**)&p_dt,   g_dt);
    cudaGetSymbolAddress((void**)&p_Bm,   g_Bm);
    cudaGetSymbolAddress((void**)&p_Cm,   g_Cm);
    cudaGetSymbolAddress((void**)&p_y,    g_y);
    cudaGetSymbolAddress((void**)&p_S,    g_S);
    cudaGetSymbolAddress((void**)&p_sd,   g_sumdt);
    cudaGetSymbolAddress((void**)&p_H0,   g_H0);
    cudaGetSymbolAddress((void**)&p_xm2,  g_xm2);
    cudaGetSymbolAddress((void**)&p_x2,   g_x2);
    cudaGetSymbolAddress((void**)&p_x3,   g_x3);
    cudaGetSymbolAddress((void**)&p_qkvw, g_qkvw);
    cudaGetSymbolAddress((void**)&p_oproj,g_oproj);

    __nv_bfloat16 *p_xh,*p_xl,*p_xnh,*p_xnl,*p_xwh,*p_xwl,*p_obh,*p_obl,
        *p_Wc1h,*p_Wc1l,*p_Wc2h,*p_Wc2l,*p_iph,*p_ipl,*p_Woh,*p_Wol;
    cudaGetSymbolAddress((void**)&p_xh,   g_xh);
    cudaGetSymbolAddress((void**)&p_xl,   g_xlo);
    cudaGetSymbolAddress((void**)&p_xnh,  g_xnh);
    cudaGetSymbolAddress((void**)&p_xnl,  g_xnl);
    cudaGetSymbolAddress((void**)&p_xwh,  g_xwh);
    cudaGetSymbolAddress((void**)&p_xwl,  g_xwl);
    cudaGetSymbolAddress((void**)&p_obh,  g_obh);
    cudaGetSymbolAddress((void**)&p_obl,  g_obl);
    cudaGetSymbolAddress((void**)&p_Wc1h, g_Wc1h);
    cudaGetSymbolAddress((void**)&p_Wc1l, g_Wc1l);
    cudaGetSymbolAddress((void**)&p_Wc2h, g_Wc2h);
    cudaGetSymbolAddress((void**)&p_Wc2l, g_Wc2l);
    cudaGetSymbolAddress((void**)&p_iph,  g_iph);
    cudaGetSymbolAddress((void**)&p_ipl,  g_ipl);
    cudaGetSymbolAddress((void**)&p_Woh,  g_Woh);
    cudaGetSymbolAddress((void**)&p_Wol,  g_Wol);

    // ---- splits: input (big) + all weights (one batched launch) ----
    k_split<<<(9175040+255)/256, 256>>>(x, p_xh, p_xl, 9175040);
    SplitArgs sa;
    sa.s[0] = {Wq,      p_Wc1h, p_Wc1l, 50176,  224, 672, 0};
    sa.s[1] = {Wkv,     p_Wc1h, p_Wc1l, 100352, 448, 672, 224};
    sa.s[2] = {in_proj, p_iph,  p_ipl,  4096,   0, 0, 0};
    sa.s[3] = {Wq1,     p_Wc2h, p_Wc2l, 50176,  224, 672, 0};
    sa.s[4] = {Wkv1,    p_Wc2h, p_Wc2l, 100352, 448, 672, 224};
    sa.s[5] = {Wo[0], p_Woh,          p_Wol,          50176, 0, 0, 0};
    sa.s[6] = {Wo[1], p_Woh + 50176,  p_Wol + 50176,  50176, 0, 0, 0};
    sa.s[7] = {Wo[2], p_Woh + 100352, p_Wol + 100352, 50176, 0, 0, 0};
    sa.s[8] = {Wo[3], p_Woh + 150528, p_Wol + 150528, 50176, 0, 0, 0};
    sa.s[9] = {Wq, p_Wc1h, p_Wc1l, 0, 0, 0, 0};   // unused
    k_split_multi<<<dim3(392, 10), 256>>>(sa);

    // stage 1: combined qkv GEMM (N=672), token-split gram, apply
    tgemm_bf<<<dim3(6, 320), 256>>>(p_xh, p_xl, p_Wc1h, p_Wc1l, p_qkvw,
                                    672, 224, 224, 672, 672);
    k_gram_part<<<dim3(32, 8, 8), 256>>>(p_qkvw, p_gp);
    k_gram_fin <<<dim3(32, 8), 256>>>(p_gp, p_attn);
    k_apply<<<dim3(40, 32), 224>>>(x, p_qkvw, p_attn, p_x1);

    // stage 2: mamba
    k_ln1<<<dim3(40, 32), 256>>>(p_x1, ln_g, ln_b, p_xn, p_xnh, p_xnl);
    tgemm_bf<<<dim3(1, 2240), 256>>>(p_xnh, p_xnl, p_iph, p_ipl, p_xz, 128, 32, 32, 128, 128);
    k_conv1d<<<2240, 256>>>(p_xz, conv1dW, conv1db, p_xc);
    sgemm_xproj<<<dim3(1, 2240), 256>>>(p_xc, x_projW, dt_projW, dt_projb,
                                        p_dt, p_Bm, p_Cm);
    k_scan1<<<8960, 256>>>(p_dt, p_xc, p_Bm, A_log, p_S, p_sd);
    k_scan2<<<128, 256>>>(p_S, p_sd, A_log, p_H0);
    k_scan3<<<8960, 256>>>(p_dt, p_xc, p_Bm, p_Cm, A_log, p_H0, p_y);
    k_final<<<4480, 256>>>(p_y, p_xc, p_xz, p_xn, Dp, out_projW, skip,
                           ln_g, ln_b, projW, projb, p_xm2);
    k_addback<<<dim3(40, 32), 256>>>(p_x1, p_xm2, p_x2);

    // stage 3: conv3d
    k_conv3d<<<dim3(40, 32), 224>>>(p_x2, conv3dW, conv3db, p_x3);

    // stage 4: DWT + combined window-qkv GEMM + window attention
    k_dwt<<<10752, 256>>>(p_x3, p_xwh, p_xwl);
    tgemm_bf<<<dim3(6, 384), 256>>>(p_xwh, p_xwl, p_Wc2h, p_Wc2l, p_qkvw,
                                    672, 224, 224, 672, 672);
    k_wattn<<<dim3(768, 4), 128>>>(p_qkvw, pos_emb, p_obh, p_obl);
    BfPtrs4 po;
    for (int s = 0; s < 4; s++) { po.Bh[s] = p_Woh + s*50176; po.Bl[s] = p_Wol + s*50176; }
    tgemm_bf_b4<<<dim3(2, 96, 4), 256>>>(p_obh, p_obl, po, p_oproj,
                                         224, 224, 224, 224, 224,
                                         (long long)12288*224, (long long)12288*224);

    // stage 5: IWT + biases + output
    k_iwt<<<8960, 256>>>(p_oproj, bo[0], bo[1], bo[2], bo[3], out);
}